// round 5
// baseline (speedup 1.0000x reference)
#include <cuda_runtime.h>

#define DINL __device__ __forceinline__

constexpr int N_NODES = 50000;
constexpr int N_EDGES = 1600000;
constexpr int NL = 5;
constexpr int NG = 4;
constexpr float EPS = 1e-5f;

__device__ float g_h  [N_NODES * 64];
__device__ float g_hd [N_NODES * 64];
__device__ float g_hs [N_NODES * 64];
__device__ float g_agg[N_NODES * 64];
__device__ float g_pool[NG * 64];
__device__ int   g_rp [N_NODES + 1];
__device__ int   g_wp [N_NODES];
__device__ int2  g_sorted[N_EDGES + 32];   // (src, orig edge id), padded

typedef unsigned long long u64;

DINL u64 pk2(float x, float y) { u64 r; asm("mov.b64 %0,{%1,%2};" : "=l"(r) : "f"(x), "f"(y)); return r; }
DINL u64 dup2(float x) { return pk2(x, x); }
DINL float2 upk(u64 v) { float2 r; asm("mov.b64 {%0,%1},%2;" : "=f"(r.x), "=f"(r.y) : "l"(v)); return r; }
DINL u64 ffma2(u64 a, u64 b, u64 c) {
    u64 d; asm("fma.rn.f32x2 %0,%1,%2,%3;" : "=l"(d) : "l"(a), "l"(b), "l"(c)); return d;
}
DINL u64 add2(u64 a, u64 b) {
    u64 d; asm("add.rn.f32x2 %0,%1,%2;" : "=l"(d) : "l"(a), "l"(b)); return d;
}
DINL void red2(float* p, float x, float y) {
    asm volatile("red.global.add.v2.f32 [%0], {%1,%2};" :: "l"(p), "f"(x), "f"(y) : "memory");
}
DINL float silu(float x) { return __fdividef(x, 1.f + __expf(-x)); }

// ============================ CSR build ============================
__global__ void k_zero_wp() {
    int i = blockIdx.x * 256 + threadIdx.x;
    if (i < N_NODES) g_wp[i] = 0;
}
__global__ void k_hist(const int* __restrict__ ei) {
    int e = blockIdx.x * 256 + threadIdx.x;
    if (e < N_EDGES) atomicAdd(&g_wp[ei[N_EDGES + e]], 1);
}
__global__ void k_scan() {   // 1 block, 1024 threads
    __shared__ int part[1024];
    int t = threadIdx.x;
    const int C = 49;   // 1024*49 = 50176 >= N_NODES
    int base = t * C;
    int sum = 0;
    for (int i = 0; i < C; i++) { int idx = base + i; if (idx < N_NODES) sum += g_wp[idx]; }
    part[t] = sum;
    __syncthreads();
    for (int off = 1; off < 1024; off <<= 1) {
        int v = (t >= off) ? part[t - off] : 0;
        __syncthreads();
        part[t] += v;
        __syncthreads();
    }
    int run = (t == 0) ? 0 : part[t - 1];
    for (int i = 0; i < C; i++) {
        int idx = base + i;
        if (idx < N_NODES) { int v = g_wp[idx]; g_rp[idx] = run; g_wp[idx] = run; run += v; }
    }
    if (t == 1023) g_rp[N_NODES] = N_EDGES;
}
__global__ void k_scatter(const int* __restrict__ ei) {
    int e = blockIdx.x * 256 + threadIdx.x;
    if (e < N_EDGES) {
        int d = ei[N_EDGES + e];
        int pos = atomicAdd(&g_wp[d], 1);
        g_sorted[pos] = make_int2(ei[e], e);
    }
}

// ============================ encoder ============================
__global__ void __launch_bounds__(256) k_encoder(
    const float* __restrict__ x, const int* __restrict__ batch,
    const float* __restrict__ casep, const float* __restrict__ bcp,
    const float* __restrict__ W1, const float* __restrict__ b1,
    const float* __restrict__ W2, const float* __restrict__ b2,
    const float* __restrict__ gam, const float* __restrict__ bet)
{
    __shared__ float sW1[16 * 64], sW2[64 * 64], sb1[64], sb2[64], sg[64], sbe[64];
    __shared__ float sH[8][64];
    int tid = threadIdx.x;
    for (int i = tid; i < 16 * 64; i += 256) sW1[i] = W1[i];
    for (int i = tid; i < 64 * 64; i += 256) sW2[i] = W2[i];
    if (tid < 64) { sb1[tid] = b1[tid]; sb2[tid] = b2[tid]; sg[tid] = gam[tid]; sbe[tid] = bet[tid]; }
    __syncthreads();
    int w = tid >> 5, ld = tid & 31, c0 = 2 * ld;
    int n = blockIdx.x * 8 + w;
    if (n >= N_NODES) return;
    float in[16];
#pragma unroll
    for (int k = 0; k < 8; k++) in[k] = __ldg(&x[n * 8 + k]);
    int g = __ldg(&batch[n]);
#pragma unroll
    for (int k = 0; k < 4; k++) { in[8 + k] = __ldg(&casep[g * 4 + k]); in[12 + k] = __ldg(&bcp[g * 4 + k]); }
    const u64* W1u = (const u64*)sW1;
    u64 acc = ((const u64*)sb1)[ld];
#pragma unroll
    for (int k = 0; k < 16; k++) acc = ffma2(dup2(in[k]), W1u[k * 32 + ld], acc);
    float2 a = upk(acc);
    a.x = silu(a.x); a.y = silu(a.y);
    sH[w][c0] = a.x; sH[w][c0 + 1] = a.y;
    __syncwarp();
    const u64* W2u = (const u64*)sW2;
    u64 acc2 = ((const u64*)sb2)[ld];
#pragma unroll 8
    for (int k = 0; k < 64; k++) acc2 = ffma2(dup2(sH[w][k]), W2u[k * 32 + ld], acc2);
    float2 v = upk(acc2);
    float s = v.x + v.y, q = v.x * v.x + v.y * v.y;
#pragma unroll
    for (int o = 16; o; o >>= 1) { s += __shfl_xor_sync(~0u, s, o); q += __shfl_xor_sync(~0u, q, o); }
    float m = s * (1.f / 64.f), var = q * (1.f / 64.f) - m * m, rs = rsqrtf(var + EPS);
    float2 out;
    out.x = (v.x - m) * rs * sg[c0] + sbe[c0];
    out.y = (v.y - m) * rs * sg[c0 + 1] + sbe[c0 + 1];
    *(float2*)(g_h + (size_t)n * 64 + c0) = out;
}

// ============================ node pre: Hd/Hs, 8 nodes/warp ============================
__global__ void __launch_bounds__(256) k_node_pre(const float* __restrict__ eW1l)
{
    extern __shared__ float ps[];
    float* sWA = ps;
    float* sWB = ps + 4096;
    float* sInAll = ps + 8192;
    int tid = threadIdx.x;
    for (int i = tid; i < 4096; i += 256) { sWA[i] = eW1l[i]; sWB[i] = eW1l[4096 + i]; }
    __syncthreads();
    int w = tid >> 5, ld = tid & 31;
    int nb = ld >> 3, cb = ld & 7;
    float* sIn = sInAll + w * (8 * 68);
    const ulonglong2* WAu = (const ulonglong2*)sWA;
    const ulonglong2* WBu = (const ulonglong2*)sWB;
    int gw = (blockIdx.x * 256 + tid) >> 5;
    int nw = (gridDim.x * 256) >> 5;
    for (int grp = gw; grp < N_NODES / 8; grp += nw) {
        int n0 = grp * 8;
        __syncwarp();
#pragma unroll
        for (int r = 0; r < 4; r++) {
            int t = r * 32 + ld;
            int n = t >> 4, c4 = (t & 15) * 4;
            float4 v = *(const float4*)(g_h + (size_t)(n0 + n) * 64 + c4);
            *(float4*)&sIn[n * 68 + c4] = v;
        }
        __syncwarp();
        u64 aA[2][4], aB[2][4];
#pragma unroll
        for (int i = 0; i < 2; i++)
#pragma unroll
            for (int j = 0; j < 4; j++) { aA[i][j] = 0ull; aB[i][j] = 0ull; }
#pragma unroll 4
        for (int k = 0; k < 64; k++) {
            u64 d0 = dup2(sIn[(nb * 2 + 0) * 68 + k]);
            u64 d1 = dup2(sIn[(nb * 2 + 1) * 68 + k]);
            ulonglong2 A0 = WAu[k * 16 + cb * 2], A1 = WAu[k * 16 + cb * 2 + 1];
            ulonglong2 B0 = WBu[k * 16 + cb * 2], B1 = WBu[k * 16 + cb * 2 + 1];
            aA[0][0] = ffma2(d0, A0.x, aA[0][0]); aA[0][1] = ffma2(d0, A0.y, aA[0][1]);
            aA[0][2] = ffma2(d0, A1.x, aA[0][2]); aA[0][3] = ffma2(d0, A1.y, aA[0][3]);
            aA[1][0] = ffma2(d1, A0.x, aA[1][0]); aA[1][1] = ffma2(d1, A0.y, aA[1][1]);
            aA[1][2] = ffma2(d1, A1.x, aA[1][2]); aA[1][3] = ffma2(d1, A1.y, aA[1][3]);
            aB[0][0] = ffma2(d0, B0.x, aB[0][0]); aB[0][1] = ffma2(d0, B0.y, aB[0][1]);
            aB[0][2] = ffma2(d0, B1.x, aB[0][2]); aB[0][3] = ffma2(d0, B1.y, aB[0][3]);
            aB[1][0] = ffma2(d1, B0.x, aB[1][0]); aB[1][1] = ffma2(d1, B0.y, aB[1][1]);
            aB[1][2] = ffma2(d1, B1.x, aB[1][2]); aB[1][3] = ffma2(d1, B1.y, aB[1][3]);
        }
#pragma unroll
        for (int i = 0; i < 2; i++) {
            int n = n0 + nb * 2 + i;
            ulonglong2 t;
            t.x = aA[i][0]; t.y = aA[i][1];
            *(ulonglong2*)(g_hd + (size_t)n * 64 + cb * 8) = t;
            t.x = aA[i][2]; t.y = aA[i][3];
            *(ulonglong2*)(g_hd + (size_t)n * 64 + cb * 8 + 4) = t;
            t.x = aB[i][0]; t.y = aB[i][1];
            *(ulonglong2*)(g_hs + (size_t)n * 64 + cb * 8) = t;
            t.x = aB[i][2]; t.y = aB[i][3];
            *(ulonglong2*)(g_hs + (size_t)n * 64 + cb * 8 + 4) = t;
        }
    }
}

// ============================ edge kernel (CSR): warp per dst node ============================
// dyn smem (floats):
//   sW2s [0,4608)   stride-72 rows (bank-conflict-free)
//   sW1c [4608,4928)  sb1[4928] sb2[4992] sg[5056] sbe[5120]
//   per-warp at 5184 + w*2368: sM[64][36] (2304) + sHd[64]
__global__ void __launch_bounds__(256, 2) k_edge_csr(
    const float* __restrict__ eattr,
    const float* __restrict__ W1c, const float* __restrict__ b1,
    const float* __restrict__ W2, const float* __restrict__ b2,
    const float* __restrict__ gam, const float* __restrict__ bet)
{
    extern __shared__ float es[];
    float* sW2s = es;
    float* sW1c = es + 4608;
    float* sb1  = es + 4928;
    float* sb2  = es + 4992;
    float* sg   = es + 5056;
    float* sbe  = es + 5120;
    float* sPer = es + 5184;
    int tid = threadIdx.x;
    for (int i = tid; i < 4096; i += 256) {
        int k = i >> 6, c = i & 63;
        sW2s[k * 72 + (c < 32 ? c : c + 4)] = W2[i];
    }
    for (int i = tid; i < 320; i += 256) sW1c[i] = W1c[i];
    if (tid < 64) { sb1[tid] = b1[tid]; sb2[tid] = b2[tid]; sg[tid] = gam[tid]; sbe[tid] = bet[tid]; }
    __syncthreads();
    int w = tid >> 5, ld = tid & 31;
    int pe = ld >> 1, half = ld & 1;          // phase-1: 16 slots x 2 halves
    int eb = ld >> 3, cb = ld & 7;            // phase-2: 4 edge-blocks x 8 col-blocks
    float* sM  = sPer + w * 2368;
    float* sHd = sM + 2304;
    int wOff = (cb < 4) ? cb * 8 : 36 + (cb - 4) * 8;
    const ulonglong2* W1cu = (const ulonglong2*)sW1c;
    const ulonglong2* b1u  = (const ulonglong2*)sb1;
    const u64* b2u = (const u64*)sb2;
    u64 gv[4], bev[4];
#pragma unroll
    for (int j = 0; j < 4; j++) { gv[j] = ((const u64*)sg)[cb * 4 + j]; bev[j] = ((const u64*)sbe)[cb * 4 + j]; }
    int gw = (blockIdx.x * 256 + tid) >> 5;
    int nw = (gridDim.x * 256) >> 5;
    for (int n = gw; n < N_NODES; n += nw) {
        int start = __ldg(&g_rp[n]);
        int end   = __ldg(&g_rp[n + 1]);
        __syncwarp();
        if (ld < 16) *(float4*)&sHd[ld * 4] = *(const float4*)(g_hd + (size_t)n * 64 + ld * 4);
        __syncwarp();
        u64 av[4] = {0ull, 0ull, 0ull, 0ull};
        for (int cs = start; cs < end; cs += 32) {
            int cnt = end - cs; if (cnt > 32) cnt = 32;
            // ---- phase 1 ----
#pragma unroll
            for (int sub = 0; sub < 2; sub++) {
                int slot = sub * 16 + pe;
                int2 se = __ldg(&g_sorted[cs + slot]);
                int sidx  = (slot < cnt) ? se.x : 0;
                int eorig = (slot < cnt) ? se.y : 0;
                u64 ead[5];
#pragma unroll
                for (int r = 0; r < 5; r++) ead[r] = dup2(__ldg(&eattr[(size_t)eorig * 5 + r]));
                const ulonglong2* hsp = (const ulonglong2*)(g_hs + (size_t)sidx * 64 + half * 32);
                const ulonglong2* hdp = (const ulonglong2*)(sHd + half * 32);
#pragma unroll
                for (int j = 0; j < 8; j++) {
                    ulonglong2 hdj = hdp[j];
                    ulonglong2 hsj = hsp[j];
                    ulonglong2 bj  = b1u[half * 8 + j];
                    u64 a0 = add2(add2(hdj.x, hsj.x), bj.x);
                    u64 a1 = add2(add2(hdj.y, hsj.y), bj.y);
#pragma unroll
                    for (int r = 0; r < 5; r++) {
                        ulonglong2 wv = W1cu[r * 16 + half * 8 + j];
                        a0 = ffma2(ead[r], wv.x, a0);
                        a1 = ffma2(ead[r], wv.y, a1);
                    }
                    float2 v0 = upk(a0), v1 = upk(a1);
                    v0.x = silu(v0.x); v0.y = silu(v0.y);
                    v1.x = silu(v1.x); v1.y = silu(v1.y);
                    int c = half * 32 + 4 * j;
                    sM[(c + 0) * 36 + slot] = v0.x;
                    sM[(c + 1) * 36 + slot] = v0.y;
                    sM[(c + 2) * 36 + slot] = v1.x;
                    sM[(c + 3) * 36 + slot] = v1.y;
                }
            }
            __syncwarp();
            // ---- phase 2 GEMM: thread = 8 edges x 8 cols ----
            u64 acc[8][4];
#pragma unroll
            for (int i = 0; i < 8; i++)
#pragma unroll
                for (int j = 0; j < 4; j++) acc[i][j] = b2u[cb * 4 + j];
#pragma unroll 4
            for (int k = 0; k < 64; k++) {
                const float4* mp = (const float4*)&sM[k * 36 + eb * 8];
                float4 m0 = mp[0], m1 = mp[1];
                ulonglong2 wA = *(const ulonglong2*)&sW2s[k * 72 + wOff];
                ulonglong2 wB = *(const ulonglong2*)&sW2s[k * 72 + wOff + 4];
                u64 mm[8];
                mm[0] = dup2(m0.x); mm[1] = dup2(m0.y); mm[2] = dup2(m0.z); mm[3] = dup2(m0.w);
                mm[4] = dup2(m1.x); mm[5] = dup2(m1.y); mm[6] = dup2(m1.z); mm[7] = dup2(m1.w);
#pragma unroll
                for (int i = 0; i < 8; i++) {
                    acc[i][0] = ffma2(mm[i], wA.x, acc[i][0]);
                    acc[i][1] = ffma2(mm[i], wA.y, acc[i][1]);
                    acc[i][2] = ffma2(mm[i], wB.x, acc[i][2]);
                    acc[i][3] = ffma2(mm[i], wB.y, acc[i][3]);
                }
            }
            // ---- LN per edge + masked register accumulation ----
            float s[8], q[8];
#pragma unroll
            for (int i = 0; i < 8; i++) {
                float2 v0 = upk(acc[i][0]), v1 = upk(acc[i][1]), v2 = upk(acc[i][2]), v3 = upk(acc[i][3]);
                s[i] = v0.x + v0.y + v1.x + v1.y + v2.x + v2.y + v3.x + v3.y;
                q[i] = v0.x * v0.x + v0.y * v0.y + v1.x * v1.x + v1.y * v1.y
                     + v2.x * v2.x + v2.y * v2.y + v3.x * v3.x + v3.y * v3.y;
            }
#pragma unroll
            for (int o = 4; o; o >>= 1) {
#pragma unroll
                for (int i = 0; i < 8; i++) {
                    s[i] += __shfl_xor_sync(~0u, s[i], o);
                    q[i] += __shfl_xor_sync(~0u, q[i], o);
                }
            }
#pragma unroll
            for (int i = 0; i < 8; i++) {
                float mn = s[i] * (1.f / 64.f);
                float rs = rsqrtf(q[i] * (1.f / 64.f) - mn * mn + EPS);
                u64 rsd = dup2(rs);
                u64 mrd = dup2(-mn * rs);
                bool valid = (eb * 8 + i) < cnt;
#pragma unroll
                for (int j = 0; j < 4; j++) {
                    u64 t = ffma2(acc[i][j], rsd, mrd);
                    u64 y = ffma2(t, gv[j], bev[j]);
                    if (valid) av[j] = add2(av[j], y);
                }
            }
            __syncwarp();   // protect sM before next chunk's phase 1
        }
        // reduce over eb groups (lanes differing in bits 3,4)
#pragma unroll
        for (int off = 8; off <= 16; off <<= 1) {
#pragma unroll
            for (int j = 0; j < 4; j++) av[j] = add2(av[j], __shfl_xor_sync(~0u, av[j], off));
        }
        if (eb == 0) {
            ulonglong2 t0; t0.x = av[0]; t0.y = av[1];
            ulonglong2 t1; t1.x = av[2]; t1.y = av[3];
            *(ulonglong2*)(g_agg + (size_t)n * 64 + cb * 8)     = t0;
            *(ulonglong2*)(g_agg + (size_t)n * 64 + cb * 8 + 4) = t1;
        }
    }
}

// ============================ node update: 8 nodes/warp, thread = 2n x 8c ============================
__global__ void __launch_bounds__(256) k_node_upd(
    const float* __restrict__ W1, const float* __restrict__ b1,
    const float* __restrict__ W2, const float* __restrict__ b2,
    const float* __restrict__ gam, const float* __restrict__ bet)
{
    extern __shared__ float us[];
    float* sW1 = us;
    float* sW2 = us + 8192;
    float* sb1 = us + 12288;
    float* sb2 = us + 12352;
    float* sg  = us + 12416;
    float* sbe = us + 12480;
    float* sPer = us + 12544;
    int tid = threadIdx.x;
    for (int i = tid; i < 8192; i += 256) sW1[i] = W1[i];
    for (int i = tid; i < 4096; i += 256) sW2[i] = W2[i];
    if (tid < 64) { sb1[tid] = b1[tid]; sb2[tid] = b2[tid]; sg[tid] = gam[tid]; sbe[tid] = bet[tid]; }
    __syncthreads();
    int w = tid >> 5, ld = tid & 31;
    int nb = ld >> 3, cb = ld & 7;
    float* sIn  = sPer + w * (8 * 132 + 8 * 70);
    float* sMid = sIn + 8 * 132;
    const ulonglong2* W1u = (const ulonglong2*)sW1;
    const ulonglong2* W2u = (const ulonglong2*)sW2;
    const u64* b1u = (const u64*)sb1;
    const u64* b2u = (const u64*)sb2;
    const float4* gv4  = (const float4*)sg;
    const float4* bev4 = (const float4*)sbe;
    int gw = (blockIdx.x * 256 + tid) >> 5;
    int nw = (gridDim.x * 256) >> 5;
    for (int grp = gw; grp < N_NODES / 8; grp += nw) {
        int n0 = grp * 8;
        __syncwarp();
#pragma unroll
        for (int r = 0; r < 8; r++) {
            int c4 = ld * 4;
            float4 v;
            if (c4 < 64) v = *(const float4*)(g_h + (size_t)(n0 + r) * 64 + c4);
            else         v = *(const float4*)(g_agg + (size_t)(n0 + r) * 64 + (c4 - 64));
            *(float4*)&sIn[r * 132 + c4] = v;
        }
        __syncwarp();
        u64 a1[2][4];
#pragma unroll
        for (int i = 0; i < 2; i++)
#pragma unroll
            for (int j = 0; j < 4; j++) a1[i][j] = b1u[cb * 4 + j];
#pragma unroll 4
        for (int k = 0; k < 128; k++) {
            u64 d0 = dup2(sIn[(nb * 2 + 0) * 132 + k]);
            u64 d1 = dup2(sIn[(nb * 2 + 1) * 132 + k]);
            ulonglong2 w0 = W1u[k * 16 + cb * 2], w1 = W1u[k * 16 + cb * 2 + 1];
            a1[0][0] = ffma2(d0, w0.x, a1[0][0]); a1[0][1] = ffma2(d0, w0.y, a1[0][1]);
            a1[0][2] = ffma2(d0, w1.x, a1[0][2]); a1[0][3] = ffma2(d0, w1.y, a1[0][3]);
            a1[1][0] = ffma2(d1, w0.x, a1[1][0]); a1[1][1] = ffma2(d1, w0.y, a1[1][1]);
            a1[1][2] = ffma2(d1, w1.x, a1[1][2]); a1[1][3] = ffma2(d1, w1.y, a1[1][3]);
        }
#pragma unroll
        for (int i = 0; i < 2; i++) {
            int n = nb * 2 + i;
#pragma unroll
            for (int j = 0; j < 4; j++) {
                float2 v = upk(a1[i][j]);
                v.x = silu(v.x); v.y = silu(v.y);
                *(float2*)&sMid[n * 70 + cb * 8 + 2 * j] = v;
            }
        }
        __syncwarp();
        u64 a2[2][4];
#pragma unroll
        for (int i = 0; i < 2; i++)
#pragma unroll
            for (int j = 0; j < 4; j++) a2[i][j] = b2u[cb * 4 + j];
#pragma unroll 4
        for (int k = 0; k < 64; k++) {
            u64 d0 = dup2(sMid[(nb * 2 + 0) * 70 + k]);
            u64 d1 = dup2(sMid[(nb * 2 + 1) * 70 + k]);
            ulonglong2 w0 = W2u[k * 16 + cb * 2], w1 = W2u[k * 16 + cb * 2 + 1];
            a2[0][0] = ffma2(d0, w0.x, a2[0][0]); a2[0][1] = ffma2(d0, w0.y, a2[0][1]);
            a2[0][2] = ffma2(d0, w1.x, a2[0][2]); a2[0][3] = ffma2(d0, w1.y, a2[0][3]);
            a2[1][0] = ffma2(d1, w0.x, a2[1][0]); a2[1][1] = ffma2(d1, w0.y, a2[1][1]);
            a2[1][2] = ffma2(d1, w1.x, a2[1][2]); a2[1][3] = ffma2(d1, w1.y, a2[1][3]);
        }
        float4 gA = gv4[cb * 2], gB = gv4[cb * 2 + 1];
        float4 beA = bev4[cb * 2], beB = bev4[cb * 2 + 1];
#pragma unroll
        for (int i = 0; i < 2; i++) {
            float2 v0 = upk(a2[i][0]), v1 = upk(a2[i][1]), v2 = upk(a2[i][2]), v3 = upk(a2[i][3]);
            float s = v0.x + v0.y + v1.x + v1.y + v2.x + v2.y + v3.x + v3.y;
            float q = v0.x * v0.x + v0.y * v0.y + v1.x * v1.x + v1.y * v1.y
                    + v2.x * v2.x + v2.y * v2.y + v3.x * v3.x + v3.y * v3.y;
#pragma unroll
            for (int o = 4; o; o >>= 1) { s += __shfl_xor_sync(~0u, s, o); q += __shfl_xor_sync(~0u, q, o); }
            float mn = s * (1.f / 64.f);
            float rs = rsqrtf(q * (1.f / 64.f) - mn * mn + EPS);
            int n = nb * 2 + i;
            float4 h0 = *(const float4*)&sIn[n * 132 + cb * 8];
            float4 h1 = *(const float4*)&sIn[n * 132 + cb * 8 + 4];
            float4 o0, o1;
            o0.x = h0.x + (v0.x - mn) * rs * gA.x + beA.x;
            o0.y = h0.y + (v0.y - mn) * rs * gA.y + beA.y;
            o0.z = h0.z + (v1.x - mn) * rs * gA.z + beA.z;
            o0.w = h0.w + (v1.y - mn) * rs * gA.w + beA.w;
            o1.x = h1.x + (v2.x - mn) * rs * gB.x + beB.x;
            o1.y = h1.y + (v2.y - mn) * rs * gB.y + beB.y;
            o1.z = h1.z + (v3.x - mn) * rs * gB.z + beB.z;
            o1.w = h1.w + (v3.y - mn) * rs * gB.w + beB.w;
            *(float4*)(g_h + (size_t)(n0 + n) * 64 + cb * 8)     = o0;
            *(float4*)(g_h + (size_t)(n0 + n) * 64 + cb * 8 + 4) = o1;
        }
    }
}

__global__ void k_zero_pool() { int t = threadIdx.x; if (t < NG * 64) g_pool[t] = 0.f; }

// ============================ local decoder + pooling ============================
__global__ void __launch_bounds__(256) k_decoder_local(
    const float* __restrict__ W1, const float* __restrict__ b1,
    const float* __restrict__ W2, const float* __restrict__ b2,
    const int* __restrict__ batch, float* __restrict__ out)
{
    __shared__ float sW1[4096], sW2[64 * 6], sb1[64], sb2_[8];
    __shared__ float sH[8][64], sU[8][64];
    int tid = threadIdx.x;
    for (int i = tid; i < 4096; i += 256) sW1[i] = W1[i];
    for (int i = tid; i < 384; i += 256) sW2[i] = W2[i];
    if (tid < 64) sb1[tid] = b1[tid];
    if (tid < 6) sb2_[tid] = b2[tid];
    __syncthreads();
    int w = tid >> 5, ld = tid & 31, c0 = 2 * ld;
    int n = blockIdx.x * 8 + w;
    if (n >= N_NODES) return;
    float2 hv = *(const float2*)(g_h + (size_t)n * 64 + c0);
    sH[w][c0] = hv.x; sH[w][c0 + 1] = hv.y;
    __syncwarp();
    const u64* W1u = (const u64*)sW1;
    u64 acc = ((const u64*)sb1)[ld];
#pragma unroll 8
    for (int k = 0; k < 64; k++) acc = ffma2(dup2(sH[w][k]), W1u[k * 32 + ld], acc);
    float2 u = upk(acc); u.x = silu(u.x); u.y = silu(u.y);
    sU[w][c0] = u.x; sU[w][c0 + 1] = u.y;
    __syncwarp();
    if (ld < 6) {
        float o = sb2_[ld];
#pragma unroll
        for (int k = 0; k < 64; k++) o += sU[w][k] * sW2[k * 6 + ld];
        out[(size_t)n * 6 + ld] = o;
    }
    int g = __ldg(&batch[n]);
    red2(g_pool + g * 64 + c0, hv.x, hv.y);
}

// ============================ global decoder ============================
__global__ void k_global(const int* __restrict__ batch,
    const float* __restrict__ W1, const float* __restrict__ b1,
    const float* __restrict__ W2, const float* __restrict__ b2,
    float* __restrict__ out)
{
    __shared__ float sp[NG * 64];
    __shared__ float su[NG * 32];
    __shared__ int bnd[NG + 1];
    int t = threadIdx.x;
    if (t <= NG) {
        int lo = 0, hi = N_NODES;
        while (lo < hi) { int mid = (lo + hi) >> 1; if (batch[mid] < t) lo = mid + 1; else hi = mid; }
        bnd[t] = lo;
    }
    __syncthreads();
    for (int i = t; i < NG * 64; i += 128) {
        int g = i >> 6;
        float cnt = (float)(bnd[g + 1] - bnd[g]);
        sp[i] = g_pool[i] / fmaxf(cnt, 1.f);
    }
    __syncthreads();
    {
        int g = t >> 5, j = t & 31;
        float a = b1[j];
#pragma unroll
        for (int k = 0; k < 64; k++) a += sp[g * 64 + k] * W1[k * 32 + j];
        su[g * 32 + j] = silu(a);
    }
    __syncthreads();
    if (t < NG * 4) {
        int g = t >> 2, j = t & 3;
        float o = b2[j];
#pragma unroll
        for (int k = 0; k < 32; k++) o += su[g * 32 + k] * W2[k * 4 + j];
        out[(size_t)N_NODES * 6 + g * 4 + j] = o;
    }
}

extern "C" void kernel_launch(void* const* d_in, const int* in_sizes, int n_in,
                              void* d_out, int out_size) {
    (void)in_sizes; (void)n_in; (void)out_size;
    const float* x     = (const float*)d_in[0];
    const int*   ei    = (const int*)d_in[1];
    const float* eattr = (const float*)d_in[2];
    const int*   batch = (const int*)d_in[3];
    const float* casep = (const float*)d_in[4];
    const float* bcp   = (const float*)d_in[5];
    const float* encW1 = (const float*)d_in[6];  const float* encb1 = (const float*)d_in[7];
    const float* encW2 = (const float*)d_in[8];  const float* encb2 = (const float*)d_in[9];
    const float* encg  = (const float*)d_in[10]; const float* encbe = (const float*)d_in[11];
    const float* eW1   = (const float*)d_in[12]; const float* eb1   = (const float*)d_in[13];
    const float* eW2   = (const float*)d_in[14]; const float* eb2   = (const float*)d_in[15];
    const float* eg    = (const float*)d_in[16]; const float* ebe   = (const float*)d_in[17];
    const float* nW1   = (const float*)d_in[18]; const float* nb1   = (const float*)d_in[19];
    const float* nW2   = (const float*)d_in[20]; const float* nb2   = (const float*)d_in[21];
    const float* ngm   = (const float*)d_in[22]; const float* nbe   = (const float*)d_in[23];
    const float* dlW1  = (const float*)d_in[24]; const float* dlb1  = (const float*)d_in[25];
    const float* dlW2  = (const float*)d_in[26]; const float* dlb2  = (const float*)d_in[27];
    const float* dgW1  = (const float*)d_in[28]; const float* dgb1  = (const float*)d_in[29];
    const float* dgW2  = (const float*)d_in[30]; const float* dgb2  = (const float*)d_in[31];
    float* out = (float*)d_out;

    size_t preSmem  = (size_t)(8192 + 8 * (8 * 68)) * sizeof(float);            // 50176 B
    size_t edgeSmem = (size_t)(5184 + 8 * 2368) * sizeof(float);                // 96512 B
    size_t updSmem  = (size_t)(12544 + 8 * (8 * 132 + 8 * 70)) * sizeof(float); // 101888 B
    cudaFuncSetAttribute(k_node_pre, cudaFuncAttributeMaxDynamicSharedMemorySize, (int)preSmem);
    cudaFuncSetAttribute(k_edge_csr, cudaFuncAttributeMaxDynamicSharedMemorySize, (int)edgeSmem);
    cudaFuncSetAttribute(k_node_upd, cudaFuncAttributeMaxDynamicSharedMemorySize, (int)updSmem);

    // CSR build (per call; graph-capturable, deterministic up to fp-sum order)
    k_zero_wp<<<(N_NODES + 255) / 256, 256>>>();
    k_hist<<<(N_EDGES + 255) / 256, 256>>>(ei);
    k_scan<<<1, 1024>>>();
    k_scatter<<<(N_EDGES + 255) / 256, 256>>>(ei);

    k_encoder<<<(N_NODES + 7) / 8, 256>>>(x, batch, casep, bcp, encW1, encb1, encW2, encb2, encg, encbe);
    for (int l = 0; l < NL; l++) {
        const float* eW1l = eW1 + (size_t)l * 133 * 64;
        k_node_pre<<<592, 256, preSmem>>>(eW1l);
        k_edge_csr<<<296, 256, edgeSmem>>>(eattr,
                              eW1l + 128 * 64, eb1 + l * 64,
                              eW2 + (size_t)l * 4096, eb2 + l * 64,
                              eg + l * 64, ebe + l * 64);
        k_node_upd<<<296, 256, updSmem>>>(nW1 + (size_t)l * 8192, nb1 + l * 64,
                                          nW2 + (size_t)l * 4096, nb2 + l * 64,
                                          ngm + l * 64, nbe + l * 64);
    }
    k_zero_pool<<<1, 256>>>();
    k_decoder_local<<<(N_NODES + 7) / 8, 256>>>(dlW1, dlb1, dlW2, dlb2, batch, out);
    k_global<<<1, 128>>>(batch, dgW1, dgb1, dgW2, dgb2, out);
}

// round 6
// speedup vs baseline: 1.2791x; 1.2791x over previous
#include <cuda_runtime.h>

#define DINL __device__ __forceinline__

constexpr int N_NODES = 50000;
constexpr int N_EDGES = 1600000;
constexpr int NL = 5;
constexpr int NG = 4;
constexpr float EPS = 1e-5f;

__device__ float g_h  [N_NODES * 64];
__device__ float g_hd [N_NODES * 64];
__device__ float g_hs [N_NODES * 64];
__device__ float g_agg[N_NODES * 64];
__device__ float g_pool[NG * 64];
__device__ int   g_wp [N_NODES];
__device__ int4  g_sor[N_EDGES];    // (src, dst, orig edge id, 0) sorted by dst

typedef unsigned long long u64;

DINL u64 pk2(float x, float y) { u64 r; asm("mov.b64 %0,{%1,%2};" : "=l"(r) : "f"(x), "f"(y)); return r; }
DINL u64 dup2(float x) { return pk2(x, x); }
DINL float2 upk(u64 v) { float2 r; asm("mov.b64 {%0,%1},%2;" : "=f"(r.x), "=f"(r.y) : "l"(v)); return r; }
DINL u64 ffma2(u64 a, u64 b, u64 c) {
    u64 d; asm("fma.rn.f32x2 %0,%1,%2,%3;" : "=l"(d) : "l"(a), "l"(b), "l"(c)); return d;
}
DINL u64 add2(u64 a, u64 b) {
    u64 d; asm("add.rn.f32x2 %0,%1,%2;" : "=l"(d) : "l"(a), "l"(b)); return d;
}
DINL void red2(float* p, float x, float y) {
    asm volatile("red.global.add.v2.f32 [%0], {%1,%2};" :: "l"(p), "f"(x), "f"(y) : "memory");
}
DINL void red4(float* p, float4 v) {
    asm volatile("red.global.add.v4.f32 [%0], {%1,%2,%3,%4};"
                 :: "l"(p), "f"(v.x), "f"(v.y), "f"(v.z), "f"(v.w) : "memory");
}
DINL float silu(float x) { return __fdividef(x, 1.f + __expf(-x)); }

// ============================ CSR build (edge sort by dst) ============================
__global__ void k_zero_wp() {
    int i = blockIdx.x * 256 + threadIdx.x;
    if (i < N_NODES) g_wp[i] = 0;
}
__global__ void k_hist(const int* __restrict__ ei) {
    int e = blockIdx.x * 256 + threadIdx.x;
    if (e < N_EDGES) atomicAdd(&g_wp[ei[N_EDGES + e]], 1);
}
__global__ void k_scan() {   // 1 block, 1024 threads
    __shared__ int part[1024];
    int t = threadIdx.x;
    const int C = 49;
    int base = t * C;
    int sum = 0;
    for (int i = 0; i < C; i++) { int idx = base + i; if (idx < N_NODES) sum += g_wp[idx]; }
    part[t] = sum;
    __syncthreads();
    for (int off = 1; off < 1024; off <<= 1) {
        int v = (t >= off) ? part[t - off] : 0;
        __syncthreads();
        part[t] += v;
        __syncthreads();
    }
    int run = (t == 0) ? 0 : part[t - 1];
    for (int i = 0; i < C; i++) {
        int idx = base + i;
        if (idx < N_NODES) { int v = g_wp[idx]; g_wp[idx] = run; run += v; }
    }
}
__global__ void k_scatter(const int* __restrict__ ei) {
    int e = blockIdx.x * 256 + threadIdx.x;
    if (e < N_EDGES) {
        int d = ei[N_EDGES + e];
        int pos = atomicAdd(&g_wp[d], 1);
        g_sor[pos] = make_int4(ei[e], d, e, 0);
    }
}

// ============================ encoder ============================
__global__ void __launch_bounds__(256) k_encoder(
    const float* __restrict__ x, const int* __restrict__ batch,
    const float* __restrict__ casep, const float* __restrict__ bcp,
    const float* __restrict__ W1, const float* __restrict__ b1,
    const float* __restrict__ W2, const float* __restrict__ b2,
    const float* __restrict__ gam, const float* __restrict__ bet)
{
    __shared__ float sW1[16 * 64], sW2[64 * 64], sb1[64], sb2[64], sg[64], sbe[64];
    __shared__ float sH[8][64];
    int tid = threadIdx.x;
    for (int i = tid; i < 16 * 64; i += 256) sW1[i] = W1[i];
    for (int i = tid; i < 64 * 64; i += 256) sW2[i] = W2[i];
    if (tid < 64) { sb1[tid] = b1[tid]; sb2[tid] = b2[tid]; sg[tid] = gam[tid]; sbe[tid] = bet[tid]; }
    __syncthreads();
    int w = tid >> 5, ld = tid & 31, c0 = 2 * ld;
    int n = blockIdx.x * 8 + w;
    if (n >= N_NODES) return;
    float in[16];
#pragma unroll
    for (int k = 0; k < 8; k++) in[k] = __ldg(&x[n * 8 + k]);
    int g = __ldg(&batch[n]);
#pragma unroll
    for (int k = 0; k < 4; k++) { in[8 + k] = __ldg(&casep[g * 4 + k]); in[12 + k] = __ldg(&bcp[g * 4 + k]); }
    const u64* W1u = (const u64*)sW1;
    u64 acc = ((const u64*)sb1)[ld];
#pragma unroll
    for (int k = 0; k < 16; k++) acc = ffma2(dup2(in[k]), W1u[k * 32 + ld], acc);
    float2 a = upk(acc);
    a.x = silu(a.x); a.y = silu(a.y);
    sH[w][c0] = a.x; sH[w][c0 + 1] = a.y;
    __syncwarp();
    const u64* W2u = (const u64*)sW2;
    u64 acc2 = ((const u64*)sb2)[ld];
#pragma unroll 8
    for (int k = 0; k < 64; k++) acc2 = ffma2(dup2(sH[w][k]), W2u[k * 32 + ld], acc2);
    float2 v = upk(acc2);
    float s = v.x + v.y, q = v.x * v.x + v.y * v.y;
#pragma unroll
    for (int o = 16; o; o >>= 1) { s += __shfl_xor_sync(~0u, s, o); q += __shfl_xor_sync(~0u, q, o); }
    float m = s * (1.f / 64.f), var = q * (1.f / 64.f) - m * m, rs = rsqrtf(var + EPS);
    float2 out;
    out.x = (v.x - m) * rs * sg[c0] + sbe[c0];
    out.y = (v.y - m) * rs * sg[c0 + 1] + sbe[c0 + 1];
    *(float2*)(g_h + (size_t)n * 64 + c0) = out;
}

// ============================ node pre: Hd/Hs + zero agg, 8 nodes/warp ============================
__global__ void __launch_bounds__(256) k_node_pre(const float* __restrict__ eW1l)
{
    extern __shared__ float ps[];
    float* sWA = ps;
    float* sWB = ps + 4096;
    float* sInAll = ps + 8192;
    int tid = threadIdx.x;
    for (int i = tid; i < 4096; i += 256) { sWA[i] = eW1l[i]; sWB[i] = eW1l[4096 + i]; }
    __syncthreads();
    int w = tid >> 5, ld = tid & 31;
    int nb = ld >> 3, cb = ld & 7;
    float* sIn = sInAll + w * (8 * 68);
    const ulonglong2* WAu = (const ulonglong2*)sWA;
    const ulonglong2* WBu = (const ulonglong2*)sWB;
    int gw = (blockIdx.x * 256 + tid) >> 5;
    int nw = (gridDim.x * 256) >> 5;
    for (int grp = gw; grp < N_NODES / 8; grp += nw) {
        int n0 = grp * 8;
        __syncwarp();
#pragma unroll
        for (int r = 0; r < 4; r++) {
            int t = r * 32 + ld;
            int n = t >> 4, c4 = (t & 15) * 4;
            float4 v = *(const float4*)(g_h + (size_t)(n0 + n) * 64 + c4);
            *(float4*)&sIn[n * 68 + c4] = v;
        }
        __syncwarp();
        u64 aA[2][4], aB[2][4];
#pragma unroll
        for (int i = 0; i < 2; i++)
#pragma unroll
            for (int j = 0; j < 4; j++) { aA[i][j] = 0ull; aB[i][j] = 0ull; }
#pragma unroll 4
        for (int k = 0; k < 64; k++) {
            u64 d0 = dup2(sIn[(nb * 2 + 0) * 68 + k]);
            u64 d1 = dup2(sIn[(nb * 2 + 1) * 68 + k]);
            ulonglong2 A0 = WAu[k * 16 + cb * 2], A1 = WAu[k * 16 + cb * 2 + 1];
            ulonglong2 B0 = WBu[k * 16 + cb * 2], B1 = WBu[k * 16 + cb * 2 + 1];
            aA[0][0] = ffma2(d0, A0.x, aA[0][0]); aA[0][1] = ffma2(d0, A0.y, aA[0][1]);
            aA[0][2] = ffma2(d0, A1.x, aA[0][2]); aA[0][3] = ffma2(d0, A1.y, aA[0][3]);
            aA[1][0] = ffma2(d1, A0.x, aA[1][0]); aA[1][1] = ffma2(d1, A0.y, aA[1][1]);
            aA[1][2] = ffma2(d1, A1.x, aA[1][2]); aA[1][3] = ffma2(d1, A1.y, aA[1][3]);
            aB[0][0] = ffma2(d0, B0.x, aB[0][0]); aB[0][1] = ffma2(d0, B0.y, aB[0][1]);
            aB[0][2] = ffma2(d0, B1.x, aB[0][2]); aB[0][3] = ffma2(d0, B1.y, aB[0][3]);
            aB[1][0] = ffma2(d1, B0.x, aB[1][0]); aB[1][1] = ffma2(d1, B0.y, aB[1][1]);
            aB[1][2] = ffma2(d1, B1.x, aB[1][2]); aB[1][3] = ffma2(d1, B1.y, aB[1][3]);
        }
#pragma unroll
        for (int i = 0; i < 2; i++) {
            int n = n0 + nb * 2 + i;
            ulonglong2 t;
            t.x = aA[i][0]; t.y = aA[i][1];
            *(ulonglong2*)(g_hd + (size_t)n * 64 + cb * 8) = t;
            t.x = aA[i][2]; t.y = aA[i][3];
            *(ulonglong2*)(g_hd + (size_t)n * 64 + cb * 8 + 4) = t;
            t.x = aB[i][0]; t.y = aB[i][1];
            *(ulonglong2*)(g_hs + (size_t)n * 64 + cb * 8) = t;
            t.x = aB[i][2]; t.y = aB[i][3];
            *(ulonglong2*)(g_hs + (size_t)n * 64 + cb * 8 + 4) = t;
            *(float4*)(g_agg + (size_t)n * 64 + cb * 8)     = make_float4(0.f, 0.f, 0.f, 0.f);
            *(float4*)(g_agg + (size_t)n * 64 + cb * 8 + 4) = make_float4(0.f, 0.f, 0.f, 0.f);
        }
    }
}

// ============================ edge kernel: dense 32-edge tiles over dst-SORTED edges ============================
// Run-length compressed scatter: consecutive same-dst edges accumulate in regs, red4 on change.
// dyn smem (floats):
//   sW2s [0,4608)   stride-72 rows (bank-conflict-free)
//   sW1c [4608,4928)  sb1[4928] sb2[4992] sg[5056] sbe[5120]
//   per-warp at 5184 + w*2336: sM[64][36] (2304) + sD int[32]
__global__ void __launch_bounds__(256, 2) k_edge(
    const float* __restrict__ eattr,
    const float* __restrict__ W1c, const float* __restrict__ b1,
    const float* __restrict__ W2, const float* __restrict__ b2,
    const float* __restrict__ gam, const float* __restrict__ bet)
{
    extern __shared__ float es[];
    float* sW2s = es;
    float* sW1c = es + 4608;
    float* sb1  = es + 4928;
    float* sb2  = es + 4992;
    float* sg   = es + 5056;
    float* sbe  = es + 5120;
    float* sPer = es + 5184;
    int tid = threadIdx.x;
    for (int i = tid; i < 4096; i += 256) {
        int k = i >> 6, c = i & 63;
        sW2s[k * 72 + (c < 32 ? c : c + 4)] = W2[i];
    }
    for (int i = tid; i < 320; i += 256) sW1c[i] = W1c[i];
    if (tid < 64) { sb1[tid] = b1[tid]; sb2[tid] = b2[tid]; sg[tid] = gam[tid]; sbe[tid] = bet[tid]; }
    __syncthreads();
    int w = tid >> 5, ld = tid & 31;
    int pe = ld >> 1, half = ld & 1;          // phase-1: 16 edges x 2 halves
    int eb = ld >> 3, cb = ld & 7;            // phase-2: 4 edge-blocks x 8 col-blocks
    float* sM = sPer + w * 2336;
    int* sD = (int*)(sM + 2304);
    int wOff = (cb < 4) ? cb * 8 : 36 + (cb - 4) * 8;
    const ulonglong2* W1cu = (const ulonglong2*)sW1c;
    const ulonglong2* b1u  = (const ulonglong2*)sb1;
    const u64* b2u = (const u64*)sb2;
    u64 gv[4], bev[4];
#pragma unroll
    for (int j = 0; j < 4; j++) { gv[j] = ((const u64*)sg)[cb * 4 + j]; bev[j] = ((const u64*)sbe)[cb * 4 + j]; }
    int gw = (blockIdx.x * 256 + tid) >> 5;
    int nw = (gridDim.x * 256) >> 5;
    for (int grp = gw; grp < N_EDGES / 32; grp += nw) {
        int e0 = grp * 32;
        __syncwarp();   // WAR: previous iteration's sM/sD reads done
        // ---- phase 1 ----
#pragma unroll
        for (int sub = 0; sub < 2; sub++) {
            int slot = sub * 16 + pe;
            int4 se = __ldg(&g_sor[e0 + slot]);
            int sidx = se.x, didx = se.y, eorig = se.z;
            if (half == 0) sD[slot] = didx;
            u64 ead[5];
#pragma unroll
            for (int r = 0; r < 5; r++) ead[r] = dup2(__ldg(&eattr[(size_t)eorig * 5 + r]));
            const ulonglong2* hdp = (const ulonglong2*)(g_hd + (size_t)didx * 64 + half * 32);
            const ulonglong2* hsp = (const ulonglong2*)(g_hs + (size_t)sidx * 64 + half * 32);
#pragma unroll
            for (int j = 0; j < 8; j++) {
                ulonglong2 hdj = hdp[j];
                ulonglong2 hsj = hsp[j];
                ulonglong2 bj  = b1u[half * 8 + j];
                u64 a0 = add2(add2(hdj.x, hsj.x), bj.x);
                u64 a1 = add2(add2(hdj.y, hsj.y), bj.y);
#pragma unroll
                for (int r = 0; r < 5; r++) {
                    ulonglong2 wv = W1cu[r * 16 + half * 8 + j];
                    a0 = ffma2(ead[r], wv.x, a0);
                    a1 = ffma2(ead[r], wv.y, a1);
                }
                float2 v0 = upk(a0), v1 = upk(a1);
                v0.x = silu(v0.x); v0.y = silu(v0.y);
                v1.x = silu(v1.x); v1.y = silu(v1.y);
                int c = half * 32 + 4 * j;
                sM[(c + 0) * 36 + slot] = v0.x;
                sM[(c + 1) * 36 + slot] = v0.y;
                sM[(c + 2) * 36 + slot] = v1.x;
                sM[(c + 3) * 36 + slot] = v1.y;
            }
        }
        __syncwarp();
        // ---- phase 2 GEMM: thread = 8 edges x 8 cols ----
        u64 acc[8][4];
#pragma unroll
        for (int i = 0; i < 8; i++)
#pragma unroll
            for (int j = 0; j < 4; j++) acc[i][j] = b2u[cb * 4 + j];
#pragma unroll 4
        for (int k = 0; k < 64; k++) {
            const float4* mp = (const float4*)&sM[k * 36 + eb * 8];
            float4 m0 = mp[0], m1 = mp[1];
            ulonglong2 wA = *(const ulonglong2*)&sW2s[k * 72 + wOff];
            ulonglong2 wB = *(const ulonglong2*)&sW2s[k * 72 + wOff + 4];
            u64 mm[8];
            mm[0] = dup2(m0.x); mm[1] = dup2(m0.y); mm[2] = dup2(m0.z); mm[3] = dup2(m0.w);
            mm[4] = dup2(m1.x); mm[5] = dup2(m1.y); mm[6] = dup2(m1.z); mm[7] = dup2(m1.w);
#pragma unroll
            for (int i = 0; i < 8; i++) {
                acc[i][0] = ffma2(mm[i], wA.x, acc[i][0]);
                acc[i][1] = ffma2(mm[i], wA.y, acc[i][1]);
                acc[i][2] = ffma2(mm[i], wB.x, acc[i][2]);
                acc[i][3] = ffma2(mm[i], wB.y, acc[i][3]);
            }
        }
        // ---- LN per edge + run-length compressed scatter ----
        float s[8], q[8];
#pragma unroll
        for (int i = 0; i < 8; i++) {
            float2 v0 = upk(acc[i][0]), v1 = upk(acc[i][1]), v2 = upk(acc[i][2]), v3 = upk(acc[i][3]);
            s[i] = v0.x + v0.y + v1.x + v1.y + v2.x + v2.y + v3.x + v3.y;
            q[i] = v0.x * v0.x + v0.y * v0.y + v1.x * v1.x + v1.y * v1.y
                 + v2.x * v2.x + v2.y * v2.y + v3.x * v3.x + v3.y * v3.y;
        }
#pragma unroll
        for (int o = 4; o; o >>= 1) {
#pragma unroll
            for (int i = 0; i < 8; i++) {
                s[i] += __shfl_xor_sync(~0u, s[i], o);
                q[i] += __shfl_xor_sync(~0u, q[i], o);
            }
        }
        int curD = sD[eb * 8];
        u64 av[4] = {0ull, 0ull, 0ull, 0ull};
#pragma unroll
        for (int i = 0; i < 8; i++) {
            int dI = sD[eb * 8 + i];
            float mn = s[i] * (1.f / 64.f);
            float rs = rsqrtf(q[i] * (1.f / 64.f) - mn * mn + EPS);
            u64 rsd = dup2(rs);
            u64 mrd = dup2(-mn * rs);
            if (dI != curD) {
                float2 a0 = upk(av[0]), a1 = upk(av[1]), a2 = upk(av[2]), a3 = upk(av[3]);
                float* base = g_agg + (size_t)curD * 64 + cb * 8;
                red4(base,     make_float4(a0.x, a0.y, a1.x, a1.y));
                red4(base + 4, make_float4(a2.x, a2.y, a3.x, a3.y));
                av[0] = av[1] = av[2] = av[3] = 0ull;
                curD = dI;
            }
#pragma unroll
            for (int j = 0; j < 4; j++) {
                u64 t = ffma2(acc[i][j], rsd, mrd);
                av[j] = add2(av[j], ffma2(t, gv[j], bev[j]));
            }
        }
        {
            float2 a0 = upk(av[0]), a1 = upk(av[1]), a2 = upk(av[2]), a3 = upk(av[3]);
            float* base = g_agg + (size_t)curD * 64 + cb * 8;
            red4(base,     make_float4(a0.x, a0.y, a1.x, a1.y));
            red4(base + 4, make_float4(a2.x, a2.y, a3.x, a3.y));
        }
    }
}

// ============================ node update: 8 nodes/warp, thread = 2n x 8c ============================
__global__ void __launch_bounds__(256) k_node_upd(
    const float* __restrict__ W1, const float* __restrict__ b1,
    const float* __restrict__ W2, const float* __restrict__ b2,
    const float* __restrict__ gam, const float* __restrict__ bet)
{
    extern __shared__ float us[];
    float* sW1 = us;
    float* sW2 = us + 8192;
    float* sb1 = us + 12288;
    float* sb2 = us + 12352;
    float* sg  = us + 12416;
    float* sbe = us + 12480;
    float* sPer = us + 12544;
    int tid = threadIdx.x;
    for (int i = tid; i < 8192; i += 256) sW1[i] = W1[i];
    for (int i = tid; i < 4096; i += 256) sW2[i] = W2[i];
    if (tid < 64) { sb1[tid] = b1[tid]; sb2[tid] = b2[tid]; sg[tid] = gam[tid]; sbe[tid] = bet[tid]; }
    __syncthreads();
    int w = tid >> 5, ld = tid & 31;
    int nb = ld >> 3, cb = ld & 7;
    float* sIn  = sPer + w * (8 * 132 + 8 * 70);
    float* sMid = sIn + 8 * 132;
    const ulonglong2* W1u = (const ulonglong2*)sW1;
    const ulonglong2* W2u = (const ulonglong2*)sW2;
    const u64* b1u = (const u64*)sb1;
    const u64* b2u = (const u64*)sb2;
    const float4* gv4  = (const float4*)sg;
    const float4* bev4 = (const float4*)sbe;
    int gw = (blockIdx.x * 256 + tid) >> 5;
    int nw = (gridDim.x * 256) >> 5;
    for (int grp = gw; grp < N_NODES / 8; grp += nw) {
        int n0 = grp * 8;
        __syncwarp();
#pragma unroll
        for (int r = 0; r < 8; r++) {
            int c4 = ld * 4;
            float4 v;
            if (c4 < 64) v = *(const float4*)(g_h + (size_t)(n0 + r) * 64 + c4);
            else         v = *(const float4*)(g_agg + (size_t)(n0 + r) * 64 + (c4 - 64));
            *(float4*)&sIn[r * 132 + c4] = v;
        }
        __syncwarp();
        u64 a1[2][4];
#pragma unroll
        for (int i = 0; i < 2; i++)
#pragma unroll
            for (int j = 0; j < 4; j++) a1[i][j] = b1u[cb * 4 + j];
#pragma unroll 4
        for (int k = 0; k < 128; k++) {
            u64 d0 = dup2(sIn[(nb * 2 + 0) * 132 + k]);
            u64 d1 = dup2(sIn[(nb * 2 + 1) * 132 + k]);
            ulonglong2 w0 = W1u[k * 16 + cb * 2], w1 = W1u[k * 16 + cb * 2 + 1];
            a1[0][0] = ffma2(d0, w0.x, a1[0][0]); a1[0][1] = ffma2(d0, w0.y, a1[0][1]);
            a1[0][2] = ffma2(d0, w1.x, a1[0][2]); a1[0][3] = ffma2(d0, w1.y, a1[0][3]);
            a1[1][0] = ffma2(d1, w0.x, a1[1][0]); a1[1][1] = ffma2(d1, w0.y, a1[1][1]);
            a1[1][2] = ffma2(d1, w1.x, a1[1][2]); a1[1][3] = ffma2(d1, w1.y, a1[1][3]);
        }
#pragma unroll
        for (int i = 0; i < 2; i++) {
            int n = nb * 2 + i;
#pragma unroll
            for (int j = 0; j < 4; j++) {
                float2 v = upk(a1[i][j]);
                v.x = silu(v.x); v.y = silu(v.y);
                *(float2*)&sMid[n * 70 + cb * 8 + 2 * j] = v;
            }
        }
        __syncwarp();
        u64 a2[2][4];
#pragma unroll
        for (int i = 0; i < 2; i++)
#pragma unroll
            for (int j = 0; j < 4; j++) a2[i][j] = b2u[cb * 4 + j];
#pragma unroll 4
        for (int k = 0; k < 64; k++) {
            u64 d0 = dup2(sMid[(nb * 2 + 0) * 70 + k]);
            u64 d1 = dup2(sMid[(nb * 2 + 1) * 70 + k]);
            ulonglong2 w0 = W2u[k * 16 + cb * 2], w1 = W2u[k * 16 + cb * 2 + 1];
            a2[0][0] = ffma2(d0, w0.x, a2[0][0]); a2[0][1] = ffma2(d0, w0.y, a2[0][1]);
            a2[0][2] = ffma2(d0, w1.x, a2[0][2]); a2[0][3] = ffma2(d0, w1.y, a2[0][3]);
            a2[1][0] = ffma2(d1, w0.x, a2[1][0]); a2[1][1] = ffma2(d1, w0.y, a2[1][1]);
            a2[1][2] = ffma2(d1, w1.x, a2[1][2]); a2[1][3] = ffma2(d1, w1.y, a2[1][3]);
        }
        float4 gA = gv4[cb * 2], gB = gv4[cb * 2 + 1];
        float4 beA = bev4[cb * 2], beB = bev4[cb * 2 + 1];
#pragma unroll
        for (int i = 0; i < 2; i++) {
            float2 v0 = upk(a2[i][0]), v1 = upk(a2[i][1]), v2 = upk(a2[i][2]), v3 = upk(a2[i][3]);
            float s = v0.x + v0.y + v1.x + v1.y + v2.x + v2.y + v3.x + v3.y;
            float q = v0.x * v0.x + v0.y * v0.y + v1.x * v1.x + v1.y * v1.y
                    + v2.x * v2.x + v2.y * v2.y + v3.x * v3.x + v3.y * v3.y;
#pragma unroll
            for (int o = 4; o; o >>= 1) { s += __shfl_xor_sync(~0u, s, o); q += __shfl_xor_sync(~0u, q, o); }
            float mn = s * (1.f / 64.f);
            float rs = rsqrtf(q * (1.f / 64.f) - mn * mn + EPS);
            int n = nb * 2 + i;
            float4 h0 = *(const float4*)&sIn[n * 132 + cb * 8];
            float4 h1 = *(const float4*)&sIn[n * 132 + cb * 8 + 4];
            float4 o0, o1;
            o0.x = h0.x + (v0.x - mn) * rs * gA.x + beA.x;
            o0.y = h0.y + (v0.y - mn) * rs * gA.y + beA.y;
            o0.z = h0.z + (v1.x - mn) * rs * gA.z + beA.z;
            o0.w = h0.w + (v1.y - mn) * rs * gA.w + beA.w;
            o1.x = h1.x + (v2.x - mn) * rs * gB.x + beB.x;
            o1.y = h1.y + (v2.y - mn) * rs * gB.y + beB.y;
            o1.z = h1.z + (v3.x - mn) * rs * gB.z + beB.z;
            o1.w = h1.w + (v3.y - mn) * rs * gB.w + beB.w;
            *(float4*)(g_h + (size_t)(n0 + n) * 64 + cb * 8)     = o0;
            *(float4*)(g_h + (size_t)(n0 + n) * 64 + cb * 8 + 4) = o1;
        }
    }
}

__global__ void k_zero_pool() { int t = threadIdx.x; if (t < NG * 64) g_pool[t] = 0.f; }

// ============================ local decoder + pooling ============================
__global__ void __launch_bounds__(256) k_decoder_local(
    const float* __restrict__ W1, const float* __restrict__ b1,
    const float* __restrict__ W2, const float* __restrict__ b2,
    const int* __restrict__ batch, float* __restrict__ out)
{
    __shared__ float sW1[4096], sW2[64 * 6], sb1[64], sb2_[8];
    __shared__ float sH[8][64], sU[8][64];
    int tid = threadIdx.x;
    for (int i = tid; i < 4096; i += 256) sW1[i] = W1[i];
    for (int i = tid; i < 384; i += 256) sW2[i] = W2[i];
    if (tid < 64) sb1[tid] = b1[tid];
    if (tid < 6) sb2_[tid] = b2[tid];
    __syncthreads();
    int w = tid >> 5, ld = tid & 31, c0 = 2 * ld;
    int n = blockIdx.x * 8 + w;
    if (n >= N_NODES) return;
    float2 hv = *(const float2*)(g_h + (size_t)n * 64 + c0);
    sH[w][c0] = hv.x; sH[w][c0 + 1] = hv.y;
    __syncwarp();
    const u64* W1u = (const u64*)sW1;
    u64 acc = ((const u64*)sb1)[ld];
#pragma unroll 8
    for (int k = 0; k < 64; k++) acc = ffma2(dup2(sH[w][k]), W1u[k * 32 + ld], acc);
    float2 u = upk(acc); u.x = silu(u.x); u.y = silu(u.y);
    sU[w][c0] = u.x; sU[w][c0 + 1] = u.y;
    __syncwarp();
    if (ld < 6) {
        float o = sb2_[ld];
#pragma unroll
        for (int k = 0; k < 64; k++) o += sU[w][k] * sW2[k * 6 + ld];
        out[(size_t)n * 6 + ld] = o;
    }
    int g = __ldg(&batch[n]);
    red2(g_pool + g * 64 + c0, hv.x, hv.y);
}

// ============================ global decoder ============================
__global__ void k_global(const int* __restrict__ batch,
    const float* __restrict__ W1, const float* __restrict__ b1,
    const float* __restrict__ W2, const float* __restrict__ b2,
    float* __restrict__ out)
{
    __shared__ float sp[NG * 64];
    __shared__ float su[NG * 32];
    __shared__ int bnd[NG + 1];
    int t = threadIdx.x;
    if (t <= NG) {
        int lo = 0, hi = N_NODES;
        while (lo < hi) { int mid = (lo + hi) >> 1; if (batch[mid] < t) lo = mid + 1; else hi = mid; }
        bnd[t] = lo;
    }
    __syncthreads();
    for (int i = t; i < NG * 64; i += 128) {
        int g = i >> 6;
        float cnt = (float)(bnd[g + 1] - bnd[g]);
        sp[i] = g_pool[i] / fmaxf(cnt, 1.f);
    }
    __syncthreads();
    {
        int g = t >> 5, j = t & 31;
        float a = b1[j];
#pragma unroll
        for (int k = 0; k < 64; k++) a += sp[g * 64 + k] * W1[k * 32 + j];
        su[g * 32 + j] = silu(a);
    }
    __syncthreads();
    if (t < NG * 4) {
        int g = t >> 2, j = t & 3;
        float o = b2[j];
#pragma unroll
        for (int k = 0; k < 32; k++) o += su[g * 32 + k] * W2[k * 4 + j];
        out[(size_t)N_NODES * 6 + g * 4 + j] = o;
    }
}

extern "C" void kernel_launch(void* const* d_in, const int* in_sizes, int n_in,
                              void* d_out, int out_size) {
    (void)in_sizes; (void)n_in; (void)out_size;
    const float* x     = (const float*)d_in[0];
    const int*   ei    = (const int*)d_in[1];
    const float* eattr = (const float*)d_in[2];
    const int*   batch = (const int*)d_in[3];
    const float* casep = (const float*)d_in[4];
    const float* bcp   = (const float*)d_in[5];
    const float* encW1 = (const float*)d_in[6];  const float* encb1 = (const float*)d_in[7];
    const float* encW2 = (const float*)d_in[8];  const float* encb2 = (const float*)d_in[9];
    const float* encg  = (const float*)d_in[10]; const float* encbe = (const float*)d_in[11];
    const float* eW1   = (const float*)d_in[12]; const float* eb1   = (const float*)d_in[13];
    const float* eW2   = (const float*)d_in[14]; const float* eb2   = (const float*)d_in[15];
    const float* eg    = (const float*)d_in[16]; const float* ebe   = (const float*)d_in[17];
    const float* nW1   = (const float*)d_in[18]; const float* nb1   = (const float*)d_in[19];
    const float* nW2   = (const float*)d_in[20]; const float* nb2   = (const float*)d_in[21];
    const float* ngm   = (const float*)d_in[22]; const float* nbe   = (const float*)d_in[23];
    const float* dlW1  = (const float*)d_in[24]; const float* dlb1  = (const float*)d_in[25];
    const float* dlW2  = (const float*)d_in[26]; const float* dlb2  = (const float*)d_in[27];
    const float* dgW1  = (const float*)d_in[28]; const float* dgb1  = (const float*)d_in[29];
    const float* dgW2  = (const float*)d_in[30]; const float* dgb2  = (const float*)d_in[31];
    float* out = (float*)d_out;

    size_t preSmem  = (size_t)(8192 + 8 * (8 * 68)) * sizeof(float);            // 50176 B
    size_t edgeSmem = (size_t)(5184 + 8 * 2336) * sizeof(float);                // 95488 B
    size_t updSmem  = (size_t)(12544 + 8 * (8 * 132 + 8 * 70)) * sizeof(float); // 101888 B
    cudaFuncSetAttribute(k_node_pre, cudaFuncAttributeMaxDynamicSharedMemorySize, (int)preSmem);
    cudaFuncSetAttribute(k_edge, cudaFuncAttributeMaxDynamicSharedMemorySize, (int)edgeSmem);
    cudaFuncSetAttribute(k_node_upd, cudaFuncAttributeMaxDynamicSharedMemorySize, (int)updSmem);

    // edge sort by dst (per call; graph-capturable)
    k_zero_wp<<<(N_NODES + 255) / 256, 256>>>();
    k_hist<<<(N_EDGES + 255) / 256, 256>>>(ei);
    k_scan<<<1, 1024>>>();
    k_scatter<<<(N_EDGES + 255) / 256, 256>>>(ei);

    k_encoder<<<(N_NODES + 7) / 8, 256>>>(x, batch, casep, bcp, encW1, encb1, encW2, encb2, encg, encbe);
    for (int l = 0; l < NL; l++) {
        const float* eW1l = eW1 + (size_t)l * 133 * 64;
        k_node_pre<<<592, 256, preSmem>>>(eW1l);
        k_edge<<<296, 256, edgeSmem>>>(eattr,
                              eW1l + 128 * 64, eb1 + l * 64,
                              eW2 + (size_t)l * 4096, eb2 + l * 64,
                              eg + l * 64, ebe + l * 64);
        k_node_upd<<<296, 256, updSmem>>>(nW1 + (size_t)l * 8192, nb1 + l * 64,
                                          nW2 + (size_t)l * 4096, nb2 + l * 64,
                                          ngm + l * 64, nbe + l * 64);
    }
    k_zero_pool<<<1, 256>>>();
    k_decoder_local<<<(N_NODES + 7) / 8, 256>>>(dlW1, dlb1, dlW2, dlb2, batch, out);
    k_global<<<1, 128>>>(batch, dgW1, dgb1, dgW2, dgb2, out);
}

// round 7
// speedup vs baseline: 1.3607x; 1.0638x over previous
#include <cuda_runtime.h>

#define DINL __device__ __forceinline__

constexpr int N_NODES = 50000;
constexpr int N_EDGES = 1600000;
constexpr int NL = 5;
constexpr int NG = 4;
constexpr float EPS = 1e-5f;

__device__ float g_h  [N_NODES * 64];
__device__ float g_hd [N_NODES * 64];
__device__ float g_hs [N_NODES * 64];
__device__ float g_agg[N_NODES * 64];
__device__ float g_pool[NG * 64];
__device__ int   g_wp [N_NODES];
__device__ float g_em [(size_t)N_EDGES * 8];   // sorted-by-dst: (src,dst,a0,a1),(a2,a3,a4,0)

typedef unsigned long long u64;

DINL u64 pk2(float x, float y) { u64 r; asm("mov.b64 %0,{%1,%2};" : "=l"(r) : "f"(x), "f"(y)); return r; }
DINL u64 dup2(float x) { return pk2(x, x); }
DINL float2 upk(u64 v) { float2 r; asm("mov.b64 {%0,%1},%2;" : "=f"(r.x), "=f"(r.y) : "l"(v)); return r; }
DINL u64 ffma2(u64 a, u64 b, u64 c) {
    u64 d; asm("fma.rn.f32x2 %0,%1,%2,%3;" : "=l"(d) : "l"(a), "l"(b), "l"(c)); return d;
}
DINL u64 add2(u64 a, u64 b) {
    u64 d; asm("add.rn.f32x2 %0,%1,%2;" : "=l"(d) : "l"(a), "l"(b)); return d;
}
DINL void red2(float* p, float x, float y) {
    asm volatile("red.global.add.v2.f32 [%0], {%1,%2};" :: "l"(p), "f"(x), "f"(y) : "memory");
}
DINL void red4(float* p, float4 v) {
    asm volatile("red.global.add.v4.f32 [%0], {%1,%2,%3,%4};"
                 :: "l"(p), "f"(v.x), "f"(v.y), "f"(v.z), "f"(v.w) : "memory");
}
DINL float silu(float x) { return __fdividef(x, 1.f + __expf(-x)); }

// ============================ CSR build (edge sort by dst, payload permuted) ============================
__global__ void k_zero_wp() {
    int i = blockIdx.x * 256 + threadIdx.x;
    if (i < N_NODES) g_wp[i] = 0;
}
__global__ void k_hist(const int* __restrict__ ei) {
    int e = blockIdx.x * 256 + threadIdx.x;
    if (e < N_EDGES) atomicAdd(&g_wp[ei[N_EDGES + e]], 1);
}
__global__ void k_scan() {   // 1 block, 1024 threads
    __shared__ int part[1024];
    int t = threadIdx.x;
    const int C = 49;
    int base = t * C;
    int sum = 0;
    for (int i = 0; i < C; i++) { int idx = base + i; if (idx < N_NODES) sum += g_wp[idx]; }
    part[t] = sum;
    __syncthreads();
    for (int off = 1; off < 1024; off <<= 1) {
        int v = (t >= off) ? part[t - off] : 0;
        __syncthreads();
        part[t] += v;
        __syncthreads();
    }
    int run = (t == 0) ? 0 : part[t - 1];
    for (int i = 0; i < C; i++) {
        int idx = base + i;
        if (idx < N_NODES) { int v = g_wp[idx]; g_wp[idx] = run; run += v; }
    }
}
__global__ void k_scatter(const int* __restrict__ ei, const float* __restrict__ eattr) {
    int e = blockIdx.x * 256 + threadIdx.x;
    if (e < N_EDGES) {
        int d = ei[N_EDGES + e];
        int pos = atomicAdd(&g_wp[d], 1);
        const float* ea = eattr + (size_t)e * 5;
        float4 f0 = make_float4(__int_as_float(ei[e]), __int_as_float(d), __ldg(ea), __ldg(ea + 1));
        float4 f1 = make_float4(__ldg(ea + 2), __ldg(ea + 3), __ldg(ea + 4), 0.f);
        size_t p8 = (size_t)pos * 8;
        *(float4*)&g_em[p8]     = f0;
        *(float4*)&g_em[p8 + 4] = f1;
    }
}

// ============================ encoder ============================
__global__ void __launch_bounds__(256) k_encoder(
    const float* __restrict__ x, const int* __restrict__ batch,
    const float* __restrict__ casep, const float* __restrict__ bcp,
    const float* __restrict__ W1, const float* __restrict__ b1,
    const float* __restrict__ W2, const float* __restrict__ b2,
    const float* __restrict__ gam, const float* __restrict__ bet)
{
    __shared__ float sW1[16 * 64], sW2[64 * 64], sb1[64], sb2[64], sg[64], sbe[64];
    __shared__ float sH[8][64];
    int tid = threadIdx.x;
    for (int i = tid; i < 16 * 64; i += 256) sW1[i] = W1[i];
    for (int i = tid; i < 64 * 64; i += 256) sW2[i] = W2[i];
    if (tid < 64) { sb1[tid] = b1[tid]; sb2[tid] = b2[tid]; sg[tid] = gam[tid]; sbe[tid] = bet[tid]; }
    __syncthreads();
    int w = tid >> 5, ld = tid & 31, c0 = 2 * ld;
    int n = blockIdx.x * 8 + w;
    if (n >= N_NODES) return;
    float in[16];
#pragma unroll
    for (int k = 0; k < 8; k++) in[k] = __ldg(&x[n * 8 + k]);
    int g = __ldg(&batch[n]);
#pragma unroll
    for (int k = 0; k < 4; k++) { in[8 + k] = __ldg(&casep[g * 4 + k]); in[12 + k] = __ldg(&bcp[g * 4 + k]); }
    const u64* W1u = (const u64*)sW1;
    u64 acc = ((const u64*)sb1)[ld];
#pragma unroll
    for (int k = 0; k < 16; k++) acc = ffma2(dup2(in[k]), W1u[k * 32 + ld], acc);
    float2 a = upk(acc);
    a.x = silu(a.x); a.y = silu(a.y);
    sH[w][c0] = a.x; sH[w][c0 + 1] = a.y;
    __syncwarp();
    const u64* W2u = (const u64*)sW2;
    u64 acc2 = ((const u64*)sb2)[ld];
#pragma unroll 8
    for (int k = 0; k < 64; k++) acc2 = ffma2(dup2(sH[w][k]), W2u[k * 32 + ld], acc2);
    float2 v = upk(acc2);
    float s = v.x + v.y, q = v.x * v.x + v.y * v.y;
#pragma unroll
    for (int o = 16; o; o >>= 1) { s += __shfl_xor_sync(~0u, s, o); q += __shfl_xor_sync(~0u, q, o); }
    float m = s * (1.f / 64.f), var = q * (1.f / 64.f) - m * m, rs = rsqrtf(var + EPS);
    float2 out;
    out.x = (v.x - m) * rs * sg[c0] + sbe[c0];
    out.y = (v.y - m) * rs * sg[c0 + 1] + sbe[c0 + 1];
    *(float2*)(g_h + (size_t)n * 64 + c0) = out;
}

// ============================ node pre: Hd/Hs + zero agg, 8 nodes/warp ============================
__global__ void __launch_bounds__(256) k_node_pre(const float* __restrict__ eW1l)
{
    extern __shared__ float ps[];
    float* sWA = ps;
    float* sWB = ps + 4096;
    float* sInAll = ps + 8192;
    int tid = threadIdx.x;
    for (int i = tid; i < 4096; i += 256) { sWA[i] = eW1l[i]; sWB[i] = eW1l[4096 + i]; }
    __syncthreads();
    int w = tid >> 5, ld = tid & 31;
    int nb = ld >> 3, cb = ld & 7;
    float* sIn = sInAll + w * (8 * 68);
    const ulonglong2* WAu = (const ulonglong2*)sWA;
    const ulonglong2* WBu = (const ulonglong2*)sWB;
    int gw = (blockIdx.x * 256 + tid) >> 5;
    int nw = (gridDim.x * 256) >> 5;
    for (int grp = gw; grp < N_NODES / 8; grp += nw) {
        int n0 = grp * 8;
        __syncwarp();
#pragma unroll
        for (int r = 0; r < 4; r++) {
            int t = r * 32 + ld;
            int n = t >> 4, c4 = (t & 15) * 4;
            float4 v = *(const float4*)(g_h + (size_t)(n0 + n) * 64 + c4);
            *(float4*)&sIn[n * 68 + c4] = v;
        }
        __syncwarp();
        u64 aA[2][4], aB[2][4];
#pragma unroll
        for (int i = 0; i < 2; i++)
#pragma unroll
            for (int j = 0; j < 4; j++) { aA[i][j] = 0ull; aB[i][j] = 0ull; }
#pragma unroll 4
        for (int k = 0; k < 64; k++) {
            u64 d0 = dup2(sIn[(nb * 2 + 0) * 68 + k]);
            u64 d1 = dup2(sIn[(nb * 2 + 1) * 68 + k]);
            ulonglong2 A0 = WAu[k * 16 + cb * 2], A1 = WAu[k * 16 + cb * 2 + 1];
            ulonglong2 B0 = WBu[k * 16 + cb * 2], B1 = WBu[k * 16 + cb * 2 + 1];
            aA[0][0] = ffma2(d0, A0.x, aA[0][0]); aA[0][1] = ffma2(d0, A0.y, aA[0][1]);
            aA[0][2] = ffma2(d0, A1.x, aA[0][2]); aA[0][3] = ffma2(d0, A1.y, aA[0][3]);
            aA[1][0] = ffma2(d1, A0.x, aA[1][0]); aA[1][1] = ffma2(d1, A0.y, aA[1][1]);
            aA[1][2] = ffma2(d1, A1.x, aA[1][2]); aA[1][3] = ffma2(d1, A1.y, aA[1][3]);
            aB[0][0] = ffma2(d0, B0.x, aB[0][0]); aB[0][1] = ffma2(d0, B0.y, aB[0][1]);
            aB[0][2] = ffma2(d0, B1.x, aB[0][2]); aB[0][3] = ffma2(d0, B1.y, aB[0][3]);
            aB[1][0] = ffma2(d1, B0.x, aB[1][0]); aB[1][1] = ffma2(d1, B0.y, aB[1][1]);
            aB[1][2] = ffma2(d1, B1.x, aB[1][2]); aB[1][3] = ffma2(d1, B1.y, aB[1][3]);
        }
#pragma unroll
        for (int i = 0; i < 2; i++) {
            int n = n0 + nb * 2 + i;
            ulonglong2 t;
            t.x = aA[i][0]; t.y = aA[i][1];
            *(ulonglong2*)(g_hd + (size_t)n * 64 + cb * 8) = t;
            t.x = aA[i][2]; t.y = aA[i][3];
            *(ulonglong2*)(g_hd + (size_t)n * 64 + cb * 8 + 4) = t;
            t.x = aB[i][0]; t.y = aB[i][1];
            *(ulonglong2*)(g_hs + (size_t)n * 64 + cb * 8) = t;
            t.x = aB[i][2]; t.y = aB[i][3];
            *(ulonglong2*)(g_hs + (size_t)n * 64 + cb * 8 + 4) = t;
            *(float4*)(g_agg + (size_t)n * 64 + cb * 8)     = make_float4(0.f, 0.f, 0.f, 0.f);
            *(float4*)(g_agg + (size_t)n * 64 + cb * 8 + 4) = make_float4(0.f, 0.f, 0.f, 0.f);
        }
    }
}

// ============================ edge kernel: dense 32-edge tiles, coalesced gathers ============================
// dyn smem (floats):
//   sW2s [0,4608)   stride-72 rows (bank-conflict-free)
//   sW1c [4608,4928)  sb1[4928] sb2[4992] sg[5056] sbe[5120]
//   per-warp at 5184 + w*2368:
//     sM   [0,2304)  : phase-A = sHs staging [32 slots][68]; phase-B = m transposed [64 k][36]
//     sD   int[32] at +2304, sSrc int[32] at +2336
__global__ void __launch_bounds__(256, 2) k_edge(
    const float* __restrict__ W1c, const float* __restrict__ b1,
    const float* __restrict__ W2, const float* __restrict__ b2,
    const float* __restrict__ gam, const float* __restrict__ bet)
{
    extern __shared__ float es[];
    float* sW2s = es;
    float* sW1c = es + 4608;
    float* sb1  = es + 4928;
    float* sb2  = es + 4992;
    float* sg   = es + 5056;
    float* sbe  = es + 5120;
    float* sPer = es + 5184;
    int tid = threadIdx.x;
    for (int i = tid; i < 4096; i += 256) {
        int k = i >> 6, c = i & 63;
        sW2s[k * 72 + (c < 32 ? c : c + 4)] = W2[i];
    }
    for (int i = tid; i < 320; i += 256) sW1c[i] = W1c[i];
    if (tid < 64) { sb1[tid] = b1[tid]; sb2[tid] = b2[tid]; sg[tid] = gam[tid]; sbe[tid] = bet[tid]; }
    __syncthreads();
    int w = tid >> 5, ld = tid & 31;
    int pe = ld >> 1, half = ld & 1;          // phase-1: 16 slot-pairs x 2 halves
    int eb = ld >> 3, cb = ld & 7;            // phase-2: 4 edge-blocks x 8 col-blocks
    float* sM   = sPer + w * 2368;
    int* sD    = (int*)(sM + 2304);
    int* sSrc  = (int*)(sM + 2336);
    int wOff = (cb < 4) ? cb * 8 : 36 + (cb - 4) * 8;
    const ulonglong2* W1cu = (const ulonglong2*)sW1c;
    const ulonglong2* b1u  = (const ulonglong2*)sb1;
    const u64* b2u = (const u64*)sb2;
    u64 gv[4], bev[4];
#pragma unroll
    for (int j = 0; j < 4; j++) { gv[j] = ((const u64*)sg)[cb * 4 + j]; bev[j] = ((const u64*)sbe)[cb * 4 + j]; }
    int gw = (blockIdx.x * 256 + tid) >> 5;
    int nw = (gridDim.x * 256) >> 5;
    for (int grp = gw; grp < N_EDGES / 32; grp += nw) {
        int e0 = grp * 32;
        __syncwarp();   // WAR: previous tile's sM/sD reads done
        // ---- metadata (coalesced, 32B/edge) ----
        int sidx[2], didx[2];
        u64 ead[2][5];
#pragma unroll
        for (int sub = 0; sub < 2; sub++) {
            int slot = sub * 16 + pe;
            const float4* emp = (const float4*)&g_em[(size_t)(e0 + slot) * 8];
            float4 f0 = __ldg(emp);
            float4 f1 = __ldg(emp + 1);
            sidx[sub] = __float_as_int(f0.x);
            didx[sub] = __float_as_int(f0.y);
            ead[sub][0] = dup2(f0.z); ead[sub][1] = dup2(f0.w);
            ead[sub][2] = dup2(f1.x); ead[sub][3] = dup2(f1.y); ead[sub][4] = dup2(f1.z);
            if (half == 0) { sD[slot] = didx[sub]; sSrc[slot] = sidx[sub]; }
        }
        __syncwarp();
        // ---- cooperative coalesced hs gather into sM (as sHs[slot][68]) ----
#pragma unroll
        for (int r = 0; r < 16; r++) {
            int chunk = r * 32 + ld;         // 512 chunks = 32 edges x 16 x 16B
            int eslot = chunk >> 4;
            int c4 = (chunk & 15) * 4;
            int s = sSrc[eslot];
            float4 v = *(const float4*)(g_hs + (size_t)s * 64 + c4);
            *(float4*)&sM[eslot * 68 + c4] = v;
        }
        __syncwarp();
        // ---- phase 1: m = silu(Hd[dst]+Hs[src]+ea@W1c+b1) into REGISTERS ----
        u64 mreg[2][16];
#pragma unroll
        for (int sub = 0; sub < 2; sub++) {
            int slot = sub * 16 + pe;
            const ulonglong2* hdp = (const ulonglong2*)(g_hd + (size_t)didx[sub] * 64 + half * 32);
            const ulonglong2* hsp = (const ulonglong2*)(sM + slot * 68 + half * 32);
#pragma unroll
            for (int j = 0; j < 8; j++) {
                ulonglong2 hdj = __ldg(hdp + j);
                ulonglong2 hsj = hsp[j];
                ulonglong2 bj  = b1u[half * 8 + j];
                u64 a0 = add2(add2(hdj.x, hsj.x), bj.x);
                u64 a1 = add2(add2(hdj.y, hsj.y), bj.y);
#pragma unroll
                for (int r = 0; r < 5; r++) {
                    ulonglong2 wv = W1cu[r * 16 + half * 8 + j];
                    a0 = ffma2(ead[sub][r], wv.x, a0);
                    a1 = ffma2(ead[sub][r], wv.y, a1);
                }
                float2 v0 = upk(a0), v1 = upk(a1);
                v0.x = silu(v0.x); v0.y = silu(v0.y);
                v1.x = silu(v1.x); v1.y = silu(v1.y);
                mreg[sub][2 * j]     = pk2(v0.x, v0.y);
                mreg[sub][2 * j + 1] = pk2(v1.x, v1.y);
            }
        }
        __syncwarp();   // all sHs reads complete before overwriting sM with m
#pragma unroll
        for (int sub = 0; sub < 2; sub++) {
            int slot = sub * 16 + pe;
#pragma unroll
            for (int j = 0; j < 8; j++) {
                float2 v0 = upk(mreg[sub][2 * j]);
                float2 v1 = upk(mreg[sub][2 * j + 1]);
                int c = half * 32 + 4 * j;
                sM[(c + 0) * 36 + slot] = v0.x;
                sM[(c + 1) * 36 + slot] = v0.y;
                sM[(c + 2) * 36 + slot] = v1.x;
                sM[(c + 3) * 36 + slot] = v1.y;
            }
        }
        __syncwarp();
        // ---- phase 2 GEMM: thread = 8 edges x 8 cols ----
        u64 acc[8][4];
#pragma unroll
        for (int i = 0; i < 8; i++)
#pragma unroll
            for (int j = 0; j < 4; j++) acc[i][j] = b2u[cb * 4 + j];
#pragma unroll 4
        for (int k = 0; k < 64; k++) {
            const float4* mp = (const float4*)&sM[k * 36 + eb * 8];
            float4 m0 = mp[0], m1 = mp[1];
            ulonglong2 wA = *(const ulonglong2*)&sW2s[k * 72 + wOff];
            ulonglong2 wB = *(const ulonglong2*)&sW2s[k * 72 + wOff + 4];
            u64 mm[8];
            mm[0] = dup2(m0.x); mm[1] = dup2(m0.y); mm[2] = dup2(m0.z); mm[3] = dup2(m0.w);
            mm[4] = dup2(m1.x); mm[5] = dup2(m1.y); mm[6] = dup2(m1.z); mm[7] = dup2(m1.w);
#pragma unroll
            for (int i = 0; i < 8; i++) {
                acc[i][0] = ffma2(mm[i], wA.x, acc[i][0]);
                acc[i][1] = ffma2(mm[i], wA.y, acc[i][1]);
                acc[i][2] = ffma2(mm[i], wB.x, acc[i][2]);
                acc[i][3] = ffma2(mm[i], wB.y, acc[i][3]);
            }
        }
        // ---- LN per edge + run-length compressed scatter ----
        float s[8], q[8];
#pragma unroll
        for (int i = 0; i < 8; i++) {
            float2 v0 = upk(acc[i][0]), v1 = upk(acc[i][1]), v2 = upk(acc[i][2]), v3 = upk(acc[i][3]);
            s[i] = v0.x + v0.y + v1.x + v1.y + v2.x + v2.y + v3.x + v3.y;
            q[i] = v0.x * v0.x + v0.y * v0.y + v1.x * v1.x + v1.y * v1.y
                 + v2.x * v2.x + v2.y * v2.y + v3.x * v3.x + v3.y * v3.y;
        }
#pragma unroll
        for (int o = 4; o; o >>= 1) {
#pragma unroll
            for (int i = 0; i < 8; i++) {
                s[i] += __shfl_xor_sync(~0u, s[i], o);
                q[i] += __shfl_xor_sync(~0u, q[i], o);
            }
        }
        int curD = sD[eb * 8];
        u64 av[4] = {0ull, 0ull, 0ull, 0ull};
#pragma unroll
        for (int i = 0; i < 8; i++) {
            int dI = sD[eb * 8 + i];
            float mn = s[i] * (1.f / 64.f);
            float rs = rsqrtf(q[i] * (1.f / 64.f) - mn * mn + EPS);
            u64 rsd = dup2(rs);
            u64 mrd = dup2(-mn * rs);
            if (dI != curD) {
                float2 a0 = upk(av[0]), a1 = upk(av[1]), a2 = upk(av[2]), a3 = upk(av[3]);
                float* base = g_agg + (size_t)curD * 64 + cb * 8;
                red4(base,     make_float4(a0.x, a0.y, a1.x, a1.y));
                red4(base + 4, make_float4(a2.x, a2.y, a3.x, a3.y));
                av[0] = av[1] = av[2] = av[3] = 0ull;
                curD = dI;
            }
#pragma unroll
            for (int j = 0; j < 4; j++) {
                u64 t = ffma2(acc[i][j], rsd, mrd);
                av[j] = add2(av[j], ffma2(t, gv[j], bev[j]));
            }
        }
        {
            float2 a0 = upk(av[0]), a1 = upk(av[1]), a2 = upk(av[2]), a3 = upk(av[3]);
            float* base = g_agg + (size_t)curD * 64 + cb * 8;
            red4(base,     make_float4(a0.x, a0.y, a1.x, a1.y));
            red4(base + 4, make_float4(a2.x, a2.y, a3.x, a3.y));
        }
    }
}

// ============================ node update: 8 nodes/warp, thread = 2n x 8c ============================
__global__ void __launch_bounds__(256) k_node_upd(
    const float* __restrict__ W1, const float* __restrict__ b1,
    const float* __restrict__ W2, const float* __restrict__ b2,
    const float* __restrict__ gam, const float* __restrict__ bet)
{
    extern __shared__ float us[];
    float* sW1 = us;
    float* sW2 = us + 8192;
    float* sb1 = us + 12288;
    float* sb2 = us + 12352;
    float* sg  = us + 12416;
    float* sbe = us + 12480;
    float* sPer = us + 12544;
    int tid = threadIdx.x;
    for (int i = tid; i < 8192; i += 256) sW1[i] = W1[i];
    for (int i = tid; i < 4096; i += 256) sW2[i] = W2[i];
    if (tid < 64) { sb1[tid] = b1[tid]; sb2[tid] = b2[tid]; sg[tid] = gam[tid]; sbe[tid] = bet[tid]; }
    __syncthreads();
    int w = tid >> 5, ld = tid & 31;
    int nb = ld >> 3, cb = ld & 7;
    float* sIn  = sPer + w * (8 * 132 + 8 * 70);
    float* sMid = sIn + 8 * 132;
    const ulonglong2* W1u = (const ulonglong2*)sW1;
    const ulonglong2* W2u = (const ulonglong2*)sW2;
    const u64* b1u = (const u64*)sb1;
    const u64* b2u = (const u64*)sb2;
    const float4* gv4  = (const float4*)sg;
    const float4* bev4 = (const float4*)sbe;
    int gw = (blockIdx.x * 256 + tid) >> 5;
    int nw = (gridDim.x * 256) >> 5;
    for (int grp = gw; grp < N_NODES / 8; grp += nw) {
        int n0 = grp * 8;
        __syncwarp();
#pragma unroll
        for (int r = 0; r < 8; r++) {
            int c4 = ld * 4;
            float4 v;
            if (c4 < 64) v = *(const float4*)(g_h + (size_t)(n0 + r) * 64 + c4);
            else         v = *(const float4*)(g_agg + (size_t)(n0 + r) * 64 + (c4 - 64));
            *(float4*)&sIn[r * 132 + c4] = v;
        }
        __syncwarp();
        u64 a1[2][4];
#pragma unroll
        for (int i = 0; i < 2; i++)
#pragma unroll
            for (int j = 0; j < 4; j++) a1[i][j] = b1u[cb * 4 + j];
#pragma unroll 4
        for (int k = 0; k < 128; k++) {
            u64 d0 = dup2(sIn[(nb * 2 + 0) * 132 + k]);
            u64 d1 = dup2(sIn[(nb * 2 + 1) * 132 + k]);
            ulonglong2 w0 = W1u[k * 16 + cb * 2], w1 = W1u[k * 16 + cb * 2 + 1];
            a1[0][0] = ffma2(d0, w0.x, a1[0][0]); a1[0][1] = ffma2(d0, w0.y, a1[0][1]);
            a1[0][2] = ffma2(d0, w1.x, a1[0][2]); a1[0][3] = ffma2(d0, w1.y, a1[0][3]);
            a1[1][0] = ffma2(d1, w0.x, a1[1][0]); a1[1][1] = ffma2(d1, w0.y, a1[1][1]);
            a1[1][2] = ffma2(d1, w1.x, a1[1][2]); a1[1][3] = ffma2(d1, w1.y, a1[1][3]);
        }
#pragma unroll
        for (int i = 0; i < 2; i++) {
            int n = nb * 2 + i;
#pragma unroll
            for (int j = 0; j < 4; j++) {
                float2 v = upk(a1[i][j]);
                v.x = silu(v.x); v.y = silu(v.y);
                *(float2*)&sMid[n * 70 + cb * 8 + 2 * j] = v;
            }
        }
        __syncwarp();
        u64 a2[2][4];
#pragma unroll
        for (int i = 0; i < 2; i++)
#pragma unroll
            for (int j = 0; j < 4; j++) a2[i][j] = b2u[cb * 4 + j];
#pragma unroll 4
        for (int k = 0; k < 64; k++) {
            u64 d0 = dup2(sMid[(nb * 2 + 0) * 70 + k]);
            u64 d1 = dup2(sMid[(nb * 2 + 1) * 70 + k]);
            ulonglong2 w0 = W2u[k * 16 + cb * 2], w1 = W2u[k * 16 + cb * 2 + 1];
            a2[0][0] = ffma2(d0, w0.x, a2[0][0]); a2[0][1] = ffma2(d0, w0.y, a2[0][1]);
            a2[0][2] = ffma2(d0, w1.x, a2[0][2]); a2[0][3] = ffma2(d0, w1.y, a2[0][3]);
            a2[1][0] = ffma2(d1, w0.x, a2[1][0]); a2[1][1] = ffma2(d1, w0.y, a2[1][1]);
            a2[1][2] = ffma2(d1, w1.x, a2[1][2]); a2[1][3] = ffma2(d1, w1.y, a2[1][3]);
        }
        float4 gA = gv4[cb * 2], gB = gv4[cb * 2 + 1];
        float4 beA = bev4[cb * 2], beB = bev4[cb * 2 + 1];
#pragma unroll
        for (int i = 0; i < 2; i++) {
            float2 v0 = upk(a2[i][0]), v1 = upk(a2[i][1]), v2 = upk(a2[i][2]), v3 = upk(a2[i][3]);
            float s = v0.x + v0.y + v1.x + v1.y + v2.x + v2.y + v3.x + v3.y;
            float q = v0.x * v0.x + v0.y * v0.y + v1.x * v1.x + v1.y * v1.y
                    + v2.x * v2.x + v2.y * v2.y + v3.x * v3.x + v3.y * v3.y;
#pragma unroll
            for (int o = 4; o; o >>= 1) { s += __shfl_xor_sync(~0u, s, o); q += __shfl_xor_sync(~0u, q, o); }
            float mn = s * (1.f / 64.f);
            float rs = rsqrtf(q * (1.f / 64.f) - mn * mn + EPS);
            int n = nb * 2 + i;
            float4 h0 = *(const float4*)&sIn[n * 132 + cb * 8];
            float4 h1 = *(const float4*)&sIn[n * 132 + cb * 8 + 4];
            float4 o0, o1;
            o0.x = h0.x + (v0.x - mn) * rs * gA.x + beA.x;
            o0.y = h0.y + (v0.y - mn) * rs * gA.y + beA.y;
            o0.z = h0.z + (v1.x - mn) * rs * gA.z + beA.z;
            o0.w = h0.w + (v1.y - mn) * rs * gA.w + beA.w;
            o1.x = h1.x + (v2.x - mn) * rs * gB.x + beB.x;
            o1.y = h1.y + (v2.y - mn) * rs * gB.y + beB.y;
            o1.z = h1.z + (v3.x - mn) * rs * gB.z + beB.z;
            o1.w = h1.w + (v3.y - mn) * rs * gB.w + beB.w;
            *(float4*)(g_h + (size_t)(n0 + n) * 64 + cb * 8)     = o0;
            *(float4*)(g_h + (size_t)(n0 + n) * 64 + cb * 8 + 4) = o1;
        }
    }
}

__global__ void k_zero_pool() { int t = threadIdx.x; if (t < NG * 64) g_pool[t] = 0.f; }

// ============================ local decoder + pooling ============================
__global__ void __launch_bounds__(256) k_decoder_local(
    const float* __restrict__ W1, const float* __restrict__ b1,
    const float* __restrict__ W2, const float* __restrict__ b2,
    const int* __restrict__ batch, float* __restrict__ out)
{
    __shared__ float sW1[4096], sW2[64 * 6], sb1[64], sb2_[8];
    __shared__ float sH[8][64], sU[8][64];
    int tid = threadIdx.x;
    for (int i = tid; i < 4096; i += 256) sW1[i] = W1[i];
    for (int i = tid; i < 384; i += 256) sW2[i] = W2[i];
    if (tid < 64) sb1[tid] = b1[tid];
    if (tid < 6) sb2_[tid] = b2[tid];
    __syncthreads();
    int w = tid >> 5, ld = tid & 31, c0 = 2 * ld;
    int n = blockIdx.x * 8 + w;
    if (n >= N_NODES) return;
    float2 hv = *(const float2*)(g_h + (size_t)n * 64 + c0);
    sH[w][c0] = hv.x; sH[w][c0 + 1] = hv.y;
    __syncwarp();
    const u64* W1u = (const u64*)sW1;
    u64 acc = ((const u64*)sb1)[ld];
#pragma unroll 8
    for (int k = 0; k < 64; k++) acc = ffma2(dup2(sH[w][k]), W1u[k * 32 + ld], acc);
    float2 u = upk(acc); u.x = silu(u.x); u.y = silu(u.y);
    sU[w][c0] = u.x; sU[w][c0 + 1] = u.y;
    __syncwarp();
    if (ld < 6) {
        float o = sb2_[ld];
#pragma unroll
        for (int k = 0; k < 64; k++) o += sU[w][k] * sW2[k * 6 + ld];
        out[(size_t)n * 6 + ld] = o;
    }
    int g = __ldg(&batch[n]);
    red2(g_pool + g * 64 + c0, hv.x, hv.y);
}

// ============================ global decoder ============================
__global__ void k_global(const int* __restrict__ batch,
    const float* __restrict__ W1, const float* __restrict__ b1,
    const float* __restrict__ W2, const float* __restrict__ b2,
    float* __restrict__ out)
{
    __shared__ float sp[NG * 64];
    __shared__ float su[NG * 32];
    __shared__ int bnd[NG + 1];
    int t = threadIdx.x;
    if (t <= NG) {
        int lo = 0, hi = N_NODES;
        while (lo < hi) { int mid = (lo + hi) >> 1; if (batch[mid] < t) lo = mid + 1; else hi = mid; }
        bnd[t] = lo;
    }
    __syncthreads();
    for (int i = t; i < NG * 64; i += 128) {
        int g = i >> 6;
        float cnt = (float)(bnd[g + 1] - bnd[g]);
        sp[i] = g_pool[i] / fmaxf(cnt, 1.f);
    }
    __syncthreads();
    {
        int g = t >> 5, j = t & 31;
        float a = b1[j];
#pragma unroll
        for (int k = 0; k < 64; k++) a += sp[g * 64 + k] * W1[k * 32 + j];
        su[g * 32 + j] = silu(a);
    }
    __syncthreads();
    if (t < NG * 4) {
        int g = t >> 2, j = t & 3;
        float o = b2[j];
#pragma unroll
        for (int k = 0; k < 32; k++) o += su[g * 32 + k] * W2[k * 4 + j];
        out[(size_t)N_NODES * 6 + g * 4 + j] = o;
    }
}

extern "C" void kernel_launch(void* const* d_in, const int* in_sizes, int n_in,
                              void* d_out, int out_size) {
    (void)in_sizes; (void)n_in; (void)out_size;
    const float* x     = (const float*)d_in[0];
    const int*   ei    = (const int*)d_in[1];
    const float* eattr = (const float*)d_in[2];
    const int*   batch = (const int*)d_in[3];
    const float* casep = (const float*)d_in[4];
    const float* bcp   = (const float*)d_in[5];
    const float* encW1 = (const float*)d_in[6];  const float* encb1 = (const float*)d_in[7];
    const float* encW2 = (const float*)d_in[8];  const float* encb2 = (const float*)d_in[9];
    const float* encg  = (const float*)d_in[10]; const float* encbe = (const float*)d_in[11];
    const float* eW1   = (const float*)d_in[12]; const float* eb1   = (const float*)d_in[13];
    const float* eW2   = (const float*)d_in[14]; const float* eb2   = (const float*)d_in[15];
    const float* eg    = (const float*)d_in[16]; const float* ebe   = (const float*)d_in[17];
    const float* nW1   = (const float*)d_in[18]; const float* nb1   = (const float*)d_in[19];
    const float* nW2   = (const float*)d_in[20]; const float* nb2   = (const float*)d_in[21];
    const float* ngm   = (const float*)d_in[22]; const float* nbe   = (const float*)d_in[23];
    const float* dlW1  = (const float*)d_in[24]; const float* dlb1  = (const float*)d_in[25];
    const float* dlW2  = (const float*)d_in[26]; const float* dlb2  = (const float*)d_in[27];
    const float* dgW1  = (const float*)d_in[28]; const float* dgb1  = (const float*)d_in[29];
    const float* dgW2  = (const float*)d_in[30]; const float* dgb2  = (const float*)d_in[31];
    float* out = (float*)d_out;

    size_t preSmem  = (size_t)(8192 + 8 * (8 * 68)) * sizeof(float);            // 50176 B
    size_t edgeSmem = (size_t)(5184 + 8 * 2368) * sizeof(float);                // 96512 B
    size_t updSmem  = (size_t)(12544 + 8 * (8 * 132 + 8 * 70)) * sizeof(float); // 101888 B
    cudaFuncSetAttribute(k_node_pre, cudaFuncAttributeMaxDynamicSharedMemorySize, (int)preSmem);
    cudaFuncSetAttribute(k_edge, cudaFuncAttributeMaxDynamicSharedMemorySize, (int)edgeSmem);
    cudaFuncSetAttribute(k_node_upd, cudaFuncAttributeMaxDynamicSharedMemorySize, (int)updSmem);

    // edge sort by dst + payload permutation (per call; graph-capturable)
    k_zero_wp<<<(N_NODES + 255) / 256, 256>>>();
    k_hist<<<(N_EDGES + 255) / 256, 256>>>(ei);
    k_scan<<<1, 1024>>>();
    k_scatter<<<(N_EDGES + 255) / 256, 256>>>(ei, eattr);

    k_encoder<<<(N_NODES + 7) / 8, 256>>>(x, batch, casep, bcp, encW1, encb1, encW2, encb2, encg, encbe);
    for (int l = 0; l < NL; l++) {
        const float* eW1l = eW1 + (size_t)l * 133 * 64;
        k_node_pre<<<592, 256, preSmem>>>(eW1l);
        k_edge<<<296, 256, edgeSmem>>>(eW1l + 128 * 64, eb1 + l * 64,
                              eW2 + (size_t)l * 4096, eb2 + l * 64,
                              eg + l * 64, ebe + l * 64);
        k_node_upd<<<296, 256, updSmem>>>(nW1 + (size_t)l * 8192, nb1 + l * 64,
                                          nW2 + (size_t)l * 4096, nb2 + l * 64,
                                          ngm + l * 64, nbe + l * 64);
    }
    k_zero_pool<<<1, 256>>>();
    k_decoder_local<<<(N_NODES + 7) / 8, 256>>>(dlW1, dlb1, dlW2, dlb2, batch, out);
    k_global<<<1, 128>>>(batch, dgW1, dgb1, dgW2, dgb2, out);
}

// round 8
// speedup vs baseline: 1.3625x; 1.0013x over previous
#include <cuda_runtime.h>

#define DINL __device__ __forceinline__

constexpr int N_NODES = 50000;
constexpr int N_EDGES = 1600000;
constexpr int NL = 5;
constexpr int NG = 4;
constexpr float EPS = 1e-5f;

__device__ float g_h  [N_NODES * 64];
__device__ float g_hd [N_NODES * 64];
__device__ float g_hs [N_NODES * 64];
__device__ float g_agg[N_NODES * 64];
__device__ float g_pool[NG * 64];
__device__ int   g_wp [N_NODES];
__device__ float g_em [(size_t)N_EDGES * 8];   // sorted-by-dst: (src,dst,a0,a1),(a2,a3,a4,0)

typedef unsigned long long u64;

DINL u64 pk2(float x, float y) { u64 r; asm("mov.b64 %0,{%1,%2};" : "=l"(r) : "f"(x), "f"(y)); return r; }
DINL u64 dup2(float x) { return pk2(x, x); }
DINL float2 upk(u64 v) { float2 r; asm("mov.b64 {%0,%1},%2;" : "=f"(r.x), "=f"(r.y) : "l"(v)); return r; }
DINL u64 ffma2(u64 a, u64 b, u64 c) {
    u64 d; asm("fma.rn.f32x2 %0,%1,%2,%3;" : "=l"(d) : "l"(a), "l"(b), "l"(c)); return d;
}
DINL u64 add2(u64 a, u64 b) {
    u64 d; asm("add.rn.f32x2 %0,%1,%2;" : "=l"(d) : "l"(a), "l"(b)); return d;
}
DINL void red2(float* p, float x, float y) {
    asm volatile("red.global.add.v2.f32 [%0], {%1,%2};" :: "l"(p), "f"(x), "f"(y) : "memory");
}
DINL void red4(float* p, float4 v) {
    asm volatile("red.global.add.v4.f32 [%0], {%1,%2,%3,%4};"
                 :: "l"(p), "f"(v.x), "f"(v.y), "f"(v.z), "f"(v.w) : "memory");
}
DINL float silu(float x) { return __fdividef(x, 1.f + __expf(-x)); }

// ============================ CSR build (edge sort by dst, payload permuted) ============================
__global__ void k_zero_wp() {
    int i = blockIdx.x * 256 + threadIdx.x;
    if (i < N_NODES) g_wp[i] = 0;
}
__global__ void k_hist(const int* __restrict__ ei) {
    int e = blockIdx.x * 256 + threadIdx.x;
    if (e < N_EDGES) atomicAdd(&g_wp[ei[N_EDGES + e]], 1);
}
__global__ void k_scan() {   // 1 block, 1024 threads
    __shared__ int part[1024];
    int t = threadIdx.x;
    const int C = 49;
    int base = t * C;
    int sum = 0;
    for (int i = 0; i < C; i++) { int idx = base + i; if (idx < N_NODES) sum += g_wp[idx]; }
    part[t] = sum;
    __syncthreads();
    for (int off = 1; off < 1024; off <<= 1) {
        int v = (t >= off) ? part[t - off] : 0;
        __syncthreads();
        part[t] += v;
        __syncthreads();
    }
    int run = (t == 0) ? 0 : part[t - 1];
    for (int i = 0; i < C; i++) {
        int idx = base + i;
        if (idx < N_NODES) { int v = g_wp[idx]; g_wp[idx] = run; run += v; }
    }
}
__global__ void k_scatter(const int* __restrict__ ei, const float* __restrict__ eattr) {
    int e = blockIdx.x * 256 + threadIdx.x;
    if (e < N_EDGES) {
        int d = ei[N_EDGES + e];
        int pos = atomicAdd(&g_wp[d], 1);
        const float* ea = eattr + (size_t)e * 5;
        float4 f0 = make_float4(__int_as_float(ei[e]), __int_as_float(d), __ldg(ea), __ldg(ea + 1));
        float4 f1 = make_float4(__ldg(ea + 2), __ldg(ea + 3), __ldg(ea + 4), 0.f);
        size_t p8 = (size_t)pos * 8;
        *(float4*)&g_em[p8]     = f0;
        *(float4*)&g_em[p8 + 4] = f1;
    }
}

// ============================ encoder ============================
__global__ void __launch_bounds__(256) k_encoder(
    const float* __restrict__ x, const int* __restrict__ batch,
    const float* __restrict__ casep, const float* __restrict__ bcp,
    const float* __restrict__ W1, const float* __restrict__ b1,
    const float* __restrict__ W2, const float* __restrict__ b2,
    const float* __restrict__ gam, const float* __restrict__ bet)
{
    __shared__ float sW1[16 * 64], sW2[64 * 64], sb1[64], sb2[64], sg[64], sbe[64];
    __shared__ float sH[8][64];
    int tid = threadIdx.x;
    for (int i = tid; i < 16 * 64; i += 256) sW1[i] = W1[i];
    for (int i = tid; i < 64 * 64; i += 256) sW2[i] = W2[i];
    if (tid < 64) { sb1[tid] = b1[tid]; sb2[tid] = b2[tid]; sg[tid] = gam[tid]; sbe[tid] = bet[tid]; }
    __syncthreads();
    int w = tid >> 5, ld = tid & 31, c0 = 2 * ld;
    int n = blockIdx.x * 8 + w;
    if (n >= N_NODES) return;
    float in[16];
#pragma unroll
    for (int k = 0; k < 8; k++) in[k] = __ldg(&x[n * 8 + k]);
    int g = __ldg(&batch[n]);
#pragma unroll
    for (int k = 0; k < 4; k++) { in[8 + k] = __ldg(&casep[g * 4 + k]); in[12 + k] = __ldg(&bcp[g * 4 + k]); }
    const u64* W1u = (const u64*)sW1;
    u64 acc = ((const u64*)sb1)[ld];
#pragma unroll
    for (int k = 0; k < 16; k++) acc = ffma2(dup2(in[k]), W1u[k * 32 + ld], acc);
    float2 a = upk(acc);
    a.x = silu(a.x); a.y = silu(a.y);
    sH[w][c0] = a.x; sH[w][c0 + 1] = a.y;
    __syncwarp();
    const u64* W2u = (const u64*)sW2;
    u64 acc2 = ((const u64*)sb2)[ld];
#pragma unroll 8
    for (int k = 0; k < 64; k++) acc2 = ffma2(dup2(sH[w][k]), W2u[k * 32 + ld], acc2);
    float2 v = upk(acc2);
    float s = v.x + v.y, q = v.x * v.x + v.y * v.y;
#pragma unroll
    for (int o = 16; o; o >>= 1) { s += __shfl_xor_sync(~0u, s, o); q += __shfl_xor_sync(~0u, q, o); }
    float m = s * (1.f / 64.f), var = q * (1.f / 64.f) - m * m, rs = rsqrtf(var + EPS);
    float2 out;
    out.x = (v.x - m) * rs * sg[c0] + sbe[c0];
    out.y = (v.y - m) * rs * sg[c0 + 1] + sbe[c0 + 1];
    *(float2*)(g_h + (size_t)n * 64 + c0) = out;
}

// ============================ node pre: Hd/Hs + zero agg, 8 nodes/warp ============================
__global__ void __launch_bounds__(256) k_node_pre(const float* __restrict__ eW1l)
{
    extern __shared__ float ps[];
    float* sWA = ps;
    float* sWB = ps + 4096;
    float* sInAll = ps + 8192;
    int tid = threadIdx.x;
    for (int i = tid; i < 4096; i += 256) { sWA[i] = eW1l[i]; sWB[i] = eW1l[4096 + i]; }
    __syncthreads();
    int w = tid >> 5, ld = tid & 31;
    int nb = ld >> 3, cb = ld & 7;
    float* sIn = sInAll + w * (8 * 68);
    const ulonglong2* WAu = (const ulonglong2*)sWA;
    const ulonglong2* WBu = (const ulonglong2*)sWB;
    int gw = (blockIdx.x * 256 + tid) >> 5;
    int nw = (gridDim.x * 256) >> 5;
    for (int grp = gw; grp < N_NODES / 8; grp += nw) {
        int n0 = grp * 8;
        __syncwarp();
#pragma unroll
        for (int r = 0; r < 4; r++) {
            int t = r * 32 + ld;
            int n = t >> 4, c4 = (t & 15) * 4;
            float4 v = *(const float4*)(g_h + (size_t)(n0 + n) * 64 + c4);
            *(float4*)&sIn[n * 68 + c4] = v;
        }
        __syncwarp();
        u64 aA[2][4], aB[2][4];
#pragma unroll
        for (int i = 0; i < 2; i++)
#pragma unroll
            for (int j = 0; j < 4; j++) { aA[i][j] = 0ull; aB[i][j] = 0ull; }
#pragma unroll 4
        for (int k = 0; k < 64; k++) {
            u64 d0 = dup2(sIn[(nb * 2 + 0) * 68 + k]);
            u64 d1 = dup2(sIn[(nb * 2 + 1) * 68 + k]);
            ulonglong2 A0 = WAu[k * 16 + cb * 2], A1 = WAu[k * 16 + cb * 2 + 1];
            ulonglong2 B0 = WBu[k * 16 + cb * 2], B1 = WBu[k * 16 + cb * 2 + 1];
            aA[0][0] = ffma2(d0, A0.x, aA[0][0]); aA[0][1] = ffma2(d0, A0.y, aA[0][1]);
            aA[0][2] = ffma2(d0, A1.x, aA[0][2]); aA[0][3] = ffma2(d0, A1.y, aA[0][3]);
            aA[1][0] = ffma2(d1, A0.x, aA[1][0]); aA[1][1] = ffma2(d1, A0.y, aA[1][1]);
            aA[1][2] = ffma2(d1, A1.x, aA[1][2]); aA[1][3] = ffma2(d1, A1.y, aA[1][3]);
            aB[0][0] = ffma2(d0, B0.x, aB[0][0]); aB[0][1] = ffma2(d0, B0.y, aB[0][1]);
            aB[0][2] = ffma2(d0, B1.x, aB[0][2]); aB[0][3] = ffma2(d0, B1.y, aB[0][3]);
            aB[1][0] = ffma2(d1, B0.x, aB[1][0]); aB[1][1] = ffma2(d1, B0.y, aB[1][1]);
            aB[1][2] = ffma2(d1, B1.x, aB[1][2]); aB[1][3] = ffma2(d1, B1.y, aB[1][3]);
        }
#pragma unroll
        for (int i = 0; i < 2; i++) {
            int n = n0 + nb * 2 + i;
            ulonglong2 t;
            t.x = aA[i][0]; t.y = aA[i][1];
            *(ulonglong2*)(g_hd + (size_t)n * 64 + cb * 8) = t;
            t.x = aA[i][2]; t.y = aA[i][3];
            *(ulonglong2*)(g_hd + (size_t)n * 64 + cb * 8 + 4) = t;
            t.x = aB[i][0]; t.y = aB[i][1];
            *(ulonglong2*)(g_hs + (size_t)n * 64 + cb * 8) = t;
            t.x = aB[i][2]; t.y = aB[i][3];
            *(ulonglong2*)(g_hs + (size_t)n * 64 + cb * 8 + 4) = t;
            *(float4*)(g_agg + (size_t)n * 64 + cb * 8)     = make_float4(0.f, 0.f, 0.f, 0.f);
            *(float4*)(g_agg + (size_t)n * 64 + cb * 8 + 4) = make_float4(0.f, 0.f, 0.f, 0.f);
        }
    }
}

// ============================ edge kernel: dense 32-edge tiles, coalesced gathers ============================
// dyn smem (floats):
//   sW2s [0,4608)   stride-72 rows (bank-conflict-free)
//   sW1c [4608,4928)  sb1[4928] sb2[4992] sg[5056] sbe[5120]
//   per-warp at 5184 + w*2368:
//     sM   [0,2304)  : phase-A = sHs staging [32 slots][68]; phase-B = m transposed [64 k][36]
//     sD   int[32] at +2304, sSrc int[32] at +2336
__global__ void __launch_bounds__(256, 2) k_edge(
    const float* __restrict__ W1c, const float* __restrict__ b1,
    const float* __restrict__ W2, const float* __restrict__ b2,
    const float* __restrict__ gam, const float* __restrict__ bet)
{
    extern __shared__ float es[];
    float* sW2s = es;
    float* sW1c = es + 4608;
    float* sb1  = es + 4928;
    float* sb2  = es + 4992;
    float* sg   = es + 5056;
    float* sbe  = es + 5120;
    float* sPer = es + 5184;
    int tid = threadIdx.x;
    for (int i = tid; i < 4096; i += 256) {
        int k = i >> 6, c = i & 63;
        sW2s[k * 72 + (c < 32 ? c : c + 4)] = W2[i];
    }
    for (int i = tid; i < 320; i += 256) sW1c[i] = W1c[i];
    if (tid < 64) { sb1[tid] = b1[tid]; sb2[tid] = b2[tid]; sg[tid] = gam[tid]; sbe[tid] = bet[tid]; }
    __syncthreads();
    int w = tid >> 5, ld = tid & 31;
    int pe = ld >> 1, half = ld & 1;          // phase-1: 16 slot-pairs x 2 halves
    int eb = ld >> 3, cb = ld & 7;            // phase-2: 4 edge-blocks x 8 col-blocks
    float* sM   = sPer + w * 2368;
    int* sD    = (int*)(sM + 2304);
    int* sSrc  = (int*)(sM + 2336);
    int wOff = (cb < 4) ? cb * 8 : 36 + (cb - 4) * 8;
    const ulonglong2* W1cu = (const ulonglong2*)sW1c;
    const ulonglong2* b1u  = (const ulonglong2*)sb1;
    const u64* b2u = (const u64*)sb2;
    u64 gv[4], bev[4];
#pragma unroll
    for (int j = 0; j < 4; j++) { gv[j] = ((const u64*)sg)[cb * 4 + j]; bev[j] = ((const u64*)sbe)[cb * 4 + j]; }
    int gw = (blockIdx.x * 256 + tid) >> 5;
    int nw = (gridDim.x * 256) >> 5;
    for (int grp = gw; grp < N_EDGES / 32; grp += nw) {
        int e0 = grp * 32;
        __syncwarp();   // WAR: previous tile's sM/sD reads done
        // ---- metadata (coalesced, 32B/edge) ----
        int sidx[2], didx[2];
        u64 ead[2][5];
#pragma unroll
        for (int sub = 0; sub < 2; sub++) {
            int slot = sub * 16 + pe;
            const float4* emp = (const float4*)&g_em[(size_t)(e0 + slot) * 8];
            float4 f0 = __ldg(emp);
            float4 f1 = __ldg(emp + 1);
            sidx[sub] = __float_as_int(f0.x);
            didx[sub] = __float_as_int(f0.y);
            ead[sub][0] = dup2(f0.z); ead[sub][1] = dup2(f0.w);
            ead[sub][2] = dup2(f1.x); ead[sub][3] = dup2(f1.y); ead[sub][4] = dup2(f1.z);
            if (half == 0) { sD[slot] = didx[sub]; sSrc[slot] = sidx[sub]; }
        }
        __syncwarp();
        // ---- cooperative coalesced hs gather into sM (as sHs[slot][68]) ----
#pragma unroll
        for (int r = 0; r < 16; r++) {
            int chunk = r * 32 + ld;         // 512 chunks = 32 edges x 16 x 16B
            int eslot = chunk >> 4;
            int c4 = (chunk & 15) * 4;
            int s = sSrc[eslot];
            float4 v = *(const float4*)(g_hs + (size_t)s * 64 + c4);
            *(float4*)&sM[eslot * 68 + c4] = v;
        }
        __syncwarp();
        // ---- phase 1: m = silu(Hd[dst]+Hs[src]+ea@W1c+b1) into REGISTERS ----
        u64 mreg[2][16];
#pragma unroll
        for (int sub = 0; sub < 2; sub++) {
            int slot = sub * 16 + pe;
            const ulonglong2* hdp = (const ulonglong2*)(g_hd + (size_t)didx[sub] * 64 + half * 32);
            const ulonglong2* hsp = (const ulonglong2*)(sM + slot * 68 + half * 32);
#pragma unroll
            for (int j = 0; j < 8; j++) {
                ulonglong2 hdj = __ldg(hdp + j);
                ulonglong2 hsj = hsp[j];
                ulonglong2 bj  = b1u[half * 8 + j];
                u64 a0 = add2(add2(hdj.x, hsj.x), bj.x);
                u64 a1 = add2(add2(hdj.y, hsj.y), bj.y);
#pragma unroll
                for (int r = 0; r < 5; r++) {
                    ulonglong2 wv = W1cu[r * 16 + half * 8 + j];
                    a0 = ffma2(ead[sub][r], wv.x, a0);
                    a1 = ffma2(ead[sub][r], wv.y, a1);
                }
                float2 v0 = upk(a0), v1 = upk(a1);
                v0.x = silu(v0.x); v0.y = silu(v0.y);
                v1.x = silu(v1.x); v1.y = silu(v1.y);
                mreg[sub][2 * j]     = pk2(v0.x, v0.y);
                mreg[sub][2 * j + 1] = pk2(v1.x, v1.y);
            }
        }
        __syncwarp();   // all sHs reads complete before overwriting sM with m
#pragma unroll
        for (int sub = 0; sub < 2; sub++) {
            int slot = sub * 16 + pe;
#pragma unroll
            for (int j = 0; j < 8; j++) {
                float2 v0 = upk(mreg[sub][2 * j]);
                float2 v1 = upk(mreg[sub][2 * j + 1]);
                int c = half * 32 + 4 * j;
                sM[(c + 0) * 36 + slot] = v0.x;
                sM[(c + 1) * 36 + slot] = v0.y;
                sM[(c + 2) * 36 + slot] = v1.x;
                sM[(c + 3) * 36 + slot] = v1.y;
            }
        }
        __syncwarp();
        // ---- phase 2 GEMM: thread = 8 edges x 8 cols ----
        u64 acc[8][4];
#pragma unroll
        for (int i = 0; i < 8; i++)
#pragma unroll
            for (int j = 0; j < 4; j++) acc[i][j] = b2u[cb * 4 + j];
#pragma unroll 4
        for (int k = 0; k < 64; k++) {
            const float4* mp = (const float4*)&sM[k * 36 + eb * 8];
            float4 m0 = mp[0], m1 = mp[1];
            ulonglong2 wA = *(const ulonglong2*)&sW2s[k * 72 + wOff];
            ulonglong2 wB = *(const ulonglong2*)&sW2s[k * 72 + wOff + 4];
            u64 mm[8];
            mm[0] = dup2(m0.x); mm[1] = dup2(m0.y); mm[2] = dup2(m0.z); mm[3] = dup2(m0.w);
            mm[4] = dup2(m1.x); mm[5] = dup2(m1.y); mm[6] = dup2(m1.z); mm[7] = dup2(m1.w);
#pragma unroll
            for (int i = 0; i < 8; i++) {
                acc[i][0] = ffma2(mm[i], wA.x, acc[i][0]);
                acc[i][1] = ffma2(mm[i], wA.y, acc[i][1]);
                acc[i][2] = ffma2(mm[i], wB.x, acc[i][2]);
                acc[i][3] = ffma2(mm[i], wB.y, acc[i][3]);
            }
        }
        // ---- LN per edge + run-length compressed scatter ----
        float s[8], q[8];
#pragma unroll
        for (int i = 0; i < 8; i++) {
            float2 v0 = upk(acc[i][0]), v1 = upk(acc[i][1]), v2 = upk(acc[i][2]), v3 = upk(acc[i][3]);
            s[i] = v0.x + v0.y + v1.x + v1.y + v2.x + v2.y + v3.x + v3.y;
            q[i] = v0.x * v0.x + v0.y * v0.y + v1.x * v1.x + v1.y * v1.y
                 + v2.x * v2.x + v2.y * v2.y + v3.x * v3.x + v3.y * v3.y;
        }
#pragma unroll
        for (int o = 4; o; o >>= 1) {
#pragma unroll
            for (int i = 0; i < 8; i++) {
                s[i] += __shfl_xor_sync(~0u, s[i], o);
                q[i] += __shfl_xor_sync(~0u, q[i], o);
            }
        }
        int curD = sD[eb * 8];
        u64 av[4] = {0ull, 0ull, 0ull, 0ull};
#pragma unroll
        for (int i = 0; i < 8; i++) {
            int dI = sD[eb * 8 + i];
            float mn = s[i] * (1.f / 64.f);
            float rs = rsqrtf(q[i] * (1.f / 64.f) - mn * mn + EPS);
            u64 rsd = dup2(rs);
            u64 mrd = dup2(-mn * rs);
            if (dI != curD) {
                float2 a0 = upk(av[0]), a1 = upk(av[1]), a2 = upk(av[2]), a3 = upk(av[3]);
                float* base = g_agg + (size_t)curD * 64 + cb * 8;
                red4(base,     make_float4(a0.x, a0.y, a1.x, a1.y));
                red4(base + 4, make_float4(a2.x, a2.y, a3.x, a3.y));
                av[0] = av[1] = av[2] = av[3] = 0ull;
                curD = dI;
            }
#pragma unroll
            for (int j = 0; j < 4; j++) {
                u64 t = ffma2(acc[i][j], rsd, mrd);
                av[j] = add2(av[j], ffma2(t, gv[j], bev[j]));
            }
        }
        {
            float2 a0 = upk(av[0]), a1 = upk(av[1]), a2 = upk(av[2]), a3 = upk(av[3]);
            float* base = g_agg + (size_t)curD * 64 + cb * 8;
            red4(base,     make_float4(a0.x, a0.y, a1.x, a1.y));
            red4(base + 4, make_float4(a2.x, a2.y, a3.x, a3.y));
        }
    }
}

// ============================ node update: 8 nodes/warp, thread = 2n x 8c ============================
__global__ void __launch_bounds__(256) k_node_upd(
    const float* __restrict__ W1, const float* __restrict__ b1,
    const float* __restrict__ W2, const float* __restrict__ b2,
    const float* __restrict__ gam, const float* __restrict__ bet)
{
    extern __shared__ float us[];
    float* sW1 = us;
    float* sW2 = us + 8192;
    float* sb1 = us + 12288;
    float* sb2 = us + 12352;
    float* sg  = us + 12416;
    float* sbe = us + 12480;
    float* sPer = us + 12544;
    int tid = threadIdx.x;
    for (int i = tid; i < 8192; i += 256) sW1[i] = W1[i];
    for (int i = tid; i < 4096; i += 256) sW2[i] = W2[i];
    if (tid < 64) { sb1[tid] = b1[tid]; sb2[tid] = b2[tid]; sg[tid] = gam[tid]; sbe[tid] = bet[tid]; }
    __syncthreads();
    int w = tid >> 5, ld = tid & 31;
    int nb = ld >> 3, cb = ld & 7;
    float* sIn  = sPer + w * (8 * 132 + 8 * 70);
    float* sMid = sIn + 8 * 132;
    const ulonglong2* W1u = (const ulonglong2*)sW1;
    const ulonglong2* W2u = (const ulonglong2*)sW2;
    const u64* b1u = (const u64*)sb1;
    const u64* b2u = (const u64*)sb2;
    const float4* gv4  = (const float4*)sg;
    const float4* bev4 = (const float4*)sbe;
    int gw = (blockIdx.x * 256 + tid) >> 5;
    int nw = (gridDim.x * 256) >> 5;
    for (int grp = gw; grp < N_NODES / 8; grp += nw) {
        int n0 = grp * 8;
        __syncwarp();
#pragma unroll
        for (int r = 0; r < 8; r++) {
            int c4 = ld * 4;
            float4 v;
            if (c4 < 64) v = *(const float4*)(g_h + (size_t)(n0 + r) * 64 + c4);
            else         v = *(const float4*)(g_agg + (size_t)(n0 + r) * 64 + (c4 - 64));
            *(float4*)&sIn[r * 132 + c4] = v;
        }
        __syncwarp();
        u64 a1[2][4];
#pragma unroll
        for (int i = 0; i < 2; i++)
#pragma unroll
            for (int j = 0; j < 4; j++) a1[i][j] = b1u[cb * 4 + j];
#pragma unroll 4
        for (int k = 0; k < 128; k++) {
            u64 d0 = dup2(sIn[(nb * 2 + 0) * 132 + k]);
            u64 d1 = dup2(sIn[(nb * 2 + 1) * 132 + k]);
            ulonglong2 w0 = W1u[k * 16 + cb * 2], w1 = W1u[k * 16 + cb * 2 + 1];
            a1[0][0] = ffma2(d0, w0.x, a1[0][0]); a1[0][1] = ffma2(d0, w0.y, a1[0][1]);
            a1[0][2] = ffma2(d0, w1.x, a1[0][2]); a1[0][3] = ffma2(d0, w1.y, a1[0][3]);
            a1[1][0] = ffma2(d1, w0.x, a1[1][0]); a1[1][1] = ffma2(d1, w0.y, a1[1][1]);
            a1[1][2] = ffma2(d1, w1.x, a1[1][2]); a1[1][3] = ffma2(d1, w1.y, a1[1][3]);
        }
#pragma unroll
        for (int i = 0; i < 2; i++) {
            int n = nb * 2 + i;
#pragma unroll
            for (int j = 0; j < 4; j++) {
                float2 v = upk(a1[i][j]);
                v.x = silu(v.x); v.y = silu(v.y);
                *(float2*)&sMid[n * 70 + cb * 8 + 2 * j] = v;
            }
        }
        __syncwarp();
        u64 a2[2][4];
#pragma unroll
        for (int i = 0; i < 2; i++)
#pragma unroll
            for (int j = 0; j < 4; j++) a2[i][j] = b2u[cb * 4 + j];
#pragma unroll 4
        for (int k = 0; k < 64; k++) {
            u64 d0 = dup2(sMid[(nb * 2 + 0) * 70 + k]);
            u64 d1 = dup2(sMid[(nb * 2 + 1) * 70 + k]);
            ulonglong2 w0 = W2u[k * 16 + cb * 2], w1 = W2u[k * 16 + cb * 2 + 1];
            a2[0][0] = ffma2(d0, w0.x, a2[0][0]); a2[0][1] = ffma2(d0, w0.y, a2[0][1]);
            a2[0][2] = ffma2(d0, w1.x, a2[0][2]); a2[0][3] = ffma2(d0, w1.y, a2[0][3]);
            a2[1][0] = ffma2(d1, w0.x, a2[1][0]); a2[1][1] = ffma2(d1, w0.y, a2[1][1]);
            a2[1][2] = ffma2(d1, w1.x, a2[1][2]); a2[1][3] = ffma2(d1, w1.y, a2[1][3]);
        }
        float4 gA = gv4[cb * 2], gB = gv4[cb * 2 + 1];
        float4 beA = bev4[cb * 2], beB = bev4[cb * 2 + 1];
#pragma unroll
        for (int i = 0; i < 2; i++) {
            float2 v0 = upk(a2[i][0]), v1 = upk(a2[i][1]), v2 = upk(a2[i][2]), v3 = upk(a2[i][3]);
            float s = v0.x + v0.y + v1.x + v1.y + v2.x + v2.y + v3.x + v3.y;
            float q = v0.x * v0.x + v0.y * v0.y + v1.x * v1.x + v1.y * v1.y
                    + v2.x * v2.x + v2.y * v2.y + v3.x * v3.x + v3.y * v3.y;
#pragma unroll
            for (int o = 4; o; o >>= 1) { s += __shfl_xor_sync(~0u, s, o); q += __shfl_xor_sync(~0u, q, o); }
            float mn = s * (1.f / 64.f);
            float rs = rsqrtf(q * (1.f / 64.f) - mn * mn + EPS);
            int n = nb * 2 + i;
            float4 h0 = *(const float4*)&sIn[n * 132 + cb * 8];
            float4 h1 = *(const float4*)&sIn[n * 132 + cb * 8 + 4];
            float4 o0, o1;
            o0.x = h0.x + (v0.x - mn) * rs * gA.x + beA.x;
            o0.y = h0.y + (v0.y - mn) * rs * gA.y + beA.y;
            o0.z = h0.z + (v1.x - mn) * rs * gA.z + beA.z;
            o0.w = h0.w + (v1.y - mn) * rs * gA.w + beA.w;
            o1.x = h1.x + (v2.x - mn) * rs * gB.x + beB.x;
            o1.y = h1.y + (v2.y - mn) * rs * gB.y + beB.y;
            o1.z = h1.z + (v3.x - mn) * rs * gB.z + beB.z;
            o1.w = h1.w + (v3.y - mn) * rs * gB.w + beB.w;
            *(float4*)(g_h + (size_t)(n0 + n) * 64 + cb * 8)     = o0;
            *(float4*)(g_h + (size_t)(n0 + n) * 64 + cb * 8 + 4) = o1;
        }
    }
}

__global__ void k_zero_pool() { int t = threadIdx.x; if (t < NG * 64) g_pool[t] = 0.f; }

// ============================ local decoder + pooling ============================
__global__ void __launch_bounds__(256) k_decoder_local(
    const float* __restrict__ W1, const float* __restrict__ b1,
    const float* __restrict__ W2, const float* __restrict__ b2,
    const int* __restrict__ batch, float* __restrict__ out)
{
    __shared__ float sW1[4096], sW2[64 * 6], sb1[64], sb2_[8];
    __shared__ float sH[8][64], sU[8][64];
    int tid = threadIdx.x;
    for (int i = tid; i < 4096; i += 256) sW1[i] = W1[i];
    for (int i = tid; i < 384; i += 256) sW2[i] = W2[i];
    if (tid < 64) sb1[tid] = b1[tid];
    if (tid < 6) sb2_[tid] = b2[tid];
    __syncthreads();
    int w = tid >> 5, ld = tid & 31, c0 = 2 * ld;
    int n = blockIdx.x * 8 + w;
    if (n >= N_NODES) return;
    float2 hv = *(const float2*)(g_h + (size_t)n * 64 + c0);
    sH[w][c0] = hv.x; sH[w][c0 + 1] = hv.y;
    __syncwarp();
    const u64* W1u = (const u64*)sW1;
    u64 acc = ((const u64*)sb1)[ld];
#pragma unroll 8
    for (int k = 0; k < 64; k++) acc = ffma2(dup2(sH[w][k]), W1u[k * 32 + ld], acc);
    float2 u = upk(acc); u.x = silu(u.x); u.y = silu(u.y);
    sU[w][c0] = u.x; sU[w][c0 + 1] = u.y;
    __syncwarp();
    if (ld < 6) {
        float o = sb2_[ld];
#pragma unroll
        for (int k = 0; k < 64; k++) o += sU[w][k] * sW2[k * 6 + ld];
        out[(size_t)n * 6 + ld] = o;
    }
    int g = __ldg(&batch[n]);
    red2(g_pool + g * 64 + c0, hv.x, hv.y);
}

// ============================ global decoder ============================
__global__ void k_global(const int* __restrict__ batch,
    const float* __restrict__ W1, const float* __restrict__ b1,
    const float* __restrict__ W2, const float* __restrict__ b2,
    float* __restrict__ out)
{
    __shared__ float sp[NG * 64];
    __shared__ float su[NG * 32];
    __shared__ int bnd[NG + 1];
    int t = threadIdx.x;
    if (t <= NG) {
        int lo = 0, hi = N_NODES;
        while (lo < hi) { int mid = (lo + hi) >> 1; if (batch[mid] < t) lo = mid + 1; else hi = mid; }
        bnd[t] = lo;
    }
    __syncthreads();
    for (int i = t; i < NG * 64; i += 128) {
        int g = i >> 6;
        float cnt = (float)(bnd[g + 1] - bnd[g]);
        sp[i] = g_pool[i] / fmaxf(cnt, 1.f);
    }
    __syncthreads();
    {
        int g = t >> 5, j = t & 31;
        float a = b1[j];
#pragma unroll
        for (int k = 0; k < 64; k++) a += sp[g * 64 + k] * W1[k * 32 + j];
        su[g * 32 + j] = silu(a);
    }
    __syncthreads();
    if (t < NG * 4) {
        int g = t >> 2, j = t & 3;
        float o = b2[j];
#pragma unroll
        for (int k = 0; k < 32; k++) o += su[g * 32 + k] * W2[k * 4 + j];
        out[(size_t)N_NODES * 6 + g * 4 + j] = o;
    }
}

extern "C" void kernel_launch(void* const* d_in, const int* in_sizes, int n_in,
                              void* d_out, int out_size) {
    (void)in_sizes; (void)n_in; (void)out_size;
    const float* x     = (const float*)d_in[0];
    const int*   ei    = (const int*)d_in[1];
    const float* eattr = (const float*)d_in[2];
    const int*   batch = (const int*)d_in[3];
    const float* casep = (const float*)d_in[4];
    const float* bcp   = (const float*)d_in[5];
    const float* encW1 = (const float*)d_in[6];  const float* encb1 = (const float*)d_in[7];
    const float* encW2 = (const float*)d_in[8];  const float* encb2 = (const float*)d_in[9];
    const float* encg  = (const float*)d_in[10]; const float* encbe = (const float*)d_in[11];
    const float* eW1   = (const float*)d_in[12]; const float* eb1   = (const float*)d_in[13];
    const float* eW2   = (const float*)d_in[14]; const float* eb2   = (const float*)d_in[15];
    const float* eg    = (const float*)d_in[16]; const float* ebe   = (const float*)d_in[17];
    const float* nW1   = (const float*)d_in[18]; const float* nb1   = (const float*)d_in[19];
    const float* nW2   = (const float*)d_in[20]; const float* nb2   = (const float*)d_in[21];
    const float* ngm   = (const float*)d_in[22]; const float* nbe   = (const float*)d_in[23];
    const float* dlW1  = (const float*)d_in[24]; const float* dlb1  = (const float*)d_in[25];
    const float* dlW2  = (const float*)d_in[26]; const float* dlb2  = (const float*)d_in[27];
    const float* dgW1  = (const float*)d_in[28]; const float* dgb1  = (const float*)d_in[29];
    const float* dgW2  = (const float*)d_in[30]; const float* dgb2  = (const float*)d_in[31];
    float* out = (float*)d_out;

    size_t preSmem  = (size_t)(8192 + 8 * (8 * 68)) * sizeof(float);            // 50176 B
    size_t edgeSmem = (size_t)(5184 + 8 * 2368) * sizeof(float);                // 96512 B
    size_t updSmem  = (size_t)(12544 + 8 * (8 * 132 + 8 * 70)) * sizeof(float); // 101888 B
    cudaFuncSetAttribute(k_node_pre, cudaFuncAttributeMaxDynamicSharedMemorySize, (int)preSmem);
    cudaFuncSetAttribute(k_edge, cudaFuncAttributeMaxDynamicSharedMemorySize, (int)edgeSmem);
    cudaFuncSetAttribute(k_node_upd, cudaFuncAttributeMaxDynamicSharedMemorySize, (int)updSmem);

    // edge sort by dst + payload permutation (per call; graph-capturable)
    k_zero_wp<<<(N_NODES + 255) / 256, 256>>>();
    k_hist<<<(N_EDGES + 255) / 256, 256>>>(ei);
    k_scan<<<1, 1024>>>();
    k_scatter<<<(N_EDGES + 255) / 256, 256>>>(ei, eattr);

    k_encoder<<<(N_NODES + 7) / 8, 256>>>(x, batch, casep, bcp, encW1, encb1, encW2, encb2, encg, encbe);
    for (int l = 0; l < NL; l++) {
        const float* eW1l = eW1 + (size_t)l * 133 * 64;
        k_node_pre<<<592, 256, preSmem>>>(eW1l);
        k_edge<<<296, 256, edgeSmem>>>(eW1l + 128 * 64, eb1 + l * 64,
                              eW2 + (size_t)l * 4096, eb2 + l * 64,
                              eg + l * 64, ebe + l * 64);
        k_node_upd<<<296, 256, updSmem>>>(nW1 + (size_t)l * 8192, nb1 + l * 64,
                                          nW2 + (size_t)l * 4096, nb2 + l * 64,
                                          ngm + l * 64, nbe + l * 64);
    }
    k_zero_pool<<<1, 256>>>();
    k_decoder_local<<<(N_NODES + 7) / 8, 256>>>(dlW1, dlb1, dlW2, dlb2, batch, out);
    k_global<<<1, 128>>>(batch, dgW1, dgb1, dgW2, dgb2, out);
}

// round 10
// speedup vs baseline: 1.5831x; 1.1619x over previous
#include <cuda_runtime.h>
#include <cstdint>
#define DINL __device__ __forceinline__
constexpr int N_NODES = 50000;
constexpr int N_EDGES = 1600000;
constexpr int NL = 5;
constexpr int NG = 4;
constexpr float EPS = 1e-5f;

__device__ float g_h  [N_NODES * 64];
__device__ float g_hd [N_NODES * 64];
__device__ float g_hs [N_NODES * 64];
__device__ float g_agg[N_NODES * 64];
__device__ float g_pool[NG * 64];
__device__ int   g_wp [N_NODES];
__device__ float g_em [(size_t)N_EDGES * 8];

typedef unsigned long long u64;
DINL u64 pk2(float x, float y) { u64 r; asm("mov.b64 %0,{%1,%2};" : "=l"(r) : "f"(x), "f"(y)); return r; }
DINL u64 dup2(float x) { return pk2(x, x); }
DINL float2 upk(u64 v) { float2 r; asm("mov.b64 {%0,%1},%2;" : "=f"(r.x), "=f"(r.y) : "l"(v)); return r; }
DINL u64 ffma2(u64 a, u64 b, u64 c) { u64 d; asm("fma.rn.f32x2 %0,%1,%2,%3;" : "=l"(d) : "l"(a), "l"(b), "l"(c)); return d; }
DINL u64 add2(u64 a, u64 b) { u64 d; asm("add.rn.f32x2 %0,%1,%2;" : "=l"(d) : "l"(a), "l"(b)); return d; }
DINL void red2(float* p, float x, float y) { asm volatile("red.global.add.v2.f32 [%0], {%1,%2};" :: "l"(p), "f"(x), "f"(y) : "memory"); }
DINL void red4(float* p, float4 v) { asm volatile("red.global.add.v4.f32 [%0], {%1,%2,%3,%4};" :: "l"(p), "f"(v.x), "f"(v.y), "f"(v.z), "f"(v.w) : "memory"); }
DINL float silu(float x) { return __fdividef(x, 1.f + __expf(-x)); }
DINL uint32_t tf32c(float f) { uint32_t r; asm("cvt.rna.tf32.f32 %0,%1;" : "=r"(r) : "f"(f)); return r; }
DINL void mma8(float* c, uint32_t a0, uint32_t a1, uint32_t a2, uint32_t a3, uint32_t b0, uint32_t b1) {
    asm volatile("mma.sync.aligned.m16n8k8.row.col.f32.tf32.tf32.f32 {%0,%1,%2,%3},{%4,%5,%6,%7},{%8,%9},{%0,%1,%2,%3};"
        : "+f"(c[0]), "+f"(c[1]), "+f"(c[2]), "+f"(c[3])
        : "r"(a0), "r"(a1), "r"(a2), "r"(a3), "r"(b0), "r"(b1));
}

// ---------------- CSR build ----------------
__global__ void k_zero_wp() { int i = blockIdx.x * 256 + threadIdx.x; if (i < N_NODES) g_wp[i] = 0; }
__global__ void k_hist(const int* __restrict__ ei) { int e = blockIdx.x * 256 + threadIdx.x; if (e < N_EDGES) atomicAdd(&g_wp[ei[N_EDGES + e]], 1); }
__global__ void k_scan() {
    __shared__ int part[1024];
    int t = threadIdx.x; const int C = 49; int base = t * C; int sum = 0;
    for (int i = 0; i < C; i++) { int idx = base + i; if (idx < N_NODES) sum += g_wp[idx]; }
    part[t] = sum; __syncthreads();
    for (int off = 1; off < 1024; off <<= 1) { int v = (t >= off) ? part[t - off] : 0; __syncthreads(); part[t] += v; __syncthreads(); }
    int run = (t == 0) ? 0 : part[t - 1];
    for (int i = 0; i < C; i++) { int idx = base + i; if (idx < N_NODES) { int v = g_wp[idx]; g_wp[idx] = run; run += v; } }
}
__global__ void k_scatter(const int* __restrict__ ei, const float* __restrict__ eattr) {
    int e = blockIdx.x * 256 + threadIdx.x;
    if (e < N_EDGES) {
        int d = ei[N_EDGES + e];
        int pos = atomicAdd(&g_wp[d], 1);
        const float* ea = eattr + (size_t)e * 5;
        float4 f0 = make_float4(__int_as_float(ei[e]), __int_as_float(d), __ldg(ea), __ldg(ea + 1));
        float4 f1 = make_float4(__ldg(ea + 2), __ldg(ea + 3), __ldg(ea + 4), 0.f);
        size_t p8 = (size_t)pos * 8;
        *(float4*)&g_em[p8] = f0; *(float4*)&g_em[p8 + 4] = f1;
    }
}

// ---------------- encoder ----------------
__global__ void __launch_bounds__(256) k_encoder(
    const float* __restrict__ x, const int* __restrict__ batch,
    const float* __restrict__ casep, const float* __restrict__ bcp,
    const float* __restrict__ W1, const float* __restrict__ b1,
    const float* __restrict__ W2, const float* __restrict__ b2,
    const float* __restrict__ gam, const float* __restrict__ bet)
{
    __shared__ float sW1[1024], sW2[4096], sb1[64], sb2[64], sg[64], sbe[64];
    __shared__ float sH[8][64];
    int tid = threadIdx.x;
    for (int i = tid; i < 1024; i += 256) sW1[i] = W1[i];
    for (int i = tid; i < 4096; i += 256) sW2[i] = W2[i];
    if (tid < 64) { sb1[tid] = b1[tid]; sb2[tid] = b2[tid]; sg[tid] = gam[tid]; sbe[tid] = bet[tid]; }
    __syncthreads();
    int w = tid >> 5, ld = tid & 31, c0 = 2 * ld;
    int n = blockIdx.x * 8 + w;
    if (n >= N_NODES) return;
    float in[16];
#pragma unroll
    for (int k = 0; k < 8; k++) in[k] = __ldg(&x[n * 8 + k]);
    int g = __ldg(&batch[n]);
#pragma unroll
    for (int k = 0; k < 4; k++) { in[8 + k] = __ldg(&casep[g * 4 + k]); in[12 + k] = __ldg(&bcp[g * 4 + k]); }
    const u64* W1u = (const u64*)sW1;
    u64 acc = ((const u64*)sb1)[ld];
#pragma unroll
    for (int k = 0; k < 16; k++) acc = ffma2(dup2(in[k]), W1u[k * 32 + ld], acc);
    float2 a = upk(acc); a.x = silu(a.x); a.y = silu(a.y);
    sH[w][c0] = a.x; sH[w][c0 + 1] = a.y;
    __syncwarp();
    const u64* W2u = (const u64*)sW2;
    u64 acc2 = ((const u64*)sb2)[ld];
#pragma unroll 8
    for (int k = 0; k < 64; k++) acc2 = ffma2(dup2(sH[w][k]), W2u[k * 32 + ld], acc2);
    float2 v = upk(acc2);
    float s = v.x + v.y, q = v.x * v.x + v.y * v.y;
#pragma unroll
    for (int o = 16; o; o >>= 1) { s += __shfl_xor_sync(~0u, s, o); q += __shfl_xor_sync(~0u, q, o); }
    float m = s * (1.f / 64.f), rs = rsqrtf(q * (1.f / 64.f) - m * m + EPS);
    float2 out;
    out.x = (v.x - m) * rs * sg[c0] + sbe[c0];
    out.y = (v.y - m) * rs * sg[c0 + 1] + sbe[c0 + 1];
    *(float2*)(g_h + (size_t)n * 64 + c0) = out;
}

// ---------------- node pre ----------------
__global__ void __launch_bounds__(256) k_node_pre(const float* __restrict__ eW1l)
{
    extern __shared__ float ps[];
    float* sWA = ps; float* sWB = ps + 4096; float* sInAll = ps + 8192;
    int tid = threadIdx.x;
    for (int i = tid; i < 4096; i += 256) { sWA[i] = eW1l[i]; sWB[i] = eW1l[4096 + i]; }
    __syncthreads();
    int w = tid >> 5, ld = tid & 31, nb = ld >> 3, cb = ld & 7;
    float* sIn = sInAll + w * 544;
    const ulonglong2* WAu = (const ulonglong2*)sWA;
    const ulonglong2* WBu = (const ulonglong2*)sWB;
    int gw = (blockIdx.x * 256 + tid) >> 5, nw = (gridDim.x * 256) >> 5;
    for (int grp = gw; grp < N_NODES / 8; grp += nw) {
        int n0 = grp * 8;
        __syncwarp();
#pragma unroll
        for (int r = 0; r < 4; r++) {
            int t = r * 32 + ld, n = t >> 4, c4 = (t & 15) * 4;
            *(float4*)&sIn[n * 68 + c4] = *(const float4*)(g_h + (size_t)(n0 + n) * 64 + c4);
        }
        __syncwarp();
        u64 aA[2][4], aB[2][4];
#pragma unroll
        for (int i = 0; i < 2; i++)
#pragma unroll
            for (int j = 0; j < 4; j++) { aA[i][j] = 0ull; aB[i][j] = 0ull; }
#pragma unroll 4
        for (int k = 0; k < 64; k++) {
            u64 d0 = dup2(sIn[(nb * 2 + 0) * 68 + k]);
            u64 d1 = dup2(sIn[(nb * 2 + 1) * 68 + k]);
            ulonglong2 A0 = WAu[k * 16 + cb * 2], A1 = WAu[k * 16 + cb * 2 + 1];
            ulonglong2 B0 = WBu[k * 16 + cb * 2], B1 = WBu[k * 16 + cb * 2 + 1];
            aA[0][0] = ffma2(d0, A0.x, aA[0][0]); aA[0][1] = ffma2(d0, A0.y, aA[0][1]);
            aA[0][2] = ffma2(d0, A1.x, aA[0][2]); aA[0][3] = ffma2(d0, A1.y, aA[0][3]);
            aA[1][0] = ffma2(d1, A0.x, aA[1][0]); aA[1][1] = ffma2(d1, A0.y, aA[1][1]);
            aA[1][2] = ffma2(d1, A1.x, aA[1][2]); aA[1][3] = ffma2(d1, A1.y, aA[1][3]);
            aB[0][0] = ffma2(d0, B0.x, aB[0][0]); aB[0][1] = ffma2(d0, B0.y, aB[0][1]);
            aB[0][2] = ffma2(d0, B1.x, aB[0][2]); aB[0][3] = ffma2(d0, B1.y, aB[0][3]);
            aB[1][0] = ffma2(d1, B0.x, aB[1][0]); aB[1][1] = ffma2(d1, B0.y, aB[1][1]);
            aB[1][2] = ffma2(d1, B1.x, aB[1][2]); aB[1][3] = ffma2(d1, B1.y, aB[1][3]);
        }
#pragma unroll
        for (int i = 0; i < 2; i++) {
            int n = n0 + nb * 2 + i;
            ulonglong2 t;
            t.x = aA[i][0]; t.y = aA[i][1]; *(ulonglong2*)(g_hd + (size_t)n * 64 + cb * 8) = t;
            t.x = aA[i][2]; t.y = aA[i][3]; *(ulonglong2*)(g_hd + (size_t)n * 64 + cb * 8 + 4) = t;
            t.x = aB[i][0]; t.y = aB[i][1]; *(ulonglong2*)(g_hs + (size_t)n * 64 + cb * 8) = t;
            t.x = aB[i][2]; t.y = aB[i][3]; *(ulonglong2*)(g_hs + (size_t)n * 64 + cb * 8 + 4) = t;
            *(float4*)(g_agg + (size_t)n * 64 + cb * 8)     = make_float4(0.f, 0.f, 0.f, 0.f);
            *(float4*)(g_agg + (size_t)n * 64 + cb * 8 + 4) = make_float4(0.f, 0.f, 0.f, 0.f);
        }
    }
}

// ---------------- edge kernel: 32-edge tiles, phase-2 via mma.sync tf32 ----------------
// smem (floats): sW2s[0,4608) [k][72] tf32 | sW1c 4608 | sb1 4928 sb2 4992 sg 5056 sbe 5120
// per-warp @5184 + w*2496: sM (staging[32][68] / D[32][76]) | sD int[32]@2432 | sSrc int[32]@2464
__global__ void __launch_bounds__(256, 2) k_edge(
    const float* __restrict__ W1c, const float* __restrict__ b1,
    const float* __restrict__ W2, const float* __restrict__ b2,
    const float* __restrict__ gam, const float* __restrict__ bet)
{
    extern __shared__ float es[];
    float* sW2s = es;
    float* sW1c = es + 4608;
    float* sb1 = es + 4928; float* sb2 = es + 4992;
    float* sg = es + 5056;  float* sbe = es + 5120;
    float* sPer = es + 5184;
    int tid = threadIdx.x;
    for (int i = tid; i < 4096; i += 256) {
        int k = i >> 6, c = i & 63;
        sW2s[k * 72 + c] = __uint_as_float(tf32c(W2[i]));
    }
    for (int i = tid; i < 320; i += 256) sW1c[i] = W1c[i];
    if (tid < 64) { sb1[tid] = b1[tid]; sb2[tid] = b2[tid]; sg[tid] = gam[tid]; sbe[tid] = bet[tid]; }
    __syncthreads();
    int w = tid >> 5, ld = tid & 31;
    int pe = ld >> 1, half = ld & 1;   // phase-1 mapping
    int eb = ld >> 3, cb = ld & 7;     // LN/scatter mapping
    int g8 = ld >> 2, q4 = ld & 3;     // mma fragment mapping
    float* sM = sPer + w * 2496;
    int* sD = (int*)(sM + 2432);
    int* sSrc = (int*)(sM + 2464);
    const ulonglong2* W1cu = (const ulonglong2*)sW1c;
    const ulonglong2* b1u = (const ulonglong2*)sb1;
    u64 gv[4], bev[4];
#pragma unroll
    for (int j = 0; j < 4; j++) { gv[j] = ((const u64*)sg)[cb * 4 + j]; bev[j] = ((const u64*)sbe)[cb * 4 + j]; }
    float b2s[8];
#pragma unroll
    for (int j = 0; j < 8; j++) b2s[j] = sb2[cb * 8 + j];
    int gw = (blockIdx.x * 256 + tid) >> 5;
    int nw = (gridDim.x * 256) >> 5;
    for (int grp = gw; grp < N_EDGES / 32; grp += nw) {
        int e0 = grp * 32;
        __syncwarp();
        // metadata
        int didx[2];
        u64 ead[2][5];
#pragma unroll
        for (int sub = 0; sub < 2; sub++) {
            int slot = sub * 16 + pe;
            const float4* emp = (const float4*)&g_em[(size_t)(e0 + slot) * 8];
            float4 f0 = __ldg(emp), f1 = __ldg(emp + 1);
            didx[sub] = __float_as_int(f0.y);
            ead[sub][0] = dup2(f0.z); ead[sub][1] = dup2(f0.w);
            ead[sub][2] = dup2(f1.x); ead[sub][3] = dup2(f1.y); ead[sub][4] = dup2(f1.z);
            if (half == 0) { sD[slot] = didx[sub]; sSrc[slot] = __float_as_int(f0.x); }
        }
        __syncwarp();
        // coalesced hs gather -> sM[slot][68]
#pragma unroll
        for (int r = 0; r < 16; r++) {
            int chunk = r * 32 + ld, eslot = chunk >> 4, c4 = (chunk & 15) * 4;
            *(float4*)&sM[eslot * 68 + c4] = *(const float4*)(g_hs + (size_t)sSrc[eslot] * 64 + c4);
        }
        __syncwarp();
        // phase-1 in place, tf32 output
#pragma unroll
        for (int sub = 0; sub < 2; sub++) {
            int slot = sub * 16 + pe;
            const ulonglong2* hdp = (const ulonglong2*)(g_hd + (size_t)didx[sub] * 64 + half * 32);
            float* mrow = sM + slot * 68 + half * 32;
#pragma unroll
            for (int j = 0; j < 8; j++) {
                ulonglong2 hdj = __ldg(hdp + j);
                ulonglong2 hsj = ((const ulonglong2*)mrow)[j];
                ulonglong2 bj = b1u[half * 8 + j];
                u64 a0 = add2(add2(hdj.x, hsj.x), bj.x);
                u64 a1 = add2(add2(hdj.y, hsj.y), bj.y);
#pragma unroll
                for (int r = 0; r < 5; r++) {
                    ulonglong2 wv = W1cu[r * 16 + half * 8 + j];
                    a0 = ffma2(ead[sub][r], wv.x, a0); a1 = ffma2(ead[sub][r], wv.y, a1);
                }
                float2 v0 = upk(a0), v1 = upk(a1);
                uint4 tw;
                tw.x = tf32c(silu(v0.x)); tw.y = tf32c(silu(v0.y));
                tw.z = tf32c(silu(v1.x)); tw.w = tf32c(silu(v1.y));
                *(uint4*)(mrow + 4 * j) = tw;
            }
        }
        __syncwarp();
        // phase-2: mma.sync tf32, warp tile 32e x 64c
        float acc[2][8][4];
#pragma unroll
        for (int mb = 0; mb < 2; mb++)
#pragma unroll
            for (int nb = 0; nb < 8; nb++)
#pragma unroll
                for (int j = 0; j < 4; j++) acc[mb][nb][j] = 0.f;
#pragma unroll
        for (int kb = 0; kb < 8; kb++) {
            int kc = kb * 8 + q4;
            const uint32_t* mu = (const uint32_t*)sM;
            uint32_t a00 = mu[(g8) * 68 + kc],      a01 = mu[(g8 + 8) * 68 + kc];
            uint32_t a02 = mu[(g8) * 68 + kc + 4],  a03 = mu[(g8 + 8) * 68 + kc + 4];
            uint32_t a10 = mu[(g8 + 16) * 68 + kc],     a11 = mu[(g8 + 24) * 68 + kc];
            uint32_t a12 = mu[(g8 + 16) * 68 + kc + 4], a13 = mu[(g8 + 24) * 68 + kc + 4];
            const uint32_t* wu = (const uint32_t*)sW2s;
#pragma unroll
            for (int nb = 0; nb < 8; nb++) {
                uint32_t b0 = wu[kc * 72 + nb * 8 + g8];
                uint32_t b1_ = wu[(kc + 4) * 72 + nb * 8 + g8];
                mma8(acc[0][nb], a00, a01, a02, a03, b0, b1_);
                mma8(acc[1][nb], a10, a11, a12, a13, b0, b1_);
            }
        }
        __syncwarp();
        // store D [e][76]
#pragma unroll
        for (int mb = 0; mb < 2; mb++)
#pragma unroll
            for (int nb = 0; nb < 8; nb++) {
                int elo = mb * 16 + g8;
                *(float2*)&sM[elo * 76 + nb * 8 + 2 * q4] = make_float2(acc[mb][nb][0], acc[mb][nb][1]);
                *(float2*)&sM[(elo + 8) * 76 + nb * 8 + 2 * q4] = make_float2(acc[mb][nb][2], acc[mb][nb][3]);
            }
        __syncwarp();
        // LN + RLE scatter: thread = 8 edges (eb*8..+7) x 8 cols (cb*8..+7)
        float4 f0a[8], f1a[8];
        float s[8], q[8];
#pragma unroll
        for (int i = 0; i < 8; i++) {
            int e = eb * 8 + i;
            float4 v0 = *(const float4*)&sM[e * 76 + cb * 8];
            float4 v1 = *(const float4*)&sM[e * 76 + cb * 8 + 4];
            v0.x += b2s[0]; v0.y += b2s[1]; v0.z += b2s[2]; v0.w += b2s[3];
            v1.x += b2s[4]; v1.y += b2s[5]; v1.z += b2s[6]; v1.w += b2s[7];
            f0a[i] = v0; f1a[i] = v1;
            s[i] = v0.x + v0.y + v0.z + v0.w + v1.x + v1.y + v1.z + v1.w;
            q[i] = v0.x * v0.x + v0.y * v0.y + v0.z * v0.z + v0.w * v0.w
                 + v1.x * v1.x + v1.y * v1.y + v1.z * v1.z + v1.w * v1.w;
        }
#pragma unroll
        for (int o = 4; o; o >>= 1) {
#pragma unroll
            for (int i = 0; i < 8; i++) { s[i] += __shfl_xor_sync(~0u, s[i], o); q[i] += __shfl_xor_sync(~0u, q[i], o); }
        }
        int curD = sD[eb * 8];
        u64 av[4] = {0ull, 0ull, 0ull, 0ull};
#pragma unroll
        for (int i = 0; i < 8; i++) {
            int dI = sD[eb * 8 + i];
            float mn = s[i] * (1.f / 64.f);
            float rs = rsqrtf(q[i] * (1.f / 64.f) - mn * mn + EPS);
            u64 rsd = dup2(rs), mrd = dup2(-mn * rs);
            if (dI != curD) {
                float2 a0 = upk(av[0]), a1 = upk(av[1]), a2 = upk(av[2]), a3 = upk(av[3]);
                float* base = g_agg + (size_t)curD * 64 + cb * 8;
                red4(base, make_float4(a0.x, a0.y, a1.x, a1.y));
                red4(base + 4, make_float4(a2.x, a2.y, a3.x, a3.y));
                av[0] = av[1] = av[2] = av[3] = 0ull;
                curD = dI;
            }
            u64 vv0 = pk2(f0a[i].x, f0a[i].y), vv1 = pk2(f0a[i].z, f0a[i].w);
            u64 vv2 = pk2(f1a[i].x, f1a[i].y), vv3 = pk2(f1a[i].z, f1a[i].w);
            av[0] = add2(av[0], ffma2(ffma2(vv0, rsd, mrd), gv[0], bev[0]));
            av[1] = add2(av[1], ffma2(ffma2(vv1, rsd, mrd), gv[1], bev[1]));
            av[2] = add2(av[2], ffma2(ffma2(vv2, rsd, mrd), gv[2], bev[2]));
            av[3] = add2(av[3], ffma2(ffma2(vv3, rsd, mrd), gv[3], bev[3]));
        }
        {
            float2 a0 = upk(av[0]), a1 = upk(av[1]), a2 = upk(av[2]), a3 = upk(av[3]);
            float* base = g_agg + (size_t)curD * 64 + cb * 8;
            red4(base, make_float4(a0.x, a0.y, a1.x, a1.y));
            red4(base + 4, make_float4(a2.x, a2.y, a3.x, a3.y));
        }
    }
}

// ---------------- node update ----------------
__global__ void __launch_bounds__(256) k_node_upd(
    const float* __restrict__ W1, const float* __restrict__ b1,
    const float* __restrict__ W2, const float* __restrict__ b2,
    const float* __restrict__ gam, const float* __restrict__ bet)
{
    extern __shared__ float us[];
    float* sW1 = us; float* sW2 = us + 8192;
    float* sb1 = us + 12288; float* sb2 = us + 12352;
    float* sg = us + 12416; float* sbe = us + 12480;
    float* sPer = us + 12544;
    int tid = threadIdx.x;
    for (int i = tid; i < 8192; i += 256) sW1[i] = W1[i];
    for (int i = tid; i < 4096; i += 256) sW2[i] = W2[i];
    if (tid < 64) { sb1[tid] = b1[tid]; sb2[tid] = b2[tid]; sg[tid] = gam[tid]; sbe[tid] = bet[tid]; }
    __syncthreads();
    int w = tid >> 5, ld = tid & 31, nb = ld >> 3, cb = ld & 7;
    float* sIn = sPer + w * (8 * 132 + 8 * 70);
    float* sMid = sIn + 8 * 132;
    const ulonglong2* W1u = (const ulonglong2*)sW1;
    const ulonglong2* W2u = (const ulonglong2*)sW2;
    const u64* b1u = (const u64*)sb1;
    const u64* b2u = (const u64*)sb2;
    const float4* gv4 = (const float4*)sg;
    const float4* bev4 = (const float4*)sbe;
    int gw = (blockIdx.x * 256 + tid) >> 5, nw = (gridDim.x * 256) >> 5;
    for (int grp = gw; grp < N_NODES / 8; grp += nw) {
        int n0 = grp * 8;
        __syncwarp();
#pragma unroll
        for (int r = 0; r < 8; r++) {
            int c4 = ld * 4;
            float4 v;
            if (c4 < 64) v = *(const float4*)(g_h + (size_t)(n0 + r) * 64 + c4);
            else         v = *(const float4*)(g_agg + (size_t)(n0 + r) * 64 + (c4 - 64));
            *(float4*)&sIn[r * 132 + c4] = v;
        }
        __syncwarp();
        u64 a1[2][4];
#pragma unroll
        for (int i = 0; i < 2; i++)
#pragma unroll
            for (int j = 0; j < 4; j++) a1[i][j] = b1u[cb * 4 + j];
#pragma unroll 4
        for (int k = 0; k < 128; k++) {
            u64 d0 = dup2(sIn[(nb * 2 + 0) * 132 + k]);
            u64 d1 = dup2(sIn[(nb * 2 + 1) * 132 + k]);
            ulonglong2 w0 = W1u[k * 16 + cb * 2], w1 = W1u[k * 16 + cb * 2 + 1];
            a1[0][0] = ffma2(d0, w0.x, a1[0][0]); a1[0][1] = ffma2(d0, w0.y, a1[0][1]);
            a1[0][2] = ffma2(d0, w1.x, a1[0][2]); a1[0][3] = ffma2(d0, w1.y, a1[0][3]);
            a1[1][0] = ffma2(d1, w0.x, a1[1][0]); a1[1][1] = ffma2(d1, w0.y, a1[1][1]);
            a1[1][2] = ffma2(d1, w1.x, a1[1][2]); a1[1][3] = ffma2(d1, w1.y, a1[1][3]);
        }
#pragma unroll
        for (int i = 0; i < 2; i++) {
            int n = nb * 2 + i;
#pragma unroll
            for (int j = 0; j < 4; j++) {
                float2 v = upk(a1[i][j]);
                v.x = silu(v.x); v.y = silu(v.y);
                *(float2*)&sMid[n * 70 + cb * 8 + 2 * j] = v;
            }
        }
        __syncwarp();
        u64 a2[2][4];
#pragma unroll
        for (int i = 0; i < 2; i++)
#pragma unroll
            for (int j = 0; j < 4; j++) a2[i][j] = b2u[cb * 4 + j];
#pragma unroll 4
        for (int k = 0; k < 64; k++) {
            u64 d0 = dup2(sMid[(nb * 2 + 0) * 70 + k]);
            u64 d1 = dup2(sMid[(nb * 2 + 1) * 70 + k]);
            ulonglong2 w0 = W2u[k * 16 + cb * 2], w1 = W2u[k * 16 + cb * 2 + 1];
            a2[0][0] = ffma2(d0, w0.x, a2[0][0]); a2[0][1] = ffma2(d0, w0.y, a2[0][1]);
            a2[0][2] = ffma2(d0, w1.x, a2[0][2]); a2[0][3] = ffma2(d0, w1.y, a2[0][3]);
            a2[1][0] = ffma2(d1, w0.x, a2[1][0]); a2[1][1] = ffma2(d1, w0.y, a2[1][1]);
            a2[1][2] = ffma2(d1, w1.x, a2[1][2]); a2[1][3] = ffma2(d1, w1.y, a2[1][3]);
        }
        float4 gA = gv4[cb * 2], gB = gv4[cb * 2 + 1];
        float4 beA = bev4[cb * 2], beB = bev4[cb * 2 + 1];
#pragma unroll
        for (int i = 0; i < 2; i++) {
            float2 v0 = upk(a2[i][0]), v1 = upk(a2[i][1]), v2 = upk(a2[i][2]), v3 = upk(a2[i][3]);
            float s = v0.x + v0.y + v1.x + v1.y + v2.x + v2.y + v3.x + v3.y;
            float q = v0.x * v0.x + v0.y * v0.y + v1.x * v1.x + v1.y * v1.y
                    + v2.x * v2.x + v2.y * v2.y + v3.x * v3.x + v3.y * v3.y;
#pragma unroll
            for (int o = 4; o; o >>= 1) { s += __shfl_xor_sync(~0u, s, o); q += __shfl_xor_sync(~0u, q, o); }
            float mn = s * (1.f / 64.f);
            float rs = rsqrtf(q * (1.f / 64.f) - mn * mn + EPS);
            int n = nb * 2 + i;
            float4 h0 = *(const float4*)&sIn[n * 132 + cb * 8];
            float4 h1 = *(const float4*)&sIn[n * 132 + cb * 8 + 4];
            float4 o0, o1;
            o0.x = h0.x + (v0.x - mn) * rs * gA.x + beA.x;
            o0.y = h0.y + (v0.y - mn) * rs * gA.y + beA.y;
            o0.z = h0.z + (v1.x - mn) * rs * gA.z + beA.z;
            o0.w = h0.w + (v1.y - mn) * rs * gA.w + beA.w;
            o1.x = h1.x + (v2.x - mn) * rs * gB.x + beB.x;
            o1.y = h1.y + (v2.y - mn) * rs * gB.y + beB.y;
            o1.z = h1.z + (v3.x - mn) * rs * gB.z + beB.z;
            o1.w = h1.w + (v3.y - mn) * rs * gB.w + beB.w;
            *(float4*)(g_h + (size_t)(n0 + n) * 64 + cb * 8)     = o0;
            *(float4*)(g_h + (size_t)(n0 + n) * 64 + cb * 8 + 4) = o1;
        }
    }
}

__global__ void k_zero_pool() { int t = threadIdx.x; if (t < NG * 64) g_pool[t] = 0.f; }

// ---------------- local decoder + pooling ----------------
__global__ void __launch_bounds__(256) k_decoder_local(
    const float* __restrict__ W1, const float* __restrict__ b1,
    const float* __restrict__ W2, const float* __restrict__ b2,
    const int* __restrict__ batch, float* __restrict__ out)
{
    __shared__ float sW1[4096], sW2[384], sb1[64], sb2_[8];
    __shared__ float sH[8][64], sU[8][64];
    int tid = threadIdx.x;
    for (int i = tid; i < 4096; i += 256) sW1[i] = W1[i];
    for (int i = tid; i < 384; i += 256) sW2[i] = W2[i];
    if (tid < 64) sb1[tid] = b1[tid];
    if (tid < 6) sb2_[tid] = b2[tid];
    __syncthreads();
    int w = tid >> 5, ld = tid & 31, c0 = 2 * ld;
    int n = blockIdx.x * 8 + w;
    if (n >= N_NODES) return;
    float2 hv = *(const float2*)(g_h + (size_t)n * 64 + c0);
    sH[w][c0] = hv.x; sH[w][c0 + 1] = hv.y;
    __syncwarp();
    const u64* W1u = (const u64*)sW1;
    u64 acc = ((const u64*)sb1)[ld];
#pragma unroll 8
    for (int k = 0; k < 64; k++) acc = ffma2(dup2(sH[w][k]), W1u[k * 32 + ld], acc);
    float2 u = upk(acc); u.x = silu(u.x); u.y = silu(u.y);
    sU[w][c0] = u.x; sU[w][c0 + 1] = u.y;
    __syncwarp();
    if (ld < 6) {
        float o = sb2_[ld];
#pragma unroll
        for (int k = 0; k < 64; k++) o += sU[w][k] * sW2[k * 6 + ld];
        out[(size_t)n * 6 + ld] = o;
    }
    int g = __ldg(&batch[n]);
    red2(g_pool + g * 64 + c0, hv.x, hv.y);
}

// ---------------- global decoder ----------------
__global__ void k_global(const int* __restrict__ batch,
    const float* __restrict__ W1, const float* __restrict__ b1,
    const float* __restrict__ W2, const float* __restrict__ b2,
    float* __restrict__ out)
{
    __shared__ float sp[NG * 64], su[NG * 32];
    __shared__ int bnd[NG + 1];
    int t = threadIdx.x;
    if (t <= NG) {
        int lo = 0, hi = N_NODES;
        while (lo < hi) { int mid = (lo + hi) >> 1; if (batch[mid] < t) lo = mid + 1; else hi = mid; }
        bnd[t] = lo;
    }
    __syncthreads();
    for (int i = t; i < NG * 64; i += 128) {
        int g = i >> 6;
        sp[i] = g_pool[i] / fmaxf((float)(bnd[g + 1] - bnd[g]), 1.f);
    }
    __syncthreads();
    {
        int g = t >> 5, j = t & 31;
        float a = b1[j];
#pragma unroll
        for (int k = 0; k < 64; k++) a += sp[g * 64 + k] * W1[k * 32 + j];
        su[g * 32 + j] = silu(a);
    }
    __syncthreads();
    if (t < NG * 4) {
        int g = t >> 2, j = t & 3;
        float o = b2[j];
#pragma unroll
        for (int k = 0; k < 32; k++) o += su[g * 32 + k] * W2[k * 4 + j];
        out[(size_t)N_NODES * 6 + g * 4 + j] = o;
    }
}

extern "C" void kernel_launch(void* const* d_in, const int* in_sizes, int n_in,
                              void* d_out, int out_size) {
    (void)in_sizes; (void)n_in; (void)out_size;
    const float* x     = (const float*)d_in[0];
    const int*   ei    = (const int*)d_in[1];
    const float* eattr = (const float*)d_in[2];
    const int*   batch = (const int*)d_in[3];
    const float* casep = (const float*)d_in[4];
    const float* bcp   = (const float*)d_in[5];
    const float* encW1 = (const float*)d_in[6];  const float* encb1 = (const float*)d_in[7];
    const float* encW2 = (const float*)d_in[8];  const float* encb2 = (const float*)d_in[9];
    const float* encg  = (const float*)d_in[10]; const float* encbe = (const float*)d_in[11];
    const float* eW1   = (const float*)d_in[12]; const float* eb1   = (const float*)d_in[13];
    const float* eW2   = (const float*)d_in[14]; const float* eb2   = (const float*)d_in[15];
    const float* eg    = (const float*)d_in[16]; const float* ebe   = (const float*)d_in[17];
    const float* nW1   = (const float*)d_in[18]; const float* nb1   = (const float*)d_in[19];
    const float* nW2   = (const float*)d_in[20]; const float* nb2   = (const float*)d_in[21];
    const float* ngm   = (const float*)d_in[22]; const float* nbe   = (const float*)d_in[23];
    const float* dlW1  = (const float*)d_in[24]; const float* dlb1  = (const float*)d_in[25];
    const float* dlW2  = (const float*)d_in[26]; const float* dlb2  = (const float*)d_in[27];
    const float* dgW1  = (const float*)d_in[28]; const float* dgb1  = (const float*)d_in[29];
    const float* dgW2  = (const float*)d_in[30]; const float* dgb2  = (const float*)d_in[31];
    float* out = (float*)d_out;

    size_t preSmem  = (size_t)(8192 + 8 * 544) * sizeof(float);
    size_t edgeSmem = (size_t)(5184 + 8 * 2496) * sizeof(float);   // 100608 B
    size_t updSmem  = (size_t)(12544 + 8 * (8 * 132 + 8 * 70)) * sizeof(float);
    cudaFuncSetAttribute(k_node_pre, cudaFuncAttributeMaxDynamicSharedMemorySize, (int)preSmem);
    cudaFuncSetAttribute(k_edge, cudaFuncAttributeMaxDynamicSharedMemorySize, (int)edgeSmem);
    cudaFuncSetAttribute(k_node_upd, cudaFuncAttributeMaxDynamicSharedMemorySize, (int)updSmem);

    k_zero_wp<<<(N_NODES + 255) / 256, 256>>>();
    k_hist<<<(N_EDGES + 255) / 256, 256>>>(ei);
    k_scan<<<1, 1024>>>();
    k_scatter<<<(N_EDGES + 255) / 256, 256>>>(ei, eattr);

    k_encoder<<<(N_NODES + 7) / 8, 256>>>(x, batch, casep, bcp, encW1, encb1, encW2, encb2, encg, encbe);
    for (int l = 0; l < NL; l++) {
        const float* eW1l = eW1 + (size_t)l * 133 * 64;
        k_node_pre<<<592, 256, preSmem>>>(eW1l);
        k_edge<<<296, 256, edgeSmem>>>(eW1l + 128 * 64, eb1 + l * 64,
                              eW2 + (size_t)l * 4096, eb2 + l * 64,
                              eg + l * 64, ebe + l * 64);
        k_node_upd<<<296, 256, updSmem>>>(nW1 + (size_t)l * 8192, nb1 + l * 64,
                                          nW2 + (size_t)l * 4096, nb2 + l * 64,
                                          ngm + l * 64, nbe + l * 64);
    }
    k_zero_pool<<<1, 256>>>();
    k_decoder_local<<<(N_NODES + 7) / 8, 256>>>(dlW1, dlb1, dlW2, dlb2, batch, out);
    k_global<<<1, 128>>>(batch, dgW1, dgb1, dgW2, dgb2, out);
}

// round 11
// speedup vs baseline: 1.8086x; 1.1424x over previous
#include <cuda_runtime.h>
#include <cstdint>
#define DINL __device__ __forceinline__
constexpr int N_NODES = 50000;
constexpr int N_EDGES = 1600000;
constexpr int NL = 5;
constexpr int NG = 4;
constexpr float EPS = 1e-5f;

__device__ float g_h  [N_NODES * 64];
__device__ float g_hd [N_NODES * 64];
__device__ float g_hs [N_NODES * 64];
__device__ float g_agg[N_NODES * 64];
__device__ float g_pool[NG * 64];
__device__ int   g_wp [N_NODES];
__device__ float g_em [(size_t)N_EDGES * 8];

typedef unsigned long long u64;
DINL u64 pk2(float x, float y) { u64 r; asm("mov.b64 %0,{%1,%2};" : "=l"(r) : "f"(x), "f"(y)); return r; }
DINL u64 dup2(float x) { return pk2(x, x); }
DINL float2 upk(u64 v) { float2 r; asm("mov.b64 {%0,%1},%2;" : "=f"(r.x), "=f"(r.y) : "l"(v)); return r; }
DINL u64 ffma2(u64 a, u64 b, u64 c) { u64 d; asm("fma.rn.f32x2 %0,%1,%2,%3;" : "=l"(d) : "l"(a), "l"(b), "l"(c)); return d; }
DINL u64 add2(u64 a, u64 b) { u64 d; asm("add.rn.f32x2 %0,%1,%2;" : "=l"(d) : "l"(a), "l"(b)); return d; }
DINL void red2(float* p, float x, float y) { asm volatile("red.global.add.v2.f32 [%0], {%1,%2};" :: "l"(p), "f"(x), "f"(y) : "memory"); }
DINL void red4(float* p, float4 v) { asm volatile("red.global.add.v4.f32 [%0], {%1,%2,%3,%4};" :: "l"(p), "f"(v.x), "f"(v.y), "f"(v.z), "f"(v.w) : "memory"); }
DINL float silu(float x) { return __fdividef(x, 1.f + __expf(-x)); }
DINL uint32_t tf32c(float f) { uint32_t r; asm("cvt.rna.tf32.f32 %0,%1;" : "=r"(r) : "f"(f)); return r; }
DINL float tf32f(float f) { return __uint_as_float(tf32c(f)); }
DINL void mma8(float* c, uint32_t a0, uint32_t a1, uint32_t a2, uint32_t a3, uint32_t b0, uint32_t b1) {
    asm volatile("mma.sync.aligned.m16n8k8.row.col.f32.tf32.tf32.f32 {%0,%1,%2,%3},{%4,%5,%6,%7},{%8,%9},{%0,%1,%2,%3};"
        : "+f"(c[0]), "+f"(c[1]), "+f"(c[2]), "+f"(c[3])
        : "r"(a0), "r"(a1), "r"(a2), "r"(a3), "r"(b0), "r"(b1));
}

// ---------------- CSR build ----------------
__global__ void k_zero_wp() { int i = blockIdx.x * 256 + threadIdx.x; if (i < N_NODES) g_wp[i] = 0; }
__global__ void k_hist(const int* __restrict__ ei) { int e = blockIdx.x * 256 + threadIdx.x; if (e < N_EDGES) atomicAdd(&g_wp[ei[N_EDGES + e]], 1); }
__global__ void k_scan() {
    __shared__ int part[1024];
    int t = threadIdx.x; const int C = 49; int base = t * C; int sum = 0;
    for (int i = 0; i < C; i++) { int idx = base + i; if (idx < N_NODES) sum += g_wp[idx]; }
    part[t] = sum; __syncthreads();
    for (int off = 1; off < 1024; off <<= 1) { int v = (t >= off) ? part[t - off] : 0; __syncthreads(); part[t] += v; __syncthreads(); }
    int run = (t == 0) ? 0 : part[t - 1];
    for (int i = 0; i < C; i++) { int idx = base + i; if (idx < N_NODES) { int v = g_wp[idx]; g_wp[idx] = run; run += v; } }
}
__global__ void k_scatter(const int* __restrict__ ei, const float* __restrict__ eattr) {
    int e = blockIdx.x * 256 + threadIdx.x;
    if (e < N_EDGES) {
        int d = ei[N_EDGES + e];
        int pos = atomicAdd(&g_wp[d], 1);
        const float* ea = eattr + (size_t)e * 5;
        float4 f0 = make_float4(__int_as_float(ei[e]), __int_as_float(d), __ldg(ea), __ldg(ea + 1));
        float4 f1 = make_float4(__ldg(ea + 2), __ldg(ea + 3), __ldg(ea + 4), 0.f);
        size_t p8 = (size_t)pos * 8;
        *(float4*)&g_em[p8] = f0; *(float4*)&g_em[p8 + 4] = f1;
    }
}

// ---------------- encoder ----------------
__global__ void __launch_bounds__(256) k_encoder(
    const float* __restrict__ x, const int* __restrict__ batch,
    const float* __restrict__ casep, const float* __restrict__ bcp,
    const float* __restrict__ W1, const float* __restrict__ b1,
    const float* __restrict__ W2, const float* __restrict__ b2,
    const float* __restrict__ gam, const float* __restrict__ bet)
{
    __shared__ float sW1[1024], sW2[4096], sb1[64], sb2[64], sg[64], sbe[64];
    __shared__ float sH[8][64];
    int tid = threadIdx.x;
    for (int i = tid; i < 1024; i += 256) sW1[i] = W1[i];
    for (int i = tid; i < 4096; i += 256) sW2[i] = W2[i];
    if (tid < 64) { sb1[tid] = b1[tid]; sb2[tid] = b2[tid]; sg[tid] = gam[tid]; sbe[tid] = bet[tid]; }
    __syncthreads();
    int w = tid >> 5, ld = tid & 31, c0 = 2 * ld;
    int n = blockIdx.x * 8 + w;
    if (n >= N_NODES) return;
    float in[16];
#pragma unroll
    for (int k = 0; k < 8; k++) in[k] = __ldg(&x[n * 8 + k]);
    int g = __ldg(&batch[n]);
#pragma unroll
    for (int k = 0; k < 4; k++) { in[8 + k] = __ldg(&casep[g * 4 + k]); in[12 + k] = __ldg(&bcp[g * 4 + k]); }
    const u64* W1u = (const u64*)sW1;
    u64 acc = ((const u64*)sb1)[ld];
#pragma unroll
    for (int k = 0; k < 16; k++) acc = ffma2(dup2(in[k]), W1u[k * 32 + ld], acc);
    float2 a = upk(acc); a.x = silu(a.x); a.y = silu(a.y);
    sH[w][c0] = a.x; sH[w][c0 + 1] = a.y;
    __syncwarp();
    const u64* W2u = (const u64*)sW2;
    u64 acc2 = ((const u64*)sb2)[ld];
#pragma unroll 8
    for (int k = 0; k < 64; k++) acc2 = ffma2(dup2(sH[w][k]), W2u[k * 32 + ld], acc2);
    float2 v = upk(acc2);
    float s = v.x + v.y, q = v.x * v.x + v.y * v.y;
#pragma unroll
    for (int o = 16; o; o >>= 1) { s += __shfl_xor_sync(~0u, s, o); q += __shfl_xor_sync(~0u, q, o); }
    float m = s * (1.f / 64.f), rs = rsqrtf(q * (1.f / 64.f) - m * m + EPS);
    float2 out;
    out.x = (v.x - m) * rs * sg[c0] + sbe[c0];
    out.y = (v.y - m) * rs * sg[c0 + 1] + sbe[c0 + 1];
    *(float2*)(g_h + (size_t)n * 64 + c0) = out;
}

// ---------------- node pre: 16-node tiles, tf32 mma, out [16 x 128] = hd|hs ----------------
// smem: sWt[64][136] tf32 (8704) | sA[16][76] tf32 (1216)  -> 39680 B
__global__ void __launch_bounds__(256) k_node_pre(const float* __restrict__ eW1l)
{
    extern __shared__ float ps[];
    float* sWt = ps;
    float* sA  = ps + 8704;
    int tid = threadIdx.x;
    for (int i = tid; i < 64 * 128; i += 256) {
        int k = i >> 7, c = i & 127;
        float v = (c < 64) ? eW1l[k * 64 + c] : eW1l[(64 + k) * 64 + (c - 64)];
        sWt[k * 136 + c] = tf32f(v);
    }
    __syncthreads();
    int w = tid >> 5, ld = tid & 31, g8 = ld >> 2, q4 = ld & 3;
    const uint32_t* au = (const uint32_t*)sA;
    const uint32_t* bu = (const uint32_t*)sWt;
    for (int t = blockIdx.x; t < N_NODES / 16; t += gridDim.x) {
        int n0 = t * 16;
        __syncthreads();
        {
            int n = tid >> 4, c4 = (tid & 15) * 4;
            float4 v = *(const float4*)(g_h + (size_t)(n0 + n) * 64 + c4);
            uint4 tv; tv.x = tf32c(v.x); tv.y = tf32c(v.y); tv.z = tf32c(v.z); tv.w = tf32c(v.w);
            *(uint4*)&sA[n * 76 + c4] = tv;
        }
        {
            int i4 = tid * 4, n = i4 >> 6, c = i4 & 63;
            *(float4*)(g_agg + (size_t)(n0 + n) * 64 + c) = make_float4(0.f, 0.f, 0.f, 0.f);
        }
        __syncthreads();
        float acc[2][4];
#pragma unroll
        for (int sbi = 0; sbi < 2; sbi++)
#pragma unroll
            for (int j = 0; j < 4; j++) acc[sbi][j] = 0.f;
#pragma unroll
        for (int kb = 0; kb < 8; kb++) {
            int kc = kb * 8 + q4;
            uint32_t a0 = au[g8 * 76 + kc], a1 = au[(g8 + 8) * 76 + kc];
            uint32_t a2 = au[g8 * 76 + kc + 4], a3 = au[(g8 + 8) * 76 + kc + 4];
#pragma unroll
            for (int sbi = 0; sbi < 2; sbi++) {
                int nb = 2 * w + sbi;
                uint32_t b0 = bu[kc * 136 + nb * 8 + g8];
                uint32_t b1 = bu[(kc + 4) * 136 + nb * 8 + g8];
                mma8(acc[sbi], a0, a1, a2, a3, b0, b1);
            }
        }
#pragma unroll
        for (int sbi = 0; sbi < 2; sbi++) {
            int c = (2 * w + sbi) * 8 + 2 * q4;
            float* base = (c < 64) ? g_hd : g_hs;
            int cl = (c < 64) ? c : c - 64;
            *(float2*)(base + (size_t)(n0 + g8) * 64 + cl)     = make_float2(acc[sbi][0], acc[sbi][1]);
            *(float2*)(base + (size_t)(n0 + g8 + 8) * 64 + cl) = make_float2(acc[sbi][2], acc[sbi][3]);
        }
    }
}

// ---------------- edge kernel: 32-edge tiles, phase-2 via mma.sync tf32 (proven R10) ----------------
__global__ void __launch_bounds__(256, 2) k_edge(
    const float* __restrict__ W1c, const float* __restrict__ b1,
    const float* __restrict__ W2, const float* __restrict__ b2,
    const float* __restrict__ gam, const float* __restrict__ bet)
{
    extern __shared__ float es[];
    float* sW2s = es;
    float* sW1c = es + 4608;
    float* sb1 = es + 4928; float* sb2 = es + 4992;
    float* sg = es + 5056;  float* sbe = es + 5120;
    float* sPer = es + 5184;
    int tid = threadIdx.x;
    for (int i = tid; i < 4096; i += 256) {
        int k = i >> 6, c = i & 63;
        sW2s[k * 72 + c] = tf32f(W2[i]);
    }
    for (int i = tid; i < 320; i += 256) sW1c[i] = W1c[i];
    if (tid < 64) { sb1[tid] = b1[tid]; sb2[tid] = b2[tid]; sg[tid] = gam[tid]; sbe[tid] = bet[tid]; }
    __syncthreads();
    int w = tid >> 5, ld = tid & 31;
    int pe = ld >> 1, half = ld & 1;
    int eb = ld >> 3, cb = ld & 7;
    int g8 = ld >> 2, q4 = ld & 3;
    float* sM = sPer + w * 2496;
    int* sD = (int*)(sM + 2432);
    int* sSrc = (int*)(sM + 2464);
    const ulonglong2* W1cu = (const ulonglong2*)sW1c;
    const ulonglong2* b1u = (const ulonglong2*)sb1;
    u64 gv[4], bev[4];
#pragma unroll
    for (int j = 0; j < 4; j++) { gv[j] = ((const u64*)sg)[cb * 4 + j]; bev[j] = ((const u64*)sbe)[cb * 4 + j]; }
    float b2s[8];
#pragma unroll
    for (int j = 0; j < 8; j++) b2s[j] = sb2[cb * 8 + j];
    int gw = (blockIdx.x * 256 + tid) >> 5;
    int nw = (gridDim.x * 256) >> 5;
    for (int grp = gw; grp < N_EDGES / 32; grp += nw) {
        int e0 = grp * 32;
        __syncwarp();
        int didx[2];
        u64 ead[2][5];
#pragma unroll
        for (int sub = 0; sub < 2; sub++) {
            int slot = sub * 16 + pe;
            const float4* emp = (const float4*)&g_em[(size_t)(e0 + slot) * 8];
            float4 f0 = __ldg(emp), f1 = __ldg(emp + 1);
            didx[sub] = __float_as_int(f0.y);
            ead[sub][0] = dup2(f0.z); ead[sub][1] = dup2(f0.w);
            ead[sub][2] = dup2(f1.x); ead[sub][3] = dup2(f1.y); ead[sub][4] = dup2(f1.z);
            if (half == 0) { sD[slot] = didx[sub]; sSrc[slot] = __float_as_int(f0.x); }
        }
        __syncwarp();
#pragma unroll
        for (int r = 0; r < 16; r++) {
            int chunk = r * 32 + ld, eslot = chunk >> 4, c4 = (chunk & 15) * 4;
            *(float4*)&sM[eslot * 68 + c4] = *(const float4*)(g_hs + (size_t)sSrc[eslot] * 64 + c4);
        }
        __syncwarp();
#pragma unroll
        for (int sub = 0; sub < 2; sub++) {
            int slot = sub * 16 + pe;
            const ulonglong2* hdp = (const ulonglong2*)(g_hd + (size_t)didx[sub] * 64 + half * 32);
            float* mrow = sM + slot * 68 + half * 32;
#pragma unroll
            for (int j = 0; j < 8; j++) {
                ulonglong2 hdj = __ldg(hdp + j);
                ulonglong2 hsj = ((const ulonglong2*)mrow)[j];
                ulonglong2 bj = b1u[half * 8 + j];
                u64 a0 = add2(add2(hdj.x, hsj.x), bj.x);
                u64 a1 = add2(add2(hdj.y, hsj.y), bj.y);
#pragma unroll
                for (int r = 0; r < 5; r++) {
                    ulonglong2 wv = W1cu[r * 16 + half * 8 + j];
                    a0 = ffma2(ead[sub][r], wv.x, a0); a1 = ffma2(ead[sub][r], wv.y, a1);
                }
                float2 v0 = upk(a0), v1 = upk(a1);
                uint4 tw;
                tw.x = tf32c(silu(v0.x)); tw.y = tf32c(silu(v0.y));
                tw.z = tf32c(silu(v1.x)); tw.w = tf32c(silu(v1.y));
                *(uint4*)(mrow + 4 * j) = tw;
            }
        }
        __syncwarp();
        float acc[2][8][4];
#pragma unroll
        for (int mb = 0; mb < 2; mb++)
#pragma unroll
            for (int nb = 0; nb < 8; nb++)
#pragma unroll
                for (int j = 0; j < 4; j++) acc[mb][nb][j] = 0.f;
#pragma unroll
        for (int kb = 0; kb < 8; kb++) {
            int kc = kb * 8 + q4;
            const uint32_t* mu = (const uint32_t*)sM;
            uint32_t a00 = mu[(g8) * 68 + kc],      a01 = mu[(g8 + 8) * 68 + kc];
            uint32_t a02 = mu[(g8) * 68 + kc + 4],  a03 = mu[(g8 + 8) * 68 + kc + 4];
            uint32_t a10 = mu[(g8 + 16) * 68 + kc],     a11 = mu[(g8 + 24) * 68 + kc];
            uint32_t a12 = mu[(g8 + 16) * 68 + kc + 4], a13 = mu[(g8 + 24) * 68 + kc + 4];
            const uint32_t* wu = (const uint32_t*)sW2s;
#pragma unroll
            for (int nb = 0; nb < 8; nb++) {
                uint32_t b0 = wu[kc * 72 + nb * 8 + g8];
                uint32_t b1_ = wu[(kc + 4) * 72 + nb * 8 + g8];
                mma8(acc[0][nb], a00, a01, a02, a03, b0, b1_);
                mma8(acc[1][nb], a10, a11, a12, a13, b0, b1_);
            }
        }
        __syncwarp();
#pragma unroll
        for (int mb = 0; mb < 2; mb++)
#pragma unroll
            for (int nb = 0; nb < 8; nb++) {
                int elo = mb * 16 + g8;
                *(float2*)&sM[elo * 76 + nb * 8 + 2 * q4] = make_float2(acc[mb][nb][0], acc[mb][nb][1]);
                *(float2*)&sM[(elo + 8) * 76 + nb * 8 + 2 * q4] = make_float2(acc[mb][nb][2], acc[mb][nb][3]);
            }
        __syncwarp();
        float4 f0a[8], f1a[8];
        float s[8], q[8];
#pragma unroll
        for (int i = 0; i < 8; i++) {
            int e = eb * 8 + i;
            float4 v0 = *(const float4*)&sM[e * 76 + cb * 8];
            float4 v1 = *(const float4*)&sM[e * 76 + cb * 8 + 4];
            v0.x += b2s[0]; v0.y += b2s[1]; v0.z += b2s[2]; v0.w += b2s[3];
            v1.x += b2s[4]; v1.y += b2s[5]; v1.z += b2s[6]; v1.w += b2s[7];
            f0a[i] = v0; f1a[i] = v1;
            s[i] = v0.x + v0.y + v0.z + v0.w + v1.x + v1.y + v1.z + v1.w;
            q[i] = v0.x * v0.x + v0.y * v0.y + v0.z * v0.z + v0.w * v0.w
                 + v1.x * v1.x + v1.y * v1.y + v1.z * v1.z + v1.w * v1.w;
        }
#pragma unroll
        for (int o = 4; o; o >>= 1) {
#pragma unroll
            for (int i = 0; i < 8; i++) { s[i] += __shfl_xor_sync(~0u, s[i], o); q[i] += __shfl_xor_sync(~0u, q[i], o); }
        }
        int curD = sD[eb * 8];
        u64 av[4] = {0ull, 0ull, 0ull, 0ull};
#pragma unroll
        for (int i = 0; i < 8; i++) {
            int dI = sD[eb * 8 + i];
            float mn = s[i] * (1.f / 64.f);
            float rs = rsqrtf(q[i] * (1.f / 64.f) - mn * mn + EPS);
            u64 rsd = dup2(rs), mrd = dup2(-mn * rs);
            if (dI != curD) {
                float2 a0 = upk(av[0]), a1 = upk(av[1]), a2 = upk(av[2]), a3 = upk(av[3]);
                float* base = g_agg + (size_t)curD * 64 + cb * 8;
                red4(base, make_float4(a0.x, a0.y, a1.x, a1.y));
                red4(base + 4, make_float4(a2.x, a2.y, a3.x, a3.y));
                av[0] = av[1] = av[2] = av[3] = 0ull;
                curD = dI;
            }
            u64 vv0 = pk2(f0a[i].x, f0a[i].y), vv1 = pk2(f0a[i].z, f0a[i].w);
            u64 vv2 = pk2(f1a[i].x, f1a[i].y), vv3 = pk2(f1a[i].z, f1a[i].w);
            av[0] = add2(av[0], ffma2(ffma2(vv0, rsd, mrd), gv[0], bev[0]));
            av[1] = add2(av[1], ffma2(ffma2(vv1, rsd, mrd), gv[1], bev[1]));
            av[2] = add2(av[2], ffma2(ffma2(vv2, rsd, mrd), gv[2], bev[2]));
            av[3] = add2(av[3], ffma2(ffma2(vv3, rsd, mrd), gv[3], bev[3]));
        }
        {
            float2 a0 = upk(av[0]), a1 = upk(av[1]), a2 = upk(av[2]), a3 = upk(av[3]);
            float* base = g_agg + (size_t)curD * 64 + cb * 8;
            red4(base, make_float4(a0.x, a0.y, a1.x, a1.y));
            red4(base + 4, make_float4(a2.x, a2.y, a3.x, a3.y));
        }
    }
}

// ---------------- node update: 16-node block tiles, tf32 mma both GEMMs ----------------
// smem floats: sW1t[128][72] (9216) | sW2t[64][72] (4608) | sA[16][140] (2240) | sH[16][68] (1088)
//              sMid[16][76] (1216) | sPart[8][16][2] (256) | sb1,sb2,sgm,sbe (256)  => 75520 B
__global__ void __launch_bounds__(256) k_node_upd(
    const float* __restrict__ W1, const float* __restrict__ b1,
    const float* __restrict__ W2, const float* __restrict__ b2,
    const float* __restrict__ gam, const float* __restrict__ bet)
{
    extern __shared__ float us[];
    float* sW1t = us;                 // 9216
    float* sW2t = us + 9216;          // 4608
    float* sA   = us + 13824;         // 2240
    float* sH   = us + 16064;         // 1088
    float* sMid = us + 17152;         // 1216
    float* sPart= us + 18368;         // 256
    float* sb1  = us + 18624;
    float* sb2  = us + 18688;
    float* sgm  = us + 18752;
    float* sbe  = us + 18816;
    int tid = threadIdx.x;
    for (int i = tid; i < 128 * 64; i += 256) { int k = i >> 6, c = i & 63; sW1t[k * 72 + c] = tf32f(W1[i]); }
    for (int i = tid; i < 64 * 64; i += 256)  { int k = i >> 6, c = i & 63; sW2t[k * 72 + c] = tf32f(W2[i]); }
    if (tid < 64) { sb1[tid] = b1[tid]; sb2[tid] = b2[tid]; sgm[tid] = gam[tid]; sbe[tid] = bet[tid]; }
    __syncthreads();
    int w = tid >> 5, ld = tid & 31, g8 = ld >> 2, q4 = ld & 3;
    const uint32_t* au = (const uint32_t*)sA;
    const uint32_t* b1w = (const uint32_t*)sW1t;
    const uint32_t* b2w = (const uint32_t*)sW2t;
    const uint32_t* mu = (const uint32_t*)sMid;
    int c0 = w * 8 + 2 * q4;
    float b1c0 = sb1[c0], b1c1 = sb1[c0 + 1];
    float b2c0 = sb2[c0], b2c1 = sb2[c0 + 1];
    float gm0 = sgm[c0], gm1 = sgm[c0 + 1];
    float be0 = sbe[c0], be1 = sbe[c0 + 1];
    for (int t = blockIdx.x; t < N_NODES / 16; t += gridDim.x) {
        int n0 = t * 16;
        __syncthreads();
        {
            int n = tid >> 4, c8 = (tid & 15) * 8;
            float4 v0, v1;
            if (c8 < 64) {
                v0 = *(const float4*)(g_h + (size_t)(n0 + n) * 64 + c8);
                v1 = *(const float4*)(g_h + (size_t)(n0 + n) * 64 + c8 + 4);
                *(float4*)&sH[n * 68 + c8] = v0;
                *(float4*)&sH[n * 68 + c8 + 4] = v1;
            } else {
                v0 = *(const float4*)(g_agg + (size_t)(n0 + n) * 64 + c8 - 64);
                v1 = *(const float4*)(g_agg + (size_t)(n0 + n) * 64 + c8 - 60);
            }
            uint4 t0; t0.x = tf32c(v0.x); t0.y = tf32c(v0.y); t0.z = tf32c(v0.z); t0.w = tf32c(v0.w);
            uint4 t1; t1.x = tf32c(v1.x); t1.y = tf32c(v1.y); t1.z = tf32c(v1.z); t1.w = tf32c(v1.w);
            *(uint4*)&sA[n * 140 + c8] = t0;
            *(uint4*)&sA[n * 140 + c8 + 4] = t1;
        }
        __syncthreads();
        // GEMM1: warp stripe nb = w
        float a1c[4] = {0.f, 0.f, 0.f, 0.f};
#pragma unroll
        for (int kb = 0; kb < 16; kb++) {
            int kc = kb * 8 + q4;
            uint32_t a0 = au[g8 * 140 + kc], a1 = au[(g8 + 8) * 140 + kc];
            uint32_t a2 = au[g8 * 140 + kc + 4], a3 = au[(g8 + 8) * 140 + kc + 4];
            uint32_t b0 = b1w[kc * 72 + w * 8 + g8];
            uint32_t b1_ = b1w[(kc + 4) * 72 + w * 8 + g8];
            mma8(a1c, a0, a1, a2, a3, b0, b1_);
        }
        sMid[g8 * 76 + c0]       = tf32f(silu(a1c[0] + b1c0));
        sMid[g8 * 76 + c0 + 1]   = tf32f(silu(a1c[1] + b1c1));
        sMid[(g8 + 8) * 76 + c0]     = tf32f(silu(a1c[2] + b1c0));
        sMid[(g8 + 8) * 76 + c0 + 1] = tf32f(silu(a1c[3] + b1c1));
        __syncthreads();
        // GEMM2
        float a2c[4] = {0.f, 0.f, 0.f, 0.f};
#pragma unroll
        for (int kb = 0; kb < 8; kb++) {
            int kc = kb * 8 + q4;
            uint32_t a0 = mu[g8 * 76 + kc], a1 = mu[(g8 + 8) * 76 + kc];
            uint32_t a2 = mu[g8 * 76 + kc + 4], a3 = mu[(g8 + 8) * 76 + kc + 4];
            uint32_t b0 = b2w[kc * 72 + w * 8 + g8];
            uint32_t b1_ = b2w[(kc + 4) * 72 + w * 8 + g8];
            mma8(a2c, a0, a1, a2, a3, b0, b1_);
        }
        float v0 = a2c[0] + b2c0, v1 = a2c[1] + b2c1;
        float v2 = a2c[2] + b2c0, v3 = a2c[3] + b2c1;
        float s0 = v0 + v1, q0 = v0 * v0 + v1 * v1;
        float s1 = v2 + v3, q1 = v2 * v2 + v3 * v3;
#pragma unroll
        for (int o = 1; o <= 2; o <<= 1) {
            s0 += __shfl_xor_sync(~0u, s0, o); q0 += __shfl_xor_sync(~0u, q0, o);
            s1 += __shfl_xor_sync(~0u, s1, o); q1 += __shfl_xor_sync(~0u, q1, o);
        }
        if (q4 == 0) {
            sPart[w * 32 + g8 * 2] = s0;       sPart[w * 32 + g8 * 2 + 1] = q0;
            sPart[w * 32 + (g8 + 8) * 2] = s1; sPart[w * 32 + (g8 + 8) * 2 + 1] = q1;
        }
        __syncthreads();
        float S0 = 0.f, Q0 = 0.f, S1 = 0.f, Q1 = 0.f;
#pragma unroll
        for (int ww = 0; ww < 8; ww++) {
            S0 += sPart[ww * 32 + g8 * 2];       Q0 += sPart[ww * 32 + g8 * 2 + 1];
            S1 += sPart[ww * 32 + (g8 + 8) * 2]; Q1 += sPart[ww * 32 + (g8 + 8) * 2 + 1];
        }
        float mn0 = S0 * (1.f / 64.f), rs0 = rsqrtf(Q0 * (1.f / 64.f) - mn0 * mn0 + EPS);
        float mn1 = S1 * (1.f / 64.f), rs1 = rsqrtf(Q1 * (1.f / 64.f) - mn1 * mn1 + EPS);
        float2 o0, o1;
        o0.x = sH[g8 * 68 + c0]     + (v0 - mn0) * rs0 * gm0 + be0;
        o0.y = sH[g8 * 68 + c0 + 1] + (v1 - mn0) * rs0 * gm1 + be1;
        o1.x = sH[(g8 + 8) * 68 + c0]     + (v2 - mn1) * rs1 * gm0 + be0;
        o1.y = sH[(g8 + 8) * 68 + c0 + 1] + (v3 - mn1) * rs1 * gm1 + be1;
        *(float2*)(g_h + (size_t)(n0 + g8) * 64 + c0)     = o0;
        *(float2*)(g_h + (size_t)(n0 + g8 + 8) * 64 + c0) = o1;
    }
}

__global__ void k_zero_pool() { int t = threadIdx.x; if (t < NG * 64) g_pool[t] = 0.f; }

// ---------------- local decoder + pooling ----------------
__global__ void __launch_bounds__(256) k_decoder_local(
    const float* __restrict__ W1, const float* __restrict__ b1,
    const float* __restrict__ W2, const float* __restrict__ b2,
    const int* __restrict__ batch, float* __restrict__ out)
{
    __shared__ float sW1[4096], sW2[384], sb1[64], sb2_[8];
    __shared__ float sH[8][64], sU[8][64];
    int tid = threadIdx.x;
    for (int i = tid; i < 4096; i += 256) sW1[i] = W1[i];
    for (int i = tid; i < 384; i += 256) sW2[i] = W2[i];
    if (tid < 64) sb1[tid] = b1[tid];
    if (tid < 6) sb2_[tid] = b2[tid];
    __syncthreads();
    int w = tid >> 5, ld = tid & 31, c0 = 2 * ld;
    int n = blockIdx.x * 8 + w;
    if (n >= N_NODES) return;
    float2 hv = *(const float2*)(g_h + (size_t)n * 64 + c0);
    sH[w][c0] = hv.x; sH[w][c0 + 1] = hv.y;
    __syncwarp();
    const u64* W1u = (const u64*)sW1;
    u64 acc = ((const u64*)sb1)[ld];
#pragma unroll 8
    for (int k = 0; k < 64; k++) acc = ffma2(dup2(sH[w][k]), W1u[k * 32 + ld], acc);
    float2 u = upk(acc); u.x = silu(u.x); u.y = silu(u.y);
    sU[w][c0] = u.x; sU[w][c0 + 1] = u.y;
    __syncwarp();
    if (ld < 6) {
        float o = sb2_[ld];
#pragma unroll
        for (int k = 0; k < 64; k++) o += sU[w][k] * sW2[k * 6 + ld];
        out[(size_t)n * 6 + ld] = o;
    }
    int g = __ldg(&batch[n]);
    red2(g_pool + g * 64 + c0, hv.x, hv.y);
}

// ---------------- global decoder ----------------
__global__ void k_global(const int* __restrict__ batch,
    const float* __restrict__ W1, const float* __restrict__ b1,
    const float* __restrict__ W2, const float* __restrict__ b2,
    float* __restrict__ out)
{
    __shared__ float sp[NG * 64], su[NG * 32];
    __shared__ int bnd[NG + 1];
    int t = threadIdx.x;
    if (t <= NG) {
        int lo = 0, hi = N_NODES;
        while (lo < hi) { int mid = (lo + hi) >> 1; if (batch[mid] < t) lo = mid + 1; else hi = mid; }
        bnd[t] = lo;
    }
    __syncthreads();
    for (int i = t; i < NG * 64; i += 128) {
        int g = i >> 6;
        sp[i] = g_pool[i] / fmaxf((float)(bnd[g + 1] - bnd[g]), 1.f);
    }
    __syncthreads();
    {
        int g = t >> 5, j = t & 31;
        float a = b1[j];
#pragma unroll
        for (int k = 0; k < 64; k++) a += sp[g * 64 + k] * W1[k * 32 + j];
        su[g * 32 + j] = silu(a);
    }
    __syncthreads();
    if (t < NG * 4) {
        int g = t >> 2, j = t & 3;
        float o = b2[j];
#pragma unroll
        for (int k = 0; k < 32; k++) o += su[g * 32 + k] * W2[k * 4 + j];
        out[(size_t)N_NODES * 6 + g * 4 + j] = o;
    }
}

extern "C" void kernel_launch(void* const* d_in, const int* in_sizes, int n_in,
                              void* d_out, int out_size) {
    (void)in_sizes; (void)n_in; (void)out_size;
    const float* x     = (const float*)d_in[0];
    const int*   ei    = (const int*)d_in[1];
    const float* eattr = (const float*)d_in[2];
    const int*   batch = (const int*)d_in[3];
    const float* casep = (const float*)d_in[4];
    const float* bcp   = (const float*)d_in[5];
    const float* encW1 = (const float*)d_in[6];  const float* encb1 = (const float*)d_in[7];
    const float* encW2 = (const float*)d_in[8];  const float* encb2 = (const float*)d_in[9];
    const float* encg  = (const float*)d_in[10]; const float* encbe = (const float*)d_in[11];
    const float* eW1   = (const float*)d_in[12]; const float* eb1   = (const float*)d_in[13];
    const float* eW2   = (const float*)d_in[14]; const float* eb2   = (const float*)d_in[15];
    const float* eg    = (const float*)d_in[16]; const float* ebe   = (const float*)d_in[17];
    const float* nW1   = (const float*)d_in[18]; const float* nb1   = (const float*)d_in[19];
    const float* nW2   = (const float*)d_in[20]; const float* nb2   = (const float*)d_in[21];
    const float* ngm   = (const float*)d_in[22]; const float* nbe   = (const float*)d_in[23];
    const float* dlW1  = (const float*)d_in[24]; const float* dlb1  = (const float*)d_in[25];
    const float* dlW2  = (const float*)d_in[26]; const float* dlb2  = (const float*)d_in[27];
    const float* dgW1  = (const float*)d_in[28]; const float* dgb1  = (const float*)d_in[29];
    const float* dgW2  = (const float*)d_in[30]; const float* dgb2  = (const float*)d_in[31];
    float* out = (float*)d_out;

    size_t preSmem  = (size_t)9920 * sizeof(float);                 // 39680 B
    size_t edgeSmem = (size_t)(5184 + 8 * 2496) * sizeof(float);    // 100608 B
    size_t updSmem  = (size_t)18880 * sizeof(float);                // 75520 B
    cudaFuncSetAttribute(k_node_pre, cudaFuncAttributeMaxDynamicSharedMemorySize, (int)preSmem);
    cudaFuncSetAttribute(k_edge, cudaFuncAttributeMaxDynamicSharedMemorySize, (int)edgeSmem);
    cudaFuncSetAttribute(k_node_upd, cudaFuncAttributeMaxDynamicSharedMemorySize, (int)updSmem);

    k_zero_wp<<<(N_NODES + 255) / 256, 256>>>();
    k_hist<<<(N_EDGES + 255) / 256, 256>>>(ei);
    k_scan<<<1, 1024>>>();
    k_scatter<<<(N_EDGES + 255) / 256, 256>>>(ei, eattr);

    k_encoder<<<(N_NODES + 7) / 8, 256>>>(x, batch, casep, bcp, encW1, encb1, encW2, encb2, encg, encbe);
    for (int l = 0; l < NL; l++) {
        const float* eW1l = eW1 + (size_t)l * 133 * 64;
        k_node_pre<<<296, 256, preSmem>>>(eW1l);
        k_edge<<<296, 256, edgeSmem>>>(eW1l + 128 * 64, eb1 + l * 64,
                              eW2 + (size_t)l * 4096, eb2 + l * 64,
                              eg + l * 64, ebe + l * 64);
        k_node_upd<<<148, 256, updSmem>>>(nW1 + (size_t)l * 8192, nb1 + l * 64,
                                          nW2 + (size_t)l * 4096, nb2 + l * 64,
                                          ngm + l * 64, nbe + l * 64);
    }
    k_zero_pool<<<1, 256>>>();
    k_decoder_local<<<(N_NODES + 7) / 8, 256>>>(dlW1, dlb1, dlW2, dlb2, batch, out);
    k_global<<<1, 128>>>(batch, dgW1, dgb1, dgW2, dgb2, out);
}

// round 12
// speedup vs baseline: 1.9101x; 1.0561x over previous
#include <cuda_runtime.h>
#include <cstdint>
#define DINL __device__ __forceinline__
constexpr int N_NODES = 50000;
constexpr int N_EDGES = 1600000;
constexpr int NL = 5;
constexpr int NG = 4;
constexpr float EPS = 1e-5f;

__device__ float g_h  [N_NODES * 64];
__device__ float g_hd [N_NODES * 64];
__device__ float g_hs [N_NODES * 64];
__device__ float g_agg[N_NODES * 64];
__device__ float g_pool[NG * 64];
__device__ int   g_wp [N_NODES];
__device__ float g_em [(size_t)N_EDGES * 8];

typedef unsigned long long u64;
DINL u64 pk2(float x, float y) { u64 r; asm("mov.b64 %0,{%1,%2};" : "=l"(r) : "f"(x), "f"(y)); return r; }
DINL u64 dup2(float x) { return pk2(x, x); }
DINL float2 upk(u64 v) { float2 r; asm("mov.b64 {%0,%1},%2;" : "=f"(r.x), "=f"(r.y) : "l"(v)); return r; }
DINL u64 ffma2(u64 a, u64 b, u64 c) { u64 d; asm("fma.rn.f32x2 %0,%1,%2,%3;" : "=l"(d) : "l"(a), "l"(b), "l"(c)); return d; }
DINL u64 add2(u64 a, u64 b) { u64 d; asm("add.rn.f32x2 %0,%1,%2;" : "=l"(d) : "l"(a), "l"(b)); return d; }
DINL void red2(float* p, float x, float y) { asm volatile("red.global.add.v2.f32 [%0], {%1,%2};" :: "l"(p), "f"(x), "f"(y) : "memory"); }
DINL void red4(float* p, float4 v) { asm volatile("red.global.add.v4.f32 [%0], {%1,%2,%3,%4};" :: "l"(p), "f"(v.x), "f"(v.y), "f"(v.z), "f"(v.w) : "memory"); }
DINL float silu(float x) { return __fdividef(x, 1.f + __expf(-x)); }
DINL uint32_t tf32c(float f) { uint32_t r; asm("cvt.rna.tf32.f32 %0,%1;" : "=r"(r) : "f"(f)); return r; }
DINL float tf32f(float f) { return __uint_as_float(tf32c(f)); }
DINL void mma8(float* c, uint32_t a0, uint32_t a1, uint32_t a2, uint32_t a3, uint32_t b0, uint32_t b1) {
    asm volatile("mma.sync.aligned.m16n8k8.row.col.f32.tf32.tf32.f32 {%0,%1,%2,%3},{%4,%5,%6,%7},{%8,%9},{%0,%1,%2,%3};"
        : "+f"(c[0]), "+f"(c[1]), "+f"(c[2]), "+f"(c[3])
        : "r"(a0), "r"(a1), "r"(a2), "r"(a3), "r"(b0), "r"(b1));
}

// ---------------- CSR build ----------------
__global__ void k_zero_wp() { int i = blockIdx.x * 256 + threadIdx.x; if (i < N_NODES) g_wp[i] = 0; }
__global__ void k_hist(const int* __restrict__ ei) { int e = blockIdx.x * 256 + threadIdx.x; if (e < N_EDGES) atomicAdd(&g_wp[ei[N_EDGES + e]], 1); }
__global__ void k_scan() {
    __shared__ int part[1024];
    int t = threadIdx.x; const int C = 49; int base = t * C; int sum = 0;
    for (int i = 0; i < C; i++) { int idx = base + i; if (idx < N_NODES) sum += g_wp[idx]; }
    part[t] = sum; __syncthreads();
    for (int off = 1; off < 1024; off <<= 1) { int v = (t >= off) ? part[t - off] : 0; __syncthreads(); part[t] += v; __syncthreads(); }
    int run = (t == 0) ? 0 : part[t - 1];
    for (int i = 0; i < C; i++) { int idx = base + i; if (idx < N_NODES) { int v = g_wp[idx]; g_wp[idx] = run; run += v; } }
}
__global__ void k_scatter(const int* __restrict__ ei, const float* __restrict__ eattr) {
    int e = blockIdx.x * 256 + threadIdx.x;
    if (e < N_EDGES) {
        int d = ei[N_EDGES + e];
        int pos = atomicAdd(&g_wp[d], 1);
        const float* ea = eattr + (size_t)e * 5;
        float4 f0 = make_float4(__int_as_float(ei[e]), __int_as_float(d), __ldg(ea), __ldg(ea + 1));
        float4 f1 = make_float4(__ldg(ea + 2), __ldg(ea + 3), __ldg(ea + 4), 0.f);
        size_t p8 = (size_t)pos * 8;
        *(float4*)&g_em[p8] = f0; *(float4*)&g_em[p8 + 4] = f1;
    }
}

// ---------------- encoder ----------------
__global__ void __launch_bounds__(256) k_encoder(
    const float* __restrict__ x, const int* __restrict__ batch,
    const float* __restrict__ casep, const float* __restrict__ bcp,
    const float* __restrict__ W1, const float* __restrict__ b1,
    const float* __restrict__ W2, const float* __restrict__ b2,
    const float* __restrict__ gam, const float* __restrict__ bet)
{
    __shared__ float sW1[1024], sW2[4096], sb1[64], sb2[64], sg[64], sbe[64];
    __shared__ float sH[8][64];
    int tid = threadIdx.x;
    for (int i = tid; i < 1024; i += 256) sW1[i] = W1[i];
    for (int i = tid; i < 4096; i += 256) sW2[i] = W2[i];
    if (tid < 64) { sb1[tid] = b1[tid]; sb2[tid] = b2[tid]; sg[tid] = gam[tid]; sbe[tid] = bet[tid]; }
    __syncthreads();
    int w = tid >> 5, ld = tid & 31, c0 = 2 * ld;
    int n = blockIdx.x * 8 + w;
    if (n >= N_NODES) return;
    float in[16];
#pragma unroll
    for (int k = 0; k < 8; k++) in[k] = __ldg(&x[n * 8 + k]);
    int g = __ldg(&batch[n]);
#pragma unroll
    for (int k = 0; k < 4; k++) { in[8 + k] = __ldg(&casep[g * 4 + k]); in[12 + k] = __ldg(&bcp[g * 4 + k]); }
    const u64* W1u = (const u64*)sW1;
    u64 acc = ((const u64*)sb1)[ld];
#pragma unroll
    for (int k = 0; k < 16; k++) acc = ffma2(dup2(in[k]), W1u[k * 32 + ld], acc);
    float2 a = upk(acc); a.x = silu(a.x); a.y = silu(a.y);
    sH[w][c0] = a.x; sH[w][c0 + 1] = a.y;
    __syncwarp();
    const u64* W2u = (const u64*)sW2;
    u64 acc2 = ((const u64*)sb2)[ld];
#pragma unroll 8
    for (int k = 0; k < 64; k++) acc2 = ffma2(dup2(sH[w][k]), W2u[k * 32 + ld], acc2);
    float2 v = upk(acc2);
    float s = v.x + v.y, q = v.x * v.x + v.y * v.y;
#pragma unroll
    for (int o = 16; o; o >>= 1) { s += __shfl_xor_sync(~0u, s, o); q += __shfl_xor_sync(~0u, q, o); }
    float m = s * (1.f / 64.f), rs = rsqrtf(q * (1.f / 64.f) - m * m + EPS);
    float2 out;
    out.x = (v.x - m) * rs * sg[c0] + sbe[c0];
    out.y = (v.y - m) * rs * sg[c0 + 1] + sbe[c0 + 1];
    *(float2*)(g_h + (size_t)n * 64 + c0) = out;
}

// ---------------- node pre (layer 0 only): 16-node tiles, tf32 mma ----------------
__global__ void __launch_bounds__(256) k_node_pre(const float* __restrict__ eW1l)
{
    extern __shared__ float ps[];
    float* sWt = ps;
    float* sA  = ps + 8704;
    int tid = threadIdx.x;
    for (int i = tid; i < 64 * 128; i += 256) {
        int k = i >> 7, c = i & 127;
        float v = (c < 64) ? eW1l[k * 64 + c] : eW1l[(64 + k) * 64 + (c - 64)];
        sWt[k * 136 + c] = tf32f(v);
    }
    __syncthreads();
    int w = tid >> 5, ld = tid & 31, g8 = ld >> 2, q4 = ld & 3;
    const uint32_t* au = (const uint32_t*)sA;
    const uint32_t* bu = (const uint32_t*)sWt;
    for (int t = blockIdx.x; t < N_NODES / 16; t += gridDim.x) {
        int n0 = t * 16;
        __syncthreads();
        {
            int n = tid >> 4, c4 = (tid & 15) * 4;
            float4 v = *(const float4*)(g_h + (size_t)(n0 + n) * 64 + c4);
            uint4 tv; tv.x = tf32c(v.x); tv.y = tf32c(v.y); tv.z = tf32c(v.z); tv.w = tf32c(v.w);
            *(uint4*)&sA[n * 76 + c4] = tv;
        }
        {
            int n = tid >> 4, c = (tid & 15) * 4;
            *(float4*)(g_agg + (size_t)(n0 + n) * 64 + c) = make_float4(0.f, 0.f, 0.f, 0.f);
        }
        __syncthreads();
        float acc[2][4];
#pragma unroll
        for (int sbi = 0; sbi < 2; sbi++)
#pragma unroll
            for (int j = 0; j < 4; j++) acc[sbi][j] = 0.f;
#pragma unroll
        for (int kb = 0; kb < 8; kb++) {
            int kc = kb * 8 + q4;
            uint32_t a0 = au[g8 * 76 + kc], a1 = au[(g8 + 8) * 76 + kc];
            uint32_t a2 = au[g8 * 76 + kc + 4], a3 = au[(g8 + 8) * 76 + kc + 4];
#pragma unroll
            for (int sbi = 0; sbi < 2; sbi++) {
                int nb = 2 * w + sbi;
                uint32_t b0 = bu[kc * 136 + nb * 8 + g8];
                uint32_t b1 = bu[(kc + 4) * 136 + nb * 8 + g8];
                mma8(acc[sbi], a0, a1, a2, a3, b0, b1);
            }
        }
#pragma unroll
        for (int sbi = 0; sbi < 2; sbi++) {
            int c = (2 * w + sbi) * 8 + 2 * q4;
            float* base = (c < 64) ? g_hd : g_hs;
            int cl = (c < 64) ? c : c - 64;
            *(float2*)(base + (size_t)(n0 + g8) * 64 + cl)     = make_float2(acc[sbi][0], acc[sbi][1]);
            *(float2*)(base + (size_t)(n0 + g8 + 8) * 64 + cl) = make_float2(acc[sbi][2], acc[sbi][3]);
        }
    }
}

// ---------------- edge kernel (R11 proven + metadata prefetch) ----------------
__global__ void __launch_bounds__(256, 2) k_edge(
    const float* __restrict__ W1c, const float* __restrict__ b1,
    const float* __restrict__ W2, const float* __restrict__ b2,
    const float* __restrict__ gam, const float* __restrict__ bet)
{
    extern __shared__ float es[];
    float* sW2s = es;
    float* sW1c = es + 4608;
    float* sb1 = es + 4928; float* sb2 = es + 4992;
    float* sg = es + 5056;  float* sbe = es + 5120;
    float* sPer = es + 5184;
    int tid = threadIdx.x;
    for (int i = tid; i < 4096; i += 256) {
        int k = i >> 6, c = i & 63;
        sW2s[k * 72 + c] = tf32f(W2[i]);
    }
    for (int i = tid; i < 320; i += 256) sW1c[i] = W1c[i];
    if (tid < 64) { sb1[tid] = b1[tid]; sb2[tid] = b2[tid]; sg[tid] = gam[tid]; sbe[tid] = bet[tid]; }
    __syncthreads();
    int w = tid >> 5, ld = tid & 31;
    int pe = ld >> 1, half = ld & 1;
    int eb = ld >> 3, cb = ld & 7;
    int g8 = ld >> 2, q4 = ld & 3;
    float* sM = sPer + w * 2496;
    int* sD = (int*)(sM + 2432);
    int* sSrc = (int*)(sM + 2464);
    const ulonglong2* W1cu = (const ulonglong2*)sW1c;
    const ulonglong2* b1u = (const ulonglong2*)sb1;
    u64 gv[4], bev[4];
#pragma unroll
    for (int j = 0; j < 4; j++) { gv[j] = ((const u64*)sg)[cb * 4 + j]; bev[j] = ((const u64*)sbe)[cb * 4 + j]; }
    float b2s[8];
#pragma unroll
    for (int j = 0; j < 8; j++) b2s[j] = sb2[cb * 8 + j];
    int gw = (blockIdx.x * 256 + tid) >> 5;
    int nw = (gridDim.x * 256) >> 5;
    const int NT = N_EDGES / 32;
    // prime metadata for first tile
    float4 pf0[2], pf1[2];
    {
        int e0 = gw * 32;
#pragma unroll
        for (int sub = 0; sub < 2; sub++) {
            const float4* emp = (const float4*)&g_em[(size_t)(e0 + sub * 16 + pe) * 8];
            pf0[sub] = __ldg(emp); pf1[sub] = __ldg(emp + 1);
        }
    }
    for (int grp = gw; grp < NT; grp += nw) {
        __syncwarp();   // WAR: previous tile's sM/sD reads done
        int didx[2];
        u64 ead[2][5];
#pragma unroll
        for (int sub = 0; sub < 2; sub++) {
            int slot = sub * 16 + pe;
            float4 f0 = pf0[sub], f1 = pf1[sub];
            didx[sub] = __float_as_int(f0.y);
            ead[sub][0] = dup2(f0.z); ead[sub][1] = dup2(f0.w);
            ead[sub][2] = dup2(f1.x); ead[sub][3] = dup2(f1.y); ead[sub][4] = dup2(f1.z);
            if (half == 0) { sD[slot] = didx[sub]; sSrc[slot] = __float_as_int(f0.x); }
        }
        __syncwarp();
#pragma unroll
        for (int r = 0; r < 16; r++) {
            int chunk = r * 32 + ld, eslot = chunk >> 4, c4 = (chunk & 15) * 4;
            *(float4*)&sM[eslot * 68 + c4] = *(const float4*)(g_hs + (size_t)sSrc[eslot] * 64 + c4);
        }
        __syncwarp();
#pragma unroll
        for (int sub = 0; sub < 2; sub++) {
            int slot = sub * 16 + pe;
            const ulonglong2* hdp = (const ulonglong2*)(g_hd + (size_t)didx[sub] * 64 + half * 32);
            float* mrow = sM + slot * 68 + half * 32;
#pragma unroll
            for (int j = 0; j < 8; j++) {
                ulonglong2 hdj = __ldg(hdp + j);
                ulonglong2 hsj = ((const ulonglong2*)mrow)[j];
                ulonglong2 bj = b1u[half * 8 + j];
                u64 a0 = add2(add2(hdj.x, hsj.x), bj.x);
                u64 a1 = add2(add2(hdj.y, hsj.y), bj.y);
#pragma unroll
                for (int r = 0; r < 5; r++) {
                    ulonglong2 wv = W1cu[r * 16 + half * 8 + j];
                    a0 = ffma2(ead[sub][r], wv.x, a0); a1 = ffma2(ead[sub][r], wv.y, a1);
                }
                float2 v0 = upk(a0), v1 = upk(a1);
                uint4 tw;
                tw.x = tf32c(silu(v0.x)); tw.y = tf32c(silu(v0.y));
                tw.z = tf32c(silu(v1.x)); tw.w = tf32c(silu(v1.y));
                *(uint4*)(mrow + 4 * j) = tw;
            }
        }
        __syncwarp();
        // prefetch next tile's metadata (latency hidden under mma + LN)
        {
            int ng = grp + nw;
            if (ng < NT) {
                int e0n = ng * 32;
#pragma unroll
                for (int sub = 0; sub < 2; sub++) {
                    const float4* emp = (const float4*)&g_em[(size_t)(e0n + sub * 16 + pe) * 8];
                    pf0[sub] = __ldg(emp); pf1[sub] = __ldg(emp + 1);
                }
            }
        }
        float acc[2][8][4];
#pragma unroll
        for (int mb = 0; mb < 2; mb++)
#pragma unroll
            for (int nb = 0; nb < 8; nb++)
#pragma unroll
                for (int j = 0; j < 4; j++) acc[mb][nb][j] = 0.f;
#pragma unroll
        for (int kb = 0; kb < 8; kb++) {
            int kc = kb * 8 + q4;
            const uint32_t* mu = (const uint32_t*)sM;
            uint32_t a00 = mu[(g8) * 68 + kc],      a01 = mu[(g8 + 8) * 68 + kc];
            uint32_t a02 = mu[(g8) * 68 + kc + 4],  a03 = mu[(g8 + 8) * 68 + kc + 4];
            uint32_t a10 = mu[(g8 + 16) * 68 + kc],     a11 = mu[(g8 + 24) * 68 + kc];
            uint32_t a12 = mu[(g8 + 16) * 68 + kc + 4], a13 = mu[(g8 + 24) * 68 + kc + 4];
            const uint32_t* wu = (const uint32_t*)sW2s;
#pragma unroll
            for (int nb = 0; nb < 8; nb++) {
                uint32_t b0 = wu[kc * 72 + nb * 8 + g8];
                uint32_t b1_ = wu[(kc + 4) * 72 + nb * 8 + g8];
                mma8(acc[0][nb], a00, a01, a02, a03, b0, b1_);
                mma8(acc[1][nb], a10, a11, a12, a13, b0, b1_);
            }
        }
        __syncwarp();
#pragma unroll
        for (int mb = 0; mb < 2; mb++)
#pragma unroll
            for (int nb = 0; nb < 8; nb++) {
                int elo = mb * 16 + g8;
                *(float2*)&sM[elo * 76 + nb * 8 + 2 * q4] = make_float2(acc[mb][nb][0], acc[mb][nb][1]);
                *(float2*)&sM[(elo + 8) * 76 + nb * 8 + 2 * q4] = make_float2(acc[mb][nb][2], acc[mb][nb][3]);
            }
        __syncwarp();
        float4 f0a[8], f1a[8];
        float s[8], q[8];
#pragma unroll
        for (int i = 0; i < 8; i++) {
            int e = eb * 8 + i;
            float4 v0 = *(const float4*)&sM[e * 76 + cb * 8];
            float4 v1 = *(const float4*)&sM[e * 76 + cb * 8 + 4];
            v0.x += b2s[0]; v0.y += b2s[1]; v0.z += b2s[2]; v0.w += b2s[3];
            v1.x += b2s[4]; v1.y += b2s[5]; v1.z += b2s[6]; v1.w += b2s[7];
            f0a[i] = v0; f1a[i] = v1;
            s[i] = v0.x + v0.y + v0.z + v0.w + v1.x + v1.y + v1.z + v1.w;
            q[i] = v0.x * v0.x + v0.y * v0.y + v0.z * v0.z + v0.w * v0.w
                 + v1.x * v1.x + v1.y * v1.y + v1.z * v1.z + v1.w * v1.w;
        }
#pragma unroll
        for (int o = 4; o; o >>= 1) {
#pragma unroll
            for (int i = 0; i < 8; i++) { s[i] += __shfl_xor_sync(~0u, s[i], o); q[i] += __shfl_xor_sync(~0u, q[i], o); }
        }
        int curD = sD[eb * 8];
        u64 av[4] = {0ull, 0ull, 0ull, 0ull};
#pragma unroll
        for (int i = 0; i < 8; i++) {
            int dI = sD[eb * 8 + i];
            float mn = s[i] * (1.f / 64.f);
            float rs = rsqrtf(q[i] * (1.f / 64.f) - mn * mn + EPS);
            u64 rsd = dup2(rs), mrd = dup2(-mn * rs);
            if (dI != curD) {
                float2 a0 = upk(av[0]), a1 = upk(av[1]), a2 = upk(av[2]), a3 = upk(av[3]);
                float* base = g_agg + (size_t)curD * 64 + cb * 8;
                red4(base, make_float4(a0.x, a0.y, a1.x, a1.y));
                red4(base + 4, make_float4(a2.x, a2.y, a3.x, a3.y));
                av[0] = av[1] = av[2] = av[3] = 0ull;
                curD = dI;
            }
            u64 vv0 = pk2(f0a[i].x, f0a[i].y), vv1 = pk2(f0a[i].z, f0a[i].w);
            u64 vv2 = pk2(f1a[i].x, f1a[i].y), vv3 = pk2(f1a[i].z, f1a[i].w);
            av[0] = add2(av[0], ffma2(ffma2(vv0, rsd, mrd), gv[0], bev[0]));
            av[1] = add2(av[1], ffma2(ffma2(vv1, rsd, mrd), gv[1], bev[1]));
            av[2] = add2(av[2], ffma2(ffma2(vv2, rsd, mrd), gv[2], bev[2]));
            av[3] = add2(av[3], ffma2(ffma2(vv3, rsd, mrd), gv[3], bev[3]));
        }
        {
            float2 a0 = upk(av[0]), a1 = upk(av[1]), a2 = upk(av[2]), a3 = upk(av[3]);
            float* base = g_agg + (size_t)curD * 64 + cb * 8;
            red4(base, make_float4(a0.x, a0.y, a1.x, a1.y));
            red4(base + 4, make_float4(a2.x, a2.y, a3.x, a3.y));
        }
    }
}

// ---------------- node update (FUSED with next-layer pre) ----------------
// smem floats: sW1t 9216 | sW2t 4608 | sA 2240 | sH 1088 | sMid 1216 | sPart 256 | biases 256 | sWp 8704 => 27584 fl = 110336 B
__global__ void __launch_bounds__(256) k_node_upd(
    const float* __restrict__ W1, const float* __restrict__ b1,
    const float* __restrict__ W2, const float* __restrict__ b2,
    const float* __restrict__ gam, const float* __restrict__ bet,
    const float* __restrict__ eW1n)
{
    extern __shared__ float us[];
    float* sW1t = us;
    float* sW2t = us + 9216;
    float* sA   = us + 13824;
    float* sH   = us + 16064;
    float* sMid = us + 17152;
    float* sPart= us + 18368;
    float* sb1  = us + 18624;
    float* sb2  = us + 18688;
    float* sgm  = us + 18752;
    float* sbe  = us + 18816;
    float* sWp  = us + 18880;   // 8704
    int tid = threadIdx.x;
    bool hn = (eW1n != nullptr);
    for (int i = tid; i < 128 * 64; i += 256) { int k = i >> 6, c = i & 63; sW1t[k * 72 + c] = tf32f(W1[i]); }
    for (int i = tid; i < 64 * 64; i += 256)  { int k = i >> 6, c = i & 63; sW2t[k * 72 + c] = tf32f(W2[i]); }
    if (hn)
        for (int i = tid; i < 64 * 128; i += 256) {
            int k = i >> 7, c = i & 127;
            float v = (c < 64) ? eW1n[k * 64 + c] : eW1n[(64 + k) * 64 + (c - 64)];
            sWp[k * 136 + c] = tf32f(v);
        }
    if (tid < 64) { sb1[tid] = b1[tid]; sb2[tid] = b2[tid]; sgm[tid] = gam[tid]; sbe[tid] = bet[tid]; }
    __syncthreads();
    int w = tid >> 5, ld = tid & 31, g8 = ld >> 2, q4 = ld & 3;
    const uint32_t* au = (const uint32_t*)sA;
    const uint32_t* b1w = (const uint32_t*)sW1t;
    const uint32_t* b2w = (const uint32_t*)sW2t;
    const uint32_t* mu = (const uint32_t*)sMid;
    const uint32_t* bpu = (const uint32_t*)sWp;
    int c0 = w * 8 + 2 * q4;
    float b1c0 = sb1[c0], b1c1 = sb1[c0 + 1];
    float b2c0 = sb2[c0], b2c1 = sb2[c0 + 1];
    float gm0 = sgm[c0], gm1 = sgm[c0 + 1];
    float be0 = sbe[c0], be1 = sbe[c0 + 1];
    for (int t = blockIdx.x; t < N_NODES / 16; t += gridDim.x) {
        int n0 = t * 16;
        __syncthreads();
        {
            int n = tid >> 4, c8 = (tid & 15) * 8;
            float4 v0, v1;
            if (c8 < 64) {
                v0 = *(const float4*)(g_h + (size_t)(n0 + n) * 64 + c8);
                v1 = *(const float4*)(g_h + (size_t)(n0 + n) * 64 + c8 + 4);
                *(float4*)&sH[n * 68 + c8] = v0;
                *(float4*)&sH[n * 68 + c8 + 4] = v1;
            } else {
                v0 = *(const float4*)(g_agg + (size_t)(n0 + n) * 64 + c8 - 64);
                v1 = *(const float4*)(g_agg + (size_t)(n0 + n) * 64 + c8 - 60);
            }
            uint4 t0; t0.x = tf32c(v0.x); t0.y = tf32c(v0.y); t0.z = tf32c(v0.z); t0.w = tf32c(v0.w);
            uint4 t1; t1.x = tf32c(v1.x); t1.y = tf32c(v1.y); t1.z = tf32c(v1.z); t1.w = tf32c(v1.w);
            *(uint4*)&sA[n * 140 + c8] = t0;
            *(uint4*)&sA[n * 140 + c8 + 4] = t1;
        }
        __syncthreads();
        float a1c[4] = {0.f, 0.f, 0.f, 0.f};
#pragma unroll
        for (int kb = 0; kb < 16; kb++) {
            int kc = kb * 8 + q4;
            uint32_t a0 = au[g8 * 140 + kc], a1 = au[(g8 + 8) * 140 + kc];
            uint32_t a2 = au[g8 * 140 + kc + 4], a3 = au[(g8 + 8) * 140 + kc + 4];
            uint32_t b0 = b1w[kc * 72 + w * 8 + g8];
            uint32_t b1_ = b1w[(kc + 4) * 72 + w * 8 + g8];
            mma8(a1c, a0, a1, a2, a3, b0, b1_);
        }
        sMid[g8 * 76 + c0]       = tf32f(silu(a1c[0] + b1c0));
        sMid[g8 * 76 + c0 + 1]   = tf32f(silu(a1c[1] + b1c1));
        sMid[(g8 + 8) * 76 + c0]     = tf32f(silu(a1c[2] + b1c0));
        sMid[(g8 + 8) * 76 + c0 + 1] = tf32f(silu(a1c[3] + b1c1));
        __syncthreads();
        float a2c[4] = {0.f, 0.f, 0.f, 0.f};
#pragma unroll
        for (int kb = 0; kb < 8; kb++) {
            int kc = kb * 8 + q4;
            uint32_t a0 = mu[g8 * 76 + kc], a1 = mu[(g8 + 8) * 76 + kc];
            uint32_t a2 = mu[g8 * 76 + kc + 4], a3 = mu[(g8 + 8) * 76 + kc + 4];
            uint32_t b0 = b2w[kc * 72 + w * 8 + g8];
            uint32_t b1_ = b2w[(kc + 4) * 72 + w * 8 + g8];
            mma8(a2c, a0, a1, a2, a3, b0, b1_);
        }
        float v0 = a2c[0] + b2c0, v1 = a2c[1] + b2c1;
        float v2 = a2c[2] + b2c0, v3 = a2c[3] + b2c1;
        float s0 = v0 + v1, q0 = v0 * v0 + v1 * v1;
        float s1 = v2 + v3, q1 = v2 * v2 + v3 * v3;
#pragma unroll
        for (int o = 1; o <= 2; o <<= 1) {
            s0 += __shfl_xor_sync(~0u, s0, o); q0 += __shfl_xor_sync(~0u, q0, o);
            s1 += __shfl_xor_sync(~0u, s1, o); q1 += __shfl_xor_sync(~0u, q1, o);
        }
        if (q4 == 0) {
            sPart[w * 32 + g8 * 2] = s0;       sPart[w * 32 + g8 * 2 + 1] = q0;
            sPart[w * 32 + (g8 + 8) * 2] = s1; sPart[w * 32 + (g8 + 8) * 2 + 1] = q1;
        }
        __syncthreads();
        float S0 = 0.f, Q0 = 0.f, S1 = 0.f, Q1 = 0.f;
#pragma unroll
        for (int ww = 0; ww < 8; ww++) {
            S0 += sPart[ww * 32 + g8 * 2];       Q0 += sPart[ww * 32 + g8 * 2 + 1];
            S1 += sPart[ww * 32 + (g8 + 8) * 2]; Q1 += sPart[ww * 32 + (g8 + 8) * 2 + 1];
        }
        float mn0 = S0 * (1.f / 64.f), rs0 = rsqrtf(Q0 * (1.f / 64.f) - mn0 * mn0 + EPS);
        float mn1 = S1 * (1.f / 64.f), rs1 = rsqrtf(Q1 * (1.f / 64.f) - mn1 * mn1 + EPS);
        float2 o0, o1;
        o0.x = sH[g8 * 68 + c0]     + (v0 - mn0) * rs0 * gm0 + be0;
        o0.y = sH[g8 * 68 + c0 + 1] + (v1 - mn0) * rs0 * gm1 + be1;
        o1.x = sH[(g8 + 8) * 68 + c0]     + (v2 - mn1) * rs1 * gm0 + be0;
        o1.y = sH[(g8 + 8) * 68 + c0 + 1] + (v3 - mn1) * rs1 * gm1 + be1;
        *(float2*)(g_h + (size_t)(n0 + g8) * 64 + c0)     = o0;
        *(float2*)(g_h + (size_t)(n0 + g8 + 8) * 64 + c0) = o1;
        if (hn) {
            // stage tf32(new h) into sMid (GEMM2 reads finished above)
            sMid[g8 * 76 + c0]       = tf32f(o0.x);
            sMid[g8 * 76 + c0 + 1]   = tf32f(o0.y);
            sMid[(g8 + 8) * 76 + c0]     = tf32f(o1.x);
            sMid[(g8 + 8) * 76 + c0 + 1] = tf32f(o1.y);
            {
                int n = tid >> 4, c = (tid & 15) * 4;
                *(float4*)(g_agg + (size_t)(n0 + n) * 64 + c) = make_float4(0.f, 0.f, 0.f, 0.f);
            }
            __syncthreads();
            float accp[2][4];
#pragma unroll
            for (int sbi = 0; sbi < 2; sbi++)
#pragma unroll
                for (int j = 0; j < 4; j++) accp[sbi][j] = 0.f;
#pragma unroll
            for (int kb = 0; kb < 8; kb++) {
                int kc = kb * 8 + q4;
                uint32_t a0 = mu[g8 * 76 + kc], a1 = mu[(g8 + 8) * 76 + kc];
                uint32_t a2 = mu[g8 * 76 + kc + 4], a3 = mu[(g8 + 8) * 76 + kc + 4];
#pragma unroll
                for (int sbi = 0; sbi < 2; sbi++) {
                    int nb = 2 * w + sbi;
                    uint32_t b0 = bpu[kc * 136 + nb * 8 + g8];
                    uint32_t b1_ = bpu[(kc + 4) * 136 + nb * 8 + g8];
                    mma8(accp[sbi], a0, a1, a2, a3, b0, b1_);
                }
            }
#pragma unroll
            for (int sbi = 0; sbi < 2; sbi++) {
                int c = (2 * w + sbi) * 8 + 2 * q4;
                float* base = (c < 64) ? g_hd : g_hs;
                int cl = (c < 64) ? c : c - 64;
                *(float2*)(base + (size_t)(n0 + g8) * 64 + cl)     = make_float2(accp[sbi][0], accp[sbi][1]);
                *(float2*)(base + (size_t)(n0 + g8 + 8) * 64 + cl) = make_float2(accp[sbi][2], accp[sbi][3]);
            }
        }
    }
}

__global__ void k_zero_pool() { int t = threadIdx.x; if (t < NG * 64) g_pool[t] = 0.f; }

// ---------------- local decoder + pooling ----------------
__global__ void __launch_bounds__(256) k_decoder_local(
    const float* __restrict__ W1, const float* __restrict__ b1,
    const float* __restrict__ W2, const float* __restrict__ b2,
    const int* __restrict__ batch, float* __restrict__ out)
{
    __shared__ float sW1[4096], sW2[384], sb1[64], sb2_[8];
    __shared__ float sH[8][64], sU[8][64];
    int tid = threadIdx.x;
    for (int i = tid; i < 4096; i += 256) sW1[i] = W1[i];
    for (int i = tid; i < 384; i += 256) sW2[i] = W2[i];
    if (tid < 64) sb1[tid] = b1[tid];
    if (tid < 6) sb2_[tid] = b2[tid];
    __syncthreads();
    int w = tid >> 5, ld = tid & 31, c0 = 2 * ld;
    int n = blockIdx.x * 8 + w;
    if (n >= N_NODES) return;
    float2 hv = *(const float2*)(g_h + (size_t)n * 64 + c0);
    sH[w][c0] = hv.x; sH[w][c0 + 1] = hv.y;
    __syncwarp();
    const u64* W1u = (const u64*)sW1;
    u64 acc = ((const u64*)sb1)[ld];
#pragma unroll 8
    for (int k = 0; k < 64; k++) acc = ffma2(dup2(sH[w][k]), W1u[k * 32 + ld], acc);
    float2 u = upk(acc); u.x = silu(u.x); u.y = silu(u.y);
    sU[w][c0] = u.x; sU[w][c0 + 1] = u.y;
    __syncwarp();
    if (ld < 6) {
        float o = sb2_[ld];
#pragma unroll
        for (int k = 0; k < 64; k++) o += sU[w][k] * sW2[k * 6 + ld];
        out[(size_t)n * 6 + ld] = o;
    }
    int g = __ldg(&batch[n]);
    red2(g_pool + g * 64 + c0, hv.x, hv.y);
}

// ---------------- global decoder ----------------
__global__ void k_global(const int* __restrict__ batch,
    const float* __restrict__ W1, const float* __restrict__ b1,
    const float* __restrict__ W2, const float* __restrict__ b2,
    float* __restrict__ out)
{
    __shared__ float sp[NG * 64], su[NG * 32];
    __shared__ int bnd[NG + 1];
    int t = threadIdx.x;
    if (t <= NG) {
        int lo = 0, hi = N_NODES;
        while (lo < hi) { int mid = (lo + hi) >> 1; if (batch[mid] < t) lo = mid + 1; else hi = mid; }
        bnd[t] = lo;
    }
    __syncthreads();
    for (int i = t; i < NG * 64; i += 128) {
        int g = i >> 6;
        sp[i] = g_pool[i] / fmaxf((float)(bnd[g + 1] - bnd[g]), 1.f);
    }
    __syncthreads();
    {
        int g = t >> 5, j = t & 31;
        float a = b1[j];
#pragma unroll
        for (int k = 0; k < 64; k++) a += sp[g * 64 + k] * W1[k * 32 + j];
        su[g * 32 + j] = silu(a);
    }
    __syncthreads();
    if (t < NG * 4) {
        int g = t >> 2, j = t & 3;
        float o = b2[j];
#pragma unroll
        for (int k = 0; k < 32; k++) o += su[g * 32 + k] * W2[k * 4 + j];
        out[(size_t)N_NODES * 6 + g * 4 + j] = o;
    }
}

extern "C" void kernel_launch(void* const* d_in, const int* in_sizes, int n_in,
                              void* d_out, int out_size) {
    (void)in_sizes; (void)n_in; (void)out_size;
    const float* x     = (const float*)d_in[0];
    const int*   ei    = (const int*)d_in[1];
    const float* eattr = (const float*)d_in[2];
    const int*   batch = (const int*)d_in[3];
    const float* casep = (const float*)d_in[4];
    const float* bcp   = (const float*)d_in[5];
    const float* encW1 = (const float*)d_in[6];  const float* encb1 = (const float*)d_in[7];
    const float* encW2 = (const float*)d_in[8];  const float* encb2 = (const float*)d_in[9];
    const float* encg  = (const float*)d_in[10]; const float* encbe = (const float*)d_in[11];
    const float* eW1   = (const float*)d_in[12]; const float* eb1   = (const float*)d_in[13];
    const float* eW2   = (const float*)d_in[14]; const float* eb2   = (const float*)d_in[15];
    const float* eg    = (const float*)d_in[16]; const float* ebe   = (const float*)d_in[17];
    const float* nW1   = (const float*)d_in[18]; const float* nb1   = (const float*)d_in[19];
    const float* nW2   = (const float*)d_in[20]; const float* nb2   = (const float*)d_in[21];
    const float* ngm   = (const float*)d_in[22]; const float* nbe   = (const float*)d_in[23];
    const float* dlW1  = (const float*)d_in[24]; const float* dlb1  = (const float*)d_in[25];
    const float* dlW2  = (const float*)d_in[26]; const float* dlb2  = (const float*)d_in[27];
    const float* dgW1  = (const float*)d_in[28]; const float* dgb1  = (const float*)d_in[29];
    const float* dgW2  = (const float*)d_in[30]; const float* dgb2  = (const float*)d_in[31];
    float* out = (float*)d_out;

    size_t preSmem  = (size_t)9920 * sizeof(float);
    size_t edgeSmem = (size_t)(5184 + 8 * 2496) * sizeof(float);
    size_t updSmem  = (size_t)27584 * sizeof(float);   // 110336 B
    cudaFuncSetAttribute(k_node_pre, cudaFuncAttributeMaxDynamicSharedMemorySize, (int)preSmem);
    cudaFuncSetAttribute(k_edge, cudaFuncAttributeMaxDynamicSharedMemorySize, (int)edgeSmem);
    cudaFuncSetAttribute(k_node_upd, cudaFuncAttributeMaxDynamicSharedMemorySize, (int)updSmem);

    k_zero_wp<<<(N_NODES + 255) / 256, 256>>>();
    k_hist<<<(N_EDGES + 255) / 256, 256>>>(ei);
    k_scan<<<1, 1024>>>();
    k_scatter<<<(N_EDGES + 255) / 256, 256>>>(ei, eattr);

    k_encoder<<<(N_NODES + 7) / 8, 256>>>(x, batch, casep, bcp, encW1, encb1, encW2, encb2, encg, encbe);
    k_node_pre<<<296, 256, preSmem>>>(eW1);   // layer-0 hd/hs + agg zero
    for (int l = 0; l < NL; l++) {
        const float* eW1l = eW1 + (size_t)l * 133 * 64;
        const float* eW1n = (l + 1 < NL) ? (eW1 + (size_t)(l + 1) * 133 * 64) : nullptr;
        k_edge<<<296, 256, edgeSmem>>>(eW1l + 128 * 64, eb1 + l * 64,
                              eW2 + (size_t)l * 4096, eb2 + l * 64,
                              eg + l * 64, ebe + l * 64);
        k_node_upd<<<296, 256, updSmem>>>(nW1 + (size_t)l * 8192, nb1 + l * 64,
                                          nW2 + (size_t)l * 4096, nb2 + l * 64,
                                          ngm + l * 64, nbe + l * 64, eW1n);
    }
    k_zero_pool<<<1, 256>>>();
    k_decoder_local<<<(N_NODES + 7) / 8, 256>>>(dlW1, dlb1, dlW2, dlb2, batch, out);
    k_global<<<1, 128>>>(batch, dgW1, dgb1, dgW2, dgb2, out);
}

// round 14
// speedup vs baseline: 1.9725x; 1.0326x over previous
#include <cuda_runtime.h>
#include <cstdint>
#define DINL __device__ __forceinline__
constexpr int N_NODES = 50000;
constexpr int N_EDGES = 1600000;
constexpr int NL = 5;
constexpr int NG = 4;
constexpr float EPS = 1e-5f;

__device__ float g_h  [N_NODES * 64];
__device__ float g_hd [N_NODES * 64];
__device__ float g_hs [N_NODES * 64];
__device__ float g_agg[N_NODES * 64];
__device__ float g_pool[NG * 64];
__device__ int   g_wp [N_NODES];
__device__ float g_em [(size_t)N_EDGES * 8];

typedef unsigned long long u64;
DINL u64 pk2(float x, float y) { u64 r; asm("mov.b64 %0,{%1,%2};" : "=l"(r) : "f"(x), "f"(y)); return r; }
DINL u64 dup2(float x) { return pk2(x, x); }
DINL float2 upk(u64 v) { float2 r; asm("mov.b64 {%0,%1},%2;" : "=f"(r.x), "=f"(r.y) : "l"(v)); return r; }
DINL u64 ffma2(u64 a, u64 b, u64 c) { u64 d; asm("fma.rn.f32x2 %0,%1,%2,%3;" : "=l"(d) : "l"(a), "l"(b), "l"(c)); return d; }
DINL u64 add2(u64 a, u64 b) { u64 d; asm("add.rn.f32x2 %0,%1,%2;" : "=l"(d) : "l"(a), "l"(b)); return d; }
DINL void red2(float* p, float x, float y) { asm volatile("red.global.add.v2.f32 [%0], {%1,%2};" :: "l"(p), "f"(x), "f"(y) : "memory"); }
DINL void red4(float* p, float4 v) { asm volatile("red.global.add.v4.f32 [%0], {%1,%2,%3,%4};" :: "l"(p), "f"(v.x), "f"(v.y), "f"(v.z), "f"(v.w) : "memory"); }
DINL float silu(float x) { return __fdividef(x, 1.f + __expf(-x)); }
DINL uint32_t tf32c(float f) { uint32_t r; asm("cvt.rna.tf32.f32 %0,%1;" : "=r"(r) : "f"(f)); return r; }
DINL float tf32f(float f) { return __uint_as_float(tf32c(f)); }
DINL void pfL1(const float* p) { asm volatile("prefetch.global.L1 [%0];" :: "l"(p)); }
DINL void mma8(float* c, uint32_t a0, uint32_t a1, uint32_t a2, uint32_t a3, uint32_t b0, uint32_t b1) {
    asm volatile("mma.sync.aligned.m16n8k8.row.col.f32.tf32.tf32.f32 {%0,%1,%2,%3},{%4,%5,%6,%7},{%8,%9},{%0,%1,%2,%3};"
        : "+f"(c[0]), "+f"(c[1]), "+f"(c[2]), "+f"(c[3])
        : "r"(a0), "r"(a1), "r"(a2), "r"(a3), "r"(b0), "r"(b1));
}

// ---------------- CSR build ----------------
__global__ void k_zero_wp() { int i = blockIdx.x * 256 + threadIdx.x; if (i < N_NODES) g_wp[i] = 0; }
__global__ void k_hist(const int* __restrict__ ei) { int e = blockIdx.x * 256 + threadIdx.x; if (e < N_EDGES) atomicAdd(&g_wp[ei[N_EDGES + e]], 1); }
__global__ void k_scan() {
    __shared__ int part[1024];
    int t = threadIdx.x; const int C = 49; int base = t * C; int sum = 0;
    for (int i = 0; i < C; i++) { int idx = base + i; if (idx < N_NODES) sum += g_wp[idx]; }
    part[t] = sum; __syncthreads();
    for (int off = 1; off < 1024; off <<= 1) { int v = (t >= off) ? part[t - off] : 0; __syncthreads(); part[t] += v; __syncthreads(); }
    int run = (t == 0) ? 0 : part[t - 1];
    for (int i = 0; i < C; i++) { int idx = base + i; if (idx < N_NODES) { int v = g_wp[idx]; g_wp[idx] = run; run += v; } }
}
__global__ void k_scatter(const int* __restrict__ ei, const float* __restrict__ eattr) {
    int e = blockIdx.x * 256 + threadIdx.x;
    if (e < N_EDGES) {
        int d = ei[N_EDGES + e];
        int pos = atomicAdd(&g_wp[d], 1);
        const float* ea = eattr + (size_t)e * 5;
        float4 f0 = make_float4(__int_as_float(ei[e]), __int_as_float(d), __ldg(ea), __ldg(ea + 1));
        float4 f1 = make_float4(__ldg(ea + 2), __ldg(ea + 3), __ldg(ea + 4), 0.f);
        size_t p8 = (size_t)pos * 8;
        *(float4*)&g_em[p8] = f0; *(float4*)&g_em[p8 + 4] = f1;
    }
}

// ---------------- encoder ----------------
__global__ void __launch_bounds__(256) k_encoder(
    const float* __restrict__ x, const int* __restrict__ batch,
    const float* __restrict__ casep, const float* __restrict__ bcp,
    const float* __restrict__ W1, const float* __restrict__ b1,
    const float* __restrict__ W2, const float* __restrict__ b2,
    const float* __restrict__ gam, const float* __restrict__ bet)
{
    __shared__ float sW1[1024], sW2[4096], sb1[64], sb2[64], sg[64], sbe[64];
    __shared__ float sH[8][64];
    int tid = threadIdx.x;
    for (int i = tid; i < 1024; i += 256) sW1[i] = W1[i];
    for (int i = tid; i < 4096; i += 256) sW2[i] = W2[i];
    if (tid < 64) { sb1[tid] = b1[tid]; sb2[tid] = b2[tid]; sg[tid] = gam[tid]; sbe[tid] = bet[tid]; }
    __syncthreads();
    int w = tid >> 5, ld = tid & 31, c0 = 2 * ld;
    int n = blockIdx.x * 8 + w;
    if (n >= N_NODES) return;
    float in[16];
#pragma unroll
    for (int k = 0; k < 8; k++) in[k] = __ldg(&x[n * 8 + k]);
    int g = __ldg(&batch[n]);
#pragma unroll
    for (int k = 0; k < 4; k++) { in[8 + k] = __ldg(&casep[g * 4 + k]); in[12 + k] = __ldg(&bcp[g * 4 + k]); }
    const u64* W1u = (const u64*)sW1;
    u64 acc = ((const u64*)sb1)[ld];
#pragma unroll
    for (int k = 0; k < 16; k++) acc = ffma2(dup2(in[k]), W1u[k * 32 + ld], acc);
    float2 a = upk(acc); a.x = silu(a.x); a.y = silu(a.y);
    sH[w][c0] = a.x; sH[w][c0 + 1] = a.y;
    __syncwarp();
    const u64* W2u = (const u64*)sW2;
    u64 acc2 = ((const u64*)sb2)[ld];
#pragma unroll 8
    for (int k = 0; k < 64; k++) acc2 = ffma2(dup2(sH[w][k]), W2u[k * 32 + ld], acc2);
    float2 v = upk(acc2);
    float s = v.x + v.y, q = v.x * v.x + v.y * v.y;
#pragma unroll
    for (int o = 16; o; o >>= 1) { s += __shfl_xor_sync(~0u, s, o); q += __shfl_xor_sync(~0u, q, o); }
    float m = s * (1.f / 64.f), rs = rsqrtf(q * (1.f / 64.f) - m * m + EPS);
    float2 out;
    out.x = (v.x - m) * rs * sg[c0] + sbe[c0];
    out.y = (v.y - m) * rs * sg[c0 + 1] + sbe[c0 + 1];
    *(float2*)(g_h + (size_t)n * 64 + c0) = out;
}

// ---------------- node pre (layer 0 only) ----------------
__global__ void __launch_bounds__(256) k_node_pre(const float* __restrict__ eW1l)
{
    extern __shared__ float ps[];
    float* sWt = ps;
    float* sA  = ps + 8704;
    int tid = threadIdx.x;
    for (int i = tid; i < 64 * 128; i += 256) {
        int k = i >> 7, c = i & 127;
        float v = (c < 64) ? eW1l[k * 64 + c] : eW1l[(64 + k) * 64 + (c - 64)];
        sWt[k * 136 + c] = tf32f(v);
    }
    __syncthreads();
    int w = tid >> 5, ld = tid & 31, g8 = ld >> 2, q4 = ld & 3;
    const uint32_t* au = (const uint32_t*)sA;
    const uint32_t* bu = (const uint32_t*)sWt;
    for (int t = blockIdx.x; t < N_NODES / 16; t += gridDim.x) {
        int n0 = t * 16;
        __syncthreads();
        {
            int n = tid >> 4, c4 = (tid & 15) * 4;
            float4 v = *(const float4*)(g_h + (size_t)(n0 + n) * 64 + c4);
            uint4 tv; tv.x = tf32c(v.x); tv.y = tf32c(v.y); tv.z = tf32c(v.z); tv.w = tf32c(v.w);
            *(uint4*)&sA[n * 76 + c4] = tv;
        }
        {
            int n = tid >> 4, c = (tid & 15) * 4;
            *(float4*)(g_agg + (size_t)(n0 + n) * 64 + c) = make_float4(0.f, 0.f, 0.f, 0.f);
        }
        __syncthreads();
        float acc[2][4];
#pragma unroll
        for (int sbi = 0; sbi < 2; sbi++)
#pragma unroll
            for (int j = 0; j < 4; j++) acc[sbi][j] = 0.f;
#pragma unroll
        for (int kb = 0; kb < 8; kb++) {
            int kc = kb * 8 + q4;
            uint32_t a0 = au[g8 * 76 + kc], a1 = au[(g8 + 8) * 76 + kc];
            uint32_t a2 = au[g8 * 76 + kc + 4], a3 = au[(g8 + 8) * 76 + kc + 4];
#pragma unroll
            for (int sbi = 0; sbi < 2; sbi++) {
                int nb = 2 * w + sbi;
                uint32_t b0 = bu[kc * 136 + nb * 8 + g8];
                uint32_t b1 = bu[(kc + 4) * 136 + nb * 8 + g8];
                mma8(acc[sbi], a0, a1, a2, a3, b0, b1);
            }
        }
#pragma unroll
        for (int sbi = 0; sbi < 2; sbi++) {
            int c = (2 * w + sbi) * 8 + 2 * q4;
            float* base = (c < 64) ? g_hd : g_hs;
            int cl = (c < 64) ? c : c - 64;
            *(float2*)(base + (size_t)(n0 + g8) * 64 + cl)     = make_float2(acc[sbi][0], acc[sbi][1]);
            *(float2*)(base + (size_t)(n0 + g8 + 8) * 64 + cl) = make_float2(acc[sbi][2], acc[sbi][3]);
        }
    }
}

// ---------------- edge kernel (R12 proven + L1 data prefetch) ----------------
__global__ void __launch_bounds__(256, 2) k_edge(
    const float* __restrict__ W1c, const float* __restrict__ b1,
    const float* __restrict__ W2, const float* __restrict__ b2,
    const float* __restrict__ gam, const float* __restrict__ bet)
{
    extern __shared__ float es[];
    float* sW2s = es;
    float* sW1c = es + 4608;
    float* sb1 = es + 4928; float* sb2 = es + 4992;
    float* sg = es + 5056;  float* sbe = es + 5120;
    float* sPer = es + 5184;
    int tid = threadIdx.x;
    for (int i = tid; i < 4096; i += 256) {
        int k = i >> 6, c = i & 63;
        sW2s[k * 72 + c] = tf32f(W2[i]);
    }
    for (int i = tid; i < 320; i += 256) sW1c[i] = W1c[i];
    if (tid < 64) { sb1[tid] = b1[tid]; sb2[tid] = b2[tid]; sg[tid] = gam[tid]; sbe[tid] = bet[tid]; }
    __syncthreads();
    int w = tid >> 5, ld = tid & 31;
    int pe = ld >> 1, half = ld & 1;
    int eb = ld >> 3, cb = ld & 7;
    int g8 = ld >> 2, q4 = ld & 3;
    float* sM = sPer + w * 2496;
    int* sD = (int*)(sM + 2432);
    int* sSrc = (int*)(sM + 2464);
    const ulonglong2* W1cu = (const ulonglong2*)sW1c;
    const ulonglong2* b1u = (const ulonglong2*)sb1;
    u64 gv[4], bev[4];
#pragma unroll
    for (int j = 0; j < 4; j++) { gv[j] = ((const u64*)sg)[cb * 4 + j]; bev[j] = ((const u64*)sbe)[cb * 4 + j]; }
    float b2s[8];
#pragma unroll
    for (int j = 0; j < 8; j++) b2s[j] = sb2[cb * 8 + j];
    int gw = (blockIdx.x * 256 + tid) >> 5;
    int nw = (gridDim.x * 256) >> 5;
    const int NT = N_EDGES / 32;
    // prime metadata + data prefetch for first tile
    float4 mf0[2], mf1[2];
    {
        int e0 = gw * 32;
#pragma unroll
        for (int sub = 0; sub < 2; sub++) {
            const float4* emp = (const float4*)&g_em[(size_t)(e0 + sub * 16 + pe) * 8];
            mf0[sub] = __ldg(emp); mf1[sub] = __ldg(emp + 1);
        }
#pragma unroll
        for (int sub = 0; sub < 2; sub++) {
            int ns = __float_as_int(mf0[sub].x), nd = __float_as_int(mf0[sub].y);
            pfL1(g_hs + (size_t)ns * 64 + half * 32);
            pfL1(g_hd + (size_t)nd * 64 + half * 32);
        }
    }
    for (int grp = gw; grp < NT; grp += nw) {
        __syncwarp();   // WAR: previous tile's sM/sD reads done
        int didx[2];
        u64 ead[2][5];
#pragma unroll
        for (int sub = 0; sub < 2; sub++) {
            int slot = sub * 16 + pe;
            float4 f0 = mf0[sub], f1 = mf1[sub];
            didx[sub] = __float_as_int(f0.y);
            ead[sub][0] = dup2(f0.z); ead[sub][1] = dup2(f0.w);
            ead[sub][2] = dup2(f1.x); ead[sub][3] = dup2(f1.y); ead[sub][4] = dup2(f1.z);
            if (half == 0) { sD[slot] = didx[sub]; sSrc[slot] = __float_as_int(f0.x); }
        }
        __syncwarp();
#pragma unroll
        for (int r = 0; r < 16; r++) {
            int chunk = r * 32 + ld, eslot = chunk >> 4, c4 = (chunk & 15) * 4;
            *(float4*)&sM[eslot * 68 + c4] = *(const float4*)(g_hs + (size_t)sSrc[eslot] * 64 + c4);
        }
        __syncwarp();
#pragma unroll
        for (int sub = 0; sub < 2; sub++) {
            int slot = sub * 16 + pe;
            const ulonglong2* hdp = (const ulonglong2*)(g_hd + (size_t)didx[sub] * 64 + half * 32);
            float* mrow = sM + slot * 68 + half * 32;
#pragma unroll
            for (int j = 0; j < 8; j++) {
                ulonglong2 hdj = __ldg(hdp + j);
                ulonglong2 hsj = ((const ulonglong2*)mrow)[j];
                ulonglong2 bj = b1u[half * 8 + j];
                u64 a0 = add2(add2(hdj.x, hsj.x), bj.x);
                u64 a1 = add2(add2(hdj.y, hsj.y), bj.y);
#pragma unroll
                for (int r = 0; r < 5; r++) {
                    ulonglong2 wv = W1cu[r * 16 + half * 8 + j];
                    a0 = ffma2(ead[sub][r], wv.x, a0); a1 = ffma2(ead[sub][r], wv.y, a1);
                }
                float2 v0 = upk(a0), v1 = upk(a1);
                uint4 tw;
                tw.x = tf32c(silu(v0.x)); tw.y = tf32c(silu(v0.y));
                tw.z = tf32c(silu(v1.x)); tw.w = tf32c(silu(v1.y));
                *(uint4*)(mrow + 4 * j) = tw;
            }
        }
        __syncwarp();
        // prefetch next tile's metadata
        int ng = grp + nw;
        if (ng < NT) {
            int e0n = ng * 32;
#pragma unroll
            for (int sub = 0; sub < 2; sub++) {
                const float4* emp = (const float4*)&g_em[(size_t)(e0n + sub * 16 + pe) * 8];
                mf0[sub] = __ldg(emp); mf1[sub] = __ldg(emp + 1);
            }
        }
        float acc[2][8][4];
#pragma unroll
        for (int mb = 0; mb < 2; mb++)
#pragma unroll
            for (int nb = 0; nb < 8; nb++)
#pragma unroll
                for (int j = 0; j < 4; j++) acc[mb][nb][j] = 0.f;
#pragma unroll
        for (int kb = 0; kb < 8; kb++) {
            int kc = kb * 8 + q4;
            const uint32_t* mu = (const uint32_t*)sM;
            uint32_t a00 = mu[(g8) * 68 + kc],      a01 = mu[(g8 + 8) * 68 + kc];
            uint32_t a02 = mu[(g8) * 68 + kc + 4],  a03 = mu[(g8 + 8) * 68 + kc + 4];
            uint32_t a10 = mu[(g8 + 16) * 68 + kc],     a11 = mu[(g8 + 24) * 68 + kc];
            uint32_t a12 = mu[(g8 + 16) * 68 + kc + 4], a13 = mu[(g8 + 24) * 68 + kc + 4];
            const uint32_t* wu = (const uint32_t*)sW2s;
#pragma unroll
            for (int nb = 0; nb < 8; nb++) {
                uint32_t b0 = wu[kc * 72 + nb * 8 + g8];
                uint32_t b1_ = wu[(kc + 4) * 72 + nb * 8 + g8];
                mma8(acc[0][nb], a00, a01, a02, a03, b0, b1_);
                mma8(acc[1][nb], a10, a11, a12, a13, b0, b1_);
            }
        }
        // data prefetch for next tile (metadata has landed during the mma loop)
        if (ng < NT) {
#pragma unroll
            for (int sub = 0; sub < 2; sub++) {
                int ns = __float_as_int(mf0[sub].x), nd = __float_as_int(mf0[sub].y);
                pfL1(g_hs + (size_t)ns * 64 + half * 32);
                pfL1(g_hd + (size_t)nd * 64 + half * 32);
            }
        }
        __syncwarp();
#pragma unroll
        for (int mb = 0; mb < 2; mb++)
#pragma unroll
            for (int nb = 0; nb < 8; nb++) {
                int elo = mb * 16 + g8;
                *(float2*)&sM[elo * 76 + nb * 8 + 2 * q4] = make_float2(acc[mb][nb][0], acc[mb][nb][1]);
                *(float2*)&sM[(elo + 8) * 76 + nb * 8 + 2 * q4] = make_float2(acc[mb][nb][2], acc[mb][nb][3]);
            }
        __syncwarp();
        float4 f0a[8], f1a[8];
        float s[8], q[8];
#pragma unroll
        for (int i = 0; i < 8; i++) {
            int e = eb * 8 + i;
            float4 v0 = *(const float4*)&sM[e * 76 + cb * 8];
            float4 v1 = *(const float4*)&sM[e * 76 + cb * 8 + 4];
            v0.x += b2s[0]; v0.y += b2s[1]; v0.z += b2s[2]; v0.w += b2s[3];
            v1.x += b2s[4]; v1.y += b2s[5]; v1.z += b2s[6]; v1.w += b2s[7];
            f0a[i] = v0; f1a[i] = v1;
            s[i] = v0.x + v0.y + v0.z + v0.w + v1.x + v1.y + v1.z + v1.w;
            q[i] = v0.x * v0.x + v0.y * v0.y + v0.z * v0.z + v0.w * v0.w
                 + v1.x * v1.x + v1.y * v1.y + v1.z * v1.z + v1.w * v1.w;
        }
#pragma unroll
        for (int o = 4; o; o >>= 1) {
#pragma unroll
            for (int i = 0; i < 8; i++) { s[i] += __shfl_xor_sync(~0u, s[i], o); q[i] += __shfl_xor_sync(~0u, q[i], o); }
        }
        int curD = sD[eb * 8];
        u64 av[4] = {0ull, 0ull, 0ull, 0ull};
#pragma unroll
        for (int i = 0; i < 8; i++) {
            int dI = sD[eb * 8 + i];
            float mn = s[i] * (1.f / 64.f);
            float rs = rsqrtf(q[i] * (1.f / 64.f) - mn * mn + EPS);
            u64 rsd = dup2(rs), mrd = dup2(-mn * rs);
            if (dI != curD) {
                float2 a0 = upk(av[0]), a1 = upk(av[1]), a2 = upk(av[2]), a3 = upk(av[3]);
                float* base = g_agg + (size_t)curD * 64 + cb * 8;
                red4(base, make_float4(a0.x, a0.y, a1.x, a1.y));
                red4(base + 4, make_float4(a2.x, a2.y, a3.x, a3.y));
                av[0] = av[1] = av[2] = av[3] = 0ull;
                curD = dI;
            }
            u64 vv0 = pk2(f0a[i].x, f0a[i].y), vv1 = pk2(f0a[i].z, f0a[i].w);
            u64 vv2 = pk2(f1a[i].x, f1a[i].y), vv3 = pk2(f1a[i].z, f1a[i].w);
            av[0] = add2(av[0], ffma2(ffma2(vv0, rsd, mrd), gv[0], bev[0]));
            av[1] = add2(av[1], ffma2(ffma2(vv1, rsd, mrd), gv[1], bev[1]));
            av[2] = add2(av[2], ffma2(ffma2(vv2, rsd, mrd), gv[2], bev[2]));
            av[3] = add2(av[3], ffma2(ffma2(vv3, rsd, mrd), gv[3], bev[3]));
        }
        {
            float2 a0 = upk(av[0]), a1 = upk(av[1]), a2 = upk(av[2]), a3 = upk(av[3]);
            float* base = g_agg + (size_t)curD * 64 + cb * 8;
            red4(base, make_float4(a0.x, a0.y, a1.x, a1.y));
            red4(base + 4, make_float4(a2.x, a2.y, a3.x, a3.y));
        }
    }
}

// ---------------- node update (FUSED with next-layer pre) ----------------
__global__ void __launch_bounds__(256) k_node_upd(
    const float* __restrict__ W1, const float* __restrict__ b1,
    const float* __restrict__ W2, const float* __restrict__ b2,
    const float* __restrict__ gam, const float* __restrict__ bet,
    const float* __restrict__ eW1n)
{
    extern __shared__ float us[];
    float* sW1t = us;
    float* sW2t = us + 9216;
    float* sA   = us + 13824;
    float* sH   = us + 16064;
    float* sMid = us + 17152;
    float* sPart= us + 18368;
    float* sb1  = us + 18624;
    float* sb2  = us + 18688;
    float* sgm  = us + 18752;
    float* sbe  = us + 18816;
    float* sWp  = us + 18880;
    int tid = threadIdx.x;
    bool hn = (eW1n != nullptr);
    for (int i = tid; i < 128 * 64; i += 256) { int k = i >> 6, c = i & 63; sW1t[k * 72 + c] = tf32f(W1[i]); }
    for (int i = tid; i < 64 * 64; i += 256)  { int k = i >> 6, c = i & 63; sW2t[k * 72 + c] = tf32f(W2[i]); }
    if (hn)
        for (int i = tid; i < 64 * 128; i += 256) {
            int k = i >> 7, c = i & 127;
            float v = (c < 64) ? eW1n[k * 64 + c] : eW1n[(64 + k) * 64 + (c - 64)];
            sWp[k * 136 + c] = tf32f(v);
        }
    if (tid < 64) { sb1[tid] = b1[tid]; sb2[tid] = b2[tid]; sgm[tid] = gam[tid]; sbe[tid] = bet[tid]; }
    __syncthreads();
    int w = tid >> 5, ld = tid & 31, g8 = ld >> 2, q4 = ld & 3;
    const uint32_t* au = (const uint32_t*)sA;
    const uint32_t* b1w = (const uint32_t*)sW1t;
    const uint32_t* b2w = (const uint32_t*)sW2t;
    const uint32_t* mu = (const uint32_t*)sMid;
    const uint32_t* bpu = (const uint32_t*)sWp;
    int c0 = w * 8 + 2 * q4;
    float b1c0 = sb1[c0], b1c1 = sb1[c0 + 1];
    float b2c0 = sb2[c0], b2c1 = sb2[c0 + 1];
    float gm0 = sgm[c0], gm1 = sgm[c0 + 1];
    float be0 = sbe[c0], be1 = sbe[c0 + 1];
    for (int t = blockIdx.x; t < N_NODES / 16; t += gridDim.x) {
        int n0 = t * 16;
        __syncthreads();
        {
            int n = tid >> 4, c8 = (tid & 15) * 8;
            float4 v0, v1;
            if (c8 < 64) {
                v0 = *(const float4*)(g_h + (size_t)(n0 + n) * 64 + c8);
                v1 = *(const float4*)(g_h + (size_t)(n0 + n) * 64 + c8 + 4);
                *(float4*)&sH[n * 68 + c8] = v0;
                *(float4*)&sH[n * 68 + c8 + 4] = v1;
            } else {
                v0 = *(const float4*)(g_agg + (size_t)(n0 + n) * 64 + c8 - 64);
                v1 = *(const float4*)(g_agg + (size_t)(n0 + n) * 64 + c8 - 60);
            }
            uint4 t0; t0.x = tf32c(v0.x); t0.y = tf32c(v0.y); t0.z = tf32c(v0.z); t0.w = tf32c(v0.w);
            uint4 t1; t1.x = tf32c(v1.x); t1.y = tf32c(v1.y); t1.z = tf32c(v1.z); t1.w = tf32c(v1.w);
            *(uint4*)&sA[n * 140 + c8] = t0;
            *(uint4*)&sA[n * 140 + c8 + 4] = t1;
        }
        __syncthreads();
        float a1c[4] = {0.f, 0.f, 0.f, 0.f};
#pragma unroll
        for (int kb = 0; kb < 16; kb++) {
            int kc = kb * 8 + q4;
            uint32_t a0 = au[g8 * 140 + kc], a1 = au[(g8 + 8) * 140 + kc];
            uint32_t a2 = au[g8 * 140 + kc + 4], a3 = au[(g8 + 8) * 140 + kc + 4];
            uint32_t b0 = b1w[kc * 72 + w * 8 + g8];
            uint32_t b1_ = b1w[(kc + 4) * 72 + w * 8 + g8];
            mma8(a1c, a0, a1, a2, a3, b0, b1_);
        }
        sMid[g8 * 76 + c0]       = tf32f(silu(a1c[0] + b1c0));
        sMid[g8 * 76 + c0 + 1]   = tf32f(silu(a1c[1] + b1c1));
        sMid[(g8 + 8) * 76 + c0]     = tf32f(silu(a1c[2] + b1c0));
        sMid[(g8 + 8) * 76 + c0 + 1] = tf32f(silu(a1c[3] + b1c1));
        __syncthreads();
        float a2c[4] = {0.f, 0.f, 0.f, 0.f};
#pragma unroll
        for (int kb = 0; kb < 8; kb++) {
            int kc = kb * 8 + q4;
            uint32_t a0 = mu[g8 * 76 + kc], a1 = mu[(g8 + 8) * 76 + kc];
            uint32_t a2 = mu[g8 * 76 + kc + 4], a3 = mu[(g8 + 8) * 76 + kc + 4];
            uint32_t b0 = b2w[kc * 72 + w * 8 + g8];
            uint32_t b1_ = b2w[(kc + 4) * 72 + w * 8 + g8];
            mma8(a2c, a0, a1, a2, a3, b0, b1_);
        }
        float v0 = a2c[0] + b2c0, v1 = a2c[1] + b2c1;
        float v2 = a2c[2] + b2c0, v3 = a2c[3] + b2c1;
        float s0 = v0 + v1, q0 = v0 * v0 + v1 * v1;
        float s1 = v2 + v3, q1 = v2 * v2 + v3 * v3;
#pragma unroll
        for (int o = 1; o <= 2; o <<= 1) {
            s0 += __shfl_xor_sync(~0u, s0, o); q0 += __shfl_xor_sync(~0u, q0, o);
            s1 += __shfl_xor_sync(~0u, s1, o); q1 += __shfl_xor_sync(~0u, q1, o);
        }
        if (q4 == 0) {
            sPart[w * 32 + g8 * 2] = s0;       sPart[w * 32 + g8 * 2 + 1] = q0;
            sPart[w * 32 + (g8 + 8) * 2] = s1; sPart[w * 32 + (g8 + 8) * 2 + 1] = q1;
        }
        __syncthreads();
        float S0 = 0.f, Q0 = 0.f, S1 = 0.f, Q1 = 0.f;
#pragma unroll
        for (int ww = 0; ww < 8; ww++) {
            S0 += sPart[ww * 32 + g8 * 2];       Q0 += sPart[ww * 32 + g8 * 2 + 1];
            S1 += sPart[ww * 32 + (g8 + 8) * 2]; Q1 += sPart[ww * 32 + (g8 + 8) * 2 + 1];
        }
        float mn0 = S0 * (1.f / 64.f), rs0 = rsqrtf(Q0 * (1.f / 64.f) - mn0 * mn0 + EPS);
        float mn1 = S1 * (1.f / 64.f), rs1 = rsqrtf(Q1 * (1.f / 64.f) - mn1 * mn1 + EPS);
        float2 o0, o1;
        o0.x = sH[g8 * 68 + c0]     + (v0 - mn0) * rs0 * gm0 + be0;
        o0.y = sH[g8 * 68 + c0 + 1] + (v1 - mn0) * rs0 * gm1 + be1;
        o1.x = sH[(g8 + 8) * 68 + c0]     + (v2 - mn1) * rs1 * gm0 + be0;
        o1.y = sH[(g8 + 8) * 68 + c0 + 1] + (v3 - mn1) * rs1 * gm1 + be1;
        *(float2*)(g_h + (size_t)(n0 + g8) * 64 + c0)     = o0;
        *(float2*)(g_h + (size_t)(n0 + g8 + 8) * 64 + c0) = o1;
        if (hn) {
            sMid[g8 * 76 + c0]       = tf32f(o0.x);
            sMid[g8 * 76 + c0 + 1]   = tf32f(o0.y);
            sMid[(g8 + 8) * 76 + c0]     = tf32f(o1.x);
            sMid[(g8 + 8) * 76 + c0 + 1] = tf32f(o1.y);
            {
                int n = tid >> 4, c = (tid & 15) * 4;
                *(float4*)(g_agg + (size_t)(n0 + n) * 64 + c) = make_float4(0.f, 0.f, 0.f, 0.f);
            }
            __syncthreads();
            float accp[2][4];
#pragma unroll
            for (int sbi = 0; sbi < 2; sbi++)
#pragma unroll
                for (int j = 0; j < 4; j++) accp[sbi][j] = 0.f;
#pragma unroll
            for (int kb = 0; kb < 8; kb++) {
                int kc = kb * 8 + q4;
                uint32_t a0 = mu[g8 * 76 + kc], a1 = mu[(g8 + 8) * 76 + kc];
                uint32_t a2 = mu[g8 * 76 + kc + 4], a3 = mu[(g8 + 8) * 76 + kc + 4];
#pragma unroll
                for (int sbi = 0; sbi < 2; sbi++) {
                    int nb = 2 * w + sbi;
                    uint32_t b0 = bpu[kc * 136 + nb * 8 + g8];
                    uint32_t b1_ = bpu[(kc + 4) * 136 + nb * 8 + g8];
                    mma8(accp[sbi], a0, a1, a2, a3, b0, b1_);
                }
            }
#pragma unroll
            for (int sbi = 0; sbi < 2; sbi++) {
                int c = (2 * w + sbi) * 8 + 2 * q4;
                float* base = (c < 64) ? g_hd : g_hs;
                int cl = (c < 64) ? c : c - 64;
                *(float2*)(base + (size_t)(n0 + g8) * 64 + cl)     = make_float2(accp[sbi][0], accp[sbi][1]);
                *(float2*)(base + (size_t)(n0 + g8 + 8) * 64 + cl) = make_float2(accp[sbi][2], accp[sbi][3]);
            }
        }
    }
}

__global__ void k_zero_pool() { int t = threadIdx.x; if (t < NG * 64) g_pool[t] = 0.f; }

// ---------------- local decoder + pooling ----------------
__global__ void __launch_bounds__(256) k_decoder_local(
    const float* __restrict__ W1, const float* __restrict__ b1,
    const float* __restrict__ W2, const float* __restrict__ b2,
    const int* __restrict__ batch, float* __restrict__ out)
{
    __shared__ float sW1[4096], sW2[384], sb1[64], sb2_[8];
    __shared__ float sH[8][64], sU[8][64];
    int tid = threadIdx.x;
    for (int i = tid; i < 4096; i += 256) sW1[i] = W1[i];
    for (int i = tid; i < 384; i += 256) sW2[i] = W2[i];
    if (tid < 64) sb1[tid] = b1[tid];
    if (tid < 6) sb2_[tid] = b2[tid];
    __syncthreads();
    int w = tid >> 5, ld = tid & 31, c0 = 2 * ld;
    int n = blockIdx.x * 8 + w;
    if (n >= N_NODES) return;
    float2 hv = *(const float2*)(g_h + (size_t)n * 64 + c0);
    sH[w][c0] = hv.x; sH[w][c0 + 1] = hv.y;
    __syncwarp();
    const u64* W1u = (const u64*)sW1;
    u64 acc = ((const u64*)sb1)[ld];
#pragma unroll 8
    for (int k = 0; k < 64; k++) acc = ffma2(dup2(sH[w][k]), W1u[k * 32 + ld], acc);
    float2 u = upk(acc); u.x = silu(u.x); u.y = silu(u.y);
    sU[w][c0] = u.x; sU[w][c0 + 1] = u.y;
    __syncwarp();
    if (ld < 6) {
        float o = sb2_[ld];
#pragma unroll
        for (int k = 0; k < 64; k++) o += sU[w][k] * sW2[k * 6 + ld];
        out[(size_t)n * 6 + ld] = o;
    }
    int g = __ldg(&batch[n]);
    red2(g_pool + g * 64 + c0, hv.x, hv.y);
}

// ---------------- global decoder ----------------
__global__ void k_global(const int* __restrict__ batch,
    const float* __restrict__ W1, const float* __restrict__ b1,
    const float* __restrict__ W2, const float* __restrict__ b2,
    float* __restrict__ out)
{
    __shared__ float sp[NG * 64], su[NG * 32];
    __shared__ int bnd[NG + 1];
    int t = threadIdx.x;
    if (t <= NG) {
        int lo = 0, hi = N_NODES;
        while (lo < hi) { int mid = (lo + hi) >> 1; if (batch[mid] < t) lo = mid + 1; else hi = mid; }
        bnd[t] = lo;
    }
    __syncthreads();
    for (int i = t; i < NG * 64; i += 128) {
        int g = i >> 6;
        sp[i] = g_pool[i] / fmaxf((float)(bnd[g + 1] - bnd[g]), 1.f);
    }
    __syncthreads();
    {
        int g = t >> 5, j = t & 31;
        float a = b1[j];
#pragma unroll
        for (int k = 0; k < 64; k++) a += sp[g * 64 + k] * W1[k * 32 + j];
        su[g * 32 + j] = silu(a);
    }
    __syncthreads();
    if (t < NG * 4) {
        int g = t >> 2, j = t & 3;
        float o = b2[j];
#pragma unroll
        for (int k = 0; k < 32; k++) o += su[g * 32 + k] * W2[k * 4 + j];
        out[(size_t)N_NODES * 6 + g * 4 + j] = o;
    }
}

extern "C" void kernel_launch(void* const* d_in, const int* in_sizes, int n_in,
                              void* d_out, int out_size) {
    (void)in_sizes; (void)n_in; (void)out_size;
    const float* x     = (const float*)d_in[0];
    const int*   ei    = (const int*)d_in[1];
    const float* eattr = (const float*)d_in[2];
    const int*   batch = (const int*)d_in[3];
    const float* casep = (const float*)d_in[4];
    const float* bcp   = (const float*)d_in[5];
    const float* encW1 = (const float*)d_in[6];  const float* encb1 = (const float*)d_in[7];
    const float* encW2 = (const float*)d_in[8];  const float* encb2 = (const float*)d_in[9];
    const float* encg  = (const float*)d_in[10]; const float* encbe = (const float*)d_in[11];
    const float* eW1   = (const float*)d_in[12]; const float* eb1   = (const float*)d_in[13];
    const float* eW2   = (const float*)d_in[14]; const float* eb2   = (const float*)d_in[15];
    const float* eg    = (const float*)d_in[16]; const float* ebe   = (const float*)d_in[17];
    const float* nW1   = (const float*)d_in[18]; const float* nb1   = (const float*)d_in[19];
    const float* nW2   = (const float*)d_in[20]; const float* nb2   = (const float*)d_in[21];
    const float* ngm   = (const float*)d_in[22]; const float* nbe   = (const float*)d_in[23];
    const float* dlW1  = (const float*)d_in[24]; const float* dlb1  = (const float*)d_in[25];
    const float* dlW2  = (const float*)d_in[26]; const float* dlb2  = (const float*)d_in[27];
    const float* dgW1  = (const float*)d_in[28]; const float* dgb1  = (const float*)d_in[29];
    const float* dgW2  = (const float*)d_in[30]; const float* dgb2  = (const float*)d_in[31];
    float* out = (float*)d_out;

    size_t preSmem  = (size_t)9920 * sizeof(float);
    size_t edgeSmem = (size_t)(5184 + 8 * 2496) * sizeof(float);
    size_t updSmem  = (size_t)27584 * sizeof(float);
    cudaFuncSetAttribute(k_node_pre, cudaFuncAttributeMaxDynamicSharedMemorySize, (int)preSmem);
    cudaFuncSetAttribute(k_edge, cudaFuncAttributeMaxDynamicSharedMemorySize, (int)edgeSmem);
    cudaFuncSetAttribute(k_node_upd, cudaFuncAttributeMaxDynamicSharedMemorySize, (int)updSmem);

    k_zero_wp<<<(N_NODES + 255) / 256, 256>>>();
    k_hist<<<(N_EDGES + 255) / 256, 256>>>(ei);
    k_scan<<<1, 1024>>>();
    k_scatter<<<(N_EDGES + 255) / 256, 256>>>(ei, eattr);

    k_encoder<<<(N_NODES + 7) / 8, 256>>>(x, batch, casep, bcp, encW1, encb1, encW2, encb2, encg, encbe);
    k_node_pre<<<296, 256, preSmem>>>(eW1);
    for (int l = 0; l < NL; l++) {
        const float* eW1l = eW1 + (size_t)l * 133 * 64;
        const float* eW1n = (l + 1 < NL) ? (eW1 + (size_t)(l + 1) * 133 * 64) : nullptr;
        k_edge<<<296, 256, edgeSmem>>>(eW1l + 128 * 64, eb1 + l * 64,
                              eW2 + (size_t)l * 4096, eb2 + l * 64,
                              eg + l * 64, ebe + l * 64);
        k_node_upd<<<296, 256, updSmem>>>(nW1 + (size_t)l * 8192, nb1 + l * 64,
                                          nW2 + (size_t)l * 4096, nb2 + l * 64,
                                          ngm + l * 64, nbe + l * 64, eW1n);
    }
    k_zero_pool<<<1, 256>>>();
    k_decoder_local<<<(N_NODES + 7) / 8, 256>>>(dlW1, dlb1, dlW2, dlb2, batch, out);
    k_global<<<1, 128>>>(batch, dgW1, dgb1, dgW2, dgb2, out);
}

// round 15
// speedup vs baseline: 2.1650x; 1.0976x over previous
#include <cuda_runtime.h>
#include <cstdint>
#define DINL __device__ __forceinline__
constexpr int N_NODES = 50000;
constexpr int N_EDGES = 1600000;
constexpr int NL = 5;
constexpr int NG = 4;
constexpr float EPS = 1e-5f;

__device__ float g_h  [N_NODES * 64];
__device__ float g_hd [N_NODES * 64];
__device__ float g_hs [N_NODES * 64];
__device__ float g_agg[N_NODES * 64];
__device__ float g_pool[NG * 64];
__device__ int   g_wp [N_NODES];
__device__ float g_em [(size_t)N_EDGES * 8];

typedef unsigned long long u64;
DINL u64 pk2(float x, float y) { u64 r; asm("mov.b64 %0,{%1,%2};" : "=l"(r) : "f"(x), "f"(y)); return r; }
DINL u64 dup2(float x) { return pk2(x, x); }
DINL float2 upk(u64 v) { float2 r; asm("mov.b64 {%0,%1},%2;" : "=f"(r.x), "=f"(r.y) : "l"(v)); return r; }
DINL u64 ffma2(u64 a, u64 b, u64 c) { u64 d; asm("fma.rn.f32x2 %0,%1,%2,%3;" : "=l"(d) : "l"(a), "l"(b), "l"(c)); return d; }
DINL u64 add2(u64 a, u64 b) { u64 d; asm("add.rn.f32x2 %0,%1,%2;" : "=l"(d) : "l"(a), "l"(b)); return d; }
DINL void red2(float* p, float x, float y) { asm volatile("red.global.add.v2.f32 [%0], {%1,%2};" :: "l"(p), "f"(x), "f"(y) : "memory"); }
DINL void red4(float* p, float4 v) { asm volatile("red.global.add.v4.f32 [%0], {%1,%2,%3,%4};" :: "l"(p), "f"(v.x), "f"(v.y), "f"(v.z), "f"(v.w) : "memory"); }
DINL float silu(float x) { return __fdividef(x, 1.f + __expf(-x)); }
DINL uint32_t tf32c(float f) { uint32_t r; asm("cvt.rna.tf32.f32 %0,%1;" : "=r"(r) : "f"(f)); return r; }
DINL float tf32f(float f) { return __uint_as_float(tf32c(f)); }
DINL void pfL1(const float* p) { asm volatile("prefetch.global.L1 [%0];" :: "l"(p)); }
DINL float rcpa(float x) { float r; asm("rcp.approx.ftz.f32 %0,%1;" : "=f"(r) : "f"(x)); return r; }
// batched silu: 4 values, one rcp of the product of denominators (exp clamped -> no overflow)
DINL void silu4(float* v) {
    float e0 = __expf(fminf(-v[0], 20.f));
    float e1 = __expf(fminf(-v[1], 20.f));
    float e2 = __expf(fminf(-v[2], 20.f));
    float e3 = __expf(fminf(-v[3], 20.f));
    float d0 = 1.f + e0, d1 = 1.f + e1, d2 = 1.f + e2, d3 = 1.f + e3;
    float pa = d0 * d1, pb = d2 * d3;
    float r = rcpa(pa * pb);
    float rab = r * pb, rcd = r * pa;
    v[0] *= rab * d1; v[1] *= rab * d0;
    v[2] *= rcd * d3; v[3] *= rcd * d2;
}
DINL void mma8(float* c, uint32_t a0, uint32_t a1, uint32_t a2, uint32_t a3, uint32_t b0, uint32_t b1) {
    asm volatile("mma.sync.aligned.m16n8k8.row.col.f32.tf32.tf32.f32 {%0,%1,%2,%3},{%4,%5,%6,%7},{%8,%9},{%0,%1,%2,%3};"
        : "+f"(c[0]), "+f"(c[1]), "+f"(c[2]), "+f"(c[3])
        : "r"(a0), "r"(a1), "r"(a2), "r"(a3), "r"(b0), "r"(b1));
}

// ---------------- CSR build ----------------
__global__ void k_zero_wp() { int i = blockIdx.x * 256 + threadIdx.x; if (i < N_NODES) g_wp[i] = 0; }
__global__ void k_hist(const int* __restrict__ ei) { int e = blockIdx.x * 256 + threadIdx.x; if (e < N_EDGES) atomicAdd(&g_wp[ei[N_EDGES + e]], 1); }
__global__ void k_scan() {
    __shared__ int part[1024];
    int t = threadIdx.x; const int C = 49; int base = t * C; int sum = 0;
    for (int i = 0; i < C; i++) { int idx = base + i; if (idx < N_NODES) sum += g_wp[idx]; }
    part[t] = sum; __syncthreads();
    for (int off = 1; off < 1024; off <<= 1) { int v = (t >= off) ? part[t - off] : 0; __syncthreads(); part[t] += v; __syncthreads(); }
    int run = (t == 0) ? 0 : part[t - 1];
    for (int i = 0; i < C; i++) { int idx = base + i; if (idx < N_NODES) { int v = g_wp[idx]; g_wp[idx] = run; run += v; } }
}
__global__ void k_scatter(const int* __restrict__ ei, const float* __restrict__ eattr) {
    int e = blockIdx.x * 256 + threadIdx.x;
    if (e < N_EDGES) {
        int d = ei[N_EDGES + e];
        int pos = atomicAdd(&g_wp[d], 1);
        const float* ea = eattr + (size_t)e * 5;
        float4 f0 = make_float4(__int_as_float(ei[e]), __int_as_float(d), __ldg(ea), __ldg(ea + 1));
        float4 f1 = make_float4(__ldg(ea + 2), __ldg(ea + 3), __ldg(ea + 4), 0.f);
        size_t p8 = (size_t)pos * 8;
        *(float4*)&g_em[p8] = f0; *(float4*)&g_em[p8 + 4] = f1;
    }
}

// ---------------- encoder ----------------
__global__ void __launch_bounds__(256) k_encoder(
    const float* __restrict__ x, const int* __restrict__ batch,
    const float* __restrict__ casep, const float* __restrict__ bcp,
    const float* __restrict__ W1, const float* __restrict__ b1,
    const float* __restrict__ W2, const float* __restrict__ b2,
    const float* __restrict__ gam, const float* __restrict__ bet)
{
    __shared__ float sW1[1024], sW2[4096], sb1[64], sb2[64], sg[64], sbe[64];
    __shared__ float sH[8][64];
    int tid = threadIdx.x;
    for (int i = tid; i < 1024; i += 256) sW1[i] = W1[i];
    for (int i = tid; i < 4096; i += 256) sW2[i] = W2[i];
    if (tid < 64) { sb1[tid] = b1[tid]; sb2[tid] = b2[tid]; sg[tid] = gam[tid]; sbe[tid] = bet[tid]; }
    __syncthreads();
    int w = tid >> 5, ld = tid & 31, c0 = 2 * ld;
    int n = blockIdx.x * 8 + w;
    if (n >= N_NODES) return;
    float in[16];
#pragma unroll
    for (int k = 0; k < 8; k++) in[k] = __ldg(&x[n * 8 + k]);
    int g = __ldg(&batch[n]);
#pragma unroll
    for (int k = 0; k < 4; k++) { in[8 + k] = __ldg(&casep[g * 4 + k]); in[12 + k] = __ldg(&bcp[g * 4 + k]); }
    const u64* W1u = (const u64*)sW1;
    u64 acc = ((const u64*)sb1)[ld];
#pragma unroll
    for (int k = 0; k < 16; k++) acc = ffma2(dup2(in[k]), W1u[k * 32 + ld], acc);
    float2 a = upk(acc); a.x = silu(a.x); a.y = silu(a.y);
    sH[w][c0] = a.x; sH[w][c0 + 1] = a.y;
    __syncwarp();
    const u64* W2u = (const u64*)sW2;
    u64 acc2 = ((const u64*)sb2)[ld];
#pragma unroll 8
    for (int k = 0; k < 64; k++) acc2 = ffma2(dup2(sH[w][k]), W2u[k * 32 + ld], acc2);
    float2 v = upk(acc2);
    float s = v.x + v.y, q = v.x * v.x + v.y * v.y;
#pragma unroll
    for (int o = 16; o; o >>= 1) { s += __shfl_xor_sync(~0u, s, o); q += __shfl_xor_sync(~0u, q, o); }
    float m = s * (1.f / 64.f), rs = rsqrtf(q * (1.f / 64.f) - m * m + EPS);
    float2 out;
    out.x = (v.x - m) * rs * sg[c0] + sbe[c0];
    out.y = (v.y - m) * rs * sg[c0 + 1] + sbe[c0 + 1];
    *(float2*)(g_h + (size_t)n * 64 + c0) = out;
}

// ---------------- node pre (layer 0 only) ----------------
__global__ void __launch_bounds__(256) k_node_pre(const float* __restrict__ eW1l)
{
    extern __shared__ float ps[];
    float* sWt = ps;
    float* sA  = ps + 8704;
    int tid = threadIdx.x;
    for (int i = tid; i < 64 * 128; i += 256) {
        int k = i >> 7, c = i & 127;
        float v = (c < 64) ? eW1l[k * 64 + c] : eW1l[(64 + k) * 64 + (c - 64)];
        sWt[k * 136 + c] = tf32f(v);
    }
    __syncthreads();
    int w = tid >> 5, ld = tid & 31, g8 = ld >> 2, q4 = ld & 3;
    const uint32_t* au = (const uint32_t*)sA;
    const uint32_t* bu = (const uint32_t*)sWt;
    for (int t = blockIdx.x; t < N_NODES / 16; t += gridDim.x) {
        int n0 = t * 16;
        __syncthreads();
        {
            int n = tid >> 4, c4 = (tid & 15) * 4;
            float4 v = *(const float4*)(g_h + (size_t)(n0 + n) * 64 + c4);
            uint4 tv; tv.x = tf32c(v.x); tv.y = tf32c(v.y); tv.z = tf32c(v.z); tv.w = tf32c(v.w);
            *(uint4*)&sA[n * 76 + c4] = tv;
        }
        {
            int n = tid >> 4, c = (tid & 15) * 4;
            *(float4*)(g_agg + (size_t)(n0 + n) * 64 + c) = make_float4(0.f, 0.f, 0.f, 0.f);
        }
        __syncthreads();
        float acc[2][4];
#pragma unroll
        for (int sbi = 0; sbi < 2; sbi++)
#pragma unroll
            for (int j = 0; j < 4; j++) acc[sbi][j] = 0.f;
#pragma unroll
        for (int kb = 0; kb < 8; kb++) {
            int kc = kb * 8 + q4;
            uint32_t a0 = au[g8 * 76 + kc], a1 = au[(g8 + 8) * 76 + kc];
            uint32_t a2 = au[g8 * 76 + kc + 4], a3 = au[(g8 + 8) * 76 + kc + 4];
#pragma unroll
            for (int sbi = 0; sbi < 2; sbi++) {
                int nb = 2 * w + sbi;
                uint32_t b0 = bu[kc * 136 + nb * 8 + g8];
                uint32_t b1 = bu[(kc + 4) * 136 + nb * 8 + g8];
                mma8(acc[sbi], a0, a1, a2, a3, b0, b1);
            }
        }
#pragma unroll
        for (int sbi = 0; sbi < 2; sbi++) {
            int c = (2 * w + sbi) * 8 + 2 * q4;
            float* base = (c < 64) ? g_hd : g_hs;
            int cl = (c < 64) ? c : c - 64;
            *(float2*)(base + (size_t)(n0 + g8) * 64 + cl)     = make_float2(acc[sbi][0], acc[sbi][1]);
            *(float2*)(base + (size_t)(n0 + g8 + 8) * 64 + cl) = make_float2(acc[sbi][2], acc[sbi][3]);
        }
    }
}

// ---------------- edge kernel (R14 + interleaved phase-1 + batched-rcp silu) ----------------
__global__ void __launch_bounds__(256, 2) k_edge(
    const float* __restrict__ W1c, const float* __restrict__ b1,
    const float* __restrict__ W2, const float* __restrict__ b2,
    const float* __restrict__ gam, const float* __restrict__ bet)
{
    extern __shared__ float es[];
    float* sW2s = es;
    float* sW1c = es + 4608;
    float* sb1 = es + 4928; float* sb2 = es + 4992;
    float* sg = es + 5056;  float* sbe = es + 5120;
    float* sPer = es + 5184;
    int tid = threadIdx.x;
    for (int i = tid; i < 4096; i += 256) {
        int k = i >> 6, c = i & 63;
        sW2s[k * 72 + c] = tf32f(W2[i]);
    }
    for (int i = tid; i < 320; i += 256) sW1c[i] = W1c[i];
    if (tid < 64) { sb1[tid] = b1[tid]; sb2[tid] = b2[tid]; sg[tid] = gam[tid]; sbe[tid] = bet[tid]; }
    __syncthreads();
    int w = tid >> 5, ld = tid & 31;
    int pe = ld >> 1, half = ld & 1;
    int eb = ld >> 3, cb = ld & 7;
    int g8 = ld >> 2, q4 = ld & 3;
    float* sM = sPer + w * 2496;
    int* sD = (int*)(sM + 2432);
    int* sSrc = (int*)(sM + 2464);
    const ulonglong2* W1cu = (const ulonglong2*)sW1c;
    const ulonglong2* b1u = (const ulonglong2*)sb1;
    u64 gv[4], bev[4];
#pragma unroll
    for (int j = 0; j < 4; j++) { gv[j] = ((const u64*)sg)[cb * 4 + j]; bev[j] = ((const u64*)sbe)[cb * 4 + j]; }
    float b2s[8];
#pragma unroll
    for (int j = 0; j < 8; j++) b2s[j] = sb2[cb * 8 + j];
    int gw = (blockIdx.x * 256 + tid) >> 5;
    int nw = (gridDim.x * 256) >> 5;
    const int NT = N_EDGES / 32;
    float4 mf0[2], mf1[2];
    {
        int e0 = gw * 32;
#pragma unroll
        for (int sub = 0; sub < 2; sub++) {
            const float4* emp = (const float4*)&g_em[(size_t)(e0 + sub * 16 + pe) * 8];
            mf0[sub] = __ldg(emp); mf1[sub] = __ldg(emp + 1);
        }
#pragma unroll
        for (int sub = 0; sub < 2; sub++) {
            int ns = __float_as_int(mf0[sub].x), nd = __float_as_int(mf0[sub].y);
            pfL1(g_hs + (size_t)ns * 64 + half * 32);
            pfL1(g_hd + (size_t)nd * 64 + half * 32);
        }
    }
    for (int grp = gw; grp < NT; grp += nw) {
        __syncwarp();   // WAR: previous tile's sM/sD reads done
        int didx[2];
        u64 ead[2][5];
#pragma unroll
        for (int sub = 0; sub < 2; sub++) {
            int slot = sub * 16 + pe;
            float4 f0 = mf0[sub], f1 = mf1[sub];
            didx[sub] = __float_as_int(f0.y);
            ead[sub][0] = dup2(f0.z); ead[sub][1] = dup2(f0.w);
            ead[sub][2] = dup2(f1.x); ead[sub][3] = dup2(f1.y); ead[sub][4] = dup2(f1.z);
            if (half == 0) { sD[slot] = didx[sub]; sSrc[slot] = __float_as_int(f0.x); }
        }
        __syncwarp();
#pragma unroll
        for (int r = 0; r < 16; r++) {
            int chunk = r * 32 + ld, eslot = chunk >> 4, c4 = (chunk & 15) * 4;
            *(float4*)&sM[eslot * 68 + c4] = *(const float4*)(g_hs + (size_t)sSrc[eslot] * 64 + c4);
        }
        __syncwarp();
        // ---- phase 1: subs interleaved (shared W1c/b1 LDS), batched-rcp silu ----
        {
            const ulonglong2* hdp0 = (const ulonglong2*)(g_hd + (size_t)didx[0] * 64 + half * 32);
            const ulonglong2* hdp1 = (const ulonglong2*)(g_hd + (size_t)didx[1] * 64 + half * 32);
            float* mrow0 = sM + pe * 68 + half * 32;
            float* mrow1 = sM + (16 + pe) * 68 + half * 32;
#pragma unroll
            for (int j = 0; j < 8; j++) {
                ulonglong2 bj = b1u[half * 8 + j];
                ulonglong2 hd0 = __ldg(hdp0 + j), hd1 = __ldg(hdp1 + j);
                ulonglong2 hs0 = ((const ulonglong2*)mrow0)[j];
                ulonglong2 hs1 = ((const ulonglong2*)mrow1)[j];
                u64 A0 = add2(add2(hd0.x, hs0.x), bj.x);
                u64 A1 = add2(add2(hd0.y, hs0.y), bj.y);
                u64 B0 = add2(add2(hd1.x, hs1.x), bj.x);
                u64 B1 = add2(add2(hd1.y, hs1.y), bj.y);
#pragma unroll
                for (int r = 0; r < 5; r++) {
                    ulonglong2 wv = W1cu[r * 16 + half * 8 + j];
                    A0 = ffma2(ead[0][r], wv.x, A0); A1 = ffma2(ead[0][r], wv.y, A1);
                    B0 = ffma2(ead[1][r], wv.x, B0); B1 = ffma2(ead[1][r], wv.y, B1);
                }
                float va[4], vb[4];
                { float2 t0 = upk(A0), t1 = upk(A1); va[0] = t0.x; va[1] = t0.y; va[2] = t1.x; va[3] = t1.y; }
                { float2 t0 = upk(B0), t1 = upk(B1); vb[0] = t0.x; vb[1] = t0.y; vb[2] = t1.x; vb[3] = t1.y; }
                silu4(va); silu4(vb);
                uint4 ta; ta.x = tf32c(va[0]); ta.y = tf32c(va[1]); ta.z = tf32c(va[2]); ta.w = tf32c(va[3]);
                uint4 tb; tb.x = tf32c(vb[0]); tb.y = tf32c(vb[1]); tb.z = tf32c(vb[2]); tb.w = tf32c(vb[3]);
                *(uint4*)(mrow0 + 4 * j) = ta;
                *(uint4*)(mrow1 + 4 * j) = tb;
            }
        }
        __syncwarp();
        int ng = grp + nw;
        if (ng < NT) {
            int e0n = ng * 32;
#pragma unroll
            for (int sub = 0; sub < 2; sub++) {
                const float4* emp = (const float4*)&g_em[(size_t)(e0n + sub * 16 + pe) * 8];
                mf0[sub] = __ldg(emp); mf1[sub] = __ldg(emp + 1);
            }
        }
        float acc[2][8][4];
#pragma unroll
        for (int mb = 0; mb < 2; mb++)
#pragma unroll
            for (int nb = 0; nb < 8; nb++)
#pragma unroll
                for (int j = 0; j < 4; j++) acc[mb][nb][j] = 0.f;
#pragma unroll
        for (int kb = 0; kb < 8; kb++) {
            int kc = kb * 8 + q4;
            const uint32_t* mu = (const uint32_t*)sM;
            uint32_t a00 = mu[(g8) * 68 + kc],      a01 = mu[(g8 + 8) * 68 + kc];
            uint32_t a02 = mu[(g8) * 68 + kc + 4],  a03 = mu[(g8 + 8) * 68 + kc + 4];
            uint32_t a10 = mu[(g8 + 16) * 68 + kc],     a11 = mu[(g8 + 24) * 68 + kc];
            uint32_t a12 = mu[(g8 + 16) * 68 + kc + 4], a13 = mu[(g8 + 24) * 68 + kc + 4];
            const uint32_t* wu = (const uint32_t*)sW2s;
#pragma unroll
            for (int nb = 0; nb < 8; nb++) {
                uint32_t b0 = wu[kc * 72 + nb * 8 + g8];
                uint32_t b1_ = wu[(kc + 4) * 72 + nb * 8 + g8];
                mma8(acc[0][nb], a00, a01, a02, a03, b0, b1_);
                mma8(acc[1][nb], a10, a11, a12, a13, b0, b1_);
            }
        }
        if (ng < NT) {
#pragma unroll
            for (int sub = 0; sub < 2; sub++) {
                int ns = __float_as_int(mf0[sub].x), nd = __float_as_int(mf0[sub].y);
                pfL1(g_hs + (size_t)ns * 64 + half * 32);
                pfL1(g_hd + (size_t)nd * 64 + half * 32);
            }
        }
        __syncwarp();
#pragma unroll
        for (int mb = 0; mb < 2; mb++)
#pragma unroll
            for (int nb = 0; nb < 8; nb++) {
                int elo = mb * 16 + g8;
                *(float2*)&sM[elo * 76 + nb * 8 + 2 * q4] = make_float2(acc[mb][nb][0], acc[mb][nb][1]);
                *(float2*)&sM[(elo + 8) * 76 + nb * 8 + 2 * q4] = make_float2(acc[mb][nb][2], acc[mb][nb][3]);
            }
        __syncwarp();
        float4 f0a[8], f1a[8];
        float s[8], q[8];
#pragma unroll
        for (int i = 0; i < 8; i++) {
            int e = eb * 8 + i;
            float4 v0 = *(const float4*)&sM[e * 76 + cb * 8];
            float4 v1 = *(const float4*)&sM[e * 76 + cb * 8 + 4];
            v0.x += b2s[0]; v0.y += b2s[1]; v0.z += b2s[2]; v0.w += b2s[3];
            v1.x += b2s[4]; v1.y += b2s[5]; v1.z += b2s[6]; v1.w += b2s[7];
            f0a[i] = v0; f1a[i] = v1;
            s[i] = v0.x + v0.y + v0.z + v0.w + v1.x + v1.y + v1.z + v1.w;
            q[i] = v0.x * v0.x + v0.y * v0.y + v0.z * v0.z + v0.w * v0.w
                 + v1.x * v1.x + v1.y * v1.y + v1.z * v1.z + v1.w * v1.w;
        }
#pragma unroll
        for (int o = 4; o; o >>= 1) {
#pragma unroll
            for (int i = 0; i < 8; i++) { s[i] += __shfl_xor_sync(~0u, s[i], o); q[i] += __shfl_xor_sync(~0u, q[i], o); }
        }
        int curD = sD[eb * 8];
        u64 av[4] = {0ull, 0ull, 0ull, 0ull};
#pragma unroll
        for (int i = 0; i < 8; i++) {
            int dI = sD[eb * 8 + i];
            float mn = s[i] * (1.f / 64.f);
            float rs = rsqrtf(q[i] * (1.f / 64.f) - mn * mn + EPS);
            u64 rsd = dup2(rs), mrd = dup2(-mn * rs);
            if (dI != curD) {
                float2 a0 = upk(av[0]), a1 = upk(av[1]), a2 = upk(av[2]), a3 = upk(av[3]);
                float* base = g_agg + (size_t)curD * 64 + cb * 8;
                red4(base, make_float4(a0.x, a0.y, a1.x, a1.y));
                red4(base + 4, make_float4(a2.x, a2.y, a3.x, a3.y));
                av[0] = av[1] = av[2] = av[3] = 0ull;
                curD = dI;
            }
            u64 vv0 = pk2(f0a[i].x, f0a[i].y), vv1 = pk2(f0a[i].z, f0a[i].w);
            u64 vv2 = pk2(f1a[i].x, f1a[i].y), vv3 = pk2(f1a[i].z, f1a[i].w);
            av[0] = add2(av[0], ffma2(ffma2(vv0, rsd, mrd), gv[0], bev[0]));
            av[1] = add2(av[1], ffma2(ffma2(vv1, rsd, mrd), gv[1], bev[1]));
            av[2] = add2(av[2], ffma2(ffma2(vv2, rsd, mrd), gv[2], bev[2]));
            av[3] = add2(av[3], ffma2(ffma2(vv3, rsd, mrd), gv[3], bev[3]));
        }
        {
            float2 a0 = upk(av[0]), a1 = upk(av[1]), a2 = upk(av[2]), a3 = upk(av[3]);
            float* base = g_agg + (size_t)curD * 64 + cb * 8;
            red4(base, make_float4(a0.x, a0.y, a1.x, a1.y));
            red4(base + 4, make_float4(a2.x, a2.y, a3.x, a3.y));
        }
    }
}

// ---------------- node update (FUSED with next-layer pre) ----------------
__global__ void __launch_bounds__(256) k_node_upd(
    const float* __restrict__ W1, const float* __restrict__ b1,
    const float* __restrict__ W2, const float* __restrict__ b2,
    const float* __restrict__ gam, const float* __restrict__ bet,
    const float* __restrict__ eW1n)
{
    extern __shared__ float us[];
    float* sW1t = us;
    float* sW2t = us + 9216;
    float* sA   = us + 13824;
    float* sH   = us + 16064;
    float* sMid = us + 17152;
    float* sPart= us + 18368;
    float* sb1  = us + 18624;
    float* sb2  = us + 18688;
    float* sgm  = us + 18752;
    float* sbe  = us + 18816;
    float* sWp  = us + 18880;
    int tid = threadIdx.x;
    bool hn = (eW1n != nullptr);
    for (int i = tid; i < 128 * 64; i += 256) { int k = i >> 6, c = i & 63; sW1t[k * 72 + c] = tf32f(W1[i]); }
    for (int i = tid; i < 64 * 64; i += 256)  { int k = i >> 6, c = i & 63; sW2t[k * 72 + c] = tf32f(W2[i]); }
    if (hn)
        for (int i = tid; i < 64 * 128; i += 256) {
            int k = i >> 7, c = i & 127;
            float v = (c < 64) ? eW1n[k * 64 + c] : eW1n[(64 + k) * 64 + (c - 64)];
            sWp[k * 136 + c] = tf32f(v);
        }
    if (tid < 64) { sb1[tid] = b1[tid]; sb2[tid] = b2[tid]; sgm[tid] = gam[tid]; sbe[tid] = bet[tid]; }
    __syncthreads();
    int w = tid >> 5, ld = tid & 31, g8 = ld >> 2, q4 = ld & 3;
    const uint32_t* au = (const uint32_t*)sA;
    const uint32_t* b1w = (const uint32_t*)sW1t;
    const uint32_t* b2w = (const uint32_t*)sW2t;
    const uint32_t* mu = (const uint32_t*)sMid;
    const uint32_t* bpu = (const uint32_t*)sWp;
    int c0 = w * 8 + 2 * q4;
    float b1c0 = sb1[c0], b1c1 = sb1[c0 + 1];
    float b2c0 = sb2[c0], b2c1 = sb2[c0 + 1];
    float gm0 = sgm[c0], gm1 = sgm[c0 + 1];
    float be0 = sbe[c0], be1 = sbe[c0 + 1];
    for (int t = blockIdx.x; t < N_NODES / 16; t += gridDim.x) {
        int n0 = t * 16;
        __syncthreads();
        {
            int n = tid >> 4, c8 = (tid & 15) * 8;
            float4 v0, v1;
            if (c8 < 64) {
                v0 = *(const float4*)(g_h + (size_t)(n0 + n) * 64 + c8);
                v1 = *(const float4*)(g_h + (size_t)(n0 + n) * 64 + c8 + 4);
                *(float4*)&sH[n * 68 + c8] = v0;
                *(float4*)&sH[n * 68 + c8 + 4] = v1;
            } else {
                v0 = *(const float4*)(g_agg + (size_t)(n0 + n) * 64 + c8 - 64);
                v1 = *(const float4*)(g_agg + (size_t)(n0 + n) * 64 + c8 - 60);
            }
            uint4 t0; t0.x = tf32c(v0.x); t0.y = tf32c(v0.y); t0.z = tf32c(v0.z); t0.w = tf32c(v0.w);
            uint4 t1; t1.x = tf32c(v1.x); t1.y = tf32c(v1.y); t1.z = tf32c(v1.z); t1.w = tf32c(v1.w);
            *(uint4*)&sA[n * 140 + c8] = t0;
            *(uint4*)&sA[n * 140 + c8 + 4] = t1;
        }
        __syncthreads();
        float a1c[4] = {0.f, 0.f, 0.f, 0.f};
#pragma unroll
        for (int kb = 0; kb < 16; kb++) {
            int kc = kb * 8 + q4;
            uint32_t a0 = au[g8 * 140 + kc], a1 = au[(g8 + 8) * 140 + kc];
            uint32_t a2 = au[g8 * 140 + kc + 4], a3 = au[(g8 + 8) * 140 + kc + 4];
            uint32_t b0 = b1w[kc * 72 + w * 8 + g8];
            uint32_t b1_ = b1w[(kc + 4) * 72 + w * 8 + g8];
            mma8(a1c, a0, a1, a2, a3, b0, b1_);
        }
        sMid[g8 * 76 + c0]       = tf32f(silu(a1c[0] + b1c0));
        sMid[g8 * 76 + c0 + 1]   = tf32f(silu(a1c[1] + b1c1));
        sMid[(g8 + 8) * 76 + c0]     = tf32f(silu(a1c[2] + b1c0));
        sMid[(g8 + 8) * 76 + c0 + 1] = tf32f(silu(a1c[3] + b1c1));
        __syncthreads();
        float a2c[4] = {0.f, 0.f, 0.f, 0.f};
#pragma unroll
        for (int kb = 0; kb < 8; kb++) {
            int kc = kb * 8 + q4;
            uint32_t a0 = mu[g8 * 76 + kc], a1 = mu[(g8 + 8) * 76 + kc];
            uint32_t a2 = mu[g8 * 76 + kc + 4], a3 = mu[(g8 + 8) * 76 + kc + 4];
            uint32_t b0 = b2w[kc * 72 + w * 8 + g8];
            uint32_t b1_ = b2w[(kc + 4) * 72 + w * 8 + g8];
            mma8(a2c, a0, a1, a2, a3, b0, b1_);
        }
        float v0 = a2c[0] + b2c0, v1 = a2c[1] + b2c1;
        float v2 = a2c[2] + b2c0, v3 = a2c[3] + b2c1;
        float s0 = v0 + v1, q0 = v0 * v0 + v1 * v1;
        float s1 = v2 + v3, q1 = v2 * v2 + v3 * v3;
#pragma unroll
        for (int o = 1; o <= 2; o <<= 1) {
            s0 += __shfl_xor_sync(~0u, s0, o); q0 += __shfl_xor_sync(~0u, q0, o);
            s1 += __shfl_xor_sync(~0u, s1, o); q1 += __shfl_xor_sync(~0u, q1, o);
        }
        if (q4 == 0) {
            sPart[w * 32 + g8 * 2] = s0;       sPart[w * 32 + g8 * 2 + 1] = q0;
            sPart[w * 32 + (g8 + 8) * 2] = s1; sPart[w * 32 + (g8 + 8) * 2 + 1] = q1;
        }
        __syncthreads();
        float S0 = 0.f, Q0 = 0.f, S1 = 0.f, Q1 = 0.f;
#pragma unroll
        for (int ww = 0; ww < 8; ww++) {
            S0 += sPart[ww * 32 + g8 * 2];       Q0 += sPart[ww * 32 + g8 * 2 + 1];
            S1 += sPart[ww * 32 + (g8 + 8) * 2]; Q1 += sPart[ww * 32 + (g8 + 8) * 2 + 1];
        }
        float mn0 = S0 * (1.f / 64.f), rs0 = rsqrtf(Q0 * (1.f / 64.f) - mn0 * mn0 + EPS);
        float mn1 = S1 * (1.f / 64.f), rs1 = rsqrtf(Q1 * (1.f / 64.f) - mn1 * mn1 + EPS);
        float2 o0, o1;
        o0.x = sH[g8 * 68 + c0]     + (v0 - mn0) * rs0 * gm0 + be0;
        o0.y = sH[g8 * 68 + c0 + 1] + (v1 - mn0) * rs0 * gm1 + be1;
        o1.x = sH[(g8 + 8) * 68 + c0]     + (v2 - mn1) * rs1 * gm0 + be0;
        o1.y = sH[(g8 + 8) * 68 + c0 + 1] + (v3 - mn1) * rs1 * gm1 + be1;
        *(float2*)(g_h + (size_t)(n0 + g8) * 64 + c0)     = o0;
        *(float2*)(g_h + (size_t)(n0 + g8 + 8) * 64 + c0) = o1;
        if (hn) {
            sMid[g8 * 76 + c0]       = tf32f(o0.x);
            sMid[g8 * 76 + c0 + 1]   = tf32f(o0.y);
            sMid[(g8 + 8) * 76 + c0]     = tf32f(o1.x);
            sMid[(g8 + 8) * 76 + c0 + 1] = tf32f(o1.y);
            {
                int n = tid >> 4, c = (tid & 15) * 4;
                *(float4*)(g_agg + (size_t)(n0 + n) * 64 + c) = make_float4(0.f, 0.f, 0.f, 0.f);
            }
            __syncthreads();
            float accp[2][4];
#pragma unroll
            for (int sbi = 0; sbi < 2; sbi++)
#pragma unroll
                for (int j = 0; j < 4; j++) accp[sbi][j] = 0.f;
#pragma unroll
            for (int kb = 0; kb < 8; kb++) {
                int kc = kb * 8 + q4;
                uint32_t a0 = mu[g8 * 76 + kc], a1 = mu[(g8 + 8) * 76 + kc];
                uint32_t a2 = mu[g8 * 76 + kc + 4], a3 = mu[(g8 + 8) * 76 + kc + 4];
#pragma unroll
                for (int sbi = 0; sbi < 2; sbi++) {
                    int nb = 2 * w + sbi;
                    uint32_t b0 = bpu[kc * 136 + nb * 8 + g8];
                    uint32_t b1_ = bpu[(kc + 4) * 136 + nb * 8 + g8];
                    mma8(accp[sbi], a0, a1, a2, a3, b0, b1_);
                }
            }
#pragma unroll
            for (int sbi = 0; sbi < 2; sbi++) {
                int c = (2 * w + sbi) * 8 + 2 * q4;
                float* base = (c < 64) ? g_hd : g_hs;
                int cl = (c < 64) ? c : c - 64;
                *(float2*)(base + (size_t)(n0 + g8) * 64 + cl)     = make_float2(accp[sbi][0], accp[sbi][1]);
                *(float2*)(base + (size_t)(n0 + g8 + 8) * 64 + cl) = make_float2(accp[sbi][2], accp[sbi][3]);
            }
        }
    }
}

__global__ void k_zero_pool() { int t = threadIdx.x; if (t < NG * 64) g_pool[t] = 0.f; }

// ---------------- local decoder + pooling ----------------
__global__ void __launch_bounds__(256) k_decoder_local(
    const float* __restrict__ W1, const float* __restrict__ b1,
    const float* __restrict__ W2, const float* __restrict__ b2,
    const int* __restrict__ batch, float* __restrict__ out)
{
    __shared__ float sW1[4096], sW2[384], sb1[64], sb2_[8];
    __shared__ float sH[8][64], sU[8][64];
    int tid = threadIdx.x;
    for (int i = tid; i < 4096; i += 256) sW1[i] = W1[i];
    for (int i = tid; i < 384; i += 256) sW2[i] = W2[i];
    if (tid < 64) sb1[tid] = b1[tid];
    if (tid < 6) sb2_[tid] = b2[tid];
    __syncthreads();
    int w = tid >> 5, ld = tid & 31, c0 = 2 * ld;
    int n = blockIdx.x * 8 + w;
    if (n >= N_NODES) return;
    float2 hv = *(const float2*)(g_h + (size_t)n * 64 + c0);
    sH[w][c0] = hv.x; sH[w][c0 + 1] = hv.y;
    __syncwarp();
    const u64* W1u = (const u64*)sW1;
    u64 acc = ((const u64*)sb1)[ld];
#pragma unroll 8
    for (int k = 0; k < 64; k++) acc = ffma2(dup2(sH[w][k]), W1u[k * 32 + ld], acc);
    float2 u = upk(acc); u.x = silu(u.x); u.y = silu(u.y);
    sU[w][c0] = u.x; sU[w][c0 + 1] = u.y;
    __syncwarp();
    if (ld < 6) {
        float o = sb2_[ld];
#pragma unroll
        for (int k = 0; k < 64; k++) o += sU[w][k] * sW2[k * 6 + ld];
        out[(size_t)n * 6 + ld] = o;
    }
    int g = __ldg(&batch[n]);
    red2(g_pool + g * 64 + c0, hv.x, hv.y);
}

// ---------------- global decoder ----------------
__global__ void k_global(const int* __restrict__ batch,
    const float* __restrict__ W1, const float* __restrict__ b1,
    const float* __restrict__ W2, const float* __restrict__ b2,
    float* __restrict__ out)
{
    __shared__ float sp[NG * 64], su[NG * 32];
    __shared__ int bnd[NG + 1];
    int t = threadIdx.x;
    if (t <= NG) {
        int lo = 0, hi = N_NODES;
        while (lo < hi) { int mid = (lo + hi) >> 1; if (batch[mid] < t) lo = mid + 1; else hi = mid; }
        bnd[t] = lo;
    }
    __syncthreads();
    for (int i = t; i < NG * 64; i += 128) {
        int g = i >> 6;
        sp[i] = g_pool[i] / fmaxf((float)(bnd[g + 1] - bnd[g]), 1.f);
    }
    __syncthreads();
    {
        int g = t >> 5, j = t & 31;
        float a = b1[j];
#pragma unroll
        for (int k = 0; k < 64; k++) a += sp[g * 64 + k] * W1[k * 32 + j];
        su[g * 32 + j] = silu(a);
    }
    __syncthreads();
    if (t < NG * 4) {
        int g = t >> 2, j = t & 3;
        float o = b2[j];
#pragma unroll
        for (int k = 0; k < 32; k++) o += su[g * 32 + k] * W2[k * 4 + j];
        out[(size_t)N_NODES * 6 + g * 4 + j] = o;
    }
}

extern "C" void kernel_launch(void* const* d_in, const int* in_sizes, int n_in,
                              void* d_out, int out_size) {
    (void)in_sizes; (void)n_in; (void)out_size;
    const float* x     = (const float*)d_in[0];
    const int*   ei    = (const int*)d_in[1];
    const float* eattr = (const float*)d_in[2];
    const int*   batch = (const int*)d_in[3];
    const float* casep = (const float*)d_in[4];
    const float* bcp   = (const float*)d_in[5];
    const float* encW1 = (const float*)d_in[6];  const float* encb1 = (const float*)d_in[7];
    const float* encW2 = (const float*)d_in[8];  const float* encb2 = (const float*)d_in[9];
    const float* encg  = (const float*)d_in[10]; const float* encbe = (const float*)d_in[11];
    const float* eW1   = (const float*)d_in[12]; const float* eb1   = (const float*)d_in[13];
    const float* eW2   = (const float*)d_in[14]; const float* eb2   = (const float*)d_in[15];
    const float* eg    = (const float*)d_in[16]; const float* ebe   = (const float*)d_in[17];
    const float* nW1   = (const float*)d_in[18]; const float* nb1   = (const float*)d_in[19];
    const float* nW2   = (const float*)d_in[20]; const float* nb2   = (const float*)d_in[21];
    const float* ngm   = (const float*)d_in[22]; const float* nbe   = (const float*)d_in[23];
    const float* dlW1  = (const float*)d_in[24]; const float* dlb1  = (const float*)d_in[25];
    const float* dlW2  = (const float*)d_in[26]; const float* dlb2  = (const float*)d_in[27];
    const float* dgW1  = (const float*)d_in[28]; const float* dgb1  = (const float*)d_in[29];
    const float* dgW2  = (const float*)d_in[30]; const float* dgb2  = (const float*)d_in[31];
    float* out = (float*)d_out;

    size_t preSmem  = (size_t)9920 * sizeof(float);
    size_t edgeSmem = (size_t)(5184 + 8 * 2496) * sizeof(float);
    size_t updSmem  = (size_t)27584 * sizeof(float);
    cudaFuncSetAttribute(k_node_pre, cudaFuncAttributeMaxDynamicSharedMemorySize, (int)preSmem);
    cudaFuncSetAttribute(k_edge, cudaFuncAttributeMaxDynamicSharedMemorySize, (int)edgeSmem);
    cudaFuncSetAttribute(k_node_upd, cudaFuncAttributeMaxDynamicSharedMemorySize, (int)updSmem);

    k_zero_wp<<<(N_NODES + 255) / 256, 256>>>();
    k_hist<<<(N_EDGES + 255) / 256, 256>>>(ei);
    k_scan<<<1, 1024>>>();
    k_scatter<<<(N_EDGES + 255) / 256, 256>>>(ei, eattr);

    k_encoder<<<(N_NODES + 7) / 8, 256>>>(x, batch, casep, bcp, encW1, encb1, encW2, encb2, encg, encbe);
    k_node_pre<<<296, 256, preSmem>>>(eW1);
    for (int l = 0; l < NL; l++) {
        const float* eW1l = eW1 + (size_t)l * 133 * 64;
        const float* eW1n = (l + 1 < NL) ? (eW1 + (size_t)(l + 1) * 133 * 64) : nullptr;
        k_edge<<<296, 256, edgeSmem>>>(eW1l + 128 * 64, eb1 + l * 64,
                              eW2 + (size_t)l * 4096, eb2 + l * 64,
                              eg + l * 64, ebe + l * 64);
        k_node_upd<<<296, 256, updSmem>>>(nW1 + (size_t)l * 8192, nb1 + l * 64,
                                          nW2 + (size_t)l * 4096, nb2 + l * 64,
                                          ngm + l * 64, nbe + l * 64, eW1n);
    }
    k_zero_pool<<<1, 256>>>();
    k_decoder_local<<<(N_NODES + 7) / 8, 256>>>(dlW1, dlb1, dlW2, dlb2, batch, out);
    k_global<<<1, 128>>>(batch, dgW1, dgb1, dgW2, dgb2, out);
}

// round 16
// speedup vs baseline: 2.1852x; 1.0094x over previous
#include <cuda_runtime.h>
#include <cstdint>
#define DINL __device__ __forceinline__
constexpr int N_NODES = 50000;
constexpr int N_EDGES = 1600000;
constexpr int NL = 5;
constexpr int NG = 4;
constexpr float EPS = 1e-5f;

__device__ float g_h  [N_NODES * 64];
__device__ float g_hd [N_NODES * 64];
__device__ float g_hs [N_NODES * 64];
__device__ float g_agg[N_NODES * 64];
__device__ float g_pool[NG * 64];
__device__ int   g_wp [N_NODES];
__device__ float g_em [(size_t)N_EDGES * 8];

typedef unsigned long long u64;
DINL u64 pk2(float x, float y) { u64 r; asm("mov.b64 %0,{%1,%2};" : "=l"(r) : "f"(x), "f"(y)); return r; }
DINL u64 dup2(float x) { return pk2(x, x); }
DINL float2 upk(u64 v) { float2 r; asm("mov.b64 {%0,%1},%2;" : "=f"(r.x), "=f"(r.y) : "l"(v)); return r; }
DINL u64 ffma2(u64 a, u64 b, u64 c) { u64 d; asm("fma.rn.f32x2 %0,%1,%2,%3;" : "=l"(d) : "l"(a), "l"(b), "l"(c)); return d; }
DINL u64 add2(u64 a, u64 b) { u64 d; asm("add.rn.f32x2 %0,%1,%2;" : "=l"(d) : "l"(a), "l"(b)); return d; }
DINL void red2(float* p, float x, float y) { asm volatile("red.global.add.v2.f32 [%0], {%1,%2};" :: "l"(p), "f"(x), "f"(y) : "memory"); }
DINL void red4(float* p, float4 v) { asm volatile("red.global.add.v4.f32 [%0], {%1,%2,%3,%4};" :: "l"(p), "f"(v.x), "f"(v.y), "f"(v.z), "f"(v.w) : "memory"); }
DINL float silu(float x) { return __fdividef(x, 1.f + __expf(-x)); }
DINL uint32_t tf32c(float f) { uint32_t r; asm("cvt.rna.tf32.f32 %0,%1;" : "=r"(r) : "f"(f)); return r; }
DINL float tf32f(float f) { return __uint_as_float(tf32c(f)); }
DINL void pfL1(const float* p) { asm volatile("prefetch.global.L1 [%0];" :: "l"(p)); }
DINL float rcpa(float x) { float r; asm("rcp.approx.ftz.f32 %0,%1;" : "=f"(r) : "f"(x)); return r; }
// batched silu: 4 values, one rcp of the product of denominators (exp clamped -> no overflow)
DINL void silu4(float* v) {
    float e0 = __expf(fminf(-v[0], 20.f));
    float e1 = __expf(fminf(-v[1], 20.f));
    float e2 = __expf(fminf(-v[2], 20.f));
    float e3 = __expf(fminf(-v[3], 20.f));
    float d0 = 1.f + e0, d1 = 1.f + e1, d2 = 1.f + e2, d3 = 1.f + e3;
    float pa = d0 * d1, pb = d2 * d3;
    float r = rcpa(pa * pb);
    float rab = r * pb, rcd = r * pa;
    v[0] *= rab * d1; v[1] *= rab * d0;
    v[2] *= rcd * d3; v[3] *= rcd * d2;
}
DINL void mma8(float* c, uint32_t a0, uint32_t a1, uint32_t a2, uint32_t a3, uint32_t b0, uint32_t b1) {
    asm volatile("mma.sync.aligned.m16n8k8.row.col.f32.tf32.tf32.f32 {%0,%1,%2,%3},{%4,%5,%6,%7},{%8,%9},{%0,%1,%2,%3};"
        : "+f"(c[0]), "+f"(c[1]), "+f"(c[2]), "+f"(c[3])
        : "r"(a0), "r"(a1), "r"(a2), "r"(a3), "r"(b0), "r"(b1));
}

// ---------------- CSR build ----------------
__global__ void k_hist(const int* __restrict__ ei) { int e = blockIdx.x * 256 + threadIdx.x; if (e < N_EDGES) atomicAdd(&g_wp[ei[N_EDGES + e]], 1); }
__global__ void k_scan() {
    __shared__ int part[1024];
    int t = threadIdx.x; const int C = 49; int base = t * C; int sum = 0;
    for (int i = 0; i < C; i++) { int idx = base + i; if (idx < N_NODES) sum += g_wp[idx]; }
    part[t] = sum; __syncthreads();
    for (int off = 1; off < 1024; off <<= 1) { int v = (t >= off) ? part[t - off] : 0; __syncthreads(); part[t] += v; __syncthreads(); }
    int run = (t == 0) ? 0 : part[t - 1];
    for (int i = 0; i < C; i++) { int idx = base + i; if (idx < N_NODES) { int v = g_wp[idx]; g_wp[idx] = run; run += v; } }
}
__global__ void k_scatter(const int* __restrict__ ei, const float* __restrict__ eattr) {
    int e = blockIdx.x * 256 + threadIdx.x;
    if (e < N_EDGES) {
        int d = ei[N_EDGES + e];
        int pos = atomicAdd(&g_wp[d], 1);
        const float* ea = eattr + (size_t)e * 5;
        float4 f0 = make_float4(__int_as_float(ei[e]), __int_as_float(d), __ldg(ea), __ldg(ea + 1));
        float4 f1 = make_float4(__ldg(ea + 2), __ldg(ea + 3), __ldg(ea + 4), 0.f);
        size_t p8 = (size_t)pos * 8;
        *(float4*)&g_em[p8] = f0; *(float4*)&g_em[p8 + 4] = f1;
    }
}

// ---------------- encoder ----------------
__global__ void __launch_bounds__(256) k_encoder(
    const float* __restrict__ x, const int* __restrict__ batch,
    const float* __restrict__ casep, const float* __restrict__ bcp,
    const float* __restrict__ W1, const float* __restrict__ b1,
    const float* __restrict__ W2, const float* __restrict__ b2,
    const float* __restrict__ gam, const float* __restrict__ bet)
{
    __shared__ float sW1[1024], sW2[4096], sb1[64], sb2[64], sg[64], sbe[64];
    __shared__ float sH[8][64];
    int tid = threadIdx.x;
    for (int i = tid; i < 1024; i += 256) sW1[i] = W1[i];
    for (int i = tid; i < 4096; i += 256) sW2[i] = W2[i];
    if (tid < 64) { sb1[tid] = b1[tid]; sb2[tid] = b2[tid]; sg[tid] = gam[tid]; sbe[tid] = bet[tid]; }
    __syncthreads();
    int w = tid >> 5, ld = tid & 31, c0 = 2 * ld;
    int n = blockIdx.x * 8 + w;
    if (n >= N_NODES) return;
    float in[16];
#pragma unroll
    for (int k = 0; k < 8; k++) in[k] = __ldg(&x[n * 8 + k]);
    int g = __ldg(&batch[n]);
#pragma unroll
    for (int k = 0; k < 4; k++) { in[8 + k] = __ldg(&casep[g * 4 + k]); in[12 + k] = __ldg(&bcp[g * 4 + k]); }
    const u64* W1u = (const u64*)sW1;
    u64 acc = ((const u64*)sb1)[ld];
#pragma unroll
    for (int k = 0; k < 16; k++) acc = ffma2(dup2(in[k]), W1u[k * 32 + ld], acc);
    float2 a = upk(acc); a.x = silu(a.x); a.y = silu(a.y);
    sH[w][c0] = a.x; sH[w][c0 + 1] = a.y;
    __syncwarp();
    const u64* W2u = (const u64*)sW2;
    u64 acc2 = ((const u64*)sb2)[ld];
#pragma unroll 8
    for (int k = 0; k < 64; k++) acc2 = ffma2(dup2(sH[w][k]), W2u[k * 32 + ld], acc2);
    float2 v = upk(acc2);
    float s = v.x + v.y, q = v.x * v.x + v.y * v.y;
#pragma unroll
    for (int o = 16; o; o >>= 1) { s += __shfl_xor_sync(~0u, s, o); q += __shfl_xor_sync(~0u, q, o); }
    float m = s * (1.f / 64.f), rs = rsqrtf(q * (1.f / 64.f) - m * m + EPS);
    float2 out;
    out.x = (v.x - m) * rs * sg[c0] + sbe[c0];
    out.y = (v.y - m) * rs * sg[c0 + 1] + sbe[c0 + 1];
    *(float2*)(g_h + (size_t)n * 64 + c0) = out;
}

// ---------------- node pre (layer 0 only) ----------------
__global__ void __launch_bounds__(256) k_node_pre(const float* __restrict__ eW1l)
{
    extern __shared__ float ps[];
    float* sWt = ps;
    float* sA  = ps + 8704;
    int tid = threadIdx.x;
    for (int i = tid; i < 64 * 128; i += 256) {
        int k = i >> 7, c = i & 127;
        float v = (c < 64) ? eW1l[k * 64 + c] : eW1l[(64 + k) * 64 + (c - 64)];
        sWt[k * 136 + c] = tf32f(v);
    }
    __syncthreads();
    int w = tid >> 5, ld = tid & 31, g8 = ld >> 2, q4 = ld & 3;
    const uint32_t* au = (const uint32_t*)sA;
    const uint32_t* bu = (const uint32_t*)sWt;
    for (int t = blockIdx.x; t < N_NODES / 16; t += gridDim.x) {
        int n0 = t * 16;
        __syncthreads();
        {
            int n = tid >> 4, c4 = (tid & 15) * 4;
            float4 v = *(const float4*)(g_h + (size_t)(n0 + n) * 64 + c4);
            uint4 tv; tv.x = tf32c(v.x); tv.y = tf32c(v.y); tv.z = tf32c(v.z); tv.w = tf32c(v.w);
            *(uint4*)&sA[n * 76 + c4] = tv;
        }
        {
            int n = tid >> 4, c = (tid & 15) * 4;
            *(float4*)(g_agg + (size_t)(n0 + n) * 64 + c) = make_float4(0.f, 0.f, 0.f, 0.f);
        }
        __syncthreads();
        float acc[2][4];
#pragma unroll
        for (int sbi = 0; sbi < 2; sbi++)
#pragma unroll
            for (int j = 0; j < 4; j++) acc[sbi][j] = 0.f;
#pragma unroll
        for (int kb = 0; kb < 8; kb++) {
            int kc = kb * 8 + q4;
            uint32_t a0 = au[g8 * 76 + kc], a1 = au[(g8 + 8) * 76 + kc];
            uint32_t a2 = au[g8 * 76 + kc + 4], a3 = au[(g8 + 8) * 76 + kc + 4];
#pragma unroll
            for (int sbi = 0; sbi < 2; sbi++) {
                int nb = 2 * w + sbi;
                uint32_t b0 = bu[kc * 136 + nb * 8 + g8];
                uint32_t b1 = bu[(kc + 4) * 136 + nb * 8 + g8];
                mma8(acc[sbi], a0, a1, a2, a3, b0, b1);
            }
        }
#pragma unroll
        for (int sbi = 0; sbi < 2; sbi++) {
            int c = (2 * w + sbi) * 8 + 2 * q4;
            float* base = (c < 64) ? g_hd : g_hs;
            int cl = (c < 64) ? c : c - 64;
            *(float2*)(base + (size_t)(n0 + g8) * 64 + cl)     = make_float2(acc[sbi][0], acc[sbi][1]);
            *(float2*)(base + (size_t)(n0 + g8 + 8) * 64 + cl) = make_float2(acc[sbi][2], acc[sbi][3]);
        }
    }
}

// ---------------- edge kernel (R15 + earlier metadata prefetch) ----------------
__global__ void __launch_bounds__(256, 2) k_edge(
    const float* __restrict__ W1c, const float* __restrict__ b1,
    const float* __restrict__ W2, const float* __restrict__ b2,
    const float* __restrict__ gam, const float* __restrict__ bet)
{
    extern __shared__ float es[];
    float* sW2s = es;
    float* sW1c = es + 4608;
    float* sb1 = es + 4928; float* sb2 = es + 4992;
    float* sg = es + 5056;  float* sbe = es + 5120;
    float* sPer = es + 5184;
    int tid = threadIdx.x;
    for (int i = tid; i < 4096; i += 256) {
        int k = i >> 6, c = i & 63;
        sW2s[k * 72 + c] = tf32f(W2[i]);
    }
    for (int i = tid; i < 320; i += 256) sW1c[i] = W1c[i];
    if (tid < 64) { sb1[tid] = b1[tid]; sb2[tid] = b2[tid]; sg[tid] = gam[tid]; sbe[tid] = bet[tid]; }
    __syncthreads();
    int w = tid >> 5, ld = tid & 31;
    int pe = ld >> 1, half = ld & 1;
    int eb = ld >> 3, cb = ld & 7;
    int g8 = ld >> 2, q4 = ld & 3;
    float* sM = sPer + w * 2496;
    int* sD = (int*)(sM + 2432);
    int* sSrc = (int*)(sM + 2464);
    const ulonglong2* W1cu = (const ulonglong2*)sW1c;
    const ulonglong2* b1u = (const ulonglong2*)sb1;
    u64 gv[4], bev[4];
#pragma unroll
    for (int j = 0; j < 4; j++) { gv[j] = ((const u64*)sg)[cb * 4 + j]; bev[j] = ((const u64*)sbe)[cb * 4 + j]; }
    float b2s[8];
#pragma unroll
    for (int j = 0; j < 8; j++) b2s[j] = sb2[cb * 8 + j];
    int gw = (blockIdx.x * 256 + tid) >> 5;
    int nw = (gridDim.x * 256) >> 5;
    const int NT = N_EDGES / 32;
    float4 mf0[2], mf1[2];
    {
        int e0 = gw * 32;
#pragma unroll
        for (int sub = 0; sub < 2; sub++) {
            const float4* emp = (const float4*)&g_em[(size_t)(e0 + sub * 16 + pe) * 8];
            mf0[sub] = __ldg(emp); mf1[sub] = __ldg(emp + 1);
        }
#pragma unroll
        for (int sub = 0; sub < 2; sub++) {
            int ns = __float_as_int(mf0[sub].x), nd = __float_as_int(mf0[sub].y);
            pfL1(g_hs + (size_t)ns * 64 + half * 32);
            pfL1(g_hd + (size_t)nd * 64 + half * 32);
        }
    }
    for (int grp = gw; grp < NT; grp += nw) {
        __syncwarp();   // WAR: previous tile's sM/sD reads done
        int didx[2];
        u64 ead[2][5];
#pragma unroll
        for (int sub = 0; sub < 2; sub++) {
            int slot = sub * 16 + pe;
            float4 f0 = mf0[sub], f1 = mf1[sub];
            didx[sub] = __float_as_int(f0.y);
            ead[sub][0] = dup2(f0.z); ead[sub][1] = dup2(f0.w);
            ead[sub][2] = dup2(f1.x); ead[sub][3] = dup2(f1.y); ead[sub][4] = dup2(f1.z);
            if (half == 0) { sD[slot] = didx[sub]; sSrc[slot] = __float_as_int(f0.x); }
        }
        // metadata for next tile: issue NOW (consumed after the mma loop; ~1.5k cyc of cover)
        int ng = grp + nw;
        if (ng < NT) {
            int e0n = ng * 32;
#pragma unroll
            for (int sub = 0; sub < 2; sub++) {
                const float4* emp = (const float4*)&g_em[(size_t)(e0n + sub * 16 + pe) * 8];
                mf0[sub] = __ldg(emp); mf1[sub] = __ldg(emp + 1);
            }
        }
        __syncwarp();
#pragma unroll
        for (int r = 0; r < 16; r++) {
            int chunk = r * 32 + ld, eslot = chunk >> 4, c4 = (chunk & 15) * 4;
            *(float4*)&sM[eslot * 68 + c4] = *(const float4*)(g_hs + (size_t)sSrc[eslot] * 64 + c4);
        }
        __syncwarp();
        // ---- phase 1: subs interleaved, batched-rcp silu ----
        {
            const ulonglong2* hdp0 = (const ulonglong2*)(g_hd + (size_t)didx[0] * 64 + half * 32);
            const ulonglong2* hdp1 = (const ulonglong2*)(g_hd + (size_t)didx[1] * 64 + half * 32);
            float* mrow0 = sM + pe * 68 + half * 32;
            float* mrow1 = sM + (16 + pe) * 68 + half * 32;
#pragma unroll
            for (int j = 0; j < 8; j++) {
                ulonglong2 bj = b1u[half * 8 + j];
                ulonglong2 hd0 = __ldg(hdp0 + j), hd1 = __ldg(hdp1 + j);
                ulonglong2 hs0 = ((const ulonglong2*)mrow0)[j];
                ulonglong2 hs1 = ((const ulonglong2*)mrow1)[j];
                u64 A0 = add2(add2(hd0.x, hs0.x), bj.x);
                u64 A1 = add2(add2(hd0.y, hs0.y), bj.y);
                u64 B0 = add2(add2(hd1.x, hs1.x), bj.x);
                u64 B1 = add2(add2(hd1.y, hs1.y), bj.y);
#pragma unroll
                for (int r = 0; r < 5; r++) {
                    ulonglong2 wv = W1cu[r * 16 + half * 8 + j];
                    A0 = ffma2(ead[0][r], wv.x, A0); A1 = ffma2(ead[0][r], wv.y, A1);
                    B0 = ffma2(ead[1][r], wv.x, B0); B1 = ffma2(ead[1][r], wv.y, B1);
                }
                float va[4], vb[4];
                { float2 t0 = upk(A0), t1 = upk(A1); va[0] = t0.x; va[1] = t0.y; va[2] = t1.x; va[3] = t1.y; }
                { float2 t0 = upk(B0), t1 = upk(B1); vb[0] = t0.x; vb[1] = t0.y; vb[2] = t1.x; vb[3] = t1.y; }
                silu4(va); silu4(vb);
                uint4 ta; ta.x = tf32c(va[0]); ta.y = tf32c(va[1]); ta.z = tf32c(va[2]); ta.w = tf32c(va[3]);
                uint4 tb; tb.x = tf32c(vb[0]); tb.y = tf32c(vb[1]); tb.z = tf32c(vb[2]); tb.w = tf32c(vb[3]);
                *(uint4*)(mrow0 + 4 * j) = ta;
                *(uint4*)(mrow1 + 4 * j) = tb;
            }
        }
        __syncwarp();
        float acc[2][8][4];
#pragma unroll
        for (int mb = 0; mb < 2; mb++)
#pragma unroll
            for (int nb = 0; nb < 8; nb++)
#pragma unroll
                for (int j = 0; j < 4; j++) acc[mb][nb][j] = 0.f;
#pragma unroll
        for (int kb = 0; kb < 8; kb++) {
            int kc = kb * 8 + q4;
            const uint32_t* mu = (const uint32_t*)sM;
            uint32_t a00 = mu[(g8) * 68 + kc],      a01 = mu[(g8 + 8) * 68 + kc];
            uint32_t a02 = mu[(g8) * 68 + kc + 4],  a03 = mu[(g8 + 8) * 68 + kc + 4];
            uint32_t a10 = mu[(g8 + 16) * 68 + kc],     a11 = mu[(g8 + 24) * 68 + kc];
            uint32_t a12 = mu[(g8 + 16) * 68 + kc + 4], a13 = mu[(g8 + 24) * 68 + kc + 4];
            const uint32_t* wu = (const uint32_t*)sW2s;
#pragma unroll
            for (int nb = 0; nb < 8; nb++) {
                uint32_t b0 = wu[kc * 72 + nb * 8 + g8];
                uint32_t b1_ = wu[(kc + 4) * 72 + nb * 8 + g8];
                mma8(acc[0][nb], a00, a01, a02, a03, b0, b1_);
                mma8(acc[1][nb], a10, a11, a12, a13, b0, b1_);
            }
        }
        if (ng < NT) {
#pragma unroll
            for (int sub = 0; sub < 2; sub++) {
                int ns = __float_as_int(mf0[sub].x), nd = __float_as_int(mf0[sub].y);
                pfL1(g_hs + (size_t)ns * 64 + half * 32);
                pfL1(g_hd + (size_t)nd * 64 + half * 32);
            }
        }
        __syncwarp();
#pragma unroll
        for (int mb = 0; mb < 2; mb++)
#pragma unroll
            for (int nb = 0; nb < 8; nb++) {
                int elo = mb * 16 + g8;
                *(float2*)&sM[elo * 76 + nb * 8 + 2 * q4] = make_float2(acc[mb][nb][0], acc[mb][nb][1]);
                *(float2*)&sM[(elo + 8) * 76 + nb * 8 + 2 * q4] = make_float2(acc[mb][nb][2], acc[mb][nb][3]);
            }
        __syncwarp();
        float4 f0a[8], f1a[8];
        float s[8], q[8];
#pragma unroll
        for (int i = 0; i < 8; i++) {
            int e = eb * 8 + i;
            float4 v0 = *(const float4*)&sM[e * 76 + cb * 8];
            float4 v1 = *(const float4*)&sM[e * 76 + cb * 8 + 4];
            v0.x += b2s[0]; v0.y += b2s[1]; v0.z += b2s[2]; v0.w += b2s[3];
            v1.x += b2s[4]; v1.y += b2s[5]; v1.z += b2s[6]; v1.w += b2s[7];
            f0a[i] = v0; f1a[i] = v1;
            s[i] = v0.x + v0.y + v0.z + v0.w + v1.x + v1.y + v1.z + v1.w;
            q[i] = v0.x * v0.x + v0.y * v0.y + v0.z * v0.z + v0.w * v0.w
                 + v1.x * v1.x + v1.y * v1.y + v1.z * v1.z + v1.w * v1.w;
        }
#pragma unroll
        for (int o = 4; o; o >>= 1) {
#pragma unroll
            for (int i = 0; i < 8; i++) { s[i] += __shfl_xor_sync(~0u, s[i], o); q[i] += __shfl_xor_sync(~0u, q[i], o); }
        }
        int curD = sD[eb * 8];
        u64 av[4] = {0ull, 0ull, 0ull, 0ull};
#pragma unroll
        for (int i = 0; i < 8; i++) {
            int dI = sD[eb * 8 + i];
            float mn = s[i] * (1.f / 64.f);
            float rs = rsqrtf(q[i] * (1.f / 64.f) - mn * mn + EPS);
            u64 rsd = dup2(rs), mrd = dup2(-mn * rs);
            if (dI != curD) {
                float2 a0 = upk(av[0]), a1 = upk(av[1]), a2 = upk(av[2]), a3 = upk(av[3]);
                float* base = g_agg + (size_t)curD * 64 + cb * 8;
                red4(base, make_float4(a0.x, a0.y, a1.x, a1.y));
                red4(base + 4, make_float4(a2.x, a2.y, a3.x, a3.y));
                av[0] = av[1] = av[2] = av[3] = 0ull;
                curD = dI;
            }
            u64 vv0 = pk2(f0a[i].x, f0a[i].y), vv1 = pk2(f0a[i].z, f0a[i].w);
            u64 vv2 = pk2(f1a[i].x, f1a[i].y), vv3 = pk2(f1a[i].z, f1a[i].w);
            av[0] = add2(av[0], ffma2(ffma2(vv0, rsd, mrd), gv[0], bev[0]));
            av[1] = add2(av[1], ffma2(ffma2(vv1, rsd, mrd), gv[1], bev[1]));
            av[2] = add2(av[2], ffma2(ffma2(vv2, rsd, mrd), gv[2], bev[2]));
            av[3] = add2(av[3], ffma2(ffma2(vv3, rsd, mrd), gv[3], bev[3]));
        }
        {
            float2 a0 = upk(av[0]), a1 = upk(av[1]), a2 = upk(av[2]), a3 = upk(av[3]);
            float* base = g_agg + (size_t)curD * 64 + cb * 8;
            red4(base, make_float4(a0.x, a0.y, a1.x, a1.y));
            red4(base + 4, make_float4(a2.x, a2.y, a3.x, a3.y));
        }
    }
}

// ---------------- node update (FUSED with next-layer pre) ----------------
__global__ void __launch_bounds__(256) k_node_upd(
    const float* __restrict__ W1, const float* __restrict__ b1,
    const float* __restrict__ W2, const float* __restrict__ b2,
    const float* __restrict__ gam, const float* __restrict__ bet,
    const float* __restrict__ eW1n)
{
    extern __shared__ float us[];
    float* sW1t = us;
    float* sW2t = us + 9216;
    float* sA   = us + 13824;
    float* sH   = us + 16064;
    float* sMid = us + 17152;
    float* sPart= us + 18368;
    float* sb1  = us + 18624;
    float* sb2  = us + 18688;
    float* sgm  = us + 18752;
    float* sbe  = us + 18816;
    float* sWp  = us + 18880;
    int tid = threadIdx.x;
    bool hn = (eW1n != nullptr);
    for (int i = tid; i < 128 * 64; i += 256) { int k = i >> 6, c = i & 63; sW1t[k * 72 + c] = tf32f(W1[i]); }
    for (int i = tid; i < 64 * 64; i += 256)  { int k = i >> 6, c = i & 63; sW2t[k * 72 + c] = tf32f(W2[i]); }
    if (hn)
        for (int i = tid; i < 64 * 128; i += 256) {
            int k = i >> 7, c = i & 127;
            float v = (c < 64) ? eW1n[k * 64 + c] : eW1n[(64 + k) * 64 + (c - 64)];
            sWp[k * 136 + c] = tf32f(v);
        }
    if (tid < 64) { sb1[tid] = b1[tid]; sb2[tid] = b2[tid]; sgm[tid] = gam[tid]; sbe[tid] = bet[tid]; }
    __syncthreads();
    int w = tid >> 5, ld = tid & 31, g8 = ld >> 2, q4 = ld & 3;
    const uint32_t* au = (const uint32_t*)sA;
    const uint32_t* b1w = (const uint32_t*)sW1t;
    const uint32_t* b2w = (const uint32_t*)sW2t;
    const uint32_t* mu = (const uint32_t*)sMid;
    const uint32_t* bpu = (const uint32_t*)sWp;
    int c0 = w * 8 + 2 * q4;
    float b1c0 = sb1[c0], b1c1 = sb1[c0 + 1];
    float b2c0 = sb2[c0], b2c1 = sb2[c0 + 1];
    float gm0 = sgm[c0], gm1 = sgm[c0 + 1];
    float be0 = sbe[c0], be1 = sbe[c0 + 1];
    for (int t = blockIdx.x; t < N_NODES / 16; t += gridDim.x) {
        int n0 = t * 16;
        __syncthreads();
        {
            int n = tid >> 4, c8 = (tid & 15) * 8;
            float4 v0, v1;
            if (c8 < 64) {
                v0 = *(const float4*)(g_h + (size_t)(n0 + n) * 64 + c8);
                v1 = *(const float4*)(g_h + (size_t)(n0 + n) * 64 + c8 + 4);
                *(float4*)&sH[n * 68 + c8] = v0;
                *(float4*)&sH[n * 68 + c8 + 4] = v1;
            } else {
                v0 = *(const float4*)(g_agg + (size_t)(n0 + n) * 64 + c8 - 64);
                v1 = *(const float4*)(g_agg + (size_t)(n0 + n) * 64 + c8 - 60);
            }
            uint4 t0; t0.x = tf32c(v0.x); t0.y = tf32c(v0.y); t0.z = tf32c(v0.z); t0.w = tf32c(v0.w);
            uint4 t1; t1.x = tf32c(v1.x); t1.y = tf32c(v1.y); t1.z = tf32c(v1.z); t1.w = tf32c(v1.w);
            *(uint4*)&sA[n * 140 + c8] = t0;
            *(uint4*)&sA[n * 140 + c8 + 4] = t1;
        }
        __syncthreads();
        float a1c[4] = {0.f, 0.f, 0.f, 0.f};
#pragma unroll
        for (int kb = 0; kb < 16; kb++) {
            int kc = kb * 8 + q4;
            uint32_t a0 = au[g8 * 140 + kc], a1 = au[(g8 + 8) * 140 + kc];
            uint32_t a2 = au[g8 * 140 + kc + 4], a3 = au[(g8 + 8) * 140 + kc + 4];
            uint32_t b0 = b1w[kc * 72 + w * 8 + g8];
            uint32_t b1_ = b1w[(kc + 4) * 72 + w * 8 + g8];
            mma8(a1c, a0, a1, a2, a3, b0, b1_);
        }
        {
            float vv[4];
            vv[0] = a1c[0] + b1c0; vv[1] = a1c[1] + b1c1;
            vv[2] = a1c[2] + b1c0; vv[3] = a1c[3] + b1c1;
            silu4(vv);
            sMid[g8 * 76 + c0]           = tf32f(vv[0]);
            sMid[g8 * 76 + c0 + 1]       = tf32f(vv[1]);
            sMid[(g8 + 8) * 76 + c0]     = tf32f(vv[2]);
            sMid[(g8 + 8) * 76 + c0 + 1] = tf32f(vv[3]);
        }
        __syncthreads();
        float a2c[4] = {0.f, 0.f, 0.f, 0.f};
#pragma unroll
        for (int kb = 0; kb < 8; kb++) {
            int kc = kb * 8 + q4;
            uint32_t a0 = mu[g8 * 76 + kc], a1 = mu[(g8 + 8) * 76 + kc];
            uint32_t a2 = mu[g8 * 76 + kc + 4], a3 = mu[(g8 + 8) * 76 + kc + 4];
            uint32_t b0 = b2w[kc * 72 + w * 8 + g8];
            uint32_t b1_ = b2w[(kc + 4) * 72 + w * 8 + g8];
            mma8(a2c, a0, a1, a2, a3, b0, b1_);
        }
        float v0 = a2c[0] + b2c0, v1 = a2c[1] + b2c1;
        float v2 = a2c[2] + b2c0, v3 = a2c[3] + b2c1;
        float s0 = v0 + v1, q0 = v0 * v0 + v1 * v1;
        float s1 = v2 + v3, q1 = v2 * v2 + v3 * v3;
#pragma unroll
        for (int o = 1; o <= 2; o <<= 1) {
            s0 += __shfl_xor_sync(~0u, s0, o); q0 += __shfl_xor_sync(~0u, q0, o);
            s1 += __shfl_xor_sync(~0u, s1, o); q1 += __shfl_xor_sync(~0u, q1, o);
        }
        if (q4 == 0) {
            sPart[w * 32 + g8 * 2] = s0;       sPart[w * 32 + g8 * 2 + 1] = q0;
            sPart[w * 32 + (g8 + 8) * 2] = s1; sPart[w * 32 + (g8 + 8) * 2 + 1] = q1;
        }
        __syncthreads();
        float S0 = 0.f, Q0 = 0.f, S1 = 0.f, Q1 = 0.f;
#pragma unroll
        for (int ww = 0; ww < 8; ww++) {
            S0 += sPart[ww * 32 + g8 * 2];       Q0 += sPart[ww * 32 + g8 * 2 + 1];
            S1 += sPart[ww * 32 + (g8 + 8) * 2]; Q1 += sPart[ww * 32 + (g8 + 8) * 2 + 1];
        }
        float mn0 = S0 * (1.f / 64.f), rs0 = rsqrtf(Q0 * (1.f / 64.f) - mn0 * mn0 + EPS);
        float mn1 = S1 * (1.f / 64.f), rs1 = rsqrtf(Q1 * (1.f / 64.f) - mn1 * mn1 + EPS);
        float2 o0, o1;
        o0.x = sH[g8 * 68 + c0]     + (v0 - mn0) * rs0 * gm0 + be0;
        o0.y = sH[g8 * 68 + c0 + 1] + (v1 - mn0) * rs0 * gm1 + be1;
        o1.x = sH[(g8 + 8) * 68 + c0]     + (v2 - mn1) * rs1 * gm0 + be0;
        o1.y = sH[(g8 + 8) * 68 + c0 + 1] + (v3 - mn1) * rs1 * gm1 + be1;
        *(float2*)(g_h + (size_t)(n0 + g8) * 64 + c0)     = o0;
        *(float2*)(g_h + (size_t)(n0 + g8 + 8) * 64 + c0) = o1;
        if (hn) {
            sMid[g8 * 76 + c0]       = tf32f(o0.x);
            sMid[g8 * 76 + c0 + 1]   = tf32f(o0.y);
            sMid[(g8 + 8) * 76 + c0]     = tf32f(o1.x);
            sMid[(g8 + 8) * 76 + c0 + 1] = tf32f(o1.y);
            {
                int n = tid >> 4, c = (tid & 15) * 4;
                *(float4*)(g_agg + (size_t)(n0 + n) * 64 + c) = make_float4(0.f, 0.f, 0.f, 0.f);
            }
            __syncthreads();
            float accp[2][4];
#pragma unroll
            for (int sbi = 0; sbi < 2; sbi++)
#pragma unroll
                for (int j = 0; j < 4; j++) accp[sbi][j] = 0.f;
#pragma unroll
            for (int kb = 0; kb < 8; kb++) {
                int kc = kb * 8 + q4;
                uint32_t a0 = mu[g8 * 76 + kc], a1 = mu[(g8 + 8) * 76 + kc];
                uint32_t a2 = mu[g8 * 76 + kc + 4], a3 = mu[(g8 + 8) * 76 + kc + 4];
#pragma unroll
                for (int sbi = 0; sbi < 2; sbi++) {
                    int nb = 2 * w + sbi;
                    uint32_t b0 = bpu[kc * 136 + nb * 8 + g8];
                    uint32_t b1_ = bpu[(kc + 4) * 136 + nb * 8 + g8];
                    mma8(accp[sbi], a0, a1, a2, a3, b0, b1_);
                }
            }
#pragma unroll
            for (int sbi = 0; sbi < 2; sbi++) {
                int c = (2 * w + sbi) * 8 + 2 * q4;
                float* base = (c < 64) ? g_hd : g_hs;
                int cl = (c < 64) ? c : c - 64;
                *(float2*)(base + (size_t)(n0 + g8) * 64 + cl)     = make_float2(accp[sbi][0], accp[sbi][1]);
                *(float2*)(base + (size_t)(n0 + g8 + 8) * 64 + cl) = make_float2(accp[sbi][2], accp[sbi][3]);
            }
        }
    }
}

__global__ void k_zero_pool() { int t = threadIdx.x; if (t < NG * 64) g_pool[t] = 0.f; }

// ---------------- local decoder + pooling ----------------
__global__ void __launch_bounds__(256) k_decoder_local(
    const float* __restrict__ W1, const float* __restrict__ b1,
    const float* __restrict__ W2, const float* __restrict__ b2,
    const int* __restrict__ batch, float* __restrict__ out)
{
    __shared__ float sW1[4096], sW2[384], sb1[64], sb2_[8];
    __shared__ float sH[8][64], sU[8][64];
    int tid = threadIdx.x;
    for (int i = tid; i < 4096; i += 256) sW1[i] = W1[i];
    for (int i = tid; i < 384; i += 256) sW2[i] = W2[i];
    if (tid < 64) sb1[tid] = b1[tid];
    if (tid < 6) sb2_[tid] = b2[tid];
    __syncthreads();
    int w = tid >> 5, ld = tid & 31, c0 = 2 * ld;
    int n = blockIdx.x * 8 + w;
    if (n >= N_NODES) return;
    float2 hv = *(const float2*)(g_h + (size_t)n * 64 + c0);
    sH[w][c0] = hv.x; sH[w][c0 + 1] = hv.y;
    __syncwarp();
    const u64* W1u = (const u64*)sW1;
    u64 acc = ((const u64*)sb1)[ld];
#pragma unroll 8
    for (int k = 0; k < 64; k++) acc = ffma2(dup2(sH[w][k]), W1u[k * 32 + ld], acc);
    float2 u = upk(acc); u.x = silu(u.x); u.y = silu(u.y);
    sU[w][c0] = u.x; sU[w][c0 + 1] = u.y;
    __syncwarp();
    if (ld < 6) {
        float o = sb2_[ld];
#pragma unroll
        for (int k = 0; k < 64; k++) o += sU[w][k] * sW2[k * 6 + ld];
        out[(size_t)n * 6 + ld] = o;
    }
    int g = __ldg(&batch[n]);
    red2(g_pool + g * 64 + c0, hv.x, hv.y);
}

// ---------------- global decoder ----------------
__global__ void k_global(const int* __restrict__ batch,
    const float* __restrict__ W1, const float* __restrict__ b1,
    const float* __restrict__ W2, const float* __restrict__ b2,
    float* __restrict__ out)
{
    __shared__ float sp[NG * 64], su[NG * 32];
    __shared__ int bnd[NG + 1];
    int t = threadIdx.x;
    if (t <= NG) {
        int lo = 0, hi = N_NODES;
        while (lo < hi) { int mid = (lo + hi) >> 1; if (batch[mid] < t) lo = mid + 1; else hi = mid; }
        bnd[t] = lo;
    }
    __syncthreads();
    for (int i = t; i < NG * 64; i += 128) {
        int g = i >> 6;
        sp[i] = g_pool[i] / fmaxf((float)(bnd[g + 1] - bnd[g]), 1.f);
    }
    __syncthreads();
    {
        int g = t >> 5, j = t & 31;
        float a = b1[j];
#pragma unroll
        for (int k = 0; k < 64; k++) a += sp[g * 64 + k] * W1[k * 32 + j];
        su[g * 32 + j] = silu(a);
    }
    __syncthreads();
    if (t < NG * 4) {
        int g = t >> 2, j = t & 3;
        float o = b2[j];
#pragma unroll
        for (int k = 0; k < 32; k++) o += su[g * 32 + k] * W2[k * 4 + j];
        out[(size_t)N_NODES * 6 + g * 4 + j] = o;
    }
}

extern "C" void kernel_launch(void* const* d_in, const int* in_sizes, int n_in,
                              void* d_out, int out_size) {
    (void)in_sizes; (void)n_in; (void)out_size;
    const float* x     = (const float*)d_in[0];
    const int*   ei    = (const int*)d_in[1];
    const float* eattr = (const float*)d_in[2];
    const int*   batch = (const int*)d_in[3];
    const float* casep = (const float*)d_in[4];
    const float* bcp   = (const float*)d_in[5];
    const float* encW1 = (const float*)d_in[6];  const float* encb1 = (const float*)d_in[7];
    const float* encW2 = (const float*)d_in[8];  const float* encb2 = (const float*)d_in[9];
    const float* encg  = (const float*)d_in[10]; const float* encbe = (const float*)d_in[11];
    const float* eW1   = (const float*)d_in[12]; const float* eb1   = (const float*)d_in[13];
    const float* eW2   = (const float*)d_in[14]; const float* eb2   = (const float*)d_in[15];
    const float* eg    = (const float*)d_in[16]; const float* ebe   = (const float*)d_in[17];
    const float* nW1   = (const float*)d_in[18]; const float* nb1   = (const float*)d_in[19];
    const float* nW2   = (const float*)d_in[20]; const float* nb2   = (const float*)d_in[21];
    const float* ngm   = (const float*)d_in[22]; const float* nbe   = (const float*)d_in[23];
    const float* dlW1  = (const float*)d_in[24]; const float* dlb1  = (const float*)d_in[25];
    const float* dlW2  = (const float*)d_in[26]; const float* dlb2  = (const float*)d_in[27];
    const float* dgW1  = (const float*)d_in[28]; const float* dgb1  = (const float*)d_in[29];
    const float* dgW2  = (const float*)d_in[30]; const float* dgb2  = (const float*)d_in[31];
    float* out = (float*)d_out;

    size_t preSmem  = (size_t)9920 * sizeof(float);
    size_t edgeSmem = (size_t)(5184 + 8 * 2496) * sizeof(float);
    size_t updSmem  = (size_t)27584 * sizeof(float);
    cudaFuncSetAttribute(k_node_pre, cudaFuncAttributeMaxDynamicSharedMemorySize, (int)preSmem);
    cudaFuncSetAttribute(k_edge, cudaFuncAttributeMaxDynamicSharedMemorySize, (int)edgeSmem);
    cudaFuncSetAttribute(k_node_upd, cudaFuncAttributeMaxDynamicSharedMemorySize, (int)updSmem);

    void* wp_ptr = nullptr;
    cudaGetSymbolAddress(&wp_ptr, g_wp);
    cudaMemsetAsync(wp_ptr, 0, N_NODES * sizeof(int));
    k_hist<<<(N_EDGES + 255) / 256, 256>>>(ei);
    k_scan<<<1, 1024>>>();
    k_scatter<<<(N_EDGES + 255) / 256, 256>>>(ei, eattr);

    k_encoder<<<(N_NODES + 7) / 8, 256>>>(x, batch, casep, bcp, encW1, encb1, encW2, encb2, encg, encbe);
    k_node_pre<<<296, 256, preSmem>>>(eW1);
    for (int l = 0; l < NL; l++) {
        const float* eW1l = eW1 + (size_t)l * 133 * 64;
        const float* eW1n = (l + 1 < NL) ? (eW1 + (size_t)(l + 1) * 133 * 64) : nullptr;
        k_edge<<<296, 256, edgeSmem>>>(eW1l + 128 * 64, eb1 + l * 64,
                              eW2 + (size_t)l * 4096, eb2 + l * 64,
                              eg + l * 64, ebe + l * 64);
        k_node_upd<<<296, 256, updSmem>>>(nW1 + (size_t)l * 8192, nb1 + l * 64,
                                          nW2 + (size_t)l * 4096, nb2 + l * 64,
                                          ngm + l * 64, nbe + l * 64, eW1n);
    }
    k_zero_pool<<<1, 256>>>();
    k_decoder_local<<<(N_NODES + 7) / 8, 256>>>(dlW1, dlb1, dlW2, dlb2, batch, out);
    k_global<<<1, 128>>>(batch, dgW1, dgb1, dgW2, dgb2, out);
}

// round 17
// speedup vs baseline: 2.2157x; 1.0139x over previous
#include <cuda_runtime.h>
#include <cstdint>
#define DINL __device__ __forceinline__
constexpr int N_NODES = 50000;
constexpr int N_EDGES = 1600000;
constexpr int NL = 5;
constexpr int NG = 4;
constexpr float EPS = 1e-5f;

__device__ float g_h  [N_NODES * 64];
__device__ float g_hd [N_NODES * 64];
__device__ float g_hs [N_NODES * 64];
__device__ float g_agg[N_NODES * 64];
__device__ float g_pool[NG * 64];
__device__ int   g_wp [N_NODES];
__device__ float g_em [(size_t)N_EDGES * 8];

typedef unsigned long long u64;
DINL u64 pk2(float x, float y) { u64 r; asm("mov.b64 %0,{%1,%2};" : "=l"(r) : "f"(x), "f"(y)); return r; }
DINL u64 dup2(float x) { return pk2(x, x); }
DINL float2 upk(u64 v) { float2 r; asm("mov.b64 {%0,%1},%2;" : "=f"(r.x), "=f"(r.y) : "l"(v)); return r; }
DINL u64 ffma2(u64 a, u64 b, u64 c) { u64 d; asm("fma.rn.f32x2 %0,%1,%2,%3;" : "=l"(d) : "l"(a), "l"(b), "l"(c)); return d; }
DINL u64 add2(u64 a, u64 b) { u64 d; asm("add.rn.f32x2 %0,%1,%2;" : "=l"(d) : "l"(a), "l"(b)); return d; }
DINL void red2(float* p, float x, float y) { asm volatile("red.global.add.v2.f32 [%0], {%1,%2};" :: "l"(p), "f"(x), "f"(y) : "memory"); }
DINL void red4(float* p, float4 v) { asm volatile("red.global.add.v4.f32 [%0], {%1,%2,%3,%4};" :: "l"(p), "f"(v.x), "f"(v.y), "f"(v.z), "f"(v.w) : "memory"); }
DINL float silu(float x) { return __fdividef(x, 1.f + __expf(-x)); }
DINL uint32_t tf32c(float f) { uint32_t r; asm("cvt.rna.tf32.f32 %0,%1;" : "=r"(r) : "f"(f)); return r; }
DINL float tf32f(float f) { return __uint_as_float(tf32c(f)); }
DINL void pfL1(const float* p) { asm volatile("prefetch.global.L1 [%0];" :: "l"(p)); }
DINL float rcpa(float x) { float r; asm("rcp.approx.ftz.f32 %0,%1;" : "=f"(r) : "f"(x)); return r; }
DINL void silu4(float* v) {
    float e0 = __expf(fminf(-v[0], 20.f));
    float e1 = __expf(fminf(-v[1], 20.f));
    float e2 = __expf(fminf(-v[2], 20.f));
    float e3 = __expf(fminf(-v[3], 20.f));
    float d0 = 1.f + e0, d1 = 1.f + e1, d2 = 1.f + e2, d3 = 1.f + e3;
    float pa = d0 * d1, pb = d2 * d3;
    float r = rcpa(pa * pb);
    float rab = r * pb, rcd = r * pa;
    v[0] *= rab * d1; v[1] *= rab * d0;
    v[2] *= rcd * d3; v[3] *= rcd * d2;
}
DINL void mma8(float* c, uint32_t a0, uint32_t a1, uint32_t a2, uint32_t a3, uint32_t b0, uint32_t b1) {
    asm volatile("mma.sync.aligned.m16n8k8.row.col.f32.tf32.tf32.f32 {%0,%1,%2,%3},{%4,%5,%6,%7},{%8,%9},{%0,%1,%2,%3};"
        : "+f"(c[0]), "+f"(c[1]), "+f"(c[2]), "+f"(c[3])
        : "r"(a0), "r"(a1), "r"(a2), "r"(a3), "r"(b0), "r"(b1));
}

// ---------------- CSR build ----------------
__global__ void k_hist(const int* __restrict__ ei) { int e = blockIdx.x * 256 + threadIdx.x; if (e < N_EDGES) atomicAdd(&g_wp[ei[N_EDGES + e]], 1); }
__global__ void k_scan() {
    __shared__ int part[1024];
    int t = threadIdx.x; const int C = 49; int base = t * C; int sum = 0;
    for (int i = 0; i < C; i++) { int idx = base + i; if (idx < N_NODES) sum += g_wp[idx]; }
    part[t] = sum; __syncthreads();
    for (int off = 1; off < 1024; off <<= 1) { int v = (t >= off) ? part[t - off] : 0; __syncthreads(); part[t] += v; __syncthreads(); }
    int run = (t == 0) ? 0 : part[t - 1];
    for (int i = 0; i < C; i++) { int idx = base + i; if (idx < N_NODES) { int v = g_wp[idx]; g_wp[idx] = run; run += v; } }
}
__global__ void k_scatter(const int* __restrict__ ei, const float* __restrict__ eattr) {
    int e = blockIdx.x * 256 + threadIdx.x;
    if (e < N_EDGES) {
        int d = ei[N_EDGES + e];
        int pos = atomicAdd(&g_wp[d], 1);
        const float* ea = eattr + (size_t)e * 5;
        float4 f0 = make_float4(__int_as_float(ei[e]), __int_as_float(d), __ldg(ea), __ldg(ea + 1));
        float4 f1 = make_float4(__ldg(ea + 2), __ldg(ea + 3), __ldg(ea + 4), 0.f);
        size_t p8 = (size_t)pos * 8;
        *(float4*)&g_em[p8] = f0; *(float4*)&g_em[p8 + 4] = f1;
    }
}

// ---------------- fused encoder + layer-0 pre: 16-node tiles, tf32 mma ----------------
// smem floats: sE1t[16][72]=1152 @0 | sE2t[64][72]=4608 @1152 | sWp[64][136]=8704 @5760
//   sIn[16][20]=320 @14464 | sMid[16][76]=1216 @14784 | sPart=256 @16000 | biases @16256..16512
__global__ void __launch_bounds__(256) k_enc_pre(
    const float* __restrict__ x, const int* __restrict__ batch,
    const float* __restrict__ casep, const float* __restrict__ bcp,
    const float* __restrict__ W1, const float* __restrict__ b1,
    const float* __restrict__ W2, const float* __restrict__ b2,
    const float* __restrict__ gam, const float* __restrict__ bet,
    const float* __restrict__ eW1l)
{
    extern __shared__ float us[];
    float* sE1t = us;
    float* sE2t = us + 1152;
    float* sWp  = us + 5760;
    float* sIn  = us + 14464;
    float* sMid = us + 14784;
    float* sPart= us + 16000;
    float* sb1  = us + 16256;
    float* sb2  = us + 16320;
    float* sgm  = us + 16384;
    float* sbe  = us + 16448;
    int tid = threadIdx.x;
    for (int i = tid; i < 16 * 64; i += 256) { int k = i >> 6, c = i & 63; sE1t[k * 72 + c] = tf32f(W1[i]); }
    for (int i = tid; i < 64 * 64; i += 256) { int k = i >> 6, c = i & 63; sE2t[k * 72 + c] = tf32f(W2[i]); }
    for (int i = tid; i < 64 * 128; i += 256) {
        int k = i >> 7, c = i & 127;
        float v = (c < 64) ? eW1l[k * 64 + c] : eW1l[(64 + k) * 64 + (c - 64)];
        sWp[k * 136 + c] = tf32f(v);
    }
    if (tid < 64) { sb1[tid] = b1[tid]; sb2[tid] = b2[tid]; sgm[tid] = gam[tid]; sbe[tid] = bet[tid]; }
    __syncthreads();
    int w = tid >> 5, ld = tid & 31, g8 = ld >> 2, q4 = ld & 3;
    const uint32_t* e1u = (const uint32_t*)sE1t;
    const uint32_t* e2u = (const uint32_t*)sE2t;
    const uint32_t* inu = (const uint32_t*)sIn;
    const uint32_t* mu  = (const uint32_t*)sMid;
    const uint32_t* bpu = (const uint32_t*)sWp;
    int c0 = w * 8 + 2 * q4;
    float b1c0 = sb1[c0], b1c1 = sb1[c0 + 1];
    float b2c0 = sb2[c0], b2c1 = sb2[c0 + 1];
    float gm0 = sgm[c0], gm1 = sgm[c0 + 1];
    float be0 = sbe[c0], be1 = sbe[c0 + 1];
    for (int t = blockIdx.x; t < N_NODES / 16; t += gridDim.x) {
        int n0 = t * 16;
        __syncthreads();
        {
            int n = tid >> 4, c = tid & 15;
            int nn = n0 + n;
            float v;
            if (c < 8) v = __ldg(&x[nn * 8 + c]);
            else {
                int g = __ldg(&batch[nn]);
                v = (c < 12) ? __ldg(&casep[g * 4 + (c - 8)]) : __ldg(&bcp[g * 4 + (c - 12)]);
            }
            sIn[n * 20 + c] = tf32f(v);
        }
        {
            int n = tid >> 4, c = (tid & 15) * 4;
            *(float4*)(g_agg + (size_t)(n0 + n) * 64 + c) = make_float4(0.f, 0.f, 0.f, 0.f);
        }
        __syncthreads();
        // GEMM1: [16 x 16] @ [16 x 64]
        float a1c[4] = {0.f, 0.f, 0.f, 0.f};
#pragma unroll
        for (int kb = 0; kb < 2; kb++) {
            int kc = kb * 8 + q4;
            uint32_t a0 = inu[g8 * 20 + kc], a1 = inu[(g8 + 8) * 20 + kc];
            uint32_t a2 = inu[g8 * 20 + kc + 4], a3 = inu[(g8 + 8) * 20 + kc + 4];
            uint32_t b0 = e1u[kc * 72 + w * 8 + g8];
            uint32_t b1_ = e1u[(kc + 4) * 72 + w * 8 + g8];
            mma8(a1c, a0, a1, a2, a3, b0, b1_);
        }
        {
            float vv[4];
            vv[0] = a1c[0] + b1c0; vv[1] = a1c[1] + b1c1;
            vv[2] = a1c[2] + b1c0; vv[3] = a1c[3] + b1c1;
            silu4(vv);
            sMid[g8 * 76 + c0]           = tf32f(vv[0]);
            sMid[g8 * 76 + c0 + 1]       = tf32f(vv[1]);
            sMid[(g8 + 8) * 76 + c0]     = tf32f(vv[2]);
            sMid[(g8 + 8) * 76 + c0 + 1] = tf32f(vv[3]);
        }
        __syncthreads();
        // GEMM2: [16 x 64] @ [64 x 64] + LN (no residual)
        float a2c[4] = {0.f, 0.f, 0.f, 0.f};
#pragma unroll
        for (int kb = 0; kb < 8; kb++) {
            int kc = kb * 8 + q4;
            uint32_t a0 = mu[g8 * 76 + kc], a1 = mu[(g8 + 8) * 76 + kc];
            uint32_t a2 = mu[g8 * 76 + kc + 4], a3 = mu[(g8 + 8) * 76 + kc + 4];
            uint32_t b0 = e2u[kc * 72 + w * 8 + g8];
            uint32_t b1_ = e2u[(kc + 4) * 72 + w * 8 + g8];
            mma8(a2c, a0, a1, a2, a3, b0, b1_);
        }
        float v0 = a2c[0] + b2c0, v1 = a2c[1] + b2c1;
        float v2 = a2c[2] + b2c0, v3 = a2c[3] + b2c1;
        float s0 = v0 + v1, q0 = v0 * v0 + v1 * v1;
        float s1 = v2 + v3, q1 = v2 * v2 + v3 * v3;
#pragma unroll
        for (int o = 1; o <= 2; o <<= 1) {
            s0 += __shfl_xor_sync(~0u, s0, o); q0 += __shfl_xor_sync(~0u, q0, o);
            s1 += __shfl_xor_sync(~0u, s1, o); q1 += __shfl_xor_sync(~0u, q1, o);
        }
        if (q4 == 0) {
            sPart[w * 32 + g8 * 2] = s0;       sPart[w * 32 + g8 * 2 + 1] = q0;
            sPart[w * 32 + (g8 + 8) * 2] = s1; sPart[w * 32 + (g8 + 8) * 2 + 1] = q1;
        }
        __syncthreads();
        float S0 = 0.f, Q0 = 0.f, S1 = 0.f, Q1 = 0.f;
#pragma unroll
        for (int ww = 0; ww < 8; ww++) {
            S0 += sPart[ww * 32 + g8 * 2];       Q0 += sPart[ww * 32 + g8 * 2 + 1];
            S1 += sPart[ww * 32 + (g8 + 8) * 2]; Q1 += sPart[ww * 32 + (g8 + 8) * 2 + 1];
        }
        float mn0 = S0 * (1.f / 64.f), rs0 = rsqrtf(Q0 * (1.f / 64.f) - mn0 * mn0 + EPS);
        float mn1 = S1 * (1.f / 64.f), rs1 = rsqrtf(Q1 * (1.f / 64.f) - mn1 * mn1 + EPS);
        float2 o0, o1;
        o0.x = (v0 - mn0) * rs0 * gm0 + be0;
        o0.y = (v1 - mn0) * rs0 * gm1 + be1;
        o1.x = (v2 - mn1) * rs1 * gm0 + be0;
        o1.y = (v3 - mn1) * rs1 * gm1 + be1;
        *(float2*)(g_h + (size_t)(n0 + g8) * 64 + c0)     = o0;
        *(float2*)(g_h + (size_t)(n0 + g8 + 8) * 64 + c0) = o1;
        // stage tf32(h) for pre-GEMM (all GEMM2 reads of sMid completed at the sPart barrier)
        sMid[g8 * 76 + c0]           = tf32f(o0.x);
        sMid[g8 * 76 + c0 + 1]       = tf32f(o0.y);
        sMid[(g8 + 8) * 76 + c0]     = tf32f(o1.x);
        sMid[(g8 + 8) * 76 + c0 + 1] = tf32f(o1.y);
        __syncthreads();
        // pre GEMM: hd|hs = h @ eW1l[0:128]
        float accp[2][4];
#pragma unroll
        for (int sbi = 0; sbi < 2; sbi++)
#pragma unroll
            for (int j = 0; j < 4; j++) accp[sbi][j] = 0.f;
#pragma unroll
        for (int kb = 0; kb < 8; kb++) {
            int kc = kb * 8 + q4;
            uint32_t a0 = mu[g8 * 76 + kc], a1 = mu[(g8 + 8) * 76 + kc];
            uint32_t a2 = mu[g8 * 76 + kc + 4], a3 = mu[(g8 + 8) * 76 + kc + 4];
#pragma unroll
            for (int sbi = 0; sbi < 2; sbi++) {
                int nb = 2 * w + sbi;
                uint32_t b0 = bpu[kc * 136 + nb * 8 + g8];
                uint32_t b1_ = bpu[(kc + 4) * 136 + nb * 8 + g8];
                mma8(accp[sbi], a0, a1, a2, a3, b0, b1_);
            }
        }
#pragma unroll
        for (int sbi = 0; sbi < 2; sbi++) {
            int c = (2 * w + sbi) * 8 + 2 * q4;
            float* base = (c < 64) ? g_hd : g_hs;
            int cl = (c < 64) ? c : c - 64;
            *(float2*)(base + (size_t)(n0 + g8) * 64 + cl)     = make_float2(accp[sbi][0], accp[sbi][1]);
            *(float2*)(base + (size_t)(n0 + g8 + 8) * 64 + cl) = make_float2(accp[sbi][2], accp[sbi][3]);
        }
    }
}

// ---------------- edge kernel (R16 proven) ----------------
__global__ void __launch_bounds__(256, 2) k_edge(
    const float* __restrict__ W1c, const float* __restrict__ b1,
    const float* __restrict__ W2, const float* __restrict__ b2,
    const float* __restrict__ gam, const float* __restrict__ bet)
{
    extern __shared__ float es[];
    float* sW2s = es;
    float* sW1c = es + 4608;
    float* sb1 = es + 4928; float* sb2 = es + 4992;
    float* sg = es + 5056;  float* sbe = es + 5120;
    float* sPer = es + 5184;
    int tid = threadIdx.x;
    for (int i = tid; i < 4096; i += 256) {
        int k = i >> 6, c = i & 63;
        sW2s[k * 72 + c] = tf32f(W2[i]);
    }
    for (int i = tid; i < 320; i += 256) sW1c[i] = W1c[i];
    if (tid < 64) { sb1[tid] = b1[tid]; sb2[tid] = b2[tid]; sg[tid] = gam[tid]; sbe[tid] = bet[tid]; }
    __syncthreads();
    int w = tid >> 5, ld = tid & 31;
    int pe = ld >> 1, half = ld & 1;
    int eb = ld >> 3, cb = ld & 7;
    int g8 = ld >> 2, q4 = ld & 3;
    float* sM = sPer + w * 2496;
    int* sD = (int*)(sM + 2432);
    int* sSrc = (int*)(sM + 2464);
    const ulonglong2* W1cu = (const ulonglong2*)sW1c;
    const ulonglong2* b1u = (const ulonglong2*)sb1;
    u64 gv[4], bev[4];
#pragma unroll
    for (int j = 0; j < 4; j++) { gv[j] = ((const u64*)sg)[cb * 4 + j]; bev[j] = ((const u64*)sbe)[cb * 4 + j]; }
    float b2s[8];
#pragma unroll
    for (int j = 0; j < 8; j++) b2s[j] = sb2[cb * 8 + j];
    int gw = (blockIdx.x * 256 + tid) >> 5;
    int nw = (gridDim.x * 256) >> 5;
    const int NT = N_EDGES / 32;
    float4 mf0[2], mf1[2];
    {
        int e0 = gw * 32;
#pragma unroll
        for (int sub = 0; sub < 2; sub++) {
            const float4* emp = (const float4*)&g_em[(size_t)(e0 + sub * 16 + pe) * 8];
            mf0[sub] = __ldg(emp); mf1[sub] = __ldg(emp + 1);
        }
#pragma unroll
        for (int sub = 0; sub < 2; sub++) {
            int ns = __float_as_int(mf0[sub].x), nd = __float_as_int(mf0[sub].y);
            pfL1(g_hs + (size_t)ns * 64 + half * 32);
            pfL1(g_hd + (size_t)nd * 64 + half * 32);
        }
    }
    for (int grp = gw; grp < NT; grp += nw) {
        __syncwarp();
        int didx[2];
        u64 ead[2][5];
#pragma unroll
        for (int sub = 0; sub < 2; sub++) {
            int slot = sub * 16 + pe;
            float4 f0 = mf0[sub], f1 = mf1[sub];
            didx[sub] = __float_as_int(f0.y);
            ead[sub][0] = dup2(f0.z); ead[sub][1] = dup2(f0.w);
            ead[sub][2] = dup2(f1.x); ead[sub][3] = dup2(f1.y); ead[sub][4] = dup2(f1.z);
            if (half == 0) { sD[slot] = didx[sub]; sSrc[slot] = __float_as_int(f0.x); }
        }
        int ng = grp + nw;
        if (ng < NT) {
            int e0n = ng * 32;
#pragma unroll
            for (int sub = 0; sub < 2; sub++) {
                const float4* emp = (const float4*)&g_em[(size_t)(e0n + sub * 16 + pe) * 8];
                mf0[sub] = __ldg(emp); mf1[sub] = __ldg(emp + 1);
            }
        }
        __syncwarp();
#pragma unroll
        for (int r = 0; r < 16; r++) {
            int chunk = r * 32 + ld, eslot = chunk >> 4, c4 = (chunk & 15) * 4;
            *(float4*)&sM[eslot * 68 + c4] = *(const float4*)(g_hs + (size_t)sSrc[eslot] * 64 + c4);
        }
        __syncwarp();
        {
            const ulonglong2* hdp0 = (const ulonglong2*)(g_hd + (size_t)didx[0] * 64 + half * 32);
            const ulonglong2* hdp1 = (const ulonglong2*)(g_hd + (size_t)didx[1] * 64 + half * 32);
            float* mrow0 = sM + pe * 68 + half * 32;
            float* mrow1 = sM + (16 + pe) * 68 + half * 32;
#pragma unroll
            for (int j = 0; j < 8; j++) {
                ulonglong2 bj = b1u[half * 8 + j];
                ulonglong2 hd0 = __ldg(hdp0 + j), hd1 = __ldg(hdp1 + j);
                ulonglong2 hs0 = ((const ulonglong2*)mrow0)[j];
                ulonglong2 hs1 = ((const ulonglong2*)mrow1)[j];
                u64 A0 = add2(add2(hd0.x, hs0.x), bj.x);
                u64 A1 = add2(add2(hd0.y, hs0.y), bj.y);
                u64 B0 = add2(add2(hd1.x, hs1.x), bj.x);
                u64 B1 = add2(add2(hd1.y, hs1.y), bj.y);
#pragma unroll
                for (int r = 0; r < 5; r++) {
                    ulonglong2 wv = W1cu[r * 16 + half * 8 + j];
                    A0 = ffma2(ead[0][r], wv.x, A0); A1 = ffma2(ead[0][r], wv.y, A1);
                    B0 = ffma2(ead[1][r], wv.x, B0); B1 = ffma2(ead[1][r], wv.y, B1);
                }
                float va[4], vb[4];
                { float2 t0 = upk(A0), t1 = upk(A1); va[0] = t0.x; va[1] = t0.y; va[2] = t1.x; va[3] = t1.y; }
                { float2 t0 = upk(B0), t1 = upk(B1); vb[0] = t0.x; vb[1] = t0.y; vb[2] = t1.x; vb[3] = t1.y; }
                silu4(va); silu4(vb);
                uint4 ta; ta.x = tf32c(va[0]); ta.y = tf32c(va[1]); ta.z = tf32c(va[2]); ta.w = tf32c(va[3]);
                uint4 tb; tb.x = tf32c(vb[0]); tb.y = tf32c(vb[1]); tb.z = tf32c(vb[2]); tb.w = tf32c(vb[3]);
                *(uint4*)(mrow0 + 4 * j) = ta;
                *(uint4*)(mrow1 + 4 * j) = tb;
            }
        }
        __syncwarp();
        float acc[2][8][4];
#pragma unroll
        for (int mb = 0; mb < 2; mb++)
#pragma unroll
            for (int nb = 0; nb < 8; nb++)
#pragma unroll
                for (int j = 0; j < 4; j++) acc[mb][nb][j] = 0.f;
#pragma unroll
        for (int kb = 0; kb < 8; kb++) {
            int kc = kb * 8 + q4;
            const uint32_t* mu = (const uint32_t*)sM;
            uint32_t a00 = mu[(g8) * 68 + kc],      a01 = mu[(g8 + 8) * 68 + kc];
            uint32_t a02 = mu[(g8) * 68 + kc + 4],  a03 = mu[(g8 + 8) * 68 + kc + 4];
            uint32_t a10 = mu[(g8 + 16) * 68 + kc],     a11 = mu[(g8 + 24) * 68 + kc];
            uint32_t a12 = mu[(g8 + 16) * 68 + kc + 4], a13 = mu[(g8 + 24) * 68 + kc + 4];
            const uint32_t* wu = (const uint32_t*)sW2s;
#pragma unroll
            for (int nb = 0; nb < 8; nb++) {
                uint32_t b0 = wu[kc * 72 + nb * 8 + g8];
                uint32_t b1_ = wu[(kc + 4) * 72 + nb * 8 + g8];
                mma8(acc[0][nb], a00, a01, a02, a03, b0, b1_);
                mma8(acc[1][nb], a10, a11, a12, a13, b0, b1_);
            }
        }
        if (ng < NT) {
#pragma unroll
            for (int sub = 0; sub < 2; sub++) {
                int ns = __float_as_int(mf0[sub].x), nd = __float_as_int(mf0[sub].y);
                pfL1(g_hs + (size_t)ns * 64 + half * 32);
                pfL1(g_hd + (size_t)nd * 64 + half * 32);
            }
        }
        __syncwarp();
#pragma unroll
        for (int mb = 0; mb < 2; mb++)
#pragma unroll
            for (int nb = 0; nb < 8; nb++) {
                int elo = mb * 16 + g8;
                *(float2*)&sM[elo * 76 + nb * 8 + 2 * q4] = make_float2(acc[mb][nb][0], acc[mb][nb][1]);
                *(float2*)&sM[(elo + 8) * 76 + nb * 8 + 2 * q4] = make_float2(acc[mb][nb][2], acc[mb][nb][3]);
            }
        __syncwarp();
        float4 f0a[8], f1a[8];
        float s[8], q[8];
#pragma unroll
        for (int i = 0; i < 8; i++) {
            int e = eb * 8 + i;
            float4 v0 = *(const float4*)&sM[e * 76 + cb * 8];
            float4 v1 = *(const float4*)&sM[e * 76 + cb * 8 + 4];
            v0.x += b2s[0]; v0.y += b2s[1]; v0.z += b2s[2]; v0.w += b2s[3];
            v1.x += b2s[4]; v1.y += b2s[5]; v1.z += b2s[6]; v1.w += b2s[7];
            f0a[i] = v0; f1a[i] = v1;
            s[i] = v0.x + v0.y + v0.z + v0.w + v1.x + v1.y + v1.z + v1.w;
            q[i] = v0.x * v0.x + v0.y * v0.y + v0.z * v0.z + v0.w * v0.w
                 + v1.x * v1.x + v1.y * v1.y + v1.z * v1.z + v1.w * v1.w;
        }
#pragma unroll
        for (int o = 4; o; o >>= 1) {
#pragma unroll
            for (int i = 0; i < 8; i++) { s[i] += __shfl_xor_sync(~0u, s[i], o); q[i] += __shfl_xor_sync(~0u, q[i], o); }
        }
        int curD = sD[eb * 8];
        u64 av[4] = {0ull, 0ull, 0ull, 0ull};
#pragma unroll
        for (int i = 0; i < 8; i++) {
            int dI = sD[eb * 8 + i];
            float mn = s[i] * (1.f / 64.f);
            float rs = rsqrtf(q[i] * (1.f / 64.f) - mn * mn + EPS);
            u64 rsd = dup2(rs), mrd = dup2(-mn * rs);
            if (dI != curD) {
                float2 a0 = upk(av[0]), a1 = upk(av[1]), a2 = upk(av[2]), a3 = upk(av[3]);
                float* base = g_agg + (size_t)curD * 64 + cb * 8;
                red4(base, make_float4(a0.x, a0.y, a1.x, a1.y));
                red4(base + 4, make_float4(a2.x, a2.y, a3.x, a3.y));
                av[0] = av[1] = av[2] = av[3] = 0ull;
                curD = dI;
            }
            u64 vv0 = pk2(f0a[i].x, f0a[i].y), vv1 = pk2(f0a[i].z, f0a[i].w);
            u64 vv2 = pk2(f1a[i].x, f1a[i].y), vv3 = pk2(f1a[i].z, f1a[i].w);
            av[0] = add2(av[0], ffma2(ffma2(vv0, rsd, mrd), gv[0], bev[0]));
            av[1] = add2(av[1], ffma2(ffma2(vv1, rsd, mrd), gv[1], bev[1]));
            av[2] = add2(av[2], ffma2(ffma2(vv2, rsd, mrd), gv[2], bev[2]));
            av[3] = add2(av[3], ffma2(ffma2(vv3, rsd, mrd), gv[3], bev[3]));
        }
        {
            float2 a0 = upk(av[0]), a1 = upk(av[1]), a2 = upk(av[2]), a3 = upk(av[3]);
            float* base = g_agg + (size_t)curD * 64 + cb * 8;
            red4(base, make_float4(a0.x, a0.y, a1.x, a1.y));
            red4(base + 4, make_float4(a2.x, a2.y, a3.x, a3.y));
        }
    }
}

// ---------------- node update (FUSED with next-layer pre) ----------------
__global__ void __launch_bounds__(256) k_node_upd(
    const float* __restrict__ W1, const float* __restrict__ b1,
    const float* __restrict__ W2, const float* __restrict__ b2,
    const float* __restrict__ gam, const float* __restrict__ bet,
    const float* __restrict__ eW1n)
{
    extern __shared__ float us[];
    float* sW1t = us;
    float* sW2t = us + 9216;
    float* sA   = us + 13824;
    float* sH   = us + 16064;
    float* sMid = us + 17152;
    float* sPart= us + 18368;
    float* sb1  = us + 18624;
    float* sb2  = us + 18688;
    float* sgm  = us + 18752;
    float* sbe  = us + 18816;
    float* sWp  = us + 18880;
    int tid = threadIdx.x;
    bool hn = (eW1n != nullptr);
    for (int i = tid; i < 128 * 64; i += 256) { int k = i >> 6, c = i & 63; sW1t[k * 72 + c] = tf32f(W1[i]); }
    for (int i = tid; i < 64 * 64; i += 256)  { int k = i >> 6, c = i & 63; sW2t[k * 72 + c] = tf32f(W2[i]); }
    if (hn)
        for (int i = tid; i < 64 * 128; i += 256) {
            int k = i >> 7, c = i & 127;
            float v = (c < 64) ? eW1n[k * 64 + c] : eW1n[(64 + k) * 64 + (c - 64)];
            sWp[k * 136 + c] = tf32f(v);
        }
    if (tid < 64) { sb1[tid] = b1[tid]; sb2[tid] = b2[tid]; sgm[tid] = gam[tid]; sbe[tid] = bet[tid]; }
    __syncthreads();
    int w = tid >> 5, ld = tid & 31, g8 = ld >> 2, q4 = ld & 3;
    const uint32_t* au = (const uint32_t*)sA;
    const uint32_t* b1w = (const uint32_t*)sW1t;
    const uint32_t* b2w = (const uint32_t*)sW2t;
    const uint32_t* mu = (const uint32_t*)sMid;
    const uint32_t* bpu = (const uint32_t*)sWp;
    int c0 = w * 8 + 2 * q4;
    float b1c0 = sb1[c0], b1c1 = sb1[c0 + 1];
    float b2c0 = sb2[c0], b2c1 = sb2[c0 + 1];
    float gm0 = sgm[c0], gm1 = sgm[c0 + 1];
    float be0 = sbe[c0], be1 = sbe[c0 + 1];
    for (int t = blockIdx.x; t < N_NODES / 16; t += gridDim.x) {
        int n0 = t * 16;
        __syncthreads();
        {
            int n = tid >> 4, c8 = (tid & 15) * 8;
            float4 v0, v1;
            if (c8 < 64) {
                v0 = *(const float4*)(g_h + (size_t)(n0 + n) * 64 + c8);
                v1 = *(const float4*)(g_h + (size_t)(n0 + n) * 64 + c8 + 4);
                *(float4*)&sH[n * 68 + c8] = v0;
                *(float4*)&sH[n * 68 + c8 + 4] = v1;
            } else {
                v0 = *(const float4*)(g_agg + (size_t)(n0 + n) * 64 + c8 - 64);
                v1 = *(const float4*)(g_agg + (size_t)(n0 + n) * 64 + c8 - 60);
            }
            uint4 t0; t0.x = tf32c(v0.x); t0.y = tf32c(v0.y); t0.z = tf32c(v0.z); t0.w = tf32c(v0.w);
            uint4 t1; t1.x = tf32c(v1.x); t1.y = tf32c(v1.y); t1.z = tf32c(v1.z); t1.w = tf32c(v1.w);
            *(uint4*)&sA[n * 140 + c8] = t0;
            *(uint4*)&sA[n * 140 + c8 + 4] = t1;
        }
        __syncthreads();
        float a1c[4] = {0.f, 0.f, 0.f, 0.f};
#pragma unroll
        for (int kb = 0; kb < 16; kb++) {
            int kc = kb * 8 + q4;
            uint32_t a0 = au[g8 * 140 + kc], a1 = au[(g8 + 8) * 140 + kc];
            uint32_t a2 = au[g8 * 140 + kc + 4], a3 = au[(g8 + 8) * 140 + kc + 4];
            uint32_t b0 = b1w[kc * 72 + w * 8 + g8];
            uint32_t b1_ = b1w[(kc + 4) * 72 + w * 8 + g8];
            mma8(a1c, a0, a1, a2, a3, b0, b1_);
        }
        {
            float vv[4];
            vv[0] = a1c[0] + b1c0; vv[1] = a1c[1] + b1c1;
            vv[2] = a1c[2] + b1c0; vv[3] = a1c[3] + b1c1;
            silu4(vv);
            sMid[g8 * 76 + c0]           = tf32f(vv[0]);
            sMid[g8 * 76 + c0 + 1]       = tf32f(vv[1]);
            sMid[(g8 + 8) * 76 + c0]     = tf32f(vv[2]);
            sMid[(g8 + 8) * 76 + c0 + 1] = tf32f(vv[3]);
        }
        __syncthreads();
        float a2c[4] = {0.f, 0.f, 0.f, 0.f};
#pragma unroll
        for (int kb = 0; kb < 8; kb++) {
            int kc = kb * 8 + q4;
            uint32_t a0 = mu[g8 * 76 + kc], a1 = mu[(g8 + 8) * 76 + kc];
            uint32_t a2 = mu[g8 * 76 + kc + 4], a3 = mu[(g8 + 8) * 76 + kc + 4];
            uint32_t b0 = b2w[kc * 72 + w * 8 + g8];
            uint32_t b1_ = b2w[(kc + 4) * 72 + w * 8 + g8];
            mma8(a2c, a0, a1, a2, a3, b0, b1_);
        }
        float v0 = a2c[0] + b2c0, v1 = a2c[1] + b2c1;
        float v2 = a2c[2] + b2c0, v3 = a2c[3] + b2c1;
        float s0 = v0 + v1, q0 = v0 * v0 + v1 * v1;
        float s1 = v2 + v3, q1 = v2 * v2 + v3 * v3;
#pragma unroll
        for (int o = 1; o <= 2; o <<= 1) {
            s0 += __shfl_xor_sync(~0u, s0, o); q0 += __shfl_xor_sync(~0u, q0, o);
            s1 += __shfl_xor_sync(~0u, s1, o); q1 += __shfl_xor_sync(~0u, q1, o);
        }
        if (q4 == 0) {
            sPart[w * 32 + g8 * 2] = s0;       sPart[w * 32 + g8 * 2 + 1] = q0;
            sPart[w * 32 + (g8 + 8) * 2] = s1; sPart[w * 32 + (g8 + 8) * 2 + 1] = q1;
        }
        __syncthreads();
        float S0 = 0.f, Q0 = 0.f, S1 = 0.f, Q1 = 0.f;
#pragma unroll
        for (int ww = 0; ww < 8; ww++) {
            S0 += sPart[ww * 32 + g8 * 2];       Q0 += sPart[ww * 32 + g8 * 2 + 1];
            S1 += sPart[ww * 32 + (g8 + 8) * 2]; Q1 += sPart[ww * 32 + (g8 + 8) * 2 + 1];
        }
        float mn0 = S0 * (1.f / 64.f), rs0 = rsqrtf(Q0 * (1.f / 64.f) - mn0 * mn0 + EPS);
        float mn1 = S1 * (1.f / 64.f), rs1 = rsqrtf(Q1 * (1.f / 64.f) - mn1 * mn1 + EPS);
        float2 o0, o1;
        o0.x = sH[g8 * 68 + c0]     + (v0 - mn0) * rs0 * gm0 + be0;
        o0.y = sH[g8 * 68 + c0 + 1] + (v1 - mn0) * rs0 * gm1 + be1;
        o1.x = sH[(g8 + 8) * 68 + c0]     + (v2 - mn1) * rs1 * gm0 + be0;
        o1.y = sH[(g8 + 8) * 68 + c0 + 1] + (v3 - mn1) * rs1 * gm1 + be1;
        *(float2*)(g_h + (size_t)(n0 + g8) * 64 + c0)     = o0;
        *(float2*)(g_h + (size_t)(n0 + g8 + 8) * 64 + c0) = o1;
        if (hn) {
            sMid[g8 * 76 + c0]       = tf32f(o0.x);
            sMid[g8 * 76 + c0 + 1]   = tf32f(o0.y);
            sMid[(g8 + 8) * 76 + c0]     = tf32f(o1.x);
            sMid[(g8 + 8) * 76 + c0 + 1] = tf32f(o1.y);
            {
                int n = tid >> 4, c = (tid & 15) * 4;
                *(float4*)(g_agg + (size_t)(n0 + n) * 64 + c) = make_float4(0.f, 0.f, 0.f, 0.f);
            }
            __syncthreads();
            float accp[2][4];
#pragma unroll
            for (int sbi = 0; sbi < 2; sbi++)
#pragma unroll
                for (int j = 0; j < 4; j++) accp[sbi][j] = 0.f;
#pragma unroll
            for (int kb = 0; kb < 8; kb++) {
                int kc = kb * 8 + q4;
                uint32_t a0 = mu[g8 * 76 + kc], a1 = mu[(g8 + 8) * 76 + kc];
                uint32_t a2 = mu[g8 * 76 + kc + 4], a3 = mu[(g8 + 8) * 76 + kc + 4];
#pragma unroll
                for (int sbi = 0; sbi < 2; sbi++) {
                    int nb = 2 * w + sbi;
                    uint32_t b0 = bpu[kc * 136 + nb * 8 + g8];
                    uint32_t b1_ = bpu[(kc + 4) * 136 + nb * 8 + g8];
                    mma8(accp[sbi], a0, a1, a2, a3, b0, b1_);
                }
            }
#pragma unroll
            for (int sbi = 0; sbi < 2; sbi++) {
                int c = (2 * w + sbi) * 8 + 2 * q4;
                float* base = (c < 64) ? g_hd : g_hs;
                int cl = (c < 64) ? c : c - 64;
                *(float2*)(base + (size_t)(n0 + g8) * 64 + cl)     = make_float2(accp[sbi][0], accp[sbi][1]);
                *(float2*)(base + (size_t)(n0 + g8 + 8) * 64 + cl) = make_float2(accp[sbi][2], accp[sbi][3]);
            }
        }
    }
}

__global__ void k_zero_pool() { int t = threadIdx.x; if (t < NG * 64) g_pool[t] = 0.f; }

// ---------------- local decoder + pooling ----------------
__global__ void __launch_bounds__(256) k_decoder_local(
    const float* __restrict__ W1, const float* __restrict__ b1,
    const float* __restrict__ W2, const float* __restrict__ b2,
    const int* __restrict__ batch, float* __restrict__ out)
{
    __shared__ float sW1[4096], sW2[384], sb1[64], sb2_[8];
    __shared__ float sH[8][64], sU[8][64];
    int tid = threadIdx.x;
    for (int i = tid; i < 4096; i += 256) sW1[i] = W1[i];
    for (int i = tid; i < 384; i += 256) sW2[i] = W2[i];
    if (tid < 64) sb1[tid] = b1[tid];
    if (tid < 6) sb2_[tid] = b2[tid];
    __syncthreads();
    int w = tid >> 5, ld = tid & 31, c0 = 2 * ld;
    int n = blockIdx.x * 8 + w;
    if (n >= N_NODES) return;
    float2 hv = *(const float2*)(g_h + (size_t)n * 64 + c0);
    sH[w][c0] = hv.x; sH[w][c0 + 1] = hv.y;
    __syncwarp();
    const u64* W1u = (const u64*)sW1;
    u64 acc = ((const u64*)sb1)[ld];
#pragma unroll 8
    for (int k = 0; k < 64; k++) acc = ffma2(dup2(sH[w][k]), W1u[k * 32 + ld], acc);
    float2 u = upk(acc); u.x = silu(u.x); u.y = silu(u.y);
    sU[w][c0] = u.x; sU[w][c0 + 1] = u.y;
    __syncwarp();
    if (ld < 6) {
        float o = sb2_[ld];
#pragma unroll
        for (int k = 0; k < 64; k++) o += sU[w][k] * sW2[k * 6 + ld];
        out[(size_t)n * 6 + ld] = o;
    }
    int g = __ldg(&batch[n]);
    red2(g_pool + g * 64 + c0, hv.x, hv.y);
}

// ---------------- global decoder ----------------
__global__ void k_global(const int* __restrict__ batch,
    const float* __restrict__ W1, const float* __restrict__ b1,
    const float* __restrict__ W2, const float* __restrict__ b2,
    float* __restrict__ out)
{
    __shared__ float sp[NG * 64], su[NG * 32];
    __shared__ int bnd[NG + 1];
    int t = threadIdx.x;
    if (t <= NG) {
        int lo = 0, hi = N_NODES;
        while (lo < hi) { int mid = (lo + hi) >> 1; if (batch[mid] < t) lo = mid + 1; else hi = mid; }
        bnd[t] = lo;
    }
    __syncthreads();
    for (int i = t; i < NG * 64; i += 128) {
        int g = i >> 6;
        sp[i] = g_pool[i] / fmaxf((float)(bnd[g + 1] - bnd[g]), 1.f);
    }
    __syncthreads();
    {
        int g = t >> 5, j = t & 31;
        float a = b1[j];
#pragma unroll
        for (int k = 0; k < 64; k++) a += sp[g * 64 + k] * W1[k * 32 + j];
        su[g * 32 + j] = silu(a);
    }
    __syncthreads();
    if (t < NG * 4) {
        int g = t >> 2, j = t & 3;
        float o = b2[j];
#pragma unroll
        for (int k = 0; k < 32; k++) o += su[g * 32 + k] * W2[k * 4 + j];
        out[(size_t)N_NODES * 6 + g * 4 + j] = o;
    }
}

extern "C" void kernel_launch(void* const* d_in, const int* in_sizes, int n_in,
                              void* d_out, int out_size) {
    (void)in_sizes; (void)n_in; (void)out_size;
    const float* x     = (const float*)d_in[0];
    const int*   ei    = (const int*)d_in[1];
    const float* eattr = (const float*)d_in[2];
    const int*   batch = (const int*)d_in[3];
    const float* casep = (const float*)d_in[4];
    const float* bcp   = (const float*)d_in[5];
    const float* encW1 = (const float*)d_in[6];  const float* encb1 = (const float*)d_in[7];
    const float* encW2 = (const float*)d_in[8];  const float* encb2 = (const float*)d_in[9];
    const float* encg  = (const float*)d_in[10]; const float* encbe = (const float*)d_in[11];
    const float* eW1   = (const float*)d_in[12]; const float* eb1   = (const float*)d_in[13];
    const float* eW2   = (const float*)d_in[14]; const float* eb2   = (const float*)d_in[15];
    const float* eg    = (const float*)d_in[16]; const float* ebe   = (const float*)d_in[17];
    const float* nW1   = (const float*)d_in[18]; const float* nb1   = (const float*)d_in[19];
    const float* nW2   = (const float*)d_in[20]; const float* nb2   = (const float*)d_in[21];
    const float* ngm   = (const float*)d_in[22]; const float* nbe   = (const float*)d_in[23];
    const float* dlW1  = (const float*)d_in[24]; const float* dlb1  = (const float*)d_in[25];
    const float* dlW2  = (const float*)d_in[26]; const float* dlb2  = (const float*)d_in[27];
    const float* dgW1  = (const float*)d_in[28]; const float* dgb1  = (const float*)d_in[29];
    const float* dgW2  = (const float*)d_in[30]; const float* dgb2  = (const float*)d_in[31];
    float* out = (float*)d_out;

    size_t encSmem  = (size_t)16512 * sizeof(float);   // 66048 B
    size_t edgeSmem = (size_t)(5184 + 8 * 2496) * sizeof(float);
    size_t updSmem  = (size_t)27584 * sizeof(float);
    cudaFuncSetAttribute(k_enc_pre, cudaFuncAttributeMaxDynamicSharedMemorySize, (int)encSmem);
    cudaFuncSetAttribute(k_edge, cudaFuncAttributeMaxDynamicSharedMemorySize, (int)edgeSmem);
    cudaFuncSetAttribute(k_node_upd, cudaFuncAttributeMaxDynamicSharedMemorySize, (int)updSmem);

    void* wp_ptr = nullptr;
    cudaGetSymbolAddress(&wp_ptr, g_wp);
    cudaMemsetAsync(wp_ptr, 0, N_NODES * sizeof(int));
    k_hist<<<(N_EDGES + 255) / 256, 256>>>(ei);
    k_scan<<<1, 1024>>>();
    k_scatter<<<(N_EDGES + 255) / 256, 256>>>(ei, eattr);

    k_enc_pre<<<296, 256, encSmem>>>(x, batch, casep, bcp, encW1, encb1, encW2, encb2, encg, encbe, eW1);
    for (int l = 0; l < NL; l++) {
        const float* eW1l = eW1 + (size_t)l * 133 * 64;
        const float* eW1n = (l + 1 < NL) ? (eW1 + (size_t)(l + 1) * 133 * 64) : nullptr;
        k_edge<<<296, 256, edgeSmem>>>(eW1l + 128 * 64, eb1 + l * 64,
                              eW2 + (size_t)l * 4096, eb2 + l * 64,
                              eg + l * 64, ebe + l * 64);
        k_node_upd<<<296, 256, updSmem>>>(nW1 + (size_t)l * 8192, nb1 + l * 64,
                                          nW2 + (size_t)l * 4096, nb2 + l * 64,
                                          ngm + l * 64, nbe + l * 64, eW1n);
    }
    k_zero_pool<<<1, 256>>>();
    k_decoder_local<<<(N_NODES + 7) / 8, 256>>>(dlW1, dlb1, dlW2, dlb2, batch, out);
    k_global<<<1, 128>>>(batch, dgW1, dgb1, dgW2, dgb2, out);
}